// round 1
// baseline (speedup 1.0000x reference)
#include <cuda_runtime.h>
#include <math.h>

// ---------------------------------------------------------------------------
// Problem constants
// ---------------------------------------------------------------------------
constexpr int Hn = 8;
constexpr int Bn = 16;
constexpr int Nn = 1024;
constexpr int Dn = 512;
constexpr int Mn = Bn * Nn;                              // 16384 rows (b,n)
constexpr size_t PROJ_ELEMS = (size_t)Hn * Mn * Dn;      // 67,108,864
constexpr size_t P_ELEMS    = (size_t)Hn * Bn * Nn * Nn; // 134,217,728

// Scratch (static device globals: allocation-free per harness rules)
__device__ float g_qp[PROJ_ELEMS];
__device__ float g_kp[PROJ_ELEMS];
__device__ float g_vp[PROJ_ELEMS];
__device__ float g_P [P_ELEMS];
__device__ float g_O [PROJ_ELEMS];
__device__ float g_outs[PROJ_ELEMS];

// ---------------------------------------------------------------------------
// Packed f32x2 helpers (Blackwell FFMA2 path — 2x scalar FFMA throughput)
// ---------------------------------------------------------------------------
typedef unsigned long long u64;

__device__ __forceinline__ u64 pk2(float x) {
    u64 r;
    asm("mov.b64 %0, {%1, %1};" : "=l"(r) : "f"(x));
    return r;
}
__device__ __forceinline__ void fma2(u64& d, u64 a, u64 b) {
    asm("fma.rn.f32x2 %0, %1, %2, %0;" : "+l"(d) : "l"(a), "l"(b));
}
__device__ __forceinline__ float2 up2(u64 v) {
    float2 r;
    asm("mov.b64 {%0, %1}, %2;" : "=f"(r.x), "=f"(r.y) : "l"(v));
    return r;
}

// ---------------------------------------------------------------------------
// Generic batched fp32 GEMM:
//   C[z] = alpha * A[z] @ op(B[z]) + bias[z]
//   A: [M,K] row-major (row stride K)
//   BT=true : B is [N,K] row-major (K contiguous)  -> C = A @ B^T
//   BT=false: B is [K,N] row-major (N contiguous)  -> C = A @ B
//   C: [M,N] row-major
// Tiles: 128x128x16, 256 threads, 8x8 per thread (split 4+4 fragments).
// Requires M%128==0, N%128==0, K%16==0 (true for all stages here).
// ---------------------------------------------------------------------------
constexpr int BM = 128, BN = 128, BK = 16;

template <bool BT, bool BIAS>
__global__ void __launch_bounds__(256, 2) gemm_f32(
    const float* __restrict__ Ag, const float* __restrict__ Bg,
    const float* __restrict__ biasg, float* __restrict__ Cg,
    int M, int N, int K,
    size_t sA, size_t sB, size_t sBias, size_t sC,
    float alpha)
{
    __shared__ __align__(16) float As[BK][BM];
    __shared__ __align__(16) float Bs[BK][BN];

    const float* A = Ag + (size_t)blockIdx.z * sA;
    const float* B = Bg + (size_t)blockIdx.z * sB;

    const int tid  = threadIdx.x;
    const int tx   = tid & 15;   // column group 0..15
    const int ty   = tid >> 4;   // row group    0..15
    const int row0 = blockIdx.y * BM;
    const int col0 = blockIdx.x * BN;

    u64 acc[8][4] = {};  // 8 rows x 4 packed col-pairs (= 8 cols)

    for (int k0 = 0; k0 < K; k0 += BK) {
        // ---- load A tile (BM x BK), transpose into As[k][m] ----
        #pragma unroll
        for (int i = 0; i < 2; i++) {
            int idx = tid + i * 256;          // 0..511 float4 slots
            int r = idx >> 2;                 // row within tile 0..127
            int c = (idx & 3) << 2;           // k offset 0,4,8,12
            float4 t = *reinterpret_cast<const float4*>(
                A + (size_t)(row0 + r) * K + k0 + c);
            As[c + 0][r] = t.x;
            As[c + 1][r] = t.y;
            As[c + 2][r] = t.z;
            As[c + 3][r] = t.w;
        }
        // ---- load B tile into Bs[k][n] ----
        if (BT) {
            #pragma unroll
            for (int i = 0; i < 2; i++) {
                int idx = tid + i * 256;
                int r = idx >> 2;             // n within tile 0..127
                int c = (idx & 3) << 2;       // k offset
                float4 t = *reinterpret_cast<const float4*>(
                    B + (size_t)(col0 + r) * K + k0 + c);
                Bs[c + 0][r] = t.x;
                Bs[c + 1][r] = t.y;
                Bs[c + 2][r] = t.z;
                Bs[c + 3][r] = t.w;
            }
        } else {
            #pragma unroll
            for (int i = 0; i < 2; i++) {
                int idx = tid + i * 256;
                int kr = idx >> 5;            // k row 0..15
                int c  = (idx & 31) << 2;     // n offset 0..124
                *reinterpret_cast<float4*>(&Bs[kr][c]) =
                    *reinterpret_cast<const float4*>(
                        B + (size_t)(k0 + kr) * N + col0 + c);
            }
        }
        __syncthreads();

        // ---- compute ----
        #pragma unroll
        for (int kk = 0; kk < BK; kk++) {
            float4 a0 = *reinterpret_cast<const float4*>(&As[kk][ty * 4]);
            float4 a1 = *reinterpret_cast<const float4*>(&As[kk][64 + ty * 4]);
            ulonglong2 q0 = *reinterpret_cast<const ulonglong2*>(&Bs[kk][tx * 4]);
            ulonglong2 q1 = *reinterpret_cast<const ulonglong2*>(&Bs[kk][64 + tx * 4]);
            u64 bb[4] = {q0.x, q0.y, q1.x, q1.y};
            float ra[8] = {a0.x, a0.y, a0.z, a0.w, a1.x, a1.y, a1.z, a1.w};
            #pragma unroll
            for (int i = 0; i < 8; i++) {
                u64 ai = pk2(ra[i]);
                #pragma unroll
                for (int j = 0; j < 4; j++) fma2(acc[i][j], ai, bb[j]);
            }
        }
        __syncthreads();
    }

    // ---- epilogue ----
    float bvv[8] = {0.f, 0.f, 0.f, 0.f, 0.f, 0.f, 0.f, 0.f};
    if (BIAS) {
        const float* bias = biasg + (size_t)blockIdx.z * sBias;
        float4 b0 = *reinterpret_cast<const float4*>(bias + col0 + tx * 4);
        float4 b1 = *reinterpret_cast<const float4*>(bias + col0 + 64 + tx * 4);
        bvv[0] = b0.x; bvv[1] = b0.y; bvv[2] = b0.z; bvv[3] = b0.w;
        bvv[4] = b1.x; bvv[5] = b1.y; bvv[6] = b1.z; bvv[7] = b1.w;
    }
    float* C = Cg + (size_t)blockIdx.z * sC;
    #pragma unroll
    for (int i = 0; i < 8; i++) {
        int r = row0 + ((i < 4) ? (ty * 4 + i) : (64 + ty * 4 + (i - 4)));
        float2 c0 = up2(acc[i][0]);
        float2 c1 = up2(acc[i][1]);
        float2 c2 = up2(acc[i][2]);
        float2 c3 = up2(acc[i][3]);
        float4 o0 = make_float4(alpha * c0.x + bvv[0], alpha * c0.y + bvv[1],
                                alpha * c1.x + bvv[2], alpha * c1.y + bvv[3]);
        float4 o1 = make_float4(alpha * c2.x + bvv[4], alpha * c2.y + bvv[5],
                                alpha * c3.x + bvv[6], alpha * c3.y + bvv[7]);
        *reinterpret_cast<float4*>(C + (size_t)r * N + col0 + tx * 4) = o0;
        *reinterpret_cast<float4*>(C + (size_t)r * N + col0 + 64 + tx * 4) = o1;
    }
}

// ---------------------------------------------------------------------------
// Row softmax over 1024-wide rows, in place. One 256-thread CTA per row.
// ---------------------------------------------------------------------------
__global__ void softmax1024(float* __restrict__ P) {
    __shared__ float red[8];
    const size_t row = blockIdx.x;
    float* p = P + row * 1024;
    const int tid = threadIdx.x;

    float4 x = *reinterpret_cast<const float4*>(p + tid * 4);
    float m = fmaxf(fmaxf(x.x, x.y), fmaxf(x.z, x.w));
    #pragma unroll
    for (int o = 16; o > 0; o >>= 1)
        m = fmaxf(m, __shfl_xor_sync(0xffffffffu, m, o));
    if ((tid & 31) == 0) red[tid >> 5] = m;
    __syncthreads();
    float bm = red[0];
    #pragma unroll
    for (int i = 1; i < 8; i++) bm = fmaxf(bm, red[i]);
    __syncthreads();

    float4 e;
    e.x = __expf(x.x - bm);
    e.y = __expf(x.y - bm);
    e.z = __expf(x.z - bm);
    e.w = __expf(x.w - bm);
    float s = e.x + e.y + e.z + e.w;
    #pragma unroll
    for (int o = 16; o > 0; o >>= 1)
        s += __shfl_xor_sync(0xffffffffu, s, o);
    if ((tid & 31) == 0) red[tid >> 5] = s;
    __syncthreads();
    float bs = 0.f;
    #pragma unroll
    for (int i = 0; i < 8; i++) bs += red[i];

    float inv = 1.0f / bs;
    e.x *= inv; e.y *= inv; e.z *= inv; e.w *= inv;
    *reinterpret_cast<float4*>(p + tid * 4) = e;
}

// ---------------------------------------------------------------------------
// Head interleave: outs[m, d*H + h] = O[h, m, d]
// (torch stack(dim=-1).view -> (d,h) interleaved feature dim)
// ---------------------------------------------------------------------------
__global__ void interleave_kernel(const float* __restrict__ O,
                                  float* __restrict__ outs) {
    size_t idx = (size_t)blockIdx.x * blockDim.x + threadIdx.x;
    int    f = (int)(idx & 4095);     // H*D - 1
    size_t m = idx >> 12;
    int    h = f & 7;
    int    d = f >> 3;
    outs[idx] = O[((size_t)h * Mn + m) * Dn + d];
}

// ---------------------------------------------------------------------------
// kernel_launch
// Inputs (metadata order): k, v, q, Wk, bk, Wv, bv, Wq, bq, Wo, bo
// ---------------------------------------------------------------------------
extern "C" void kernel_launch(void* const* d_in, const int* in_sizes, int n_in,
                              void* d_out, int out_size) {
    (void)in_sizes; (void)n_in; (void)out_size;
    const float* k  = (const float*)d_in[0];
    const float* v  = (const float*)d_in[1];
    const float* q  = (const float*)d_in[2];
    const float* Wk = (const float*)d_in[3];
    const float* bk = (const float*)d_in[4];
    const float* Wv = (const float*)d_in[5];
    const float* bv = (const float*)d_in[6];
    const float* Wq = (const float*)d_in[7];
    const float* bq = (const float*)d_in[8];
    const float* Wo = (const float*)d_in[9];
    const float* bo = (const float*)d_in[10];
    float* out = (float*)d_out;

    float *qp, *kp, *vp, *P, *O, *outs;
    cudaGetSymbolAddress((void**)&qp,   g_qp);
    cudaGetSymbolAddress((void**)&kp,   g_kp);
    cudaGetSymbolAddress((void**)&vp,   g_vp);
    cudaGetSymbolAddress((void**)&P,    g_P);
    cudaGetSymbolAddress((void**)&O,    g_O);
    cudaGetSymbolAddress((void**)&outs, g_outs);

    dim3 blk(256);

    // 1) Projections: Y[h,m,e] = X[m,:] @ W[h]^T + b[h]   (z = head)
    dim3 gproj(Dn / BN, Mn / BM, Hn);
    gemm_f32<true, true><<<gproj, blk>>>(q, Wq, bq, qp, Mn, Dn, Dn,
        0, (size_t)Dn * Dn, (size_t)Dn, (size_t)Mn * Dn, 1.0f);
    gemm_f32<true, true><<<gproj, blk>>>(k, Wk, bk, kp, Mn, Dn, Dn,
        0, (size_t)Dn * Dn, (size_t)Dn, (size_t)Mn * Dn, 1.0f);
    gemm_f32<true, true><<<gproj, blk>>>(v, Wv, bv, vp, Mn, Dn, Dn,
        0, (size_t)Dn * Dn, (size_t)Dn, (size_t)Mn * Dn, 1.0f);

    // 2) Scores: S = (Q @ K^T) / sqrt(D)   (z = h*B + b)
    const float inv_scale = 1.0f / sqrtf((float)Dn);
    dim3 gsc(Nn / BN, Nn / BM, Hn * Bn);
    gemm_f32<true, false><<<gsc, blk>>>(qp, kp, nullptr, P, Nn, Nn, Dn,
        (size_t)Nn * Dn, (size_t)Nn * Dn, 0, (size_t)Nn * Nn, inv_scale);

    // 3) Softmax rows (in place)
    softmax1024<<<Hn * Bn * Nn, 256>>>(P);

    // 4) O = P @ V   (NN gemm, z = h*B + b)
    dim3 gpv(Dn / BN, Nn / BM, Hn * Bn);
    gemm_f32<false, false><<<gpv, blk>>>(P, vp, nullptr, O, Nn, Dn, Nn,
        (size_t)Nn * Nn, (size_t)Nn * Dn, 0, (size_t)Nn * Dn, 1.0f);

    // 5) Interleave heads: outs[m, d*H+h] = O[h, m, d]
    interleave_kernel<<<(unsigned)(PROJ_ELEMS / 256), 256>>>(O, outs);

    // 6) Output projection: rep = outs @ Wo^T + bo
    dim3 gfin(Dn / BN, Mn / BM, 1);
    gemm_f32<true, true><<<gfin, blk>>>(outs, Wo, bo, out, Mn, Dn, Hn * Dn,
        0, 0, 0, 0, 1.0f);
}

// round 3
// speedup vs baseline: 1.8849x; 1.8849x over previous
#include <cuda_runtime.h>
#include <cuda_bf16.h>
#include <math.h>
#include <stdint.h>

// ---------------------------------------------------------------------------
// Problem constants
// ---------------------------------------------------------------------------
constexpr int Hn = 8, Bn = 16, Nn = 1024, Dn = 512;
constexpr int Mn = Bn * Nn;                               // 16384
constexpr size_t XEL  = (size_t)Mn * Dn;                  // 8,388,608
constexpr size_t WEL  = (size_t)Hn * Dn * Dn;             // 2,097,152
constexpr size_t PROJ = (size_t)Hn * Mn * Dn;             // 67,108,864
constexpr size_t PEL  = (size_t)Hn * Bn * Nn * Nn;        // 134,217,728

// ---------------------------------------------------------------------------
// Scratch (__device__ globals — allocation-free)
// ---------------------------------------------------------------------------
__device__ __nv_bfloat16 g_xq_hi[XEL], g_xq_lo[XEL];
__device__ __nv_bfloat16 g_xk_hi[XEL], g_xk_lo[XEL];
__device__ __nv_bfloat16 g_xv_hi[XEL], g_xv_lo[XEL];
__device__ __nv_bfloat16 g_wq_hi[WEL], g_wq_lo[WEL];
__device__ __nv_bfloat16 g_wk_hi[WEL], g_wk_lo[WEL];
__device__ __nv_bfloat16 g_wv_hi[WEL], g_wv_lo[WEL];
__device__ __nv_bfloat16 g_wo_hi[WEL], g_wo_lo[WEL];
__device__ __nv_bfloat16 g_qp_hi[PROJ], g_qp_lo[PROJ];
__device__ __nv_bfloat16 g_kp_hi[PROJ], g_kp_lo[PROJ];
__device__ float         g_vpf[PROJ];
__device__ __nv_bfloat16 g_vt_hi[PROJ], g_vt_lo[PROJ];
__device__ float         g_P[PEL];
__device__ __nv_bfloat16 g_phi[PEL], g_plo[PEL];
__device__ float         g_Of[PROJ];
__device__ __nv_bfloat16 g_out_hi[PROJ], g_out_lo[PROJ];

// ---------------------------------------------------------------------------
// Helpers
// ---------------------------------------------------------------------------
__device__ __forceinline__ uint32_t s2u(const void* p) {
    uint32_t a;
    asm("{ .reg .u64 t; cvta.to.shared.u64 t, %1; cvt.u32.u64 %0, t; }"
        : "=r"(a) : "l"(p));
    return a;
}

__device__ __forceinline__ void cp16(uint32_t saddr, const void* gaddr) {
    asm volatile("cp.async.cg.shared.global [%0], [%1], 16;"
                 :: "r"(saddr), "l"(gaddr) : "memory");
}
__device__ __forceinline__ void cp_commit() {
    asm volatile("cp.async.commit_group;" ::: "memory");
}
template <int N>
__device__ __forceinline__ void cp_wait() {
    asm volatile("cp.async.wait_group %0;" :: "n"(N) : "memory");
}

__device__ __forceinline__ void ldsm4(uint32_t* r, uint32_t addr) {
    asm volatile("ldmatrix.sync.aligned.m8n8.x4.shared.b16 {%0,%1,%2,%3}, [%4];"
        : "=r"(r[0]), "=r"(r[1]), "=r"(r[2]), "=r"(r[3]) : "r"(addr));
}

__device__ __forceinline__ void mma16816(float* d, const uint32_t* a,
                                         uint32_t b0, uint32_t b1) {
    asm volatile(
        "mma.sync.aligned.m16n8k16.row.col.f32.bf16.bf16.f32 "
        "{%0,%1,%2,%3}, {%4,%5,%6,%7}, {%8,%9}, {%0,%1,%2,%3};"
        : "+f"(d[0]), "+f"(d[1]), "+f"(d[2]), "+f"(d[3])
        : "r"(a[0]), "r"(a[1]), "r"(a[2]), "r"(a[3]), "r"(b0), "r"(b1));
}

__device__ __forceinline__ void split2(float x, uint16_t& h, uint16_t& l) {
    __nv_bfloat16 hb = __float2bfloat16(x);
    __nv_bfloat16 lb = __float2bfloat16(x - __bfloat162float(hb));
    h = *reinterpret_cast<uint16_t*>(&hb);
    l = *reinterpret_cast<uint16_t*>(&lb);
}

// ---------------------------------------------------------------------------
// bf16-split batched GEMM via mma.sync (HMMA):
//   C[z] = alpha * (Ahi+Alo)[z] @ (Bhi+Blo)[z]^T (+ bias[z])
//   A: [M,K] K-major bf16, B: [N,K] K-major bf16
//   3 products: hi*hi + hi*lo + lo*hi (fp32 accum)
// Tile 128x128, BK=32, 8 warps (64x32 each), 2-stage cp.async pipeline.
// SMEM rows padded to 80B -> conflict-free ldmatrix.
// ---------------------------------------------------------------------------
constexpr int ROWB   = 80;                       // bytes per SMEM row (32*2 + 16 pad)
constexpr int TILE_B = 128 * ROWB;               // 10240 B per tile
constexpr int STAGE  = 4 * TILE_B;               // Ahi,Alo,Bhi,Blo
constexpr int GSMEM  = 2 * STAGE + 512;          // + bias

template <bool BIAS, int OUTM>
__global__ void __launch_bounds__(256) hmma_gemm(
    const __nv_bfloat16* __restrict__ Ahi, const __nv_bfloat16* __restrict__ Alo,
    const __nv_bfloat16* __restrict__ Bhi, const __nv_bfloat16* __restrict__ Blo,
    const float* __restrict__ biasg,
    float* __restrict__ Cf,
    __nv_bfloat16* __restrict__ Chi, __nv_bfloat16* __restrict__ Clo,
    int M, int N, int K,
    size_t sA, size_t sB, size_t sBias, size_t sC, float alpha)
{
    extern __shared__ __align__(16) char smem[];
    const uint32_t sb = s2u(smem);
    float* sbias = reinterpret_cast<float*>(smem + 2 * STAGE);

    const int tid  = threadIdx.x;
    const int wid  = tid >> 5, lane = tid & 31;
    const int wr   = wid >> 2, wc = wid & 3;      // warp grid 2x4
    const int col0 = blockIdx.x * 128, row0 = blockIdx.y * 128;
    const size_t z = blockIdx.z;
    Ahi += z * sA; Alo += z * sA; Bhi += z * sB; Blo += z * sB;

    if (BIAS && tid < 128) sbias[tid] = biasg[z * sBias + col0 + tid];

    const __nv_bfloat16* srcs[4] = {Ahi, Alo, Bhi, Blo};
    const int rb[4] = {row0, row0, col0, col0};

    const int nCh = K >> 5;          // BK = 32

    // prefetch helper (inlined twice)
    auto prefetch = [&](int c, int buf) {
        const int k0 = c << 5;
        const uint32_t boff = sb + buf * STAGE;
        #pragma unroll
        for (int t = 0; t < 4; t++) {
            const __nv_bfloat16* s = srcs[t];
            const uint32_t tb = boff + t * TILE_B;
            #pragma unroll
            for (int i = 0; i < 2; i++) {
                int idx = i * 256 + tid;          // 0..511
                int r = idx >> 2, ch = idx & 3;
                cp16(tb + r * ROWB + ch * 16,
                     s + (size_t)(rb[t] + r) * K + k0 + ch * 8);
            }
        }
        cp_commit();
    };

    float acc[4][4][4] = {};

    prefetch(0, 0);

    for (int c = 0; c < nCh; ++c) {
        if (c + 1 < nCh) { prefetch(c + 1, (c + 1) & 1); cp_wait<1>(); }
        else             { cp_wait<0>(); }
        __syncthreads();

        const uint32_t boff = sb + (c & 1) * STAGE;
        const uint32_t aHiB = boff,              aLoB = boff + TILE_B;
        const uint32_t bHiB = boff + 2 * TILE_B, bLoB = boff + 3 * TILE_B;
        const int lrow = lane & 15, lhalf = lane >> 4;

        #pragma unroll
        for (int ks = 0; ks < 2; ks++) {
            const uint32_t kcol = (ks * 16 + lhalf * 8) * 2;
            // B fragments: 4 n8-tiles per operand, via 2 ldmatrix.x4 each
            uint32_t bh[4][2], bl[4][2];
            #pragma unroll
            for (int np = 0; np < 2; np++) {
                uint32_t r = (uint32_t)(wc * 32 + np * 16 + lrow);
                uint32_t t[4];
                ldsm4(t, bHiB + r * ROWB + kcol);
                bh[np*2+0][0] = t[0]; bh[np*2+0][1] = t[2];
                bh[np*2+1][0] = t[1]; bh[np*2+1][1] = t[3];
                ldsm4(t, bLoB + r * ROWB + kcol);
                bl[np*2+0][0] = t[0]; bl[np*2+0][1] = t[2];
                bl[np*2+1][0] = t[1]; bl[np*2+1][1] = t[3];
            }
            #pragma unroll
            for (int mt = 0; mt < 4; mt++) {
                uint32_t r = (uint32_t)(wr * 64 + mt * 16 + lrow);
                uint32_t ah[4], al[4];
                ldsm4(ah, aHiB + r * ROWB + kcol);
                ldsm4(al, aLoB + r * ROWB + kcol);
                #pragma unroll
                for (int nt = 0; nt < 4; nt++) {
                    mma16816(acc[mt][nt], ah, bh[nt][0], bh[nt][1]);
                    mma16816(acc[mt][nt], ah, bl[nt][0], bl[nt][1]);
                    mma16816(acc[mt][nt], al, bh[nt][0], bh[nt][1]);
                }
            }
        }
        __syncthreads();
    }

    // ---- epilogue ----
    const int qr = lane >> 2, qc = lane & 3;
    #pragma unroll
    for (int mt = 0; mt < 4; mt++) {
        #pragma unroll
        for (int nt = 0; nt < 4; nt++) {
            const int lcol = wc * 32 + nt * 8 + qc * 2;
            const float b0 = BIAS ? sbias[lcol]     : 0.f;
            const float b1 = BIAS ? sbias[lcol + 1] : 0.f;
            const int r0 = row0 + wr * 64 + mt * 16 + qr;
            const float v00 = alpha * acc[mt][nt][0] + b0;
            const float v01 = alpha * acc[mt][nt][1] + b1;
            const float v10 = alpha * acc[mt][nt][2] + b0;
            const float v11 = alpha * acc[mt][nt][3] + b1;
            if (OUTM == 0) {
                float* cp = Cf + z * sC + (size_t)r0 * N + col0 + lcol;
                *reinterpret_cast<float2*>(cp)         = make_float2(v00, v01);
                *reinterpret_cast<float2*>(cp + 8ull * N) = make_float2(v10, v11);
            } else {
                uint16_t h0,l0,h1,l1,h2,l2,h3,l3;
                split2(v00, h0, l0); split2(v01, h1, l1);
                split2(v10, h2, l2); split2(v11, h3, l3);
                size_t o0 = z * sC + (size_t)r0 * N + col0 + lcol;
                size_t o1 = o0 + 8ull * N;
                *reinterpret_cast<uint32_t*>(
                    reinterpret_cast<uint16_t*>(Chi) + o0) = (uint32_t)h0 | ((uint32_t)h1 << 16);
                *reinterpret_cast<uint32_t*>(
                    reinterpret_cast<uint16_t*>(Clo) + o0) = (uint32_t)l0 | ((uint32_t)l1 << 16);
                *reinterpret_cast<uint32_t*>(
                    reinterpret_cast<uint16_t*>(Chi) + o1) = (uint32_t)h2 | ((uint32_t)h3 << 16);
                *reinterpret_cast<uint32_t*>(
                    reinterpret_cast<uint16_t*>(Clo) + o1) = (uint32_t)l2 | ((uint32_t)l3 << 16);
            }
        }
    }
}

// ---------------------------------------------------------------------------
// fp32 -> bf16 hi/lo elementwise split
// ---------------------------------------------------------------------------
__global__ void conv_hl(const float* __restrict__ s,
                        __nv_bfloat16* __restrict__ h,
                        __nv_bfloat16* __restrict__ l) {
    size_t i = ((size_t)blockIdx.x * 256 + threadIdx.x) * 4;
    float4 v = *reinterpret_cast<const float4*>(s + i);
    uint16_t h0,l0,h1,l1,h2,l2,h3,l3;
    split2(v.x, h0, l0); split2(v.y, h1, l1);
    split2(v.z, h2, l2); split2(v.w, h3, l3);
    *reinterpret_cast<uint2*>(h + i) =
        make_uint2((uint32_t)h0 | ((uint32_t)h1 << 16),
                   (uint32_t)h2 | ((uint32_t)h3 << 16));
    *reinterpret_cast<uint2*>(l + i) =
        make_uint2((uint32_t)l0 | ((uint32_t)l1 << 16),
                   (uint32_t)l2 | ((uint32_t)l3 << 16));
}

// ---------------------------------------------------------------------------
// V transpose + split: Vt[z][d][n] = Vp[z][n][d]   (z = h*B+b)
// ---------------------------------------------------------------------------
__global__ void transpose_hl(const float* __restrict__ in,
                             __nv_bfloat16* __restrict__ oh,
                             __nv_bfloat16* __restrict__ ol) {
    __shared__ float t[32][33];
    const size_t z = blockIdx.z;
    in += z * (size_t)(Nn * Dn);
    oh += z * (size_t)(Dn * Nn);
    ol += z * (size_t)(Dn * Nn);
    const int x0 = blockIdx.x * 32;   // d
    const int y0 = blockIdx.y * 32;   // n
    #pragma unroll
    for (int i = 0; i < 4; i++)
        t[threadIdx.y + i * 8][threadIdx.x] =
            in[(size_t)(y0 + threadIdx.y + i * 8) * Dn + x0 + threadIdx.x];
    __syncthreads();
    #pragma unroll
    for (int i = 0; i < 4; i++) {
        float v = t[threadIdx.x][threadIdx.y + i * 8];
        uint16_t h, l;
        split2(v, h, l);
        size_t o = (size_t)(x0 + threadIdx.y + i * 8) * Nn + y0 + threadIdx.x;
        reinterpret_cast<uint16_t*>(oh)[o] = h;
        reinterpret_cast<uint16_t*>(ol)[o] = l;
    }
}

// ---------------------------------------------------------------------------
// Softmax over 1024-wide rows -> bf16 hi/lo output
// ---------------------------------------------------------------------------
__global__ void softmax1024_hl(const float* __restrict__ P,
                               __nv_bfloat16* __restrict__ Ph,
                               __nv_bfloat16* __restrict__ Pl) {
    __shared__ float red[8];
    const size_t row = blockIdx.x;
    const float* p = P + row * 1024;
    const int tid = threadIdx.x;

    float4 x = *reinterpret_cast<const float4*>(p + tid * 4);
    float m = fmaxf(fmaxf(x.x, x.y), fmaxf(x.z, x.w));
    #pragma unroll
    for (int o = 16; o > 0; o >>= 1)
        m = fmaxf(m, __shfl_xor_sync(0xffffffffu, m, o));
    if ((tid & 31) == 0) red[tid >> 5] = m;
    __syncthreads();
    float bm = red[0];
    #pragma unroll
    for (int i = 1; i < 8; i++) bm = fmaxf(bm, red[i]);
    __syncthreads();

    float e0 = __expf(x.x - bm), e1 = __expf(x.y - bm);
    float e2 = __expf(x.z - bm), e3 = __expf(x.w - bm);
    float s = e0 + e1 + e2 + e3;
    #pragma unroll
    for (int o = 16; o > 0; o >>= 1)
        s += __shfl_xor_sync(0xffffffffu, s, o);
    if ((tid & 31) == 0) red[tid >> 5] = s;
    __syncthreads();
    float bs = 0.f;
    #pragma unroll
    for (int i = 0; i < 8; i++) bs += red[i];
    float inv = 1.0f / bs;

    uint16_t h0,l0,h1,l1,h2,l2,h3,l3;
    split2(e0 * inv, h0, l0); split2(e1 * inv, h1, l1);
    split2(e2 * inv, h2, l2); split2(e3 * inv, h3, l3);
    size_t o = row * 1024 + tid * 4;
    *reinterpret_cast<uint2*>(Ph + o) =
        make_uint2((uint32_t)h0 | ((uint32_t)h1 << 16),
                   (uint32_t)h2 | ((uint32_t)h3 << 16));
    *reinterpret_cast<uint2*>(Pl + o) =
        make_uint2((uint32_t)l0 | ((uint32_t)l1 << 16),
                   (uint32_t)l2 | ((uint32_t)l3 << 16));
}

// ---------------------------------------------------------------------------
// Head interleave + split: outs[m, d*H+h] = Of[h, m, d]
// ---------------------------------------------------------------------------
__global__ void inter_hl(const float* __restrict__ Of,
                         __nv_bfloat16* __restrict__ oh,
                         __nv_bfloat16* __restrict__ ol) {
    size_t idx = (size_t)blockIdx.x * 256 + threadIdx.x;
    int    f = (int)(idx & 4095);
    size_t m = idx >> 12;
    int    h = f & 7;
    int    d = f >> 3;
    float v = Of[((size_t)h * Mn + m) * Dn + d];
    uint16_t hh, ll;
    split2(v, hh, ll);
    reinterpret_cast<uint16_t*>(oh)[idx] = hh;
    reinterpret_cast<uint16_t*>(ol)[idx] = ll;
}

// ---------------------------------------------------------------------------
// kernel_launch — inputs: k, v, q, Wk, bk, Wv, bv, Wq, bq, Wo, bo
// ---------------------------------------------------------------------------
extern "C" void kernel_launch(void* const* d_in, const int* in_sizes, int n_in,
                              void* d_out, int out_size) {
    (void)in_sizes; (void)n_in; (void)out_size;
    const float* k  = (const float*)d_in[0];
    const float* v  = (const float*)d_in[1];
    const float* q  = (const float*)d_in[2];
    const float* Wk = (const float*)d_in[3];
    const float* bk = (const float*)d_in[4];
    const float* Wv = (const float*)d_in[5];
    const float* bv = (const float*)d_in[6];
    const float* Wq = (const float*)d_in[7];
    const float* bq = (const float*)d_in[8];
    const float* Wo = (const float*)d_in[9];
    const float* bo = (const float*)d_in[10];
    float* out = (float*)d_out;

    cudaFuncSetAttribute(hmma_gemm<true, 0>,
        cudaFuncAttributeMaxDynamicSharedMemorySize, GSMEM);
    cudaFuncSetAttribute(hmma_gemm<false, 0>,
        cudaFuncAttributeMaxDynamicSharedMemorySize, GSMEM);
    cudaFuncSetAttribute(hmma_gemm<true, 1>,
        cudaFuncAttributeMaxDynamicSharedMemorySize, GSMEM);

    __nv_bfloat16 *xq_h,*xq_l,*xk_h,*xk_l,*xv_h,*xv_l;
    __nv_bfloat16 *wq_h,*wq_l,*wk_h,*wk_l,*wv_h,*wv_l,*wo_h,*wo_l;
    __nv_bfloat16 *qp_h,*qp_l,*kp_h,*kp_l,*vt_h,*vt_l,*ph,*pl,*ot_h,*ot_l;
    float *vpf,*P,*Of;
    cudaGetSymbolAddress((void**)&xq_h, g_xq_hi); cudaGetSymbolAddress((void**)&xq_l, g_xq_lo);
    cudaGetSymbolAddress((void**)&xk_h, g_xk_hi); cudaGetSymbolAddress((void**)&xk_l, g_xk_lo);
    cudaGetSymbolAddress((void**)&xv_h, g_xv_hi); cudaGetSymbolAddress((void**)&xv_l, g_xv_lo);
    cudaGetSymbolAddress((void**)&wq_h, g_wq_hi); cudaGetSymbolAddress((void**)&wq_l, g_wq_lo);
    cudaGetSymbolAddress((void**)&wk_h, g_wk_hi); cudaGetSymbolAddress((void**)&wk_l, g_wk_lo);
    cudaGetSymbolAddress((void**)&wv_h, g_wv_hi); cudaGetSymbolAddress((void**)&wv_l, g_wv_lo);
    cudaGetSymbolAddress((void**)&wo_h, g_wo_hi); cudaGetSymbolAddress((void**)&wo_l, g_wo_lo);
    cudaGetSymbolAddress((void**)&qp_h, g_qp_hi); cudaGetSymbolAddress((void**)&qp_l, g_qp_lo);
    cudaGetSymbolAddress((void**)&kp_h, g_kp_hi); cudaGetSymbolAddress((void**)&kp_l, g_kp_lo);
    cudaGetSymbolAddress((void**)&vt_h, g_vt_hi); cudaGetSymbolAddress((void**)&vt_l, g_vt_lo);
    cudaGetSymbolAddress((void**)&ph,   g_phi);   cudaGetSymbolAddress((void**)&pl,   g_plo);
    cudaGetSymbolAddress((void**)&ot_h, g_out_hi);cudaGetSymbolAddress((void**)&ot_l, g_out_lo);
    cudaGetSymbolAddress((void**)&vpf,  g_vpf);
    cudaGetSymbolAddress((void**)&P,    g_P);
    cudaGetSymbolAddress((void**)&Of,   g_Of);

    // ---- 0) input / weight splits ----
    conv_hl<<<(unsigned)(XEL / 1024), 256>>>(q,  xq_h, xq_l);
    conv_hl<<<(unsigned)(XEL / 1024), 256>>>(k,  xk_h, xk_l);
    conv_hl<<<(unsigned)(XEL / 1024), 256>>>(v,  xv_h, xv_l);
    conv_hl<<<(unsigned)(WEL / 1024), 256>>>(Wq, wq_h, wq_l);
    conv_hl<<<(unsigned)(WEL / 1024), 256>>>(Wk, wk_h, wk_l);
    conv_hl<<<(unsigned)(WEL / 1024), 256>>>(Wv, wv_h, wv_l);
    conv_hl<<<(unsigned)(WEL / 1024), 256>>>(Wo, wo_h, wo_l);

    // ---- 1) projections (z = head) ----
    dim3 gproj(Dn / 128, Mn / 128, Hn);
    hmma_gemm<true, 1><<<gproj, 256, GSMEM>>>(
        xq_h, xq_l, wq_h, wq_l, bq, nullptr, qp_h, qp_l,
        Mn, Dn, Dn, 0, (size_t)Dn * Dn, (size_t)Dn, (size_t)Mn * Dn, 1.0f);
    hmma_gemm<true, 1><<<gproj, 256, GSMEM>>>(
        xk_h, xk_l, wk_h, wk_l, bk, nullptr, kp_h, kp_l,
        Mn, Dn, Dn, 0, (size_t)Dn * Dn, (size_t)Dn, (size_t)Mn * Dn, 1.0f);
    hmma_gemm<true, 0><<<gproj, 256, GSMEM>>>(
        xv_h, xv_l, wv_h, wv_l, bv, vpf, nullptr, nullptr,
        Mn, Dn, Dn, 0, (size_t)Dn * Dn, (size_t)Dn, (size_t)Mn * Dn, 1.0f);

    // ---- 2) V transpose+split per (h,b) ----
    transpose_hl<<<dim3(Dn / 32, Nn / 32, Hn * Bn), dim3(32, 8)>>>(vpf, vt_h, vt_l);

    // ---- 3) scores S = Qp @ Kp^T / sqrt(D)  (z = h*B+b) ----
    const float inv_scale = 1.0f / sqrtf((float)Dn);
    dim3 gsc(Nn / 128, Nn / 128, Hn * Bn);
    hmma_gemm<false, 0><<<gsc, 256, GSMEM>>>(
        qp_h, qp_l, kp_h, kp_l, nullptr, P, nullptr, nullptr,
        Nn, Nn, Dn, (size_t)Nn * Dn, (size_t)Nn * Dn, 0, (size_t)Nn * Nn, inv_scale);

    // ---- 4) softmax -> hi/lo ----
    softmax1024_hl<<<Hn * Bn * Nn, 256>>>(P, ph, pl);

    // ---- 5) O = P @ Vt^T  (B operand = Vt [d][n], K-major over n) ----
    dim3 gpv(Dn / 128, Nn / 128, Hn * Bn);
    hmma_gemm<false, 0><<<gpv, 256, GSMEM>>>(
        ph, pl, vt_h, vt_l, nullptr, Of, nullptr, nullptr,
        Nn, Dn, Nn, (size_t)Nn * Nn, (size_t)Dn * Nn, 0, (size_t)Nn * Dn, 1.0f);

    // ---- 6) interleave heads + split ----
    inter_hl<<<(unsigned)(PROJ / 256), 256>>>(Of, ot_h, ot_l);

    // ---- 7) output projection ----
    dim3 gfin(Dn / 128, Mn / 128, 1);
    hmma_gemm<true, 0><<<gfin, 256, GSMEM>>>(
        ot_h, ot_l, wo_h, wo_l, bo, out, nullptr, nullptr,
        Mn, Dn, Hn * Dn, 0, 0, 0, 0, 1.0f);
}

// round 4
// speedup vs baseline: 2.1487x; 1.1400x over previous
#include <cuda_runtime.h>
#include <cuda_bf16.h>
#include <math.h>
#include <stdint.h>

// ---------------------------------------------------------------------------
// Problem constants
// ---------------------------------------------------------------------------
constexpr int Hn = 8, Bn = 16, Nn = 1024, Dn = 512;
constexpr int Mn = Bn * Nn;                               // 16384
constexpr size_t XEL  = (size_t)Mn * Dn;                  // 8,388,608
constexpr size_t WEL  = (size_t)Hn * Dn * Dn;             // 2,097,152
constexpr size_t PROJ = (size_t)Hn * Mn * Dn;             // 67,108,864
constexpr size_t PEL  = (size_t)Hn * Bn * Nn * Nn;        // 134,217,728

// ---------------------------------------------------------------------------
// Scratch (__device__ globals — allocation-free)
// ---------------------------------------------------------------------------
__device__ __nv_bfloat16 g_xq_hi[XEL], g_xq_lo[XEL];
__device__ __nv_bfloat16 g_xk_hi[XEL], g_xk_lo[XEL];
__device__ __nv_bfloat16 g_xv_hi[XEL], g_xv_lo[XEL];
__device__ __nv_bfloat16 g_wq_hi[WEL], g_wq_lo[WEL];
__device__ __nv_bfloat16 g_wk_hi[WEL], g_wk_lo[WEL];
__device__ __nv_bfloat16 g_wv_hi[WEL], g_wv_lo[WEL];
__device__ __nv_bfloat16 g_wo_hi[WEL], g_wo_lo[WEL];
__device__ __nv_bfloat16 g_qp_hi[PROJ], g_qp_lo[PROJ];
__device__ __nv_bfloat16 g_kp_hi[PROJ], g_kp_lo[PROJ];
__device__ float         g_vpf[PROJ];
__device__ __nv_bfloat16 g_vt_hi[PROJ], g_vt_lo[PROJ];
__device__ float         g_P[PEL];
__device__ __nv_bfloat16 g_phi[PEL], g_plo[PEL];
__device__ float         g_Of[PROJ];
__device__ __nv_bfloat16 g_out_hi[PROJ], g_out_lo[PROJ];

// ---------------------------------------------------------------------------
// Helpers
// ---------------------------------------------------------------------------
__device__ __forceinline__ uint32_t s2u(const void* p) {
    uint32_t a;
    asm("{ .reg .u64 t; cvta.to.shared.u64 t, %1; cvt.u32.u64 %0, t; }"
        : "=r"(a) : "l"(p));
    return a;
}

__device__ __forceinline__ void cp16(uint32_t saddr, const void* gaddr) {
    asm volatile("cp.async.cg.shared.global [%0], [%1], 16;"
                 :: "r"(saddr), "l"(gaddr) : "memory");
}
__device__ __forceinline__ void cp_commit() {
    asm volatile("cp.async.commit_group;" ::: "memory");
}
template <int N>
__device__ __forceinline__ void cp_wait() {
    asm volatile("cp.async.wait_group %0;" :: "n"(N) : "memory");
}

__device__ __forceinline__ void ldsm4(uint32_t* r, uint32_t addr) {
    asm volatile("ldmatrix.sync.aligned.m8n8.x4.shared.b16 {%0,%1,%2,%3}, [%4];"
        : "=r"(r[0]), "=r"(r[1]), "=r"(r[2]), "=r"(r[3]) : "r"(addr));
}

__device__ __forceinline__ void mma16816(float* d, const uint32_t* a,
                                         uint32_t b0, uint32_t b1) {
    asm volatile(
        "mma.sync.aligned.m16n8k16.row.col.f32.bf16.bf16.f32 "
        "{%0,%1,%2,%3}, {%4,%5,%6,%7}, {%8,%9}, {%0,%1,%2,%3};"
        : "+f"(d[0]), "+f"(d[1]), "+f"(d[2]), "+f"(d[3])
        : "r"(a[0]), "r"(a[1]), "r"(a[2]), "r"(a[3]), "r"(b0), "r"(b1));
}

__device__ __forceinline__ void split2(float x, uint16_t& h, uint16_t& l) {
    __nv_bfloat16 hb = __float2bfloat16(x);
    __nv_bfloat16 lb = __float2bfloat16(x - __bfloat162float(hb));
    h = *reinterpret_cast<uint16_t*>(&hb);
    l = *reinterpret_cast<uint16_t*>(&lb);
}

// XOR chunk swizzle for 64B rows (4 x 16B chunks): conflict-free ldmatrix.
__device__ __forceinline__ uint32_t swz(uint32_t r, uint32_t ch) {
    return r * 64u + ((ch ^ ((r >> 1) & 3u)) << 4);
}

// ---------------------------------------------------------------------------
// bf16-split batched GEMM via mma.sync (HMMA):
//   C[z] = alpha * (Ahi+Alo)[z] @ (Bhi+Blo)[z]^T (+ bias[z])
//   A: [M,K] K-major bf16, B: [N,K] K-major bf16
//   3 products: hi*hi + hi*lo + lo*hi (fp32 accum)
// Tile 128x128, BK=32, 8 warps (64x32 each), 2-stage cp.async pipeline.
// 64B swizzled rows -> 64.5KB SMEM -> 2 CTAs/SM.
// ---------------------------------------------------------------------------
constexpr int ROWB   = 64;                       // bytes per SMEM row
constexpr int TILE_B = 128 * ROWB;               // 8192 B per tile
constexpr int STAGE  = 4 * TILE_B;               // Ahi,Alo,Bhi,Blo = 32768
constexpr int GSMEM  = 2 * STAGE + 512;          // + bias = 66048

template <bool BIAS, int OUTM>
__global__ void __launch_bounds__(256, 2) hmma_gemm(
    const __nv_bfloat16* __restrict__ Ahi, const __nv_bfloat16* __restrict__ Alo,
    const __nv_bfloat16* __restrict__ Bhi, const __nv_bfloat16* __restrict__ Blo,
    const float* __restrict__ biasg,
    float* __restrict__ Cf,
    __nv_bfloat16* __restrict__ Chi, __nv_bfloat16* __restrict__ Clo,
    int M, int N, int K,
    size_t sA, size_t sB, size_t sBias, size_t sC, float alpha)
{
    extern __shared__ __align__(16) char smem[];
    const uint32_t sb = s2u(smem);
    float* sbias = reinterpret_cast<float*>(smem + 2 * STAGE);

    const int tid  = threadIdx.x;
    const int wid  = tid >> 5, lane = tid & 31;
    const int wr   = wid >> 2, wc = wid & 3;      // warp grid 2x4
    const int col0 = blockIdx.x * 128, row0 = blockIdx.y * 128;
    const size_t z = blockIdx.z;
    Ahi += z * sA; Alo += z * sA; Bhi += z * sB; Blo += z * sB;

    if (BIAS && tid < 128) sbias[tid] = biasg[z * sBias + col0 + tid];

    const __nv_bfloat16* srcs[4] = {Ahi, Alo, Bhi, Blo};
    const int rb[4] = {row0, row0, col0, col0};

    const int nCh = K >> 5;          // BK = 32

    auto prefetch = [&](int c, int buf) {
        const int k0 = c << 5;
        const uint32_t boff = sb + buf * STAGE;
        #pragma unroll
        for (int t = 0; t < 4; t++) {
            const __nv_bfloat16* s = srcs[t];
            const uint32_t tb = boff + t * TILE_B;
            #pragma unroll
            for (int i = 0; i < 2; i++) {
                uint32_t idx = (uint32_t)(i * 256 + tid);   // 0..511
                uint32_t r = idx >> 2, ch = idx & 3;
                cp16(tb + swz(r, ch),
                     s + (size_t)(rb[t] + r) * K + k0 + ch * 8);
            }
        }
        cp_commit();
    };

    float acc[4][4][4] = {};

    prefetch(0, 0);

    for (int c = 0; c < nCh; ++c) {
        if (c + 1 < nCh) { prefetch(c + 1, (c + 1) & 1); cp_wait<1>(); }
        else             { cp_wait<0>(); }
        __syncthreads();

        const uint32_t boff = sb + (c & 1) * STAGE;
        const uint32_t aHiB = boff,              aLoB = boff + TILE_B;
        const uint32_t bHiB = boff + 2 * TILE_B, bLoB = boff + 3 * TILE_B;
        const uint32_t lrow = (uint32_t)(lane & 15), lhalf = (uint32_t)(lane >> 4);

        #pragma unroll
        for (int ks = 0; ks < 2; ks++) {
            const uint32_t kch = (uint32_t)ks * 2u + lhalf;   // 16B chunk index
            // B fragments: 4 n8-tiles per operand
            uint32_t bh[4][2], bl[4][2];
            #pragma unroll
            for (int np = 0; np < 2; np++) {
                uint32_t r = (uint32_t)(wc * 32 + np * 16) + lrow;
                uint32_t t[4];
                ldsm4(t, bHiB + swz(r, kch));
                bh[np*2+0][0] = t[0]; bh[np*2+0][1] = t[2];
                bh[np*2+1][0] = t[1]; bh[np*2+1][1] = t[3];
                ldsm4(t, bLoB + swz(r, kch));
                bl[np*2+0][0] = t[0]; bl[np*2+0][1] = t[2];
                bl[np*2+1][0] = t[1]; bl[np*2+1][1] = t[3];
            }
            #pragma unroll
            for (int mt = 0; mt < 4; mt++) {
                uint32_t r = (uint32_t)(wr * 64 + mt * 16) + lrow;
                uint32_t ah[4], al[4];
                ldsm4(ah, aHiB + swz(r, kch));
                ldsm4(al, aLoB + swz(r, kch));
                #pragma unroll
                for (int nt = 0; nt < 4; nt++) {
                    mma16816(acc[mt][nt], ah, bh[nt][0], bh[nt][1]);
                    mma16816(acc[mt][nt], ah, bl[nt][0], bl[nt][1]);
                    mma16816(acc[mt][nt], al, bh[nt][0], bh[nt][1]);
                }
            }
        }
        __syncthreads();
    }

    // ---- epilogue ----
    const int qr = lane >> 2, qc = lane & 3;
    #pragma unroll
    for (int mt = 0; mt < 4; mt++) {
        #pragma unroll
        for (int nt = 0; nt < 4; nt++) {
            const int lcol = wc * 32 + nt * 8 + qc * 2;
            const float b0 = BIAS ? sbias[lcol]     : 0.f;
            const float b1 = BIAS ? sbias[lcol + 1] : 0.f;
            const int r0 = row0 + wr * 64 + mt * 16 + qr;
            const float v00 = alpha * acc[mt][nt][0] + b0;
            const float v01 = alpha * acc[mt][nt][1] + b1;
            const float v10 = alpha * acc[mt][nt][2] + b0;
            const float v11 = alpha * acc[mt][nt][3] + b1;
            if (OUTM == 0) {
                float* cp = Cf + z * sC + (size_t)r0 * N + col0 + lcol;
                *reinterpret_cast<float2*>(cp)            = make_float2(v00, v01);
                *reinterpret_cast<float2*>(cp + 8ull * N) = make_float2(v10, v11);
            } else {
                uint16_t h0,l0,h1,l1,h2,l2,h3,l3;
                split2(v00, h0, l0); split2(v01, h1, l1);
                split2(v10, h2, l2); split2(v11, h3, l3);
                size_t o0 = z * sC + (size_t)r0 * N + col0 + lcol;
                size_t o1 = o0 + 8ull * N;
                *reinterpret_cast<uint32_t*>(
                    reinterpret_cast<uint16_t*>(Chi) + o0) = (uint32_t)h0 | ((uint32_t)h1 << 16);
                *reinterpret_cast<uint32_t*>(
                    reinterpret_cast<uint16_t*>(Clo) + o0) = (uint32_t)l0 | ((uint32_t)l1 << 16);
                *reinterpret_cast<uint32_t*>(
                    reinterpret_cast<uint16_t*>(Chi) + o1) = (uint32_t)h2 | ((uint32_t)h3 << 16);
                *reinterpret_cast<uint32_t*>(
                    reinterpret_cast<uint16_t*>(Clo) + o1) = (uint32_t)l2 | ((uint32_t)l3 << 16);
            }
        }
    }
}

// ---------------------------------------------------------------------------
// fp32 -> bf16 hi/lo elementwise split
// ---------------------------------------------------------------------------
__global__ void conv_hl(const float* __restrict__ s,
                        __nv_bfloat16* __restrict__ h,
                        __nv_bfloat16* __restrict__ l) {
    size_t i = ((size_t)blockIdx.x * 256 + threadIdx.x) * 4;
    float4 v = *reinterpret_cast<const float4*>(s + i);
    uint16_t h0,l0,h1,l1,h2,l2,h3,l3;
    split2(v.x, h0, l0); split2(v.y, h1, l1);
    split2(v.z, h2, l2); split2(v.w, h3, l3);
    *reinterpret_cast<uint2*>(h + i) =
        make_uint2((uint32_t)h0 | ((uint32_t)h1 << 16),
                   (uint32_t)h2 | ((uint32_t)h3 << 16));
    *reinterpret_cast<uint2*>(l + i) =
        make_uint2((uint32_t)l0 | ((uint32_t)l1 << 16),
                   (uint32_t)l2 | ((uint32_t)l3 << 16));
}

// ---------------------------------------------------------------------------
// V transpose + split: Vt[z][d][n] = Vp[z][n][d]   (z = h*B+b)
// ---------------------------------------------------------------------------
__global__ void transpose_hl(const float* __restrict__ in,
                             __nv_bfloat16* __restrict__ oh,
                             __nv_bfloat16* __restrict__ ol) {
    __shared__ float t[32][33];
    const size_t z = blockIdx.z;
    in += z * (size_t)(Nn * Dn);
    oh += z * (size_t)(Dn * Nn);
    ol += z * (size_t)(Dn * Nn);
    const int x0 = blockIdx.x * 32;   // d
    const int y0 = blockIdx.y * 32;   // n
    #pragma unroll
    for (int i = 0; i < 4; i++)
        t[threadIdx.y + i * 8][threadIdx.x] =
            in[(size_t)(y0 + threadIdx.y + i * 8) * Dn + x0 + threadIdx.x];
    __syncthreads();
    #pragma unroll
    for (int i = 0; i < 4; i++) {
        float v = t[threadIdx.x][threadIdx.y + i * 8];
        uint16_t h, l;
        split2(v, h, l);
        size_t o = (size_t)(x0 + threadIdx.y + i * 8) * Nn + y0 + threadIdx.x;
        reinterpret_cast<uint16_t*>(oh)[o] = h;
        reinterpret_cast<uint16_t*>(ol)[o] = l;
    }
}

// ---------------------------------------------------------------------------
// Softmax over 1024-wide rows -> bf16 hi/lo output
// ---------------------------------------------------------------------------
__global__ void softmax1024_hl(const float* __restrict__ P,
                               __nv_bfloat16* __restrict__ Ph,
                               __nv_bfloat16* __restrict__ Pl) {
    __shared__ float red[8];
    const size_t row = blockIdx.x;
    const float* p = P + row * 1024;
    const int tid = threadIdx.x;

    float4 x = *reinterpret_cast<const float4*>(p + tid * 4);
    float m = fmaxf(fmaxf(x.x, x.y), fmaxf(x.z, x.w));
    #pragma unroll
    for (int o = 16; o > 0; o >>= 1)
        m = fmaxf(m, __shfl_xor_sync(0xffffffffu, m, o));
    if ((tid & 31) == 0) red[tid >> 5] = m;
    __syncthreads();
    float bm = red[0];
    #pragma unroll
    for (int i = 1; i < 8; i++) bm = fmaxf(bm, red[i]);
    __syncthreads();

    float e0 = __expf(x.x - bm), e1 = __expf(x.y - bm);
    float e2 = __expf(x.z - bm), e3 = __expf(x.w - bm);
    float s = e0 + e1 + e2 + e3;
    #pragma unroll
    for (int o = 16; o > 0; o >>= 1)
        s += __shfl_xor_sync(0xffffffffu, s, o);
    if ((tid & 31) == 0) red[tid >> 5] = s;
    __syncthreads();
    float bs = 0.f;
    #pragma unroll
    for (int i = 0; i < 8; i++) bs += red[i];
    float inv = 1.0f / bs;

    uint16_t h0,l0,h1,l1,h2,l2,h3,l3;
    split2(e0 * inv, h0, l0); split2(e1 * inv, h1, l1);
    split2(e2 * inv, h2, l2); split2(e3 * inv, h3, l3);
    size_t o = row * 1024 + tid * 4;
    *reinterpret_cast<uint2*>(Ph + o) =
        make_uint2((uint32_t)h0 | ((uint32_t)h1 << 16),
                   (uint32_t)h2 | ((uint32_t)h3 << 16));
    *reinterpret_cast<uint2*>(Pl + o) =
        make_uint2((uint32_t)l0 | ((uint32_t)l1 << 16),
                   (uint32_t)l2 | ((uint32_t)l3 << 16));
}

// ---------------------------------------------------------------------------
// Head interleave + split: outs[m, d*H+h] = Of[h, m, d]
// ---------------------------------------------------------------------------
__global__ void inter_hl(const float* __restrict__ Of,
                         __nv_bfloat16* __restrict__ oh,
                         __nv_bfloat16* __restrict__ ol) {
    size_t idx = (size_t)blockIdx.x * 256 + threadIdx.x;
    int    f = (int)(idx & 4095);
    size_t m = idx >> 12;
    int    h = f & 7;
    int    d = f >> 3;
    float v = Of[((size_t)h * Mn + m) * Dn + d];
    uint16_t hh, ll;
    split2(v, hh, ll);
    reinterpret_cast<uint16_t*>(oh)[idx] = hh;
    reinterpret_cast<uint16_t*>(ol)[idx] = ll;
}

// ---------------------------------------------------------------------------
// kernel_launch — inputs: k, v, q, Wk, bk, Wv, bv, Wq, bq, Wo, bo
// Launch order arranged so launch #6 is a projection hmma_gemm (ncu -s 5 -c 1).
// ---------------------------------------------------------------------------
extern "C" void kernel_launch(void* const* d_in, const int* in_sizes, int n_in,
                              void* d_out, int out_size) {
    (void)in_sizes; (void)n_in; (void)out_size;
    const float* k  = (const float*)d_in[0];
    const float* v  = (const float*)d_in[1];
    const float* q  = (const float*)d_in[2];
    const float* Wk = (const float*)d_in[3];
    const float* bk = (const float*)d_in[4];
    const float* Wv = (const float*)d_in[5];
    const float* bv = (const float*)d_in[6];
    const float* Wq = (const float*)d_in[7];
    const float* bq = (const float*)d_in[8];
    const float* Wo = (const float*)d_in[9];
    const float* bo = (const float*)d_in[10];
    float* out = (float*)d_out;

    cudaFuncSetAttribute(hmma_gemm<true, 0>,
        cudaFuncAttributeMaxDynamicSharedMemorySize, GSMEM);
    cudaFuncSetAttribute(hmma_gemm<false, 0>,
        cudaFuncAttributeMaxDynamicSharedMemorySize, GSMEM);
    cudaFuncSetAttribute(hmma_gemm<true, 1>,
        cudaFuncAttributeMaxDynamicSharedMemorySize, GSMEM);

    __nv_bfloat16 *xq_h,*xq_l,*xk_h,*xk_l,*xv_h,*xv_l;
    __nv_bfloat16 *wq_h,*wq_l,*wk_h,*wk_l,*wv_h,*wv_l,*wo_h,*wo_l;
    __nv_bfloat16 *qp_h,*qp_l,*kp_h,*kp_l,*vt_h,*vt_l,*ph,*pl,*ot_h,*ot_l;
    float *vpf,*P,*Of;
    cudaGetSymbolAddress((void**)&xq_h, g_xq_hi); cudaGetSymbolAddress((void**)&xq_l, g_xq_lo);
    cudaGetSymbolAddress((void**)&xk_h, g_xk_hi); cudaGetSymbolAddress((void**)&xk_l, g_xk_lo);
    cudaGetSymbolAddress((void**)&xv_h, g_xv_hi); cudaGetSymbolAddress((void**)&xv_l, g_xv_lo);
    cudaGetSymbolAddress((void**)&wq_h, g_wq_hi); cudaGetSymbolAddress((void**)&wq_l, g_wq_lo);
    cudaGetSymbolAddress((void**)&wk_h, g_wk_hi); cudaGetSymbolAddress((void**)&wk_l, g_wk_lo);
    cudaGetSymbolAddress((void**)&wv_h, g_wv_hi); cudaGetSymbolAddress((void**)&wv_l, g_wv_lo);
    cudaGetSymbolAddress((void**)&wo_h, g_wo_hi); cudaGetSymbolAddress((void**)&wo_l, g_wo_lo);
    cudaGetSymbolAddress((void**)&qp_h, g_qp_hi); cudaGetSymbolAddress((void**)&qp_l, g_qp_lo);
    cudaGetSymbolAddress((void**)&kp_h, g_kp_hi); cudaGetSymbolAddress((void**)&kp_l, g_kp_lo);
    cudaGetSymbolAddress((void**)&vt_h, g_vt_hi); cudaGetSymbolAddress((void**)&vt_l, g_vt_lo);
    cudaGetSymbolAddress((void**)&ph,   g_phi);   cudaGetSymbolAddress((void**)&pl,   g_plo);
    cudaGetSymbolAddress((void**)&ot_h, g_out_hi);cudaGetSymbolAddress((void**)&ot_l, g_out_lo);
    cudaGetSymbolAddress((void**)&vpf,  g_vpf);
    cudaGetSymbolAddress((void**)&P,    g_P);
    cudaGetSymbolAddress((void**)&Of,   g_Of);

    dim3 gproj(Dn / 128, Mn / 128, Hn);

    // ---- launches 1..5: splits needed for Q projection ----
    conv_hl<<<(unsigned)(XEL / 1024), 256>>>(q,  xq_h, xq_l);
    conv_hl<<<(unsigned)(XEL / 1024), 256>>>(k,  xk_h, xk_l);
    conv_hl<<<(unsigned)(XEL / 1024), 256>>>(v,  xv_h, xv_l);
    conv_hl<<<(unsigned)(WEL / 1024), 256>>>(Wq, wq_h, wq_l);
    conv_hl<<<(unsigned)(WEL / 1024), 256>>>(Wk, wk_h, wk_l);

    // ---- launch 6 (ncu -s 5 -c 1 profiles this): Q projection GEMM ----
    hmma_gemm<true, 1><<<gproj, 256, GSMEM>>>(
        xq_h, xq_l, wq_h, wq_l, bq, nullptr, qp_h, qp_l,
        Mn, Dn, Dn, 0, (size_t)Dn * Dn, (size_t)Dn, (size_t)Mn * Dn, 1.0f);

    // ---- remaining splits ----
    conv_hl<<<(unsigned)(WEL / 1024), 256>>>(Wv, wv_h, wv_l);
    conv_hl<<<(unsigned)(WEL / 1024), 256>>>(Wo, wo_h, wo_l);

    // ---- K / V projections ----
    hmma_gemm<true, 1><<<gproj, 256, GSMEM>>>(
        xk_h, xk_l, wk_h, wk_l, bk, nullptr, kp_h, kp_l,
        Mn, Dn, Dn, 0, (size_t)Dn * Dn, (size_t)Dn, (size_t)Mn * Dn, 1.0f);
    hmma_gemm<true, 0><<<gproj, 256, GSMEM>>>(
        xv_h, xv_l, wv_h, wv_l, bv, vpf, nullptr, nullptr,
        Mn, Dn, Dn, 0, (size_t)Dn * Dn, (size_t)Dn, (size_t)Mn * Dn, 1.0f);

    // ---- V transpose+split per (h,b) ----
    transpose_hl<<<dim3(Dn / 32, Nn / 32, Hn * Bn), dim3(32, 8)>>>(vpf, vt_h, vt_l);

    // ---- scores S = Qp @ Kp^T / sqrt(D)  (z = h*B+b) ----
    const float inv_scale = 1.0f / sqrtf((float)Dn);
    dim3 gsc(Nn / 128, Nn / 128, Hn * Bn);
    hmma_gemm<false, 0><<<gsc, 256, GSMEM>>>(
        qp_h, qp_l, kp_h, kp_l, nullptr, P, nullptr, nullptr,
        Nn, Nn, Dn, (size_t)Nn * Dn, (size_t)Nn * Dn, 0, (size_t)Nn * Nn, inv_scale);

    // ---- softmax -> hi/lo ----
    softmax1024_hl<<<Hn * Bn * Nn, 256>>>(P, ph, pl);

    // ---- O = P @ Vt^T  (B operand = Vt [d][n], K-major over n) ----
    dim3 gpv(Dn / 128, Nn / 128, Hn * Bn);
    hmma_gemm<false, 0><<<gpv, 256, GSMEM>>>(
        ph, pl, vt_h, vt_l, nullptr, Of, nullptr, nullptr,
        Nn, Dn, Nn, (size_t)Nn * Nn, (size_t)Dn * Nn, 0, (size_t)Nn * Dn, 1.0f);

    // ---- interleave heads + split ----
    inter_hl<<<(unsigned)(PROJ / 256), 256>>>(Of, ot_h, ot_l);

    // ---- output projection ----
    dim3 gfin(Dn / 128, Mn / 128, 1);
    hmma_gemm<true, 0><<<gfin, 256, GSMEM>>>(
        ot_h, ot_l, wo_h, wo_l, bo, out, nullptr, nullptr,
        Mn, Dn, Hn * Dn, 0, 0, 0, 0, 1.0f);
}

// round 5
// speedup vs baseline: 2.2534x; 1.0487x over previous
#include <cuda_runtime.h>
#include <cuda_bf16.h>
#include <math.h>
#include <stdint.h>

// ---------------------------------------------------------------------------
// Problem constants
// ---------------------------------------------------------------------------
constexpr int Hn = 8, Bn = 16, Nn = 1024, Dn = 512;
constexpr int Mn = Bn * Nn;                               // 16384
constexpr size_t XEL  = (size_t)Mn * Dn;                  // 8,388,608
constexpr size_t WEL  = (size_t)Hn * Dn * Dn;             // 2,097,152
constexpr size_t PROJ = (size_t)Hn * Mn * Dn;             // 67,108,864
constexpr size_t PEL  = (size_t)Hn * Bn * Nn * Nn;        // 134,217,728
constexpr size_t AHBLK = (size_t)Mn * Dn;                 // h-block stride in ot

// ---------------------------------------------------------------------------
// Scratch (__device__ globals — allocation-free)
// ---------------------------------------------------------------------------
__device__ __nv_bfloat16 g_xq_hi[XEL], g_xq_lo[XEL];
__device__ __nv_bfloat16 g_xk_hi[XEL], g_xk_lo[XEL];
__device__ __nv_bfloat16 g_xv_hi[XEL], g_xv_lo[XEL];
__device__ __nv_bfloat16 g_wq_hi[WEL], g_wq_lo[WEL];
__device__ __nv_bfloat16 g_wk_hi[WEL], g_wk_lo[WEL];
__device__ __nv_bfloat16 g_wv_hi[WEL], g_wv_lo[WEL];
__device__ __nv_bfloat16 g_wop_hi[WEL], g_wop_lo[WEL];    // permuted Wo
__device__ __nv_bfloat16 g_qp_hi[PROJ], g_qp_lo[PROJ];
__device__ __nv_bfloat16 g_kp_hi[PROJ], g_kp_lo[PROJ];
__device__ __nv_bfloat16 g_vt_hi[PROJ], g_vt_lo[PROJ];    // V transposed [z][d][n]
__device__ float         g_P[PEL];
__device__ __nv_bfloat16 g_phi[PEL], g_plo[PEL];
__device__ __nv_bfloat16 g_ot_hi[PROJ], g_ot_lo[PROJ];    // PV out [h][m][d]

// ---------------------------------------------------------------------------
// Helpers
// ---------------------------------------------------------------------------
__device__ __forceinline__ uint32_t s2u(const void* p) {
    uint32_t a;
    asm("{ .reg .u64 t; cvta.to.shared.u64 t, %1; cvt.u32.u64 %0, t; }"
        : "=r"(a) : "l"(p));
    return a;
}

__device__ __forceinline__ void cp16(uint32_t saddr, const void* gaddr) {
    asm volatile("cp.async.cg.shared.global [%0], [%1], 16;"
                 :: "r"(saddr), "l"(gaddr) : "memory");
}
__device__ __forceinline__ void cp_commit() {
    asm volatile("cp.async.commit_group;" ::: "memory");
}
template <int N>
__device__ __forceinline__ void cp_wait() {
    asm volatile("cp.async.wait_group %0;" :: "n"(N) : "memory");
}

__device__ __forceinline__ void ldsm4(uint32_t* r, uint32_t addr) {
    asm volatile("ldmatrix.sync.aligned.m8n8.x4.shared.b16 {%0,%1,%2,%3}, [%4];"
        : "=r"(r[0]), "=r"(r[1]), "=r"(r[2]), "=r"(r[3]) : "r"(addr));
}

__device__ __forceinline__ void mma16816(float* d, const uint32_t* a,
                                         uint32_t b0, uint32_t b1) {
    asm volatile(
        "mma.sync.aligned.m16n8k16.row.col.f32.bf16.bf16.f32 "
        "{%0,%1,%2,%3}, {%4,%5,%6,%7}, {%8,%9}, {%0,%1,%2,%3};"
        : "+f"(d[0]), "+f"(d[1]), "+f"(d[2]), "+f"(d[3])
        : "r"(a[0]), "r"(a[1]), "r"(a[2]), "r"(a[3]), "r"(b0), "r"(b1));
}

__device__ __forceinline__ void split2(float x, uint16_t& h, uint16_t& l) {
    __nv_bfloat16 hb = __float2bfloat16(x);
    __nv_bfloat16 lb = __float2bfloat16(x - __bfloat162float(hb));
    h = *reinterpret_cast<uint16_t*>(&hb);
    l = *reinterpret_cast<uint16_t*>(&lb);
}

// XOR chunk swizzle for 64B rows (4 x 16B chunks): conflict-free ldmatrix.
__device__ __forceinline__ uint32_t swz(uint32_t r, uint32_t ch) {
    return r * 64u + ((ch ^ ((r >> 1) & 3u)) << 4);
}

// ---------------------------------------------------------------------------
// bf16-split batched GEMM via mma.sync (HMMA):
//   C[z] = alpha * (Ahi+Alo)[z] @ (Bhi+Blo)[z]^T (+ bias[z])
//   3 products: hi*hi + hi*lo + lo*hi (fp32 accum)
// OUTM: 0=fp32 C, 1=bf16 hi/lo C, 2=bf16 hi/lo TRANSPOSED (Vt[z*16+b][col][n])
// AHB : A column index h-blocked: A[m, g] = Abase[(g>>9)*AHBLK + m*lda + (g&511)]
// Tile 128x128, BK=32, 8 warps, 3-stage cp.async pipeline, 1 sync/chunk.
// 96.5KB SMEM -> 2 CTAs/SM.
// ---------------------------------------------------------------------------
constexpr int ROWB   = 64;                       // bytes per SMEM row
constexpr int TILE_B = 128 * ROWB;               // 8192 B per tile
constexpr int STAGE  = 4 * TILE_B;               // Ahi,Alo,Bhi,Blo = 32768
constexpr int GSMEM  = 3 * STAGE + 512;          // 98816

template <bool BIAS, int OUTM, bool AHB>
__global__ void __launch_bounds__(256, 2) hmma_gemm(
    const __nv_bfloat16* __restrict__ Ahi, const __nv_bfloat16* __restrict__ Alo,
    const __nv_bfloat16* __restrict__ Bhi, const __nv_bfloat16* __restrict__ Blo,
    const float* __restrict__ biasg,
    float* __restrict__ Cf,
    __nv_bfloat16* __restrict__ Chi, __nv_bfloat16* __restrict__ Clo,
    int N, int K, int lda, int ldb,
    size_t sA, size_t sB, size_t sBias, size_t sC, float alpha)
{
    extern __shared__ __align__(16) char smem[];
    const uint32_t sb = s2u(smem);
    float* sbias = reinterpret_cast<float*>(smem + 3 * STAGE);

    const int tid  = threadIdx.x;
    const int wid  = tid >> 5, lane = tid & 31;
    const int wr   = wid >> 2, wc = wid & 3;      // warp grid 2x4
    const int col0 = blockIdx.x * 128, row0 = blockIdx.y * 128;
    const size_t z = blockIdx.z;
    Ahi += z * sA; Alo += z * sA; Bhi += z * sB; Blo += z * sB;

    if (BIAS && tid < 128) sbias[tid] = biasg[z * sBias + col0 + tid];

    const int nCh = K >> 5;          // BK = 32

    auto prefetch = [&](int c) {
        const int k0 = c << 5;
        const uint32_t boff = sb + (uint32_t)(c % 3) * STAGE;
        size_t aoff;
        if (AHB) aoff = ((size_t)(k0 >> 9)) * AHBLK + (size_t)(k0 & 511);
        else     aoff = (size_t)k0;
        #pragma unroll
        for (int t = 0; t < 4; t++) {
            const __nv_bfloat16* s = (t == 0) ? Ahi : (t == 1) ? Alo
                                   : (t == 2) ? Bhi : Blo;
            const uint32_t tb = boff + t * TILE_B;
            #pragma unroll
            for (int i = 0; i < 2; i++) {
                uint32_t idx = (uint32_t)(i * 256 + tid);   // 0..511
                uint32_t r = idx >> 2, ch = idx & 3;
                const __nv_bfloat16* g;
                if (t < 2) g = s + aoff + (size_t)(row0 + r) * lda + ch * 8;
                else       g = s + (size_t)k0 + (size_t)(col0 + r) * ldb + ch * 8;
                cp16(tb + swz(r, ch), g);
            }
        }
        cp_commit();
    };

    float acc[4][4][4] = {};

    prefetch(0);
    prefetch(1);

    for (int c = 0; c < nCh; ++c) {
        if (c + 1 < nCh) cp_wait<1>(); else cp_wait<0>();
        __syncthreads();
        if (c + 2 < nCh) prefetch(c + 2);

        const uint32_t boff = sb + (uint32_t)(c % 3) * STAGE;
        const uint32_t aHiB = boff,              aLoB = boff + TILE_B;
        const uint32_t bHiB = boff + 2 * TILE_B, bLoB = boff + 3 * TILE_B;
        const uint32_t lrow = (uint32_t)(lane & 15), lhalf = (uint32_t)(lane >> 4);

        #pragma unroll
        for (int ks = 0; ks < 2; ks++) {
            const uint32_t kch = (uint32_t)ks * 2u + lhalf;   // 16B chunk index
            uint32_t bh[4][2], bl[4][2];
            #pragma unroll
            for (int np = 0; np < 2; np++) {
                uint32_t r = (uint32_t)(wc * 32 + np * 16) + lrow;
                uint32_t t[4];
                ldsm4(t, bHiB + swz(r, kch));
                bh[np*2+0][0] = t[0]; bh[np*2+0][1] = t[2];
                bh[np*2+1][0] = t[1]; bh[np*2+1][1] = t[3];
                ldsm4(t, bLoB + swz(r, kch));
                bl[np*2+0][0] = t[0]; bl[np*2+0][1] = t[2];
                bl[np*2+1][0] = t[1]; bl[np*2+1][1] = t[3];
            }
            #pragma unroll
            for (int mt = 0; mt < 4; mt++) {
                uint32_t r = (uint32_t)(wr * 64 + mt * 16) + lrow;
                uint32_t ah[4], al[4];
                ldsm4(ah, aHiB + swz(r, kch));
                ldsm4(al, aLoB + swz(r, kch));
                #pragma unroll
                for (int nt = 0; nt < 4; nt++) {
                    mma16816(acc[mt][nt], ah, bh[nt][0], bh[nt][1]);
                    mma16816(acc[mt][nt], ah, bl[nt][0], bl[nt][1]);
                    mma16816(acc[mt][nt], al, bh[nt][0], bh[nt][1]);
                }
            }
        }
    }

    // ---- epilogue ----
    const int qr = lane >> 2, qc = lane & 3;
    #pragma unroll
    for (int mt = 0; mt < 4; mt++) {
        #pragma unroll
        for (int nt = 0; nt < 4; nt++) {
            const int lcol = wc * 32 + nt * 8 + qc * 2;
            const float b0 = BIAS ? sbias[lcol]     : 0.f;
            const float b1 = BIAS ? sbias[lcol + 1] : 0.f;
            const int r0 = row0 + wr * 64 + mt * 16 + qr;
            const float v00 = alpha * acc[mt][nt][0] + b0;
            const float v01 = alpha * acc[mt][nt][1] + b1;
            const float v10 = alpha * acc[mt][nt][2] + b0;
            const float v11 = alpha * acc[mt][nt][3] + b1;
            if (OUTM == 0) {
                float* cp = Cf + z * sC + (size_t)r0 * N + col0 + lcol;
                *reinterpret_cast<float2*>(cp)            = make_float2(v00, v01);
                *reinterpret_cast<float2*>(cp + 8ull * N) = make_float2(v10, v11);
            } else if (OUTM == 1) {
                uint16_t h0,l0,h1,l1,h2,l2,h3,l3;
                split2(v00, h0, l0); split2(v01, h1, l1);
                split2(v10, h2, l2); split2(v11, h3, l3);
                size_t o0 = z * sC + (size_t)r0 * N + col0 + lcol;
                size_t o1 = o0 + 8ull * N;
                *reinterpret_cast<uint32_t*>(
                    reinterpret_cast<uint16_t*>(Chi) + o0) = (uint32_t)h0 | ((uint32_t)h1 << 16);
                *reinterpret_cast<uint32_t*>(
                    reinterpret_cast<uint16_t*>(Clo) + o0) = (uint32_t)l0 | ((uint32_t)l1 << 16);
                *reinterpret_cast<uint32_t*>(
                    reinterpret_cast<uint16_t*>(Chi) + o1) = (uint32_t)h2 | ((uint32_t)h3 << 16);
                *reinterpret_cast<uint32_t*>(
                    reinterpret_cast<uint16_t*>(Clo) + o1) = (uint32_t)l2 | ((uint32_t)l3 << 16);
            } else {
                // OUTM == 2: transposed store  Vt[z*16 + b][col][n]
                uint16_t* oh = reinterpret_cast<uint16_t*>(Chi);
                uint16_t* ol = reinterpret_cast<uint16_t*>(Clo);
                const size_t zt = z * (size_t)Bn + (size_t)(row0 >> 10);
                const int n0 = (r0 & 1023);
                const size_t c0a = (zt * 512 + (size_t)(col0 + lcol)) * 1024;
                const size_t c1a = c0a + 1024;       // col+1
                uint16_t h, l;
                split2(v00, h, l); oh[c0a + n0]     = h; ol[c0a + n0]     = l;
                split2(v01, h, l); oh[c1a + n0]     = h; ol[c1a + n0]     = l;
                split2(v10, h, l); oh[c0a + n0 + 8] = h; ol[c0a + n0 + 8] = l;
                split2(v11, h, l); oh[c1a + n0 + 8] = h; ol[c1a + n0 + 8] = l;
            }
        }
    }
}

// ---------------------------------------------------------------------------
// fp32 -> bf16 hi/lo elementwise split
// ---------------------------------------------------------------------------
__global__ void conv_hl(const float* __restrict__ s,
                        __nv_bfloat16* __restrict__ h,
                        __nv_bfloat16* __restrict__ l) {
    size_t i = ((size_t)blockIdx.x * 256 + threadIdx.x) * 4;
    float4 v = *reinterpret_cast<const float4*>(s + i);
    uint16_t h0,l0,h1,l1,h2,l2,h3,l3;
    split2(v.x, h0, l0); split2(v.y, h1, l1);
    split2(v.z, h2, l2); split2(v.w, h3, l3);
    *reinterpret_cast<uint2*>(h + i) =
        make_uint2((uint32_t)h0 | ((uint32_t)h1 << 16),
                   (uint32_t)h2 | ((uint32_t)h3 << 16));
    *reinterpret_cast<uint2*>(l + i) =
        make_uint2((uint32_t)l0 | ((uint32_t)l1 << 16),
                   (uint32_t)l2 | ((uint32_t)l3 << 16));
}

// ---------------------------------------------------------------------------
// Wo permute + split: wo_p[o][h*512+d] = Wo[o][d*8+h]
// ---------------------------------------------------------------------------
__global__ void conv_wo_p(const float* __restrict__ Wo,
                          __nv_bfloat16* __restrict__ oh,
                          __nv_bfloat16* __restrict__ ol) {
    size_t idx = (size_t)blockIdx.x * 256 + threadIdx.x;   // o*4096 + g
    int g = (int)(idx & 4095);
    size_t o = idx >> 12;
    int f = ((g & 511) << 3) | (g >> 9);
    float v = Wo[(o << 12) + f];
    uint16_t h, l;
    split2(v, h, l);
    reinterpret_cast<uint16_t*>(oh)[idx] = h;
    reinterpret_cast<uint16_t*>(ol)[idx] = l;
}

// ---------------------------------------------------------------------------
// Softmax over 1024-wide rows -> bf16 hi/lo output
// ---------------------------------------------------------------------------
__global__ void softmax1024_hl(const float* __restrict__ P,
                               __nv_bfloat16* __restrict__ Ph,
                               __nv_bfloat16* __restrict__ Pl) {
    __shared__ float red[8];
    const size_t row = blockIdx.x;
    const float* p = P + row * 1024;
    const int tid = threadIdx.x;

    float4 x = *reinterpret_cast<const float4*>(p + tid * 4);
    float m = fmaxf(fmaxf(x.x, x.y), fmaxf(x.z, x.w));
    #pragma unroll
    for (int o = 16; o > 0; o >>= 1)
        m = fmaxf(m, __shfl_xor_sync(0xffffffffu, m, o));
    if ((tid & 31) == 0) red[tid >> 5] = m;
    __syncthreads();
    float bm = red[0];
    #pragma unroll
    for (int i = 1; i < 8; i++) bm = fmaxf(bm, red[i]);
    __syncthreads();

    float e0 = __expf(x.x - bm), e1 = __expf(x.y - bm);
    float e2 = __expf(x.z - bm), e3 = __expf(x.w - bm);
    float s = e0 + e1 + e2 + e3;
    #pragma unroll
    for (int o = 16; o > 0; o >>= 1)
        s += __shfl_xor_sync(0xffffffffu, s, o);
    if ((tid & 31) == 0) red[tid >> 5] = s;
    __syncthreads();
    float bs = 0.f;
    #pragma unroll
    for (int i = 0; i < 8; i++) bs += red[i];
    float inv = 1.0f / bs;

    uint16_t h0,l0,h1,l1,h2,l2,h3,l3;
    split2(e0 * inv, h0, l0); split2(e1 * inv, h1, l1);
    split2(e2 * inv, h2, l2); split2(e3 * inv, h3, l3);
    size_t o = row * 1024 + tid * 4;
    *reinterpret_cast<uint2*>(Ph + o) =
        make_uint2((uint32_t)h0 | ((uint32_t)h1 << 16),
                   (uint32_t)h2 | ((uint32_t)h3 << 16));
    *reinterpret_cast<uint2*>(Pl + o) =
        make_uint2((uint32_t)l0 | ((uint32_t)l1 << 16),
                   (uint32_t)l2 | ((uint32_t)l3 << 16));
}

// ---------------------------------------------------------------------------
// kernel_launch — inputs: k, v, q, Wk, bk, Wv, bv, Wq, bq, Wo, bo
// Launches 5 & 6 are hmma_gemm (for ncu -s 5 -c 1 with unknown harness offset)
// ---------------------------------------------------------------------------
extern "C" void kernel_launch(void* const* d_in, const int* in_sizes, int n_in,
                              void* d_out, int out_size) {
    (void)in_sizes; (void)n_in; (void)out_size;
    const float* k  = (const float*)d_in[0];
    const float* v  = (const float*)d_in[1];
    const float* q  = (const float*)d_in[2];
    const float* Wk = (const float*)d_in[3];
    const float* bk = (const float*)d_in[4];
    const float* Wv = (const float*)d_in[5];
    const float* bv = (const float*)d_in[6];
    const float* Wq = (const float*)d_in[7];
    const float* bq = (const float*)d_in[8];
    const float* Wo = (const float*)d_in[9];
    const float* bo = (const float*)d_in[10];
    float* out = (float*)d_out;

    cudaFuncSetAttribute(hmma_gemm<true, 1, false>,
        cudaFuncAttributeMaxDynamicSharedMemorySize, GSMEM);
    cudaFuncSetAttribute(hmma_gemm<true, 2, false>,
        cudaFuncAttributeMaxDynamicSharedMemorySize, GSMEM);
    cudaFuncSetAttribute(hmma_gemm<false, 0, false>,
        cudaFuncAttributeMaxDynamicSharedMemorySize, GSMEM);
    cudaFuncSetAttribute(hmma_gemm<false, 1, false>,
        cudaFuncAttributeMaxDynamicSharedMemorySize, GSMEM);
    cudaFuncSetAttribute(hmma_gemm<true, 0, true>,
        cudaFuncAttributeMaxDynamicSharedMemorySize, GSMEM);

    __nv_bfloat16 *xq_h,*xq_l,*xk_h,*xk_l,*xv_h,*xv_l;
    __nv_bfloat16 *wq_h,*wq_l,*wk_h,*wk_l,*wv_h,*wv_l,*wop_h,*wop_l;
    __nv_bfloat16 *qp_h,*qp_l,*kp_h,*kp_l,*vt_h,*vt_l,*ph,*pl,*ot_h,*ot_l;
    float *P;
    cudaGetSymbolAddress((void**)&xq_h, g_xq_hi); cudaGetSymbolAddress((void**)&xq_l, g_xq_lo);
    cudaGetSymbolAddress((void**)&xk_h, g_xk_hi); cudaGetSymbolAddress((void**)&xk_l, g_xk_lo);
    cudaGetSymbolAddress((void**)&xv_h, g_xv_hi); cudaGetSymbolAddress((void**)&xv_l, g_xv_lo);
    cudaGetSymbolAddress((void**)&wq_h, g_wq_hi); cudaGetSymbolAddress((void**)&wq_l, g_wq_lo);
    cudaGetSymbolAddress((void**)&wk_h, g_wk_hi); cudaGetSymbolAddress((void**)&wk_l, g_wk_lo);
    cudaGetSymbolAddress((void**)&wv_h, g_wv_hi); cudaGetSymbolAddress((void**)&wv_l, g_wv_lo);
    cudaGetSymbolAddress((void**)&wop_h,g_wop_hi);cudaGetSymbolAddress((void**)&wop_l,g_wop_lo);
    cudaGetSymbolAddress((void**)&qp_h, g_qp_hi); cudaGetSymbolAddress((void**)&qp_l, g_qp_lo);
    cudaGetSymbolAddress((void**)&kp_h, g_kp_hi); cudaGetSymbolAddress((void**)&kp_l, g_kp_lo);
    cudaGetSymbolAddress((void**)&vt_h, g_vt_hi); cudaGetSymbolAddress((void**)&vt_l, g_vt_lo);
    cudaGetSymbolAddress((void**)&ph,   g_phi);   cudaGetSymbolAddress((void**)&pl,   g_plo);
    cudaGetSymbolAddress((void**)&ot_h, g_ot_hi); cudaGetSymbolAddress((void**)&ot_l, g_ot_lo);
    cudaGetSymbolAddress((void**)&P,    g_P);

    dim3 gproj(Dn / 128, Mn / 128, Hn);

    // launches 1-4: minimal splits for Q/K projections
    conv_hl<<<(unsigned)(XEL / 1024), 256>>>(q,  xq_h, xq_l);
    conv_hl<<<(unsigned)(WEL / 1024), 256>>>(Wq, wq_h, wq_l);
    conv_hl<<<(unsigned)(XEL / 1024), 256>>>(k,  xk_h, xk_l);
    conv_hl<<<(unsigned)(WEL / 1024), 256>>>(Wk, wk_h, wk_l);

    // launches 5 & 6: Q / K projection GEMMs (ncu target)
    hmma_gemm<true, 1, false><<<gproj, 256, GSMEM>>>(
        xq_h, xq_l, wq_h, wq_l, bq, nullptr, qp_h, qp_l,
        Dn, Dn, Dn, Dn, 0, (size_t)Dn * Dn, (size_t)Dn, (size_t)Mn * Dn, 1.0f);
    hmma_gemm<true, 1, false><<<gproj, 256, GSMEM>>>(
        xk_h, xk_l, wk_h, wk_l, bk, nullptr, kp_h, kp_l,
        Dn, Dn, Dn, Dn, 0, (size_t)Dn * Dn, (size_t)Dn, (size_t)Mn * Dn, 1.0f);

    // remaining splits
    conv_hl<<<(unsigned)(XEL / 1024), 256>>>(v,  xv_h, xv_l);
    conv_hl<<<(unsigned)(WEL / 1024), 256>>>(Wv, wv_h, wv_l);
    conv_wo_p<<<(unsigned)(WEL / 256), 256>>>(Wo, wop_h, wop_l);

    // V projection -> transposed Vt hi/lo directly (OUTM=2)
    hmma_gemm<true, 2, false><<<gproj, 256, GSMEM>>>(
        xv_h, xv_l, wv_h, wv_l, bv, nullptr, vt_h, vt_l,
        Dn, Dn, Dn, Dn, 0, (size_t)Dn * Dn, (size_t)Dn, 0, 1.0f);

    // scores S = Qp @ Kp^T / sqrt(D)  (z = h*B+b)
    const float inv_scale = 1.0f / sqrtf((float)Dn);
    dim3 gsc(Nn / 128, Nn / 128, Hn * Bn);
    hmma_gemm<false, 0, false><<<gsc, 256, GSMEM>>>(
        qp_h, qp_l, kp_h, kp_l, nullptr, P, nullptr, nullptr,
        Nn, Dn, Dn, Dn, (size_t)Nn * Dn, (size_t)Nn * Dn, 0, (size_t)Nn * Nn,
        inv_scale);

    // softmax -> hi/lo
    softmax1024_hl<<<Hn * Bn * Nn, 256>>>(P, ph, pl);

    // O = P @ Vt^T  -> ot hi/lo in [h][m][d] layout (z*sC matches exactly)
    dim3 gpv(Dn / 128, Nn / 128, Hn * Bn);
    hmma_gemm<false, 1, false><<<gpv, 256, GSMEM>>>(
        ph, pl, vt_h, vt_l, nullptr, nullptr, ot_h, ot_l,
        Dn, Nn, Nn, Nn, (size_t)Nn * Nn, (size_t)Dn * Nn, 0, (size_t)Nn * Dn,
        1.0f);

    // output projection: rep = ot(h-blocked) @ wo_p^T + bo   (AHB A addressing)
    dim3 gfin(Dn / 128, Mn / 128, 1);
    hmma_gemm<true, 0, true><<<gfin, 256, GSMEM>>>(
        ot_h, ot_l, wop_h, wop_l, bo, out, nullptr, nullptr,
        Dn, Hn * Dn, Dn /*lda=512*/, Hn * Dn /*ldb=4096*/, 0, 0, 0, 0, 1.0f);
}

// round 6
// speedup vs baseline: 2.5155x; 1.1163x over previous
#include <cuda_runtime.h>
#include <cuda_bf16.h>
#include <math.h>
#include <stdint.h>

// ---------------------------------------------------------------------------
// Problem constants
// ---------------------------------------------------------------------------
constexpr int Hn = 8, Bn = 16, Nn = 1024, Dn = 512;
constexpr int Mn = Bn * Nn;                               // 16384
constexpr size_t XEL  = (size_t)Mn * Dn;                  // 8,388,608
constexpr size_t WEL  = (size_t)Hn * Dn * Dn;             // 2,097,152
constexpr size_t PROJ = (size_t)Hn * Mn * Dn;             // 67,108,864
constexpr size_t PEL  = (size_t)Hn * Bn * Nn * Nn;        // 134,217,728
constexpr size_t AHBLK = (size_t)Mn * Dn;                 // h-block stride in ot

// ---------------------------------------------------------------------------
// Scratch (__device__ globals — allocation-free)
// ---------------------------------------------------------------------------
__device__ __nv_bfloat16 g_xq_hi[XEL], g_xq_lo[XEL];
__device__ __nv_bfloat16 g_xk_hi[XEL], g_xk_lo[XEL];
__device__ __nv_bfloat16 g_xv_hi[XEL], g_xv_lo[XEL];
__device__ __nv_bfloat16 g_wqt_hi[WEL], g_wqt_lo[WEL];    // Wq^T per head
__device__ __nv_bfloat16 g_wkt_hi[WEL], g_wkt_lo[WEL];    // Wk^T per head
__device__ __nv_bfloat16 g_mt_hi[WEL], g_mt_lo[WEL];      // Mt = Wk^T Wq
__device__ __nv_bfloat16 g_wv_hi[WEL], g_wv_lo[WEL];
__device__ __nv_bfloat16 g_wop_hi[WEL], g_wop_lo[WEL];    // permuted Wo
__device__ __nv_bfloat16 g_qp_hi[PROJ], g_qp_lo[PROJ];    // q~ = q @ Mt^T
__device__ __nv_bfloat16 g_vt_hi[PROJ], g_vt_lo[PROJ];    // V' transposed [z][d][n]
__device__ float         g_P[PEL];
__device__ __nv_bfloat16 g_phi[PEL], g_plo[PEL];
__device__ __nv_bfloat16 g_ot_hi[PROJ], g_ot_lo[PROJ];    // PV out [h][m][d]
__device__ float         g_wvec[Hn * Dn];                 // Wk^T bq per head
__device__ float         g_colv[(size_t)Hn * Bn * Nn];    // scaled col terms

// ---------------------------------------------------------------------------
// Helpers
// ---------------------------------------------------------------------------
__device__ __forceinline__ uint32_t s2u(const void* p) {
    uint32_t a;
    asm("{ .reg .u64 t; cvta.to.shared.u64 t, %1; cvt.u32.u64 %0, t; }"
        : "=r"(a) : "l"(p));
    return a;
}

__device__ __forceinline__ void cp16(uint32_t saddr, const void* gaddr) {
    asm volatile("cp.async.cg.shared.global [%0], [%1], 16;"
                 :: "r"(saddr), "l"(gaddr) : "memory");
}
__device__ __forceinline__ void cp_commit() {
    asm volatile("cp.async.commit_group;" ::: "memory");
}
template <int N>
__device__ __forceinline__ void cp_wait() {
    asm volatile("cp.async.wait_group %0;" :: "n"(N) : "memory");
}

__device__ __forceinline__ void ldsm4(uint32_t* r, uint32_t addr) {
    asm volatile("ldmatrix.sync.aligned.m8n8.x4.shared.b16 {%0,%1,%2,%3}, [%4];"
        : "=r"(r[0]), "=r"(r[1]), "=r"(r[2]), "=r"(r[3]) : "r"(addr));
}

__device__ __forceinline__ void mma16816(float* d, const uint32_t* a,
                                         uint32_t b0, uint32_t b1) {
    asm volatile(
        "mma.sync.aligned.m16n8k16.row.col.f32.bf16.bf16.f32 "
        "{%0,%1,%2,%3}, {%4,%5,%6,%7}, {%8,%9}, {%0,%1,%2,%3};"
        : "+f"(d[0]), "+f"(d[1]), "+f"(d[2]), "+f"(d[3])
        : "r"(a[0]), "r"(a[1]), "r"(a[2]), "r"(a[3]), "r"(b0), "r"(b1));
}

__device__ __forceinline__ void split2(float x, uint16_t& h, uint16_t& l) {
    __nv_bfloat16 hb = __float2bfloat16(x);
    __nv_bfloat16 lb = __float2bfloat16(x - __bfloat162float(hb));
    h = *reinterpret_cast<uint16_t*>(&hb);
    l = *reinterpret_cast<uint16_t*>(&lb);
}

// XOR chunk swizzle for 64B rows (4 x 16B chunks): conflict-free ldmatrix.
__device__ __forceinline__ uint32_t swz(uint32_t r, uint32_t ch) {
    return r * 64u + ((ch ^ ((r >> 1) & 3u)) << 4);
}

// ---------------------------------------------------------------------------
// bf16-split batched GEMM via mma.sync (HMMA):
//   C[z] = alpha * (Ahi+Alo)[z] @ (Bhi+Blo)[z]^T (+ bias[z])
//   3 products: hi*hi + hi*lo + lo*hi (fp32 accum)
// OUTM : 0=fp32 C, 1=bf16 hi/lo C, 2=bf16 hi/lo TRANSPOSED (Vt[z*16+b][col][n])
// AHB  : A column h-blocked (final projection reads ot in [h][m][d])
// BMODB: B z-index = z & 15 (B shared across heads, z = h*16+b)
// Tile 128x128, BK=32, 8 warps, 3-stage cp.async pipeline, 1 sync/chunk.
// ---------------------------------------------------------------------------
constexpr int ROWB   = 64;                       // bytes per SMEM row
constexpr int TILE_B = 128 * ROWB;               // 8192 B per tile
constexpr int STAGE  = 4 * TILE_B;               // Ahi,Alo,Bhi,Blo = 32768
constexpr int GSMEM  = 3 * STAGE + 512;          // 98816

template <bool BIAS, int OUTM, bool AHB, bool BMODB>
__global__ void __launch_bounds__(256, 2) hmma_gemm(
    const __nv_bfloat16* __restrict__ Ahi, const __nv_bfloat16* __restrict__ Alo,
    const __nv_bfloat16* __restrict__ Bhi, const __nv_bfloat16* __restrict__ Blo,
    const float* __restrict__ biasg,
    float* __restrict__ Cf,
    __nv_bfloat16* __restrict__ Chi, __nv_bfloat16* __restrict__ Clo,
    int N, int K, int lda, int ldb,
    size_t sA, size_t sB, size_t sBias, size_t sC, float alpha)
{
    extern __shared__ __align__(16) char smem[];
    const uint32_t sb = s2u(smem);
    float* sbias = reinterpret_cast<float*>(smem + 3 * STAGE);

    const int tid  = threadIdx.x;
    const int wid  = tid >> 5, lane = tid & 31;
    const int wr   = wid >> 2, wc = wid & 3;      // warp grid 2x4
    const int col0 = blockIdx.x * 128, row0 = blockIdx.y * 128;
    const size_t z = blockIdx.z;
    const size_t zb = BMODB ? (z & 15) : z;
    Ahi += z * sA; Alo += z * sA; Bhi += zb * sB; Blo += zb * sB;

    if (BIAS && tid < 128) sbias[tid] = biasg[z * sBias + col0 + tid];

    const int nCh = K >> 5;          // BK = 32

    auto prefetch = [&](int c) {
        const int k0 = c << 5;
        const uint32_t boff = sb + (uint32_t)(c % 3) * STAGE;
        size_t aoff;
        if (AHB) aoff = ((size_t)(k0 >> 9)) * AHBLK + (size_t)(k0 & 511);
        else     aoff = (size_t)k0;
        #pragma unroll
        for (int t = 0; t < 4; t++) {
            const __nv_bfloat16* s = (t == 0) ? Ahi : (t == 1) ? Alo
                                   : (t == 2) ? Bhi : Blo;
            const uint32_t tb = boff + t * TILE_B;
            #pragma unroll
            for (int i = 0; i < 2; i++) {
                uint32_t idx = (uint32_t)(i * 256 + tid);   // 0..511
                uint32_t r = idx >> 2, ch = idx & 3;
                const __nv_bfloat16* g;
                if (t < 2) g = s + aoff + (size_t)(row0 + r) * lda + ch * 8;
                else       g = s + (size_t)k0 + (size_t)(col0 + r) * ldb + ch * 8;
                cp16(tb + swz(r, ch), g);
            }
        }
        cp_commit();
    };

    float acc[4][4][4] = {};

    prefetch(0);
    prefetch(1);

    for (int c = 0; c < nCh; ++c) {
        if (c + 1 < nCh) cp_wait<1>(); else cp_wait<0>();
        __syncthreads();
        if (c + 2 < nCh) prefetch(c + 2);

        const uint32_t boff = sb + (uint32_t)(c % 3) * STAGE;
        const uint32_t aHiB = boff,              aLoB = boff + TILE_B;
        const uint32_t bHiB = boff + 2 * TILE_B, bLoB = boff + 3 * TILE_B;
        const uint32_t lrow = (uint32_t)(lane & 15), lhalf = (uint32_t)(lane >> 4);

        #pragma unroll
        for (int ks = 0; ks < 2; ks++) {
            const uint32_t kch = (uint32_t)ks * 2u + lhalf;   // 16B chunk index
            uint32_t bh[4][2], bl[4][2];
            #pragma unroll
            for (int np = 0; np < 2; np++) {
                uint32_t r = (uint32_t)(wc * 32 + np * 16) + lrow;
                uint32_t t[4];
                ldsm4(t, bHiB + swz(r, kch));
                bh[np*2+0][0] = t[0]; bh[np*2+0][1] = t[2];
                bh[np*2+1][0] = t[1]; bh[np*2+1][1] = t[3];
                ldsm4(t, bLoB + swz(r, kch));
                bl[np*2+0][0] = t[0]; bl[np*2+0][1] = t[2];
                bl[np*2+1][0] = t[1]; bl[np*2+1][1] = t[3];
            }
            #pragma unroll
            for (int mt = 0; mt < 4; mt++) {
                uint32_t r = (uint32_t)(wr * 64 + mt * 16) + lrow;
                uint32_t ah[4], al[4];
                ldsm4(ah, aHiB + swz(r, kch));
                ldsm4(al, aLoB + swz(r, kch));
                #pragma unroll
                for (int nt = 0; nt < 4; nt++) {
                    mma16816(acc[mt][nt], ah, bh[nt][0], bh[nt][1]);
                    mma16816(acc[mt][nt], ah, bl[nt][0], bl[nt][1]);
                    mma16816(acc[mt][nt], al, bh[nt][0], bh[nt][1]);
                }
            }
        }
    }

    // ---- epilogue ----
    const int qr = lane >> 2, qc = lane & 3;
    #pragma unroll
    for (int mt = 0; mt < 4; mt++) {
        #pragma unroll
        for (int nt = 0; nt < 4; nt++) {
            const int lcol = wc * 32 + nt * 8 + qc * 2;
            const float b0 = BIAS ? sbias[lcol]     : 0.f;
            const float b1 = BIAS ? sbias[lcol + 1] : 0.f;
            const int r0 = row0 + wr * 64 + mt * 16 + qr;
            const float v00 = alpha * acc[mt][nt][0] + b0;
            const float v01 = alpha * acc[mt][nt][1] + b1;
            const float v10 = alpha * acc[mt][nt][2] + b0;
            const float v11 = alpha * acc[mt][nt][3] + b1;
            if (OUTM == 0) {
                float* cp = Cf + z * sC + (size_t)r0 * N + col0 + lcol;
                *reinterpret_cast<float2*>(cp)            = make_float2(v00, v01);
                *reinterpret_cast<float2*>(cp + 8ull * N) = make_float2(v10, v11);
            } else if (OUTM == 1) {
                uint16_t h0,l0,h1,l1,h2,l2,h3,l3;
                split2(v00, h0, l0); split2(v01, h1, l1);
                split2(v10, h2, l2); split2(v11, h3, l3);
                size_t o0 = z * sC + (size_t)r0 * N + col0 + lcol;
                size_t o1 = o0 + 8ull * N;
                *reinterpret_cast<uint32_t*>(
                    reinterpret_cast<uint16_t*>(Chi) + o0) = (uint32_t)h0 | ((uint32_t)h1 << 16);
                *reinterpret_cast<uint32_t*>(
                    reinterpret_cast<uint16_t*>(Clo) + o0) = (uint32_t)l0 | ((uint32_t)l1 << 16);
                *reinterpret_cast<uint32_t*>(
                    reinterpret_cast<uint16_t*>(Chi) + o1) = (uint32_t)h2 | ((uint32_t)h3 << 16);
                *reinterpret_cast<uint32_t*>(
                    reinterpret_cast<uint16_t*>(Clo) + o1) = (uint32_t)l2 | ((uint32_t)l3 << 16);
            } else {
                // OUTM == 2: transposed store  Vt[z*16 + b][col][n]
                uint16_t* oh = reinterpret_cast<uint16_t*>(Chi);
                uint16_t* ol = reinterpret_cast<uint16_t*>(Clo);
                const size_t zt = z * (size_t)Bn + (size_t)(row0 >> 10);
                const int n0 = (r0 & 1023);
                const size_t c0a = (zt * 512 + (size_t)(col0 + lcol)) * 1024;
                const size_t c1a = c0a + 1024;       // col+1
                uint16_t h, l;
                split2(v00, h, l); oh[c0a + n0]     = h; ol[c0a + n0]     = l;
                split2(v01, h, l); oh[c1a + n0]     = h; ol[c1a + n0]     = l;
                split2(v10, h, l); oh[c0a + n0 + 8] = h; ol[c0a + n0 + 8] = l;
                split2(v11, h, l); oh[c1a + n0 + 8] = h; ol[c1a + n0 + 8] = l;
            }
        }
    }
}

// ---------------------------------------------------------------------------
// fp32 -> bf16 hi/lo elementwise split
// ---------------------------------------------------------------------------
__global__ void conv_hl(const float* __restrict__ s,
                        __nv_bfloat16* __restrict__ h,
                        __nv_bfloat16* __restrict__ l) {
    size_t i = ((size_t)blockIdx.x * 256 + threadIdx.x) * 4;
    float4 v = *reinterpret_cast<const float4*>(s + i);
    uint16_t h0,l0,h1,l1,h2,l2,h3,l3;
    split2(v.x, h0, l0); split2(v.y, h1, l1);
    split2(v.z, h2, l2); split2(v.w, h3, l3);
    *reinterpret_cast<uint2*>(h + i) =
        make_uint2((uint32_t)h0 | ((uint32_t)h1 << 16),
                   (uint32_t)h2 | ((uint32_t)h3 << 16));
    *reinterpret_cast<uint2*>(l + i) =
        make_uint2((uint32_t)l0 | ((uint32_t)l1 << 16),
                   (uint32_t)l2 | ((uint32_t)l3 << 16));
}

// ---------------------------------------------------------------------------
// Per-head 512x512 transpose + split: out[h][d][e] = in[h][e][d]
// ---------------------------------------------------------------------------
__global__ void transpose_w_hl(const float* __restrict__ in,
                               __nv_bfloat16* __restrict__ oh,
                               __nv_bfloat16* __restrict__ ol) {
    __shared__ float t[32][33];
    const size_t z = blockIdx.z;
    in += z * (size_t)(Dn * Dn);
    oh += z * (size_t)(Dn * Dn);
    ol += z * (size_t)(Dn * Dn);
    const int x0 = blockIdx.x * 32;   // d
    const int y0 = blockIdx.y * 32;   // e
    #pragma unroll
    for (int i = 0; i < 4; i++)
        t[threadIdx.y + i * 8][threadIdx.x] =
            in[(size_t)(y0 + threadIdx.y + i * 8) * Dn + x0 + threadIdx.x];
    __syncthreads();
    #pragma unroll
    for (int i = 0; i < 4; i++) {
        float v = t[threadIdx.x][threadIdx.y + i * 8];
        uint16_t h, l;
        split2(v, h, l);
        size_t o = (size_t)(x0 + threadIdx.y + i * 8) * Dn + y0 + threadIdx.x;
        reinterpret_cast<uint16_t*>(oh)[o] = h;
        reinterpret_cast<uint16_t*>(ol)[o] = l;
    }
}

// ---------------------------------------------------------------------------
// Wo permute + split: wo_p[o][h*512+d] = Wo[o][d*8+h]
// ---------------------------------------------------------------------------
__global__ void conv_wo_p(const float* __restrict__ Wo,
                          __nv_bfloat16* __restrict__ oh,
                          __nv_bfloat16* __restrict__ ol) {
    size_t idx = (size_t)blockIdx.x * 256 + threadIdx.x;   // o*4096 + g
    int g = (int)(idx & 4095);
    size_t o = idx >> 12;
    int f = ((g & 511) << 3) | (g >> 9);
    float v = Wo[(o << 12) + f];
    uint16_t h, l;
    split2(v, h, l);
    reinterpret_cast<uint16_t*>(oh)[idx] = h;
    reinterpret_cast<uint16_t*>(ol)[idx] = l;
}

// ---------------------------------------------------------------------------
// wvec[h][d] = sum_e bq[h][e] * Wk[h][e][d]   (block = head, thread = d)
// ---------------------------------------------------------------------------
__global__ void wvec_kernel(const float* __restrict__ Wk,
                            const float* __restrict__ bq,
                            float* __restrict__ wvec) {
    const int h = blockIdx.x, d = threadIdx.x;
    const float* wk = Wk + (size_t)h * Dn * Dn;
    const float* b  = bq + (size_t)h * Dn;
    float s = 0.f;
    for (int e = 0; e < Dn; e++) s += b[e] * wk[(size_t)e * Dn + d];
    wvec[h * Dn + d] = s;
}

// ---------------------------------------------------------------------------
// colv[(h*16+b)][j] = inv_scale * k[b][j] . wvec[h]
// block = (b*1024+j), 256 threads: 8 warps, warp w handles head w.
// ---------------------------------------------------------------------------
__global__ void colv_kernel(const float* __restrict__ k,
                            const float* __restrict__ wvec,
                            float* __restrict__ colv, float inv_scale) {
    __shared__ float kr[Dn];
    const size_t bj = blockIdx.x;            // b*1024 + j
    const int tid = threadIdx.x, w = tid >> 5, lane = tid & 31;
    const float* kp = k + bj * Dn;
    #pragma unroll
    for (int i = 0; i < 2; i++) kr[tid + i * 256] = kp[tid + i * 256];
    __syncthreads();
    const float* wv = wvec + w * Dn;
    float s = 0.f;
    #pragma unroll
    for (int t = 0; t < 16; t++) {
        int d = lane + t * 32;
        s += kr[d] * wv[d];
    }
    #pragma unroll
    for (int o = 16; o > 0; o >>= 1)
        s += __shfl_xor_sync(0xffffffffu, s, o);
    if (lane == 0) {
        size_t b = bj >> 10, j = bj & 1023;
        colv[((size_t)w * 16 + b) * 1024 + j] = s * inv_scale;
    }
}

// ---------------------------------------------------------------------------
// Softmax over 1024-wide rows (+ per-column bias term) -> bf16 hi/lo
// ---------------------------------------------------------------------------
__global__ void softmax1024_hl(const float* __restrict__ P,
                               const float* __restrict__ colv,
                               __nv_bfloat16* __restrict__ Ph,
                               __nv_bfloat16* __restrict__ Pl) {
    __shared__ float red[8];
    const size_t row = blockIdx.x;
    const size_t z = row >> 10;
    const float* p = P + row * 1024;
    const int tid = threadIdx.x;

    float4 x = *reinterpret_cast<const float4*>(p + tid * 4);
    float4 cv = *reinterpret_cast<const float4*>(colv + z * 1024 + tid * 4);
    x.x += cv.x; x.y += cv.y; x.z += cv.z; x.w += cv.w;

    float m = fmaxf(fmaxf(x.x, x.y), fmaxf(x.z, x.w));
    #pragma unroll
    for (int o = 16; o > 0; o >>= 1)
        m = fmaxf(m, __shfl_xor_sync(0xffffffffu, m, o));
    if ((tid & 31) == 0) red[tid >> 5] = m;
    __syncthreads();
    float bm = red[0];
    #pragma unroll
    for (int i = 1; i < 8; i++) bm = fmaxf(bm, red[i]);
    __syncthreads();

    float e0 = __expf(x.x - bm), e1 = __expf(x.y - bm);
    float e2 = __expf(x.z - bm), e3 = __expf(x.w - bm);
    float s = e0 + e1 + e2 + e3;
    #pragma unroll
    for (int o = 16; o > 0; o >>= 1)
        s += __shfl_xor_sync(0xffffffffu, s, o);
    if ((tid & 31) == 0) red[tid >> 5] = s;
    __syncthreads();
    float bs = 0.f;
    #pragma unroll
    for (int i = 0; i < 8; i++) bs += red[i];
    float inv = 1.0f / bs;

    uint16_t h0,l0,h1,l1,h2,l2,h3,l3;
    split2(e0 * inv, h0, l0); split2(e1 * inv, h1, l1);
    split2(e2 * inv, h2, l2); split2(e3 * inv, h3, l3);
    size_t o = row * 1024 + tid * 4;
    *reinterpret_cast<uint2*>(Ph + o) =
        make_uint2((uint32_t)h0 | ((uint32_t)h1 << 16),
                   (uint32_t)h2 | ((uint32_t)h3 << 16));
    *reinterpret_cast<uint2*>(Pl + o) =
        make_uint2((uint32_t)l0 | ((uint32_t)l1 << 16),
                   (uint32_t)l2 | ((uint32_t)l3 << 16));
}

// ---------------------------------------------------------------------------
// kernel_launch — inputs: k, v, q, Wk, bk, Wv, bv, Wq, bq, Wo, bo
// ---------------------------------------------------------------------------
extern "C" void kernel_launch(void* const* d_in, const int* in_sizes, int n_in,
                              void* d_out, int out_size) {
    (void)in_sizes; (void)n_in; (void)out_size;
    const float* k  = (const float*)d_in[0];
    const float* v  = (const float*)d_in[1];
    const float* q  = (const float*)d_in[2];
    const float* Wk = (const float*)d_in[3];
    const float* Wv = (const float*)d_in[5];
    const float* bv = (const float*)d_in[6];
    const float* Wq = (const float*)d_in[7];
    const float* bq = (const float*)d_in[8];
    const float* Wo = (const float*)d_in[9];
    const float* bo = (const float*)d_in[10];
    float* out = (float*)d_out;

    cudaFuncSetAttribute(hmma_gemm<false, 1, false, false>,
        cudaFuncAttributeMaxDynamicSharedMemorySize, GSMEM);
    cudaFuncSetAttribute(hmma_gemm<true, 2, false, false>,
        cudaFuncAttributeMaxDynamicSharedMemorySize, GSMEM);
    cudaFuncSetAttribute(hmma_gemm<false, 0, false, true>,
        cudaFuncAttributeMaxDynamicSharedMemorySize, GSMEM);
    cudaFuncSetAttribute(hmma_gemm<true, 0, true, false>,
        cudaFuncAttributeMaxDynamicSharedMemorySize, GSMEM);

    __nv_bfloat16 *xq_h,*xq_l,*xk_h,*xk_l,*xv_h,*xv_l;
    __nv_bfloat16 *wqt_h,*wqt_l,*wkt_h,*wkt_l,*mt_h,*mt_l;
    __nv_bfloat16 *wv_h,*wv_l,*wop_h,*wop_l;
    __nv_bfloat16 *qp_h,*qp_l,*vt_h,*vt_l,*ph,*pl,*ot_h,*ot_l;
    float *P,*wvec,*colv;
    cudaGetSymbolAddress((void**)&xq_h, g_xq_hi); cudaGetSymbolAddress((void**)&xq_l, g_xq_lo);
    cudaGetSymbolAddress((void**)&xk_h, g_xk_hi); cudaGetSymbolAddress((void**)&xk_l, g_xk_lo);
    cudaGetSymbolAddress((void**)&xv_h, g_xv_hi); cudaGetSymbolAddress((void**)&xv_l, g_xv_lo);
    cudaGetSymbolAddress((void**)&wqt_h,g_wqt_hi);cudaGetSymbolAddress((void**)&wqt_l,g_wqt_lo);
    cudaGetSymbolAddress((void**)&wkt_h,g_wkt_hi);cudaGetSymbolAddress((void**)&wkt_l,g_wkt_lo);
    cudaGetSymbolAddress((void**)&mt_h, g_mt_hi); cudaGetSymbolAddress((void**)&mt_l, g_mt_lo);
    cudaGetSymbolAddress((void**)&wv_h, g_wv_hi); cudaGetSymbolAddress((void**)&wv_l, g_wv_lo);
    cudaGetSymbolAddress((void**)&wop_h,g_wop_hi);cudaGetSymbolAddress((void**)&wop_l,g_wop_lo);
    cudaGetSymbolAddress((void**)&qp_h, g_qp_hi); cudaGetSymbolAddress((void**)&qp_l, g_qp_lo);
    cudaGetSymbolAddress((void**)&vt_h, g_vt_hi); cudaGetSymbolAddress((void**)&vt_l, g_vt_lo);
    cudaGetSymbolAddress((void**)&ph,   g_phi);   cudaGetSymbolAddress((void**)&pl,   g_plo);
    cudaGetSymbolAddress((void**)&ot_h, g_ot_hi); cudaGetSymbolAddress((void**)&ot_l, g_ot_lo);
    cudaGetSymbolAddress((void**)&P,    g_P);
    cudaGetSymbolAddress((void**)&wvec, g_wvec);
    cudaGetSymbolAddress((void**)&colv, g_colv);

    const float inv_scale = 1.0f / sqrtf((float)Dn);
    const size_t WW = (size_t)Dn * Dn;

    // ---- splits / transposes ----
    transpose_w_hl<<<dim3(16, 16, Hn), dim3(32, 8)>>>(Wq, wqt_h, wqt_l);
    transpose_w_hl<<<dim3(16, 16, Hn), dim3(32, 8)>>>(Wk, wkt_h, wkt_l);
    conv_hl<<<(unsigned)(XEL / 1024), 256>>>(q,  xq_h, xq_l);
    conv_hl<<<(unsigned)(XEL / 1024), 256>>>(k,  xk_h, xk_l);
    conv_hl<<<(unsigned)(XEL / 1024), 256>>>(v,  xv_h, xv_l);
    conv_hl<<<(unsigned)(WEL / 1024), 256>>>(Wv, wv_h, wv_l);
    conv_wo_p<<<(unsigned)(WEL / 256), 256>>>(Wo, wop_h, wop_l);

    // ---- Mt[h] = Wk^T Wq : C[d2][d1] = sum_e wkt[d2][e] wqt[d1][e] ----
    hmma_gemm<false, 1, false, false><<<dim3(4, 4, Hn), 256, GSMEM>>>(
        wkt_h, wkt_l, wqt_h, wqt_l, nullptr, nullptr, mt_h, mt_l,
        Dn, Dn, Dn, Dn, WW, WW, 0, WW, 1.0f);

    // ---- q~ = q @ Mt^T per head ----
    dim3 gproj(Dn / 128, Mn / 128, Hn);
    hmma_gemm<false, 1, false, false><<<gproj, 256, GSMEM>>>(
        xq_h, xq_l, mt_h, mt_l, nullptr, nullptr, qp_h, qp_l,
        Dn, Dn, Dn, Dn, 0, WW, 0, (size_t)Mn * Dn, 1.0f);

    // ---- column bias terms: wvec = Wk^T bq ; colv = k . wvec / scale ----
    wvec_kernel<<<Hn, Dn>>>(Wk, bq, wvec);
    colv_kernel<<<Mn, 256>>>(k, wvec, colv, inv_scale);

    // ---- V projection -> transposed Vt hi/lo directly (OUTM=2) ----
    hmma_gemm<true, 2, false, false><<<gproj, 256, GSMEM>>>(
        xv_h, xv_l, wv_h, wv_l, bv, nullptr, vt_h, vt_l,
        Dn, Dn, Dn, Dn, 0, WW, (size_t)Dn, 0, 1.0f);

    // ---- scores core: P = q~ @ k^T / scale  (z = h*16+b; B = raw k per b) ----
    dim3 gsc(Nn / 128, Nn / 128, Hn * Bn);
    hmma_gemm<false, 0, false, true><<<gsc, 256, GSMEM>>>(
        qp_h, qp_l, xk_h, xk_l, nullptr, P, nullptr, nullptr,
        Nn, Dn, Dn, Dn, (size_t)Nn * Dn, (size_t)Nn * Dn, 0, (size_t)Nn * Nn,
        inv_scale);

    // ---- softmax (+colv) -> hi/lo ----
    softmax1024_hl<<<Hn * Bn * Nn, 256>>>(P, colv, ph, pl);

    // ---- O = P @ Vt^T -> ot hi/lo in [h][m][d] layout ----
    dim3 gpv(Dn / 128, Nn / 128, Hn * Bn);
    hmma_gemm<false, 1, false, false><<<gpv, 256, GSMEM>>>(
        ph, pl, vt_h, vt_l, nullptr, nullptr, ot_h, ot_l,
        Dn, Nn, Nn, Nn, (size_t)Nn * Nn, (size_t)Dn * Nn, 0, (size_t)Nn * Dn,
        1.0f);

    // ---- output projection: rep = ot(h-blocked) @ wo_p^T + bo ----
    dim3 gfin(Dn / 128, Mn / 128, 1);
    hmma_gemm<true, 0, true, false><<<gfin, 256, GSMEM>>>(
        ot_h, ot_l, wop_h, wop_l, bo, out, nullptr, nullptr,
        Dn, Hn * Dn, Dn, Hn * Dn, 0, 0, 0, 0, 1.0f);
}

// round 7
// speedup vs baseline: 3.2983x; 1.3112x over previous
#include <cuda_runtime.h>
#include <cuda_fp16.h>
#include <math.h>
#include <stdint.h>

// ---------------------------------------------------------------------------
// Problem constants
// ---------------------------------------------------------------------------
constexpr int Hn = 8, Bn = 16, Nn = 1024, Dn = 512;
constexpr int Mn = Bn * Nn;                               // 16384
constexpr size_t XEL  = (size_t)Mn * Dn;                  // 8,388,608
constexpr size_t WEL  = (size_t)Hn * Dn * Dn;             // 2,097,152
constexpr size_t PROJ = (size_t)Hn * Mn * Dn;             // 67,108,864
constexpr size_t PEL  = (size_t)Hn * Bn * Nn * Nn;        // 134,217,728
constexpr size_t AHBLK = (size_t)Mn * Dn;                 // h-block stride in ot

// ---------------------------------------------------------------------------
// Scratch (__device__ globals — allocation-free). All fp16 now.
// ---------------------------------------------------------------------------
__device__ __half g_xq_hi[XEL], g_xq_lo[XEL];
__device__ __half g_xk_hi[XEL], g_xk_lo[XEL];
__device__ __half g_xv_hi[XEL], g_xv_lo[XEL];
__device__ __half g_wqt_hi[WEL], g_wqt_lo[WEL];    // Wq^T per head
__device__ __half g_wkt_hi[WEL], g_wkt_lo[WEL];    // Wk^T per head
__device__ __half g_mt_hi[WEL], g_mt_lo[WEL];      // Mt = Wk^T Wq
__device__ __half g_wv_hi[WEL], g_wv_lo[WEL];
__device__ __half g_wop_hi[WEL], g_wop_lo[WEL];    // permuted Wo
__device__ __half g_qp[PROJ];                      // q~ single fp16
__device__ __half g_vt_hi[PROJ], g_vt_lo[PROJ];    // V' transposed [z][d][n]
__device__ float  g_P[PEL];
__device__ __half g_ph[PEL];                       // softmax out, single fp16
__device__ __half g_ot[PROJ];                      // PV out [h][m][d], single
__device__ float  g_wvec[Hn * Dn];                 // Wk^T bq per head
__device__ float  g_colv[(size_t)Hn * Bn * Nn];    // scaled col terms

// ---------------------------------------------------------------------------
// Helpers
// ---------------------------------------------------------------------------
__device__ __forceinline__ uint32_t s2u(const void* p) {
    uint32_t a;
    asm("{ .reg .u64 t; cvta.to.shared.u64 t, %1; cvt.u32.u64 %0, t; }"
        : "=r"(a) : "l"(p));
    return a;
}

__device__ __forceinline__ void cp16(uint32_t saddr, const void* gaddr) {
    asm volatile("cp.async.cg.shared.global [%0], [%1], 16;"
                 :: "r"(saddr), "l"(gaddr) : "memory");
}
__device__ __forceinline__ void cp_commit() {
    asm volatile("cp.async.commit_group;" ::: "memory");
}
template <int N>
__device__ __forceinline__ void cp_wait() {
    asm volatile("cp.async.wait_group %0;" :: "n"(N) : "memory");
}

__device__ __forceinline__ void ldsm4(uint32_t* r, uint32_t addr) {
    asm volatile("ldmatrix.sync.aligned.m8n8.x4.shared.b16 {%0,%1,%2,%3}, [%4];"
        : "=r"(r[0]), "=r"(r[1]), "=r"(r[2]), "=r"(r[3]) : "r"(addr));
}

__device__ __forceinline__ void mma16816(float* d, const uint32_t* a,
                                         uint32_t b0, uint32_t b1) {
    asm volatile(
        "mma.sync.aligned.m16n8k16.row.col.f32.f16.f16.f32 "
        "{%0,%1,%2,%3}, {%4,%5,%6,%7}, {%8,%9}, {%0,%1,%2,%3};"
        : "+f"(d[0]), "+f"(d[1]), "+f"(d[2]), "+f"(d[3])
        : "r"(a[0]), "r"(a[1]), "r"(a[2]), "r"(a[3]), "r"(b0), "r"(b1));
}

__device__ __forceinline__ void split2h(float x, uint16_t& h, uint16_t& l) {
    __half hb = __float2half_rn(x);
    __half lb = __float2half_rn(x - __half2float(hb));
    h = *reinterpret_cast<uint16_t*>(&hb);
    l = *reinterpret_cast<uint16_t*>(&lb);
}
__device__ __forceinline__ uint16_t h1(float x) {
    __half hb = __float2half_rn(x);
    return *reinterpret_cast<uint16_t*>(&hb);
}

// XOR chunk swizzle for 64B rows (4 x 16B chunks): conflict-free ldmatrix.
__device__ __forceinline__ uint32_t swz(uint32_t r, uint32_t ch) {
    return r * 64u + ((ch ^ ((r >> 1) & 3u)) << 4);
}

// ---------------------------------------------------------------------------
// fp16-split batched GEMM via mma.sync (HMMA):
// TERMS=3:  C = alpha*(Ahi+Alo)@(Bhi+Blo)^T, MMAs: ah*bh + ah*bl + al*bh
//           SMEM tiles per stage: Ahi,Alo,Bhi,Blo (4)
// TERMS=2:  C = alpha* A @(Bhi+Blo)^T (A single fp16), MMAs: a*bh + a*bl
//           SMEM tiles per stage: A,Bhi,Blo (3)
// OUTM : 0=fp32 C, 1=fp16 hi/lo C, 2=fp16 hi/lo TRANSPOSED (Vt), 3=single fp16
// AHB  : A column h-blocked (final projection reads ot in [h][m][d])
// BMODB: B z-index = z & 15 (B shared across heads, z = h*16+b)
// Tile 128x128, BK=32, 8 warps, 3-stage cp.async pipeline, 1 sync/chunk.
// ---------------------------------------------------------------------------
constexpr int TILE_B = 128 * 64;                 // 8192 B per tile

template <int TERMS> struct Cfg {
    static constexpr int NT    = (TERMS == 3) ? 4 : 3;
    static constexpr int STAGE = NT * TILE_B;
    static constexpr int SMEM  = 3 * STAGE + 512;
};

template <int TERMS, bool BIAS, int OUTM, bool AHB, bool BMODB>
__global__ void __launch_bounds__(256, 2) hmma_gemm(
    const __half* __restrict__ Ahi, const __half* __restrict__ Alo,
    const __half* __restrict__ Bhi, const __half* __restrict__ Blo,
    const float* __restrict__ biasg,
    float* __restrict__ Cf,
    __half* __restrict__ Chi, __half* __restrict__ Clo,
    int N, int K, int lda, int ldb,
    size_t sA, size_t sB, size_t sBias, size_t sC, float alpha)
{
    constexpr int STAGE = Cfg<TERMS>::STAGE;
    extern __shared__ __align__(16) char smem[];
    const uint32_t sb = s2u(smem);
    float* sbias = reinterpret_cast<float*>(smem + 3 * STAGE);

    const int tid  = threadIdx.x;
    const int wid  = tid >> 5, lane = tid & 31;
    const int wr   = wid >> 2, wc = wid & 3;      // warp grid 2x4
    const int col0 = blockIdx.x * 128, row0 = blockIdx.y * 128;
    const size_t z = blockIdx.z;
    const size_t zb = BMODB ? (z & 15) : z;
    Ahi += z * sA; if (TERMS == 3) Alo += z * sA;
    Bhi += zb * sB; Blo += zb * sB;

    if (BIAS && tid < 128) sbias[tid] = biasg[z * sBias + col0 + tid];

    const int nCh = K >> 5;          // BK = 32

    auto prefetch = [&](int c) {
        const int k0 = c << 5;
        const uint32_t boff = sb + (uint32_t)(c % 3) * STAGE;
        size_t aoff;
        if (AHB) aoff = ((size_t)(k0 >> 9)) * AHBLK + (size_t)(k0 & 511);
        else     aoff = (size_t)k0;
        constexpr int NT = Cfg<TERMS>::NT;
        constexpr int NA = (TERMS == 3) ? 2 : 1;
        #pragma unroll
        for (int t = 0; t < NT; t++) {
            const __half* s;
            if (TERMS == 3) s = (t == 0) ? Ahi : (t == 1) ? Alo
                              : (t == 2) ? Bhi : Blo;
            else            s = (t == 0) ? Ahi : (t == 1) ? Bhi : Blo;
            const uint32_t tb = boff + t * TILE_B;
            #pragma unroll
            for (int i = 0; i < 2; i++) {
                uint32_t idx = (uint32_t)(i * 256 + tid);   // 0..511
                uint32_t r = idx >> 2, ch = idx & 3;
                const __half* g;
                if (t < NA) g = s + aoff + (size_t)(row0 + r) * lda + ch * 8;
                else        g = s + (size_t)k0 + (size_t)(col0 + r) * ldb + ch * 8;
                cp16(tb + swz(r, ch), g);
            }
        }
        cp_commit();
    };

    float acc[4][4][4] = {};

    prefetch(0);
    prefetch(1);

    for (int c = 0; c < nCh; ++c) {
        if (c + 1 < nCh) cp_wait<1>(); else cp_wait<0>();
        __syncthreads();
        if (c + 2 < nCh) prefetch(c + 2);

        const uint32_t boff = sb + (uint32_t)(c % 3) * STAGE;
        const uint32_t aHiB = boff;
        const uint32_t aLoB = boff + TILE_B;                 // TERMS==3 only
        const uint32_t bHiB = boff + ((TERMS == 3) ? 2 : 1) * TILE_B;
        const uint32_t bLoB = boff + ((TERMS == 3) ? 3 : 2) * TILE_B;
        const uint32_t lrow = (uint32_t)(lane & 15), lhalf = (uint32_t)(lane >> 4);

        #pragma unroll
        for (int ks = 0; ks < 2; ks++) {
            const uint32_t kch = (uint32_t)ks * 2u + lhalf;   // 16B chunk index
            uint32_t bh[4][2], bl[4][2];
            #pragma unroll
            for (int np = 0; np < 2; np++) {
                uint32_t r = (uint32_t)(wc * 32 + np * 16) + lrow;
                uint32_t t[4];
                ldsm4(t, bHiB + swz(r, kch));
                bh[np*2+0][0] = t[0]; bh[np*2+0][1] = t[2];
                bh[np*2+1][0] = t[1]; bh[np*2+1][1] = t[3];
                ldsm4(t, bLoB + swz(r, kch));
                bl[np*2+0][0] = t[0]; bl[np*2+0][1] = t[2];
                bl[np*2+1][0] = t[1]; bl[np*2+1][1] = t[3];
            }
            #pragma unroll
            for (int mt = 0; mt < 4; mt++) {
                uint32_t r = (uint32_t)(wr * 64 + mt * 16) + lrow;
                uint32_t ah[4], al[4];
                ldsm4(ah, aHiB + swz(r, kch));
                if (TERMS == 3) ldsm4(al, aLoB + swz(r, kch));
                #pragma unroll
                for (int nt = 0; nt < 4; nt++) {
                    mma16816(acc[mt][nt], ah, bh[nt][0], bh[nt][1]);
                    mma16816(acc[mt][nt], ah, bl[nt][0], bl[nt][1]);
                    if (TERMS == 3)
                        mma16816(acc[mt][nt], al, bh[nt][0], bh[nt][1]);
                }
            }
        }
    }

    // ---- epilogue ----
    const int qr = lane >> 2, qc = lane & 3;
    #pragma unroll
    for (int mt = 0; mt < 4; mt++) {
        #pragma unroll
        for (int nt = 0; nt < 4; nt++) {
            const int lcol = wc * 32 + nt * 8 + qc * 2;
            const float b0 = BIAS ? sbias[lcol]     : 0.f;
            const float b1 = BIAS ? sbias[lcol + 1] : 0.f;
            const int r0 = row0 + wr * 64 + mt * 16 + qr;
            const float v00 = alpha * acc[mt][nt][0] + b0;
            const float v01 = alpha * acc[mt][nt][1] + b1;
            const float v10 = alpha * acc[mt][nt][2] + b0;
            const float v11 = alpha * acc[mt][nt][3] + b1;
            if (OUTM == 0) {
                float* cp = Cf + z * sC + (size_t)r0 * N + col0 + lcol;
                *reinterpret_cast<float2*>(cp)            = make_float2(v00, v01);
                *reinterpret_cast<float2*>(cp + 8ull * N) = make_float2(v10, v11);
            } else if (OUTM == 1) {
                uint16_t h0,l0,h1b,l1,h2,l2,h3,l3;
                split2h(v00, h0, l0); split2h(v01, h1b, l1);
                split2h(v10, h2, l2); split2h(v11, h3, l3);
                size_t o0 = z * sC + (size_t)r0 * N + col0 + lcol;
                size_t o1 = o0 + 8ull * N;
                *reinterpret_cast<uint32_t*>(
                    reinterpret_cast<uint16_t*>(Chi) + o0) = (uint32_t)h0 | ((uint32_t)h1b << 16);
                *reinterpret_cast<uint32_t*>(
                    reinterpret_cast<uint16_t*>(Clo) + o0) = (uint32_t)l0 | ((uint32_t)l1 << 16);
                *reinterpret_cast<uint32_t*>(
                    reinterpret_cast<uint16_t*>(Chi) + o1) = (uint32_t)h2 | ((uint32_t)h3 << 16);
                *reinterpret_cast<uint32_t*>(
                    reinterpret_cast<uint16_t*>(Clo) + o1) = (uint32_t)l2 | ((uint32_t)l3 << 16);
            } else if (OUTM == 2) {
                // transposed store  Vt[z*16 + b][col][n]
                uint16_t* oh = reinterpret_cast<uint16_t*>(Chi);
                uint16_t* ol = reinterpret_cast<uint16_t*>(Clo);
                const size_t zt = z * (size_t)Bn + (size_t)(row0 >> 10);
                const int n0 = (r0 & 1023);
                const size_t c0a = (zt * 512 + (size_t)(col0 + lcol)) * 1024;
                const size_t c1a = c0a + 1024;       // col+1
                uint16_t h, l;
                split2h(v00, h, l); oh[c0a + n0]     = h; ol[c0a + n0]     = l;
                split2h(v01, h, l); oh[c1a + n0]     = h; ol[c1a + n0]     = l;
                split2h(v10, h, l); oh[c0a + n0 + 8] = h; ol[c0a + n0 + 8] = l;
                split2h(v11, h, l); oh[c1a + n0 + 8] = h; ol[c1a + n0 + 8] = l;
            } else {
                // OUTM == 3: single fp16 store
                size_t o0 = z * sC + (size_t)r0 * N + col0 + lcol;
                size_t o1 = o0 + 8ull * N;
                *reinterpret_cast<uint32_t*>(
                    reinterpret_cast<uint16_t*>(Chi) + o0) =
                    (uint32_t)h1(v00) | ((uint32_t)h1(v01) << 16);
                *reinterpret_cast<uint32_t*>(
                    reinterpret_cast<uint16_t*>(Chi) + o1) =
                    (uint32_t)h1(v10) | ((uint32_t)h1(v11) << 16);
            }
        }
    }
}

// ---------------------------------------------------------------------------
// fp32 -> fp16 hi/lo elementwise split
// ---------------------------------------------------------------------------
__global__ void conv_hl(const float* __restrict__ s,
                        __half* __restrict__ h,
                        __half* __restrict__ l) {
    size_t i = ((size_t)blockIdx.x * 256 + threadIdx.x) * 4;
    float4 v = *reinterpret_cast<const float4*>(s + i);
    uint16_t h0,l0,h1b,l1,h2,l2,h3,l3;
    split2h(v.x, h0, l0); split2h(v.y, h1b, l1);
    split2h(v.z, h2, l2); split2h(v.w, h3, l3);
    *reinterpret_cast<uint2*>(h + i) =
        make_uint2((uint32_t)h0 | ((uint32_t)h1b << 16),
                   (uint32_t)h2 | ((uint32_t)h3 << 16));
    *reinterpret_cast<uint2*>(l + i) =
        make_uint2((uint32_t)l0 | ((uint32_t)l1 << 16),
                   (uint32_t)l2 | ((uint32_t)l3 << 16));
}

// ---------------------------------------------------------------------------
// Per-head 512x512 transpose + split: out[h][d][e] = in[h][e][d]
// ---------------------------------------------------------------------------
__global__ void transpose_w_hl(const float* __restrict__ in,
                               __half* __restrict__ oh,
                               __half* __restrict__ ol) {
    __shared__ float t[32][33];
    const size_t z = blockIdx.z;
    in += z * (size_t)(Dn * Dn);
    oh += z * (size_t)(Dn * Dn);
    ol += z * (size_t)(Dn * Dn);
    const int x0 = blockIdx.x * 32;   // d
    const int y0 = blockIdx.y * 32;   // e
    #pragma unroll
    for (int i = 0; i < 4; i++)
        t[threadIdx.y + i * 8][threadIdx.x] =
            in[(size_t)(y0 + threadIdx.y + i * 8) * Dn + x0 + threadIdx.x];
    __syncthreads();
    #pragma unroll
    for (int i = 0; i < 4; i++) {
        float v = t[threadIdx.x][threadIdx.y + i * 8];
        uint16_t h, l;
        split2h(v, h, l);
        size_t o = (size_t)(x0 + threadIdx.y + i * 8) * Dn + y0 + threadIdx.x;
        reinterpret_cast<uint16_t*>(oh)[o] = h;
        reinterpret_cast<uint16_t*>(ol)[o] = l;
    }
}

// ---------------------------------------------------------------------------
// Wo permute + split: wo_p[o][h*512+d] = Wo[o][d*8+h]
// ---------------------------------------------------------------------------
__global__ void conv_wo_p(const float* __restrict__ Wo,
                          __half* __restrict__ oh,
                          __half* __restrict__ ol) {
    size_t idx = (size_t)blockIdx.x * 256 + threadIdx.x;   // o*4096 + g
    int g = (int)(idx & 4095);
    size_t o = idx >> 12;
    int f = ((g & 511) << 3) | (g >> 9);
    float v = Wo[(o << 12) + f];
    uint16_t h, l;
    split2h(v, h, l);
    reinterpret_cast<uint16_t*>(oh)[idx] = h;
    reinterpret_cast<uint16_t*>(ol)[idx] = l;
}

// ---------------------------------------------------------------------------
// wvec[h][d] = sum_e bq[h][e] * Wk[h][e][d]
// ---------------------------------------------------------------------------
__global__ void wvec_kernel(const float* __restrict__ Wk,
                            const float* __restrict__ bq,
                            float* __restrict__ wvec) {
    const int h = blockIdx.x, d = threadIdx.x;
    const float* wk = Wk + (size_t)h * Dn * Dn;
    const float* b  = bq + (size_t)h * Dn;
    float s = 0.f;
    for (int e = 0; e < Dn; e++) s += b[e] * wk[(size_t)e * Dn + d];
    wvec[h * Dn + d] = s;
}

// ---------------------------------------------------------------------------
// colv[(h*16+b)][j] = inv_scale * k[b][j] . wvec[h]
// ---------------------------------------------------------------------------
__global__ void colv_kernel(const float* __restrict__ k,
                            const float* __restrict__ wvec,
                            float* __restrict__ colv, float inv_scale) {
    __shared__ float kr[Dn];
    const size_t bj = blockIdx.x;            // b*1024 + j
    const int tid = threadIdx.x, w = tid >> 5, lane = tid & 31;
    const float* kp = k + bj * Dn;
    #pragma unroll
    for (int i = 0; i < 2; i++) kr[tid + i * 256] = kp[tid + i * 256];
    __syncthreads();
    const float* wv = wvec + w * Dn;
    float s = 0.f;
    #pragma unroll
    for (int t = 0; t < 16; t++) {
        int d = lane + t * 32;
        s += kr[d] * wv[d];
    }
    #pragma unroll
    for (int o = 16; o > 0; o >>= 1)
        s += __shfl_xor_sync(0xffffffffu, s, o);
    if (lane == 0) {
        size_t b = bj >> 10, j = bj & 1023;
        colv[((size_t)w * 16 + b) * 1024 + j] = s * inv_scale;
    }
}

// ---------------------------------------------------------------------------
// Softmax over 1024-wide rows (+ per-column bias term) -> single fp16
// ---------------------------------------------------------------------------
__global__ void softmax1024_h(const float* __restrict__ P,
                              const float* __restrict__ colv,
                              __half* __restrict__ Ph) {
    __shared__ float red[8];
    const size_t row = blockIdx.x;
    const size_t z = row >> 10;
    const float* p = P + row * 1024;
    const int tid = threadIdx.x;

    float4 x = *reinterpret_cast<const float4*>(p + tid * 4);
    float4 cv = *reinterpret_cast<const float4*>(colv + z * 1024 + tid * 4);
    x.x += cv.x; x.y += cv.y; x.z += cv.z; x.w += cv.w;

    float m = fmaxf(fmaxf(x.x, x.y), fmaxf(x.z, x.w));
    #pragma unroll
    for (int o = 16; o > 0; o >>= 1)
        m = fmaxf(m, __shfl_xor_sync(0xffffffffu, m, o));
    if ((tid & 31) == 0) red[tid >> 5] = m;
    __syncthreads();
    float bm = red[0];
    #pragma unroll
    for (int i = 1; i < 8; i++) bm = fmaxf(bm, red[i]);
    __syncthreads();

    float e0 = __expf(x.x - bm), e1 = __expf(x.y - bm);
    float e2 = __expf(x.z - bm), e3 = __expf(x.w - bm);
    float s = e0 + e1 + e2 + e3;
    #pragma unroll
    for (int o = 16; o > 0; o >>= 1)
        s += __shfl_xor_sync(0xffffffffu, s, o);
    if ((tid & 31) == 0) red[tid >> 5] = s;
    __syncthreads();
    float bs = 0.f;
    #pragma unroll
    for (int i = 0; i < 8; i++) bs += red[i];
    float inv = 1.0f / bs;

    size_t o = row * 1024 + tid * 4;
    *reinterpret_cast<uint2*>(Ph + o) = make_uint2(
        (uint32_t)h1(e0 * inv) | ((uint32_t)h1(e1 * inv) << 16),
        (uint32_t)h1(e2 * inv) | ((uint32_t)h1(e3 * inv) << 16));
}

// ---------------------------------------------------------------------------
// kernel_launch — inputs: k, v, q, Wk, bk, Wv, bv, Wq, bq, Wo, bo
// ---------------------------------------------------------------------------
extern "C" void kernel_launch(void* const* d_in, const int* in_sizes, int n_in,
                              void* d_out, int out_size) {
    (void)in_sizes; (void)n_in; (void)out_size;
    const float* k  = (const float*)d_in[0];
    const float* v  = (const float*)d_in[1];
    const float* q  = (const float*)d_in[2];
    const float* Wk = (const float*)d_in[3];
    const float* Wv = (const float*)d_in[5];
    const float* bv = (const float*)d_in[6];
    const float* Wq = (const float*)d_in[7];
    const float* bq = (const float*)d_in[8];
    const float* Wo = (const float*)d_in[9];
    const float* bo = (const float*)d_in[10];
    float* out = (float*)d_out;

    constexpr int SM3 = Cfg<3>::SMEM;     // 98816
    constexpr int SM2 = Cfg<2>::SMEM;     // 74240
    cudaFuncSetAttribute(hmma_gemm<3, false, 1, false, false>,
        cudaFuncAttributeMaxDynamicSharedMemorySize, SM3);
    cudaFuncSetAttribute(hmma_gemm<3, false, 3, false, false>,
        cudaFuncAttributeMaxDynamicSharedMemorySize, SM3);
    cudaFuncSetAttribute(hmma_gemm<3, true, 2, false, false>,
        cudaFuncAttributeMaxDynamicSharedMemorySize, SM3);
    cudaFuncSetAttribute(hmma_gemm<2, false, 0, false, true>,
        cudaFuncAttributeMaxDynamicSharedMemorySize, SM2);
    cudaFuncSetAttribute(hmma_gemm<2, false, 3, false, false>,
        cudaFuncAttributeMaxDynamicSharedMemorySize, SM2);
    cudaFuncSetAttribute(hmma_gemm<2, true, 0, true, false>,
        cudaFuncAttributeMaxDynamicSharedMemorySize, SM2);

    __half *xq_h,*xq_l,*xk_h,*xk_l,*xv_h,*xv_l;
    __half *wqt_h,*wqt_l,*wkt_h,*wkt_l,*mt_h,*mt_l;
    __half *wv_h,*wv_l,*wop_h,*wop_l;
    __half *qp,*vt_h,*vt_l,*ph,*ot;
    float *P,*wvec,*colv;
    cudaGetSymbolAddress((void**)&xq_h, g_xq_hi); cudaGetSymbolAddress((void**)&xq_l, g_xq_lo);
    cudaGetSymbolAddress((void**)&xk_h, g_xk_hi); cudaGetSymbolAddress((void**)&xk_l, g_xk_lo);
    cudaGetSymbolAddress((void**)&xv_h, g_xv_hi); cudaGetSymbolAddress((void**)&xv_l, g_xv_lo);
    cudaGetSymbolAddress((void**)&wqt_h,g_wqt_hi);cudaGetSymbolAddress((void**)&wqt_l,g_wqt_lo);
    cudaGetSymbolAddress((void**)&wkt_h,g_wkt_hi);cudaGetSymbolAddress((void**)&wkt_l,g_wkt_lo);
    cudaGetSymbolAddress((void**)&mt_h, g_mt_hi); cudaGetSymbolAddress((void**)&mt_l, g_mt_lo);
    cudaGetSymbolAddress((void**)&wv_h, g_wv_hi); cudaGetSymbolAddress((void**)&wv_l, g_wv_lo);
    cudaGetSymbolAddress((void**)&wop_h,g_wop_hi);cudaGetSymbolAddress((void**)&wop_l,g_wop_lo);
    cudaGetSymbolAddress((void**)&qp,   g_qp);
    cudaGetSymbolAddress((void**)&vt_h, g_vt_hi); cudaGetSymbolAddress((void**)&vt_l, g_vt_lo);
    cudaGetSymbolAddress((void**)&ph,   g_ph);
    cudaGetSymbolAddress((void**)&ot,   g_ot);
    cudaGetSymbolAddress((void**)&P,    g_P);
    cudaGetSymbolAddress((void**)&wvec, g_wvec);
    cudaGetSymbolAddress((void**)&colv, g_colv);

    const float inv_scale = 1.0f / sqrtf((float)Dn);
    const size_t WW = (size_t)Dn * Dn;

    // ---- splits / transposes ----
    transpose_w_hl<<<dim3(16, 16, Hn), dim3(32, 8)>>>(Wq, wqt_h, wqt_l);
    transpose_w_hl<<<dim3(16, 16, Hn), dim3(32, 8)>>>(Wk, wkt_h, wkt_l);
    conv_hl<<<(unsigned)(XEL / 1024), 256>>>(q,  xq_h, xq_l);
    conv_hl<<<(unsigned)(XEL / 1024), 256>>>(k,  xk_h, xk_l);
    conv_hl<<<(unsigned)(XEL / 1024), 256>>>(v,  xv_h, xv_l);
    conv_hl<<<(unsigned)(WEL / 1024), 256>>>(Wv, wv_h, wv_l);
    conv_wo_p<<<(unsigned)(WEL / 256), 256>>>(Wo, wop_h, wop_l);

    // ---- Mt[h] = Wk^T Wq (3-term, hi/lo out) ----
    hmma_gemm<3, false, 1, false, false><<<dim3(4, 4, Hn), 256, SM3>>>(
        wkt_h, wkt_l, wqt_h, wqt_l, nullptr, nullptr, mt_h, mt_l,
        Dn, Dn, Dn, Dn, WW, WW, 0, WW, 1.0f);

    // ---- q~ = q @ Mt^T per head (3-term, single fp16 out) ----
    dim3 gproj(Dn / 128, Mn / 128, Hn);
    hmma_gemm<3, false, 3, false, false><<<gproj, 256, SM3>>>(
        xq_h, xq_l, mt_h, mt_l, nullptr, nullptr, qp, nullptr,
        Dn, Dn, Dn, Dn, 0, WW, 0, (size_t)Mn * Dn, 1.0f);

    // ---- column bias terms ----
    wvec_kernel<<<Hn, Dn>>>(Wk, bq, wvec);
    colv_kernel<<<Mn, 256>>>(k, wvec, colv, inv_scale);

    // ---- V projection -> transposed Vt hi/lo (3-term, OUTM=2) ----
    hmma_gemm<3, true, 2, false, false><<<gproj, 256, SM3>>>(
        xv_h, xv_l, wv_h, wv_l, bv, nullptr, vt_h, vt_l,
        Dn, Dn, Dn, Dn, 0, WW, (size_t)Dn, 0, 1.0f);

    // ---- scores: P = q~ @ k^T / scale (2-term, A single fp16) ----
    dim3 gsc(Nn / 128, Nn / 128, Hn * Bn);
    hmma_gemm<2, false, 0, false, true><<<gsc, 256, SM2>>>(
        qp, nullptr, xk_h, xk_l, nullptr, P, nullptr, nullptr,
        Nn, Dn, Dn, Dn, (size_t)Nn * Dn, (size_t)Nn * Dn, 0, (size_t)Nn * Nn,
        inv_scale);

    // ---- softmax (+colv) -> single fp16 ----
    softmax1024_h<<<Hn * Bn * Nn, 256>>>(P, colv, ph);

    // ---- O = P @ Vt^T -> ot single fp16 in [h][m][d] (2-term) ----
    dim3 gpv(Dn / 128, Nn / 128, Hn * Bn);
    hmma_gemm<2, false, 3, false, false><<<gpv, 256, SM2>>>(
        ph, nullptr, vt_h, vt_l, nullptr, nullptr, ot, nullptr,
        Dn, Nn, Nn, Nn, (size_t)Nn * Nn, (size_t)Dn * Nn, 0, (size_t)Nn * Dn,
        1.0f);

    // ---- output projection: rep = ot(h-blocked) @ wo_p^T + bo (2-term) ----
    dim3 gfin(Dn / 128, Mn / 128, 1);
    hmma_gemm<2, true, 0, true, false><<<gfin, 256, SM2>>>(
        ot, nullptr, wop_h, wop_l, bo, out, nullptr, nullptr,
        Dn, Hn * Dn, Dn, Hn * Dn, 0, 0, 0, 0, 1.0f);
}

// round 8
// speedup vs baseline: 4.1660x; 1.2631x over previous
#include <cuda_runtime.h>
#include <cuda_fp16.h>
#include <math.h>
#include <stdint.h>

// ---------------------------------------------------------------------------
// Problem constants
// ---------------------------------------------------------------------------
constexpr int Hn = 8, Bn = 16, Nn = 1024, Dn = 512;
constexpr int Mn = Bn * Nn;                               // 16384
constexpr size_t XEL  = (size_t)Mn * Dn;                  // 8,388,608
constexpr size_t WEL  = (size_t)Hn * Dn * Dn;             // 2,097,152
constexpr size_t PROJ = (size_t)Hn * Mn * Dn;             // 67,108,864
constexpr size_t PEL  = (size_t)Hn * Bn * Nn * Nn;        // 134,217,728
constexpr size_t AHBLK = (size_t)Mn * Dn;                 // h-block stride in ot

// ---------------------------------------------------------------------------
// Scratch (__device__ globals — allocation-free)
// ---------------------------------------------------------------------------
__device__ __half g_xq[XEL];                       // q single fp16
__device__ __half g_xk_hi[XEL], g_xk_lo[XEL];      // k hi/lo (scores B)
__device__ __half g_xv[XEL];                       // v single fp16
__device__ __half g_wqt_hi[WEL], g_wqt_lo[WEL];    // Wq^T per head
__device__ __half g_wkt_hi[WEL], g_wkt_lo[WEL];    // Wk^T per head
__device__ __half g_mt_hi[WEL], g_mt_lo[WEL];      // Mt = Wk^T Wq
__device__ __half g_wv_hi[WEL], g_wv_lo[WEL];
__device__ __half g_wop_hi[WEL], g_wop_lo[WEL];    // permuted Wo
__device__ __half g_qp[PROJ];                      // q~ single fp16
__device__ __half g_vt[PROJ];                      // V' transposed, single
__device__ __half g_Ps[PEL];                       // raw scores, fp16
__device__ __half g_ph[PEL];                       // softmax out, fp16
__device__ __half g_ot[PROJ];                      // PV out [h][m][d], single
__device__ float  g_wvec[Hn * Dn];                 // Wk^T bq per head
__device__ float  g_colv[(size_t)Hn * Bn * Nn];    // scaled col terms

// ---------------------------------------------------------------------------
// Helpers
// ---------------------------------------------------------------------------
__device__ __forceinline__ uint32_t s2u(const void* p) {
    uint32_t a;
    asm("{ .reg .u64 t; cvta.to.shared.u64 t, %1; cvt.u32.u64 %0, t; }"
        : "=r"(a) : "l"(p));
    return a;
}

__device__ __forceinline__ void cp16(uint32_t saddr, const void* gaddr) {
    asm volatile("cp.async.cg.shared.global [%0], [%1], 16;"
                 :: "r"(saddr), "l"(gaddr) : "memory");
}
__device__ __forceinline__ void cp_commit() {
    asm volatile("cp.async.commit_group;" ::: "memory");
}
template <int N>
__device__ __forceinline__ void cp_wait() {
    asm volatile("cp.async.wait_group %0;" :: "n"(N) : "memory");
}

__device__ __forceinline__ void ldsm4(uint32_t* r, uint32_t addr) {
    asm volatile("ldmatrix.sync.aligned.m8n8.x4.shared.b16 {%0,%1,%2,%3}, [%4];"
        : "=r"(r[0]), "=r"(r[1]), "=r"(r[2]), "=r"(r[3]) : "r"(addr));
}

__device__ __forceinline__ void mma16816(float* d, const uint32_t* a,
                                         uint32_t b0, uint32_t b1) {
    asm volatile(
        "mma.sync.aligned.m16n8k16.row.col.f32.f16.f16.f32 "
        "{%0,%1,%2,%3}, {%4,%5,%6,%7}, {%8,%9}, {%0,%1,%2,%3};"
        : "+f"(d[0]), "+f"(d[1]), "+f"(d[2]), "+f"(d[3])
        : "r"(a[0]), "r"(a[1]), "r"(a[2]), "r"(a[3]), "r"(b0), "r"(b1));
}

__device__ __forceinline__ void split2h(float x, uint16_t& h, uint16_t& l) {
    __half hb = __float2half_rn(x);
    __half lb = __float2half_rn(x - __half2float(hb));
    h = *reinterpret_cast<uint16_t*>(&hb);
    l = *reinterpret_cast<uint16_t*>(&lb);
}
__device__ __forceinline__ uint16_t h1(float x) {
    __half hb = __float2half_rn(x);
    return *reinterpret_cast<uint16_t*>(&hb);
}

// XOR chunk swizzle for 64B rows (4 x 16B chunks): conflict-free ldmatrix.
__device__ __forceinline__ uint32_t swz(uint32_t r, uint32_t ch) {
    return r * 64u + ((ch ^ ((r >> 1) & 3u)) << 4);
}

// ---------------------------------------------------------------------------
// fp16-split batched GEMM via mma.sync (HMMA):
// TERMS=3:  C = alpha*(Ahi+Alo)@(Bhi+Blo)^T  — MMAs: ah*bh + ah*bl + al*bh
// TERMS=2:  C = alpha* A @(Bhi+Blo)^T (A single) — MMAs: a*bh + a*bl
// TERMS=1:  C = alpha* A @ B^T (both single)     — MMA:  a*b
// OUTM : 0=fp32, 1=fp16 hi/lo, 2=hi/lo transposed, 3=single, 4=single transposed
// AHB  : A column h-blocked (final projection reads ot in [h][m][d])
// BMODB: B z-index = z & 15 (B shared across heads, z = h*16+b)
// Tile 128x128, BK=32, 8 warps, 3-stage cp.async pipeline, 1 sync/chunk.
// ---------------------------------------------------------------------------
constexpr int TILE_B = 128 * 64;                 // 8192 B per tile

template <int TERMS> struct Cfg {
    static constexpr int NT    = (TERMS == 3) ? 4 : (TERMS == 2) ? 3 : 2;
    static constexpr int STAGE = NT * TILE_B;
    static constexpr int SMEM  = 3 * STAGE + 512;
};

template <int TERMS, bool BIAS, int OUTM, bool AHB, bool BMODB>
__global__ void __launch_bounds__(256, 2) hmma_gemm(
    const __half* __restrict__ Ahi, const __half* __restrict__ Alo,
    const __half* __restrict__ Bhi, const __half* __restrict__ Blo,
    const float* __restrict__ biasg,
    float* __restrict__ Cf,
    __half* __restrict__ Chi, __half* __restrict__ Clo,
    int N, int K, int lda, int ldb,
    size_t sA, size_t sB, size_t sBias, size_t sC, float alpha)
{
    constexpr int STAGE = Cfg<TERMS>::STAGE;
    extern __shared__ __align__(16) char smem[];
    const uint32_t sb = s2u(smem);
    float* sbias = reinterpret_cast<float*>(smem + 3 * STAGE);

    const int tid  = threadIdx.x;
    const int wid  = tid >> 5, lane = tid & 31;
    const int wr   = wid >> 2, wc = wid & 3;      // warp grid 2x4
    const int col0 = blockIdx.x * 128, row0 = blockIdx.y * 128;
    const size_t z = blockIdx.z;
    const size_t zb = BMODB ? (z & 15) : z;
    Ahi += z * sA; if (TERMS == 3) Alo += z * sA;
    Bhi += zb * sB; if (TERMS >= 2) Blo += zb * sB;

    if (BIAS && tid < 128) sbias[tid] = biasg[z * sBias + col0 + tid];

    const int nCh = K >> 5;          // BK = 32

    auto prefetch = [&](int c) {
        const int k0 = c << 5;
        const uint32_t boff = sb + (uint32_t)(c % 3) * STAGE;
        size_t aoff;
        if (AHB) aoff = ((size_t)(k0 >> 9)) * AHBLK + (size_t)(k0 & 511);
        else     aoff = (size_t)k0;
        constexpr int NT = Cfg<TERMS>::NT;
        constexpr int NA = (TERMS == 3) ? 2 : 1;
        #pragma unroll
        for (int t = 0; t < NT; t++) {
            const __half* s;
            if (TERMS == 3) s = (t == 0) ? Ahi : (t == 1) ? Alo
                              : (t == 2) ? Bhi : Blo;
            else if (TERMS == 2) s = (t == 0) ? Ahi : (t == 1) ? Bhi : Blo;
            else                 s = (t == 0) ? Ahi : Bhi;
            const uint32_t tb = boff + t * TILE_B;
            #pragma unroll
            for (int i = 0; i < 2; i++) {
                uint32_t idx = (uint32_t)(i * 256 + tid);   // 0..511
                uint32_t r = idx >> 2, ch = idx & 3;
                const __half* g;
                if (t < NA) g = s + aoff + (size_t)(row0 + r) * lda + ch * 8;
                else        g = s + (size_t)k0 + (size_t)(col0 + r) * ldb + ch * 8;
                cp16(tb + swz(r, ch), g);
            }
        }
        cp_commit();
    };

    float acc[4][4][4] = {};

    prefetch(0);
    prefetch(1);

    for (int c = 0; c < nCh; ++c) {
        if (c + 1 < nCh) cp_wait<1>(); else cp_wait<0>();
        __syncthreads();
        if (c + 2 < nCh) prefetch(c + 2);

        const uint32_t boff = sb + (uint32_t)(c % 3) * STAGE;
        const uint32_t aHiB = boff;
        const uint32_t aLoB = boff + TILE_B;                 // TERMS==3 only
        const uint32_t bHiB = boff + ((TERMS == 3) ? 2 : 1) * TILE_B;
        const uint32_t bLoB = bHiB + TILE_B;                 // TERMS>=2 only
        const uint32_t lrow = (uint32_t)(lane & 15), lhalf = (uint32_t)(lane >> 4);

        #pragma unroll
        for (int ks = 0; ks < 2; ks++) {
            const uint32_t kch = (uint32_t)ks * 2u + lhalf;   // 16B chunk index
            uint32_t bh[4][2], bl[4][2];
            #pragma unroll
            for (int np = 0; np < 2; np++) {
                uint32_t r = (uint32_t)(wc * 32 + np * 16) + lrow;
                uint32_t t[4];
                ldsm4(t, bHiB + swz(r, kch));
                bh[np*2+0][0] = t[0]; bh[np*2+0][1] = t[2];
                bh[np*2+1][0] = t[1]; bh[np*2+1][1] = t[3];
                if (TERMS >= 2) {
                    ldsm4(t, bLoB + swz(r, kch));
                    bl[np*2+0][0] = t[0]; bl[np*2+0][1] = t[2];
                    bl[np*2+1][0] = t[1]; bl[np*2+1][1] = t[3];
                }
            }
            #pragma unroll
            for (int mt = 0; mt < 4; mt++) {
                uint32_t r = (uint32_t)(wr * 64 + mt * 16) + lrow;
                uint32_t ah[4], al[4];
                ldsm4(ah, aHiB + swz(r, kch));
                if (TERMS == 3) ldsm4(al, aLoB + swz(r, kch));
                #pragma unroll
                for (int nt = 0; nt < 4; nt++) {
                    mma16816(acc[mt][nt], ah, bh[nt][0], bh[nt][1]);
                    if (TERMS >= 2)
                        mma16816(acc[mt][nt], ah, bl[nt][0], bl[nt][1]);
                    if (TERMS == 3)
                        mma16816(acc[mt][nt], al, bh[nt][0], bh[nt][1]);
                }
            }
        }
    }

    // ---- epilogue ----
    const int qr = lane >> 2, qc = lane & 3;
    #pragma unroll
    for (int mt = 0; mt < 4; mt++) {
        #pragma unroll
        for (int nt = 0; nt < 4; nt++) {
            const int lcol = wc * 32 + nt * 8 + qc * 2;
            const float b0 = BIAS ? sbias[lcol]     : 0.f;
            const float b1 = BIAS ? sbias[lcol + 1] : 0.f;
            const int r0 = row0 + wr * 64 + mt * 16 + qr;
            const float v00 = alpha * acc[mt][nt][0] + b0;
            const float v01 = alpha * acc[mt][nt][1] + b1;
            const float v10 = alpha * acc[mt][nt][2] + b0;
            const float v11 = alpha * acc[mt][nt][3] + b1;
            if (OUTM == 0) {
                float* cp = Cf + z * sC + (size_t)r0 * N + col0 + lcol;
                *reinterpret_cast<float2*>(cp)            = make_float2(v00, v01);
                *reinterpret_cast<float2*>(cp + 8ull * N) = make_float2(v10, v11);
            } else if (OUTM == 1) {
                uint16_t h0,l0,h1b,l1,h2,l2,h3,l3;
                split2h(v00, h0, l0); split2h(v01, h1b, l1);
                split2h(v10, h2, l2); split2h(v11, h3, l3);
                size_t o0 = z * sC + (size_t)r0 * N + col0 + lcol;
                size_t o1 = o0 + 8ull * N;
                *reinterpret_cast<uint32_t*>(
                    reinterpret_cast<uint16_t*>(Chi) + o0) = (uint32_t)h0 | ((uint32_t)h1b << 16);
                *reinterpret_cast<uint32_t*>(
                    reinterpret_cast<uint16_t*>(Clo) + o0) = (uint32_t)l0 | ((uint32_t)l1 << 16);
                *reinterpret_cast<uint32_t*>(
                    reinterpret_cast<uint16_t*>(Chi) + o1) = (uint32_t)h2 | ((uint32_t)h3 << 16);
                *reinterpret_cast<uint32_t*>(
                    reinterpret_cast<uint16_t*>(Clo) + o1) = (uint32_t)l2 | ((uint32_t)l3 << 16);
            } else if (OUTM == 2) {
                uint16_t* oh = reinterpret_cast<uint16_t*>(Chi);
                uint16_t* ol = reinterpret_cast<uint16_t*>(Clo);
                const size_t zt = z * (size_t)Bn + (size_t)(row0 >> 10);
                const int n0 = (r0 & 1023);
                const size_t c0a = (zt * 512 + (size_t)(col0 + lcol)) * 1024;
                const size_t c1a = c0a + 1024;
                uint16_t h, l;
                split2h(v00, h, l); oh[c0a + n0]     = h; ol[c0a + n0]     = l;
                split2h(v01, h, l); oh[c1a + n0]     = h; ol[c1a + n0]     = l;
                split2h(v10, h, l); oh[c0a + n0 + 8] = h; ol[c0a + n0 + 8] = l;
                split2h(v11, h, l); oh[c1a + n0 + 8] = h; ol[c1a + n0 + 8] = l;
            } else if (OUTM == 3) {
                size_t o0 = z * sC + (size_t)r0 * N + col0 + lcol;
                size_t o1 = o0 + 8ull * N;
                *reinterpret_cast<uint32_t*>(
                    reinterpret_cast<uint16_t*>(Chi) + o0) =
                    (uint32_t)h1(v00) | ((uint32_t)h1(v01) << 16);
                *reinterpret_cast<uint32_t*>(
                    reinterpret_cast<uint16_t*>(Chi) + o1) =
                    (uint32_t)h1(v10) | ((uint32_t)h1(v11) << 16);
            } else {
                // OUTM == 4: single fp16 transposed store  Vt[z*16+b][col][n]
                uint16_t* oh = reinterpret_cast<uint16_t*>(Chi);
                const size_t zt = z * (size_t)Bn + (size_t)(row0 >> 10);
                const int n0 = (r0 & 1023);
                const size_t c0a = (zt * 512 + (size_t)(col0 + lcol)) * 1024;
                const size_t c1a = c0a + 1024;
                oh[c0a + n0]     = h1(v00);
                oh[c1a + n0]     = h1(v01);
                oh[c0a + n0 + 8] = h1(v10);
                oh[c1a + n0 + 8] = h1(v11);
            }
        }
    }
}

// ---------------------------------------------------------------------------
// fp32 -> fp16 single / hi-lo elementwise conversions
// ---------------------------------------------------------------------------
__global__ void conv_h(const float* __restrict__ s, __half* __restrict__ h) {
    size_t i = ((size_t)blockIdx.x * 256 + threadIdx.x) * 4;
    float4 v = *reinterpret_cast<const float4*>(s + i);
    *reinterpret_cast<uint2*>(h + i) = make_uint2(
        (uint32_t)h1(v.x) | ((uint32_t)h1(v.y) << 16),
        (uint32_t)h1(v.z) | ((uint32_t)h1(v.w) << 16));
}

__global__ void conv_hl(const float* __restrict__ s,
                        __half* __restrict__ h,
                        __half* __restrict__ l) {
    size_t i = ((size_t)blockIdx.x * 256 + threadIdx.x) * 4;
    float4 v = *reinterpret_cast<const float4*>(s + i);
    uint16_t h0,l0,h1b,l1,h2,l2,h3,l3;
    split2h(v.x, h0, l0); split2h(v.y, h1b, l1);
    split2h(v.z, h2, l2); split2h(v.w, h3, l3);
    *reinterpret_cast<uint2*>(h + i) =
        make_uint2((uint32_t)h0 | ((uint32_t)h1b << 16),
                   (uint32_t)h2 | ((uint32_t)h3 << 16));
    *reinterpret_cast<uint2*>(l + i) =
        make_uint2((uint32_t)l0 | ((uint32_t)l1 << 16),
                   (uint32_t)l2 | ((uint32_t)l3 << 16));
}

// ---------------------------------------------------------------------------
// Per-head 512x512 transpose + split: out[h][d][e] = in[h][e][d]
// ---------------------------------------------------------------------------
__global__ void transpose_w_hl(const float* __restrict__ in,
                               __half* __restrict__ oh,
                               __half* __restrict__ ol) {
    __shared__ float t[32][33];
    const size_t z = blockIdx.z;
    in += z * (size_t)(Dn * Dn);
    oh += z * (size_t)(Dn * Dn);
    ol += z * (size_t)(Dn * Dn);
    const int x0 = blockIdx.x * 32;
    const int y0 = blockIdx.y * 32;
    #pragma unroll
    for (int i = 0; i < 4; i++)
        t[threadIdx.y + i * 8][threadIdx.x] =
            in[(size_t)(y0 + threadIdx.y + i * 8) * Dn + x0 + threadIdx.x];
    __syncthreads();
    #pragma unroll
    for (int i = 0; i < 4; i++) {
        float v = t[threadIdx.x][threadIdx.y + i * 8];
        uint16_t h, l;
        split2h(v, h, l);
        size_t o = (size_t)(x0 + threadIdx.y + i * 8) * Dn + y0 + threadIdx.x;
        reinterpret_cast<uint16_t*>(oh)[o] = h;
        reinterpret_cast<uint16_t*>(ol)[o] = l;
    }
}

// ---------------------------------------------------------------------------
// Wo permute + split: wo_p[o][h*512+d] = Wo[o][d*8+h]
// ---------------------------------------------------------------------------
__global__ void conv_wo_p(const float* __restrict__ Wo,
                          __half* __restrict__ oh,
                          __half* __restrict__ ol) {
    size_t idx = (size_t)blockIdx.x * 256 + threadIdx.x;
    int g = (int)(idx & 4095);
    size_t o = idx >> 12;
    int f = ((g & 511) << 3) | (g >> 9);
    float v = Wo[(o << 12) + f];
    uint16_t h, l;
    split2h(v, h, l);
    reinterpret_cast<uint16_t*>(oh)[idx] = h;
    reinterpret_cast<uint16_t*>(ol)[idx] = l;
}

// ---------------------------------------------------------------------------
// wvec[h][d] = sum_e bq[h][e] * Wk[h][e][d]
// ---------------------------------------------------------------------------
__global__ void wvec_kernel(const float* __restrict__ Wk,
                            const float* __restrict__ bq,
                            float* __restrict__ wvec) {
    const int h = blockIdx.x, d = threadIdx.x;
    const float* wk = Wk + (size_t)h * Dn * Dn;
    const float* b  = bq + (size_t)h * Dn;
    float s = 0.f;
    for (int e = 0; e < Dn; e++) s += b[e] * wk[(size_t)e * Dn + d];
    wvec[h * Dn + d] = s;
}

// ---------------------------------------------------------------------------
// colv[(h*16+b)][j] = inv_scale * k[b][j] . wvec[h]
// ---------------------------------------------------------------------------
__global__ void colv_kernel(const float* __restrict__ k,
                            const float* __restrict__ wvec,
                            float* __restrict__ colv, float inv_scale) {
    __shared__ float kr[Dn];
    const size_t bj = blockIdx.x;
    const int tid = threadIdx.x, w = tid >> 5, lane = tid & 31;
    const float* kp = k + bj * Dn;
    #pragma unroll
    for (int i = 0; i < 2; i++) kr[tid + i * 256] = kp[tid + i * 256];
    __syncthreads();
    const float* wv = wvec + w * Dn;
    float s = 0.f;
    #pragma unroll
    for (int t = 0; t < 16; t++) {
        int d = lane + t * 32;
        s += kr[d] * wv[d];
    }
    #pragma unroll
    for (int o = 16; o > 0; o >>= 1)
        s += __shfl_xor_sync(0xffffffffu, s, o);
    if (lane == 0) {
        size_t b = bj >> 10, j = bj & 1023;
        colv[((size_t)w * 16 + b) * 1024 + j] = s * inv_scale;
    }
}

// ---------------------------------------------------------------------------
// Softmax over 1024-wide fp16 rows (+ per-column bias term) -> single fp16
// ---------------------------------------------------------------------------
__global__ void softmax1024_h(const __half* __restrict__ P,
                              const float* __restrict__ colv,
                              __half* __restrict__ Ph) {
    __shared__ float red[8];
    const size_t row = blockIdx.x;
    const size_t z = row >> 10;
    const int tid = threadIdx.x;

    uint2 pr = *reinterpret_cast<const uint2*>(P + row * 1024 + tid * 4);
    __half2 p01 = *reinterpret_cast<__half2*>(&pr.x);
    __half2 p23 = *reinterpret_cast<__half2*>(&pr.y);
    float4 cv = *reinterpret_cast<const float4*>(colv + z * 1024 + tid * 4);
    float x0 = __half2float(__low2half(p01))  + cv.x;
    float x1 = __half2float(__high2half(p01)) + cv.y;
    float x2 = __half2float(__low2half(p23))  + cv.z;
    float x3 = __half2float(__high2half(p23)) + cv.w;

    float m = fmaxf(fmaxf(x0, x1), fmaxf(x2, x3));
    #pragma unroll
    for (int o = 16; o > 0; o >>= 1)
        m = fmaxf(m, __shfl_xor_sync(0xffffffffu, m, o));
    if ((tid & 31) == 0) red[tid >> 5] = m;
    __syncthreads();
    float bm = red[0];
    #pragma unroll
    for (int i = 1; i < 8; i++) bm = fmaxf(bm, red[i]);
    __syncthreads();

    float e0 = __expf(x0 - bm), e1 = __expf(x1 - bm);
    float e2 = __expf(x2 - bm), e3 = __expf(x3 - bm);
    float s = e0 + e1 + e2 + e3;
    #pragma unroll
    for (int o = 16; o > 0; o >>= 1)
        s += __shfl_xor_sync(0xffffffffu, s, o);
    if ((tid & 31) == 0) red[tid >> 5] = s;
    __syncthreads();
    float bs = 0.f;
    #pragma unroll
    for (int i = 0; i < 8; i++) bs += red[i];
    float inv = 1.0f / bs;

    size_t o = row * 1024 + tid * 4;
    *reinterpret_cast<uint2*>(Ph + o) = make_uint2(
        (uint32_t)h1(e0 * inv) | ((uint32_t)h1(e1 * inv) << 16),
        (uint32_t)h1(e2 * inv) | ((uint32_t)h1(e3 * inv) << 16));
}

// ---------------------------------------------------------------------------
// kernel_launch — inputs: k, v, q, Wk, bk, Wv, bv, Wq, bq, Wo, bo
// ---------------------------------------------------------------------------
extern "C" void kernel_launch(void* const* d_in, const int* in_sizes, int n_in,
                              void* d_out, int out_size) {
    (void)in_sizes; (void)n_in; (void)out_size;
    const float* k  = (const float*)d_in[0];
    const float* v  = (const float*)d_in[1];
    const float* q  = (const float*)d_in[2];
    const float* Wk = (const float*)d_in[3];
    const float* Wv = (const float*)d_in[5];
    const float* bv = (const float*)d_in[6];
    const float* Wq = (const float*)d_in[7];
    const float* bq = (const float*)d_in[8];
    const float* Wo = (const float*)d_in[9];
    const float* bo = (const float*)d_in[10];
    float* out = (float*)d_out;

    constexpr int SM3 = Cfg<3>::SMEM;
    constexpr int SM2 = Cfg<2>::SMEM;
    constexpr int SM1 = Cfg<1>::SMEM;
    cudaFuncSetAttribute(hmma_gemm<3, false, 1, false, false>,
        cudaFuncAttributeMaxDynamicSharedMemorySize, SM3);
    cudaFuncSetAttribute(hmma_gemm<2, false, 3, false, false>,
        cudaFuncAttributeMaxDynamicSharedMemorySize, SM2);
    cudaFuncSetAttribute(hmma_gemm<2, true, 4, false, false>,
        cudaFuncAttributeMaxDynamicSharedMemorySize, SM2);
    cudaFuncSetAttribute(hmma_gemm<2, false, 3, false, true>,
        cudaFuncAttributeMaxDynamicSharedMemorySize, SM2);
    cudaFuncSetAttribute(hmma_gemm<1, false, 3, false, false>,
        cudaFuncAttributeMaxDynamicSharedMemorySize, SM1);
    cudaFuncSetAttribute(hmma_gemm<2, true, 0, true, false>,
        cudaFuncAttributeMaxDynamicSharedMemorySize, SM2);

    __half *xq,*xk_h,*xk_l,*xv;
    __half *wqt_h,*wqt_l,*wkt_h,*wkt_l,*mt_h,*mt_l;
    __half *wv_h,*wv_l,*wop_h,*wop_l;
    __half *qp,*vt,*Ps,*ph,*ot;
    float *wvec,*colv;
    cudaGetSymbolAddress((void**)&xq,   g_xq);
    cudaGetSymbolAddress((void**)&xk_h, g_xk_hi); cudaGetSymbolAddress((void**)&xk_l, g_xk_lo);
    cudaGetSymbolAddress((void**)&xv,   g_xv);
    cudaGetSymbolAddress((void**)&wqt_h,g_wqt_hi);cudaGetSymbolAddress((void**)&wqt_l,g_wqt_lo);
    cudaGetSymbolAddress((void**)&wkt_h,g_wkt_hi);cudaGetSymbolAddress((void**)&wkt_l,g_wkt_lo);
    cudaGetSymbolAddress((void**)&mt_h, g_mt_hi); cudaGetSymbolAddress((void**)&mt_l, g_mt_lo);
    cudaGetSymbolAddress((void**)&wv_h, g_wv_hi); cudaGetSymbolAddress((void**)&wv_l, g_wv_lo);
    cudaGetSymbolAddress((void**)&wop_h,g_wop_hi);cudaGetSymbolAddress((void**)&wop_l,g_wop_lo);
    cudaGetSymbolAddress((void**)&qp,   g_qp);
    cudaGetSymbolAddress((void**)&vt,   g_vt);
    cudaGetSymbolAddress((void**)&Ps,   g_Ps);
    cudaGetSymbolAddress((void**)&ph,   g_ph);
    cudaGetSymbolAddress((void**)&ot,   g_ot);
    cudaGetSymbolAddress((void**)&wvec, g_wvec);
    cudaGetSymbolAddress((void**)&colv, g_colv);

    const float inv_scale = 1.0f / sqrtf((float)Dn);
    const size_t WW = (size_t)Dn * Dn;

    // ---- conversions ----
    transpose_w_hl<<<dim3(16, 16, Hn), dim3(32, 8)>>>(Wq, wqt_h, wqt_l);
    transpose_w_hl<<<dim3(16, 16, Hn), dim3(32, 8)>>>(Wk, wkt_h, wkt_l);
    conv_h <<<(unsigned)(XEL / 1024), 256>>>(q, xq);
    conv_hl<<<(unsigned)(XEL / 1024), 256>>>(k, xk_h, xk_l);
    conv_h <<<(unsigned)(XEL / 1024), 256>>>(v, xv);
    conv_hl<<<(unsigned)(WEL / 1024), 256>>>(Wv, wv_h, wv_l);
    conv_wo_p<<<(unsigned)(WEL / 256), 256>>>(Wo, wop_h, wop_l);

    // ---- Mt[h] = Wk^T Wq (3-term, hi/lo out) ----
    hmma_gemm<3, false, 1, false, false><<<dim3(4, 4, Hn), 256, SM3>>>(
        wkt_h, wkt_l, wqt_h, wqt_l, nullptr, nullptr, mt_h, mt_l,
        Dn, Dn, Dn, Dn, WW, WW, 0, WW, 1.0f);

    // ---- q~ = q @ Mt^T per head (2-term: q single x Mt hi/lo) ----
    dim3 gproj(Dn / 128, Mn / 128, Hn);
    hmma_gemm<2, false, 3, false, false><<<gproj, 256, SM2>>>(
        xq, nullptr, mt_h, mt_l, nullptr, nullptr, qp, nullptr,
        Dn, Dn, Dn, Dn, 0, WW, 0, (size_t)Mn * Dn, 1.0f);

    // ---- column bias terms ----
    wvec_kernel<<<Hn, Dn>>>(Wk, bq, wvec);
    colv_kernel<<<Mn, 256>>>(k, wvec, colv, inv_scale);

    // ---- V projection (2-term) -> transposed single fp16 Vt (OUTM=4) ----
    hmma_gemm<2, true, 4, false, false><<<gproj, 256, SM2>>>(
        xv, nullptr, wv_h, wv_l, bv, nullptr, vt, nullptr,
        Dn, Dn, Dn, Dn, 0, WW, (size_t)Dn, 0, 1.0f);

    // ---- scores: Ps = q~ @ k^T / scale (2-term) -> fp16 ----
    dim3 gsc(Nn / 128, Nn / 128, Hn * Bn);
    hmma_gemm<2, false, 3, false, true><<<gsc, 256, SM2>>>(
        qp, nullptr, xk_h, xk_l, nullptr, nullptr, Ps, nullptr,
        Nn, Dn, Dn, Dn, (size_t)Nn * Dn, (size_t)Nn * Dn, 0, (size_t)Nn * Nn,
        inv_scale);

    // ---- softmax (+colv), fp16 in -> fp16 out ----
    softmax1024_h<<<Hn * Bn * Nn, 256>>>(Ps, colv, ph);

    // ---- O = P @ Vt^T (1-term: both single fp16) -> ot [h][m][d] ----
    dim3 gpv(Dn / 128, Nn / 128, Hn * Bn);
    hmma_gemm<1, false, 3, false, false><<<gpv, 256, SM1>>>(
        ph, nullptr, vt, nullptr, nullptr, nullptr, ot, nullptr,
        Dn, Nn, Nn, Nn, (size_t)Nn * Nn, (size_t)Dn * Nn, 0, (size_t)Nn * Dn,
        1.0f);

    // ---- output projection: rep = ot(h-blocked) @ wo_p^T + bo (2-term) ----
    dim3 gfin(Dn / 128, Mn / 128, 1);
    hmma_gemm<2, true, 0, true, false><<<gfin, 256, SM2>>>(
        ot, nullptr, wop_h, wop_l, bo, out, nullptr, nullptr,
        Dn, Hn * Dn, Dn, Hn * Dn, 0, 0, 0, 0, 1.0f);
}

// round 9
// speedup vs baseline: 4.7744x; 1.1461x over previous
#include <cuda_runtime.h>
#include <cuda_fp16.h>
#include <math.h>
#include <stdint.h>

// ---------------------------------------------------------------------------
// Problem constants
// ---------------------------------------------------------------------------
constexpr int Hn = 8, Bn = 16, Nn = 1024, Dn = 512;
constexpr int Mn = Bn * Nn;                               // 16384
constexpr size_t XEL  = (size_t)Mn * Dn;                  // 8,388,608
constexpr size_t WEL  = (size_t)Hn * Dn * Dn;             // 2,097,152
constexpr size_t PROJ = (size_t)Hn * Mn * Dn;             // 67,108,864
constexpr size_t PEL  = (size_t)Hn * Bn * Nn * Nn;        // 134,217,728
constexpr size_t HBLK2 = (size_t)Bn * Nn * Nn;            // 16M: h-block in P

// ---------------------------------------------------------------------------
// Scratch (__device__ globals — allocation-free)
// ---------------------------------------------------------------------------
__device__ __half g_xq[XEL];                       // q single fp16
__device__ __half g_xk_hi[XEL], g_xk_lo[XEL];      // k hi/lo (scores B)
__device__ __half g_xv[XEL];                       // v single fp16
__device__ __half g_wqt_hi[WEL], g_wqt_lo[WEL];    // Wq^T per head
__device__ __half g_wkt_hi[WEL], g_wkt_lo[WEL];    // Wk^T per head
__device__ __half g_wvt_hi[WEL], g_wvt_lo[WEL];    // Wv^T per head
__device__ __half g_mt_hi[WEL], g_mt_lo[WEL];      // Mt = Wk^T Wq
__device__ __half g_wvo_hi[WEL], g_wvo_lo[WEL];    // Wvo = Wo_h @ Wv_h
__device__ __half g_wop_hi[WEL], g_wop_lo[WEL];    // permuted Wo
__device__ __half g_qp[PROJ];                      // q~ single fp16
__device__ __half g_vt2[PROJ];                     // v~ [b][o][h*1024+j]
__device__ __half g_Ps[PEL];                       // raw scores, fp16
__device__ __half g_ph[PEL];                       // softmax out, fp16
__device__ float  g_wvec[Hn * Dn];                 // Wk^T bq per head
__device__ float  g_colv[(size_t)Hn * Bn * Nn];    // scaled col terms
__device__ float  g_bfin[Dn];                      // bo + sum_h Wo_h bv_h

// ---------------------------------------------------------------------------
// Helpers
// ---------------------------------------------------------------------------
__device__ __forceinline__ uint32_t s2u(const void* p) {
    uint32_t a;
    asm("{ .reg .u64 t; cvta.to.shared.u64 t, %1; cvt.u32.u64 %0, t; }"
        : "=r"(a) : "l"(p));
    return a;
}

__device__ __forceinline__ void cp16(uint32_t saddr, const void* gaddr) {
    asm volatile("cp.async.cg.shared.global [%0], [%1], 16;"
                 :: "r"(saddr), "l"(gaddr) : "memory");
}
__device__ __forceinline__ void cp_commit() {
    asm volatile("cp.async.commit_group;" ::: "memory");
}
template <int N>
__device__ __forceinline__ void cp_wait() {
    asm volatile("cp.async.wait_group %0;" :: "n"(N) : "memory");
}

__device__ __forceinline__ void ldsm4(uint32_t* r, uint32_t addr) {
    asm volatile("ldmatrix.sync.aligned.m8n8.x4.shared.b16 {%0,%1,%2,%3}, [%4];"
        : "=r"(r[0]), "=r"(r[1]), "=r"(r[2]), "=r"(r[3]) : "r"(addr));
}

__device__ __forceinline__ void mma16816(float* d, const uint32_t* a,
                                         uint32_t b0, uint32_t b1) {
    asm volatile(
        "mma.sync.aligned.m16n8k16.row.col.f32.f16.f16.f32 "
        "{%0,%1,%2,%3}, {%4,%5,%6,%7}, {%8,%9}, {%0,%1,%2,%3};"
        : "+f"(d[0]), "+f"(d[1]), "+f"(d[2]), "+f"(d[3])
        : "r"(a[0]), "r"(a[1]), "r"(a[2]), "r"(a[3]), "r"(b0), "r"(b1));
}

__device__ __forceinline__ void split2h(float x, uint16_t& h, uint16_t& l) {
    __half hb = __float2half_rn(x);
    __half lb = __float2half_rn(x - __half2float(hb));
    h = *reinterpret_cast<uint16_t*>(&hb);
    l = *reinterpret_cast<uint16_t*>(&lb);
}
__device__ __forceinline__ uint16_t h1(float x) {
    __half hb = __float2half_rn(x);
    return *reinterpret_cast<uint16_t*>(&hb);
}

// XOR chunk swizzle for 64B rows (4 x 16B chunks): conflict-free ldmatrix.
__device__ __forceinline__ uint32_t swz(uint32_t r, uint32_t ch) {
    return r * 64u + ((ch ^ ((r >> 1) & 3u)) << 4);
}

// ---------------------------------------------------------------------------
// fp16-split batched GEMM via mma.sync (HMMA):
// TERMS=3:  C = alpha*(Ahi+Alo)@(Bhi+Blo)^T
// TERMS=2:  C = alpha* A @(Bhi+Blo)^T (A single)
// TERMS=1:  C = alpha* A @ B^T (both single)
// OUTM : 0=fp32, 1=fp16 hi/lo, 3=single fp16,
//        5=single fp16 to vt2 layout [b][col][z*1024 + (row&1023)]
// AHB  : 0=plain A cols; 2=A col g decomposed (g>>10)*HBLK2 + (g&1023)
// BMODB: B z-index = z & 15 (B shared across heads, z = h*16+b)
// Tile 128x128, BK=32, 8 warps, 3-stage cp.async pipeline, 1 sync/chunk.
// ---------------------------------------------------------------------------
constexpr int TILE_B = 128 * 64;                 // 8192 B per tile

template <int TERMS> struct Cfg {
    static constexpr int NT    = (TERMS == 3) ? 4 : (TERMS == 2) ? 3 : 2;
    static constexpr int STAGE = NT * TILE_B;
    static constexpr int SMEM  = 3 * STAGE + 512;
};

template <int TERMS, bool BIAS, int OUTM, int AHB, bool BMODB>
__global__ void __launch_bounds__(256, 2) hmma_gemm(
    const __half* __restrict__ Ahi, const __half* __restrict__ Alo,
    const __half* __restrict__ Bhi, const __half* __restrict__ Blo,
    const float* __restrict__ biasg,
    float* __restrict__ Cf,
    __half* __restrict__ Chi, __half* __restrict__ Clo,
    int N, int K, int lda, int ldb,
    size_t sA, size_t sB, size_t sBias, size_t sC, float alpha)
{
    constexpr int STAGE = Cfg<TERMS>::STAGE;
    extern __shared__ __align__(16) char smem[];
    const uint32_t sb = s2u(smem);
    float* sbias = reinterpret_cast<float*>(smem + 3 * STAGE);

    const int tid  = threadIdx.x;
    const int wid  = tid >> 5, lane = tid & 31;
    const int wr   = wid >> 2, wc = wid & 3;      // warp grid 2x4
    const int col0 = blockIdx.x * 128, row0 = blockIdx.y * 128;
    const size_t z = blockIdx.z;
    const size_t zb = BMODB ? (z & 15) : z;
    Ahi += z * sA; if (TERMS == 3) Alo += z * sA;
    Bhi += zb * sB; if (TERMS >= 2) Blo += zb * sB;

    if (BIAS && tid < 128) sbias[tid] = biasg[z * sBias + col0 + tid];

    const int nCh = K >> 5;          // BK = 32

    auto prefetch = [&](int c) {
        const int k0 = c << 5;
        const uint32_t boff = sb + (uint32_t)(c % 3) * STAGE;
        size_t aoff;
        if (AHB == 2) aoff = ((size_t)(k0 >> 10)) * HBLK2 + (size_t)(k0 & 1023);
        else          aoff = (size_t)k0;
        constexpr int NT = Cfg<TERMS>::NT;
        constexpr int NA = (TERMS == 3) ? 2 : 1;
        #pragma unroll
        for (int t = 0; t < NT; t++) {
            const __half* s;
            if (TERMS == 3) s = (t == 0) ? Ahi : (t == 1) ? Alo
                              : (t == 2) ? Bhi : Blo;
            else if (TERMS == 2) s = (t == 0) ? Ahi : (t == 1) ? Bhi : Blo;
            else                 s = (t == 0) ? Ahi : Bhi;
            const uint32_t tb = boff + t * TILE_B;
            #pragma unroll
            for (int i = 0; i < 2; i++) {
                uint32_t idx = (uint32_t)(i * 256 + tid);   // 0..511
                uint32_t r = idx >> 2, ch = idx & 3;
                const __half* g;
                if (t < NA) g = s + aoff + (size_t)(row0 + r) * lda + ch * 8;
                else        g = s + (size_t)k0 + (size_t)(col0 + r) * ldb + ch * 8;
                cp16(tb + swz(r, ch), g);
            }
        }
        cp_commit();
    };

    float acc[4][4][4] = {};

    prefetch(0);
    prefetch(1);

    for (int c = 0; c < nCh; ++c) {
        if (c + 1 < nCh) cp_wait<1>(); else cp_wait<0>();
        __syncthreads();
        if (c + 2 < nCh) prefetch(c + 2);

        const uint32_t boff = sb + (uint32_t)(c % 3) * STAGE;
        const uint32_t aHiB = boff;
        const uint32_t aLoB = boff + TILE_B;                 // TERMS==3 only
        const uint32_t bHiB = boff + ((TERMS == 3) ? 2 : 1) * TILE_B;
        const uint32_t bLoB = bHiB + TILE_B;                 // TERMS>=2 only
        const uint32_t lrow = (uint32_t)(lane & 15), lhalf = (uint32_t)(lane >> 4);

        #pragma unroll
        for (int ks = 0; ks < 2; ks++) {
            const uint32_t kch = (uint32_t)ks * 2u + lhalf;   // 16B chunk index
            uint32_t bh[4][2], bl[4][2];
            #pragma unroll
            for (int np = 0; np < 2; np++) {
                uint32_t r = (uint32_t)(wc * 32 + np * 16) + lrow;
                uint32_t t[4];
                ldsm4(t, bHiB + swz(r, kch));
                bh[np*2+0][0] = t[0]; bh[np*2+0][1] = t[2];
                bh[np*2+1][0] = t[1]; bh[np*2+1][1] = t[3];
                if (TERMS >= 2) {
                    ldsm4(t, bLoB + swz(r, kch));
                    bl[np*2+0][0] = t[0]; bl[np*2+0][1] = t[2];
                    bl[np*2+1][0] = t[1]; bl[np*2+1][1] = t[3];
                }
            }
            #pragma unroll
            for (int mt = 0; mt < 4; mt++) {
                uint32_t r = (uint32_t)(wr * 64 + mt * 16) + lrow;
                uint32_t ah[4], al[4];
                ldsm4(ah, aHiB + swz(r, kch));
                if (TERMS == 3) ldsm4(al, aLoB + swz(r, kch));
                #pragma unroll
                for (int nt = 0; nt < 4; nt++) {
                    mma16816(acc[mt][nt], ah, bh[nt][0], bh[nt][1]);
                    if (TERMS >= 2)
                        mma16816(acc[mt][nt], ah, bl[nt][0], bl[nt][1]);
                    if (TERMS == 3)
                        mma16816(acc[mt][nt], al, bh[nt][0], bh[nt][1]);
                }
            }
        }
    }

    // ---- epilogue ----
    const int qr = lane >> 2, qc = lane & 3;
    #pragma unroll
    for (int mt = 0; mt < 4; mt++) {
        #pragma unroll
        for (int nt = 0; nt < 4; nt++) {
            const int lcol = wc * 32 + nt * 8 + qc * 2;
            const float b0 = BIAS ? sbias[lcol]     : 0.f;
            const float b1 = BIAS ? sbias[lcol + 1] : 0.f;
            const int r0 = row0 + wr * 64 + mt * 16 + qr;
            const float v00 = alpha * acc[mt][nt][0] + b0;
            const float v01 = alpha * acc[mt][nt][1] + b1;
            const float v10 = alpha * acc[mt][nt][2] + b0;
            const float v11 = alpha * acc[mt][nt][3] + b1;
            if (OUTM == 0) {
                float* cp = Cf + z * sC + (size_t)r0 * N + col0 + lcol;
                *reinterpret_cast<float2*>(cp)            = make_float2(v00, v01);
                *reinterpret_cast<float2*>(cp + 8ull * N) = make_float2(v10, v11);
            } else if (OUTM == 1) {
                uint16_t h0,l0,h1b,l1,h2,l2,h3,l3;
                split2h(v00, h0, l0); split2h(v01, h1b, l1);
                split2h(v10, h2, l2); split2h(v11, h3, l3);
                size_t o0 = z * sC + (size_t)r0 * N + col0 + lcol;
                size_t o1 = o0 + 8ull * N;
                *reinterpret_cast<uint32_t*>(
                    reinterpret_cast<uint16_t*>(Chi) + o0) = (uint32_t)h0 | ((uint32_t)h1b << 16);
                *reinterpret_cast<uint32_t*>(
                    reinterpret_cast<uint16_t*>(Clo) + o0) = (uint32_t)l0 | ((uint32_t)l1 << 16);
                *reinterpret_cast<uint32_t*>(
                    reinterpret_cast<uint16_t*>(Chi) + o1) = (uint32_t)h2 | ((uint32_t)h3 << 16);
                *reinterpret_cast<uint32_t*>(
                    reinterpret_cast<uint16_t*>(Clo) + o1) = (uint32_t)l2 | ((uint32_t)l3 << 16);
            } else if (OUTM == 3) {
                size_t o0 = z * sC + (size_t)r0 * N + col0 + lcol;
                size_t o1 = o0 + 8ull * N;
                *reinterpret_cast<uint32_t*>(
                    reinterpret_cast<uint16_t*>(Chi) + o0) =
                    (uint32_t)h1(v00) | ((uint32_t)h1(v01) << 16);
                *reinterpret_cast<uint32_t*>(
                    reinterpret_cast<uint16_t*>(Chi) + o1) =
                    (uint32_t)h1(v10) | ((uint32_t)h1(v11) << 16);
            } else {
                // OUTM == 5: vt2[b][col][z*1024 + j],  b = r0>>10, j = r0&1023
                uint16_t* oh = reinterpret_cast<uint16_t*>(Chi);
                const size_t bb = (size_t)(r0 >> 10);
                const int j0 = r0 & 1023;
                const size_t c0a = (bb * 512 + (size_t)(col0 + lcol)) * 8192
                                 + (size_t)z * 1024;
                const size_t c1a = c0a + 8192;       // col+1
                oh[c0a + j0]     = h1(v00);
                oh[c1a + j0]     = h1(v01);
                oh[c0a + j0 + 8] = h1(v10);
                oh[c1a + j0 + 8] = h1(v11);
            }
        }
    }
}

// ---------------------------------------------------------------------------
// fp32 -> fp16 single / hi-lo elementwise conversions
// ---------------------------------------------------------------------------
__global__ void conv_h(const float* __restrict__ s, __half* __restrict__ h) {
    size_t i = ((size_t)blockIdx.x * 256 + threadIdx.x) * 4;
    float4 v = *reinterpret_cast<const float4*>(s + i);
    *reinterpret_cast<uint2*>(h + i) = make_uint2(
        (uint32_t)h1(v.x) | ((uint32_t)h1(v.y) << 16),
        (uint32_t)h1(v.z) | ((uint32_t)h1(v.w) << 16));
}

__global__ void conv_hl(const float* __restrict__ s,
                        __half* __restrict__ h,
                        __half* __restrict__ l) {
    size_t i = ((size_t)blockIdx.x * 256 + threadIdx.x) * 4;
    float4 v = *reinterpret_cast<const float4*>(s + i);
    uint16_t h0,l0,h1b,l1,h2,l2,h3,l3;
    split2h(v.x, h0, l0); split2h(v.y, h1b, l1);
    split2h(v.z, h2, l2); split2h(v.w, h3, l3);
    *reinterpret_cast<uint2*>(h + i) =
        make_uint2((uint32_t)h0 | ((uint32_t)h1b << 16),
                   (uint32_t)h2 | ((uint32_t)h3 << 16));
    *reinterpret_cast<uint2*>(l + i) =
        make_uint2((uint32_t)l0 | ((uint32_t)l1 << 16),
                   (uint32_t)l2 | ((uint32_t)l3 << 16));
}

// ---------------------------------------------------------------------------
// Per-head 512x512 transpose + split: out[h][d][e] = in[h][e][d]
// ---------------------------------------------------------------------------
__global__ void transpose_w_hl(const float* __restrict__ in,
                               __half* __restrict__ oh,
                               __half* __restrict__ ol) {
    __shared__ float t[32][33];
    const size_t z = blockIdx.z;
    in += z * (size_t)(Dn * Dn);
    oh += z * (size_t)(Dn * Dn);
    ol += z * (size_t)(Dn * Dn);
    const int x0 = blockIdx.x * 32;
    const int y0 = blockIdx.y * 32;
    #pragma unroll
    for (int i = 0; i < 4; i++)
        t[threadIdx.y + i * 8][threadIdx.x] =
            in[(size_t)(y0 + threadIdx.y + i * 8) * Dn + x0 + threadIdx.x];
    __syncthreads();
    #pragma unroll
    for (int i = 0; i < 4; i++) {
        float v = t[threadIdx.x][threadIdx.y + i * 8];
        uint16_t h, l;
        split2h(v, h, l);
        size_t o = (size_t)(x0 + threadIdx.y + i * 8) * Dn + y0 + threadIdx.x;
        reinterpret_cast<uint16_t*>(oh)[o] = h;
        reinterpret_cast<uint16_t*>(ol)[o] = l;
    }
}

// ---------------------------------------------------------------------------
// Wo permute + split: wo_p[o][h*512+d] = Wo[o][d*8+h]
// ---------------------------------------------------------------------------
__global__ void conv_wo_p(const float* __restrict__ Wo,
                          __half* __restrict__ oh,
                          __half* __restrict__ ol) {
    size_t idx = (size_t)blockIdx.x * 256 + threadIdx.x;
    int g = (int)(idx & 4095);
    size_t o = idx >> 12;
    int f = ((g & 511) << 3) | (g >> 9);
    float v = Wo[(o << 12) + f];
    uint16_t h, l;
    split2h(v, h, l);
    reinterpret_cast<uint16_t*>(oh)[idx] = h;
    reinterpret_cast<uint16_t*>(ol)[idx] = l;
}

// ---------------------------------------------------------------------------
// bfin[o] = bo[o] + sum_f Wo[o][f] * bv[f&7][f>>3]
// ---------------------------------------------------------------------------
__global__ void bfin_kernel(const float* __restrict__ Wo,
                            const float* __restrict__ bv,
                            const float* __restrict__ bo,
                            float* __restrict__ bfin) {
    __shared__ float red[8];
    const int o = blockIdx.x, tid = threadIdx.x;
    const float* wr = Wo + (size_t)o * 4096;
    float s = 0.f;
    for (int f = tid; f < 4096; f += 256)
        s += wr[f] * bv[(f & 7) * Dn + (f >> 3)];
    #pragma unroll
    for (int off = 16; off > 0; off >>= 1)
        s += __shfl_xor_sync(0xffffffffu, s, off);
    if ((tid & 31) == 0) red[tid >> 5] = s;
    __syncthreads();
    if (tid == 0) {
        float t = 0.f;
        #pragma unroll
        for (int i = 0; i < 8; i++) t += red[i];
        bfin[o] = bo[o] + t;
    }
}

// ---------------------------------------------------------------------------
// wvec[h][d] = sum_e bq[h][e] * Wk[h][e][d]
// ---------------------------------------------------------------------------
__global__ void wvec_kernel(const float* __restrict__ Wk,
                            const float* __restrict__ bq,
                            float* __restrict__ wvec) {
    const int h = blockIdx.x, d = threadIdx.x;
    const float* wk = Wk + (size_t)h * Dn * Dn;
    const float* b  = bq + (size_t)h * Dn;
    float s = 0.f;
    for (int e = 0; e < Dn; e++) s += b[e] * wk[(size_t)e * Dn + d];
    wvec[h * Dn + d] = s;
}

// ---------------------------------------------------------------------------
// colv[(h*16+b)][j] = inv_scale * k[b][j] . wvec[h]
// ---------------------------------------------------------------------------
__global__ void colv_kernel(const float* __restrict__ k,
                            const float* __restrict__ wvec,
                            float* __restrict__ colv, float inv_scale) {
    __shared__ float kr[Dn];
    const size_t bj = blockIdx.x;
    const int tid = threadIdx.x, w = tid >> 5, lane = tid & 31;
    const float* kp = k + bj * Dn;
    #pragma unroll
    for (int i = 0; i < 2; i++) kr[tid + i * 256] = kp[tid + i * 256];
    __syncthreads();
    const float* wv = wvec + w * Dn;
    float s = 0.f;
    #pragma unroll
    for (int t = 0; t < 16; t++) {
        int d = lane + t * 32;
        s += kr[d] * wv[d];
    }
    #pragma unroll
    for (int o = 16; o > 0; o >>= 1)
        s += __shfl_xor_sync(0xffffffffu, s, o);
    if (lane == 0) {
        size_t b = bj >> 10, j = bj & 1023;
        colv[((size_t)w * 16 + b) * 1024 + j] = s * inv_scale;
    }
}

// ---------------------------------------------------------------------------
// Softmax over 1024-wide fp16 rows (+ per-column bias term) -> single fp16
// ---------------------------------------------------------------------------
__global__ void softmax1024_h(const __half* __restrict__ P,
                              const float* __restrict__ colv,
                              __half* __restrict__ Ph) {
    __shared__ float red[8];
    const size_t row = blockIdx.x;
    const size_t z = row >> 10;
    const int tid = threadIdx.x;

    uint2 pr = *reinterpret_cast<const uint2*>(P + row * 1024 + tid * 4);
    __half2 p01 = *reinterpret_cast<__half2*>(&pr.x);
    __half2 p23 = *reinterpret_cast<__half2*>(&pr.y);
    float4 cv = *reinterpret_cast<const float4*>(colv + z * 1024 + tid * 4);
    float x0 = __half2float(__low2half(p01))  + cv.x;
    float x1 = __half2float(__high2half(p01)) + cv.y;
    float x2 = __half2float(__low2half(p23))  + cv.z;
    float x3 = __half2float(__high2half(p23)) + cv.w;

    float m = fmaxf(fmaxf(x0, x1), fmaxf(x2, x3));
    #pragma unroll
    for (int o = 16; o > 0; o >>= 1)
        m = fmaxf(m, __shfl_xor_sync(0xffffffffu, m, o));
    if ((tid & 31) == 0) red[tid >> 5] = m;
    __syncthreads();
    float bm = red[0];
    #pragma unroll
    for (int i = 1; i < 8; i++) bm = fmaxf(bm, red[i]);
    __syncthreads();

    float e0 = __expf(x0 - bm), e1 = __expf(x1 - bm);
    float e2 = __expf(x2 - bm), e3 = __expf(x3 - bm);
    float s = e0 + e1 + e2 + e3;
    #pragma unroll
    for (int o = 16; o > 0; o >>= 1)
        s += __shfl_xor_sync(0xffffffffu, s, o);
    if ((tid & 31) == 0) red[tid >> 5] = s;
    __syncthreads();
    float bs = 0.f;
    #pragma unroll
    for (int i = 0; i < 8; i++) bs += red[i];
    float inv = 1.0f / bs;

    size_t o = row * 1024 + tid * 4;
    *reinterpret_cast<uint2*>(Ph + o) = make_uint2(
        (uint32_t)h1(e0 * inv) | ((uint32_t)h1(e1 * inv) << 16),
        (uint32_t)h1(e2 * inv) | ((uint32_t)h1(e3 * inv) << 16));
}

// ---------------------------------------------------------------------------
// kernel_launch — inputs: k, v, q, Wk, bk, Wv, bv, Wq, bq, Wo, bo
// ---------------------------------------------------------------------------
extern "C" void kernel_launch(void* const* d_in, const int* in_sizes, int n_in,
                              void* d_out, int out_size) {
    (void)in_sizes; (void)n_in; (void)out_size;
    const float* k  = (const float*)d_in[0];
    const float* v  = (const float*)d_in[1];
    const float* q  = (const float*)d_in[2];
    const float* Wk = (const float*)d_in[3];
    const float* Wv = (const float*)d_in[5];
    const float* bv = (const float*)d_in[6];
    const float* Wq = (const float*)d_in[7];
    const float* bq = (const float*)d_in[8];
    const float* Wo = (const float*)d_in[9];
    const float* bo = (const float*)d_in[10];
    float* out = (float*)d_out;

    constexpr int SM3 = Cfg<3>::SMEM;
    constexpr int SM2 = Cfg<2>::SMEM;
    constexpr int SM1 = Cfg<1>::SMEM;
    cudaFuncSetAttribute(hmma_gemm<3, false, 1, 0, false>,
        cudaFuncAttributeMaxDynamicSharedMemorySize, SM3);
    cudaFuncSetAttribute(hmma_gemm<2, false, 3, 0, false>,
        cudaFuncAttributeMaxDynamicSharedMemorySize, SM2);
    cudaFuncSetAttribute(hmma_gemm<2, false, 5, 0, false>,
        cudaFuncAttributeMaxDynamicSharedMemorySize, SM2);
    cudaFuncSetAttribute(hmma_gemm<2, false, 3, 0, true>,
        cudaFuncAttributeMaxDynamicSharedMemorySize, SM2);
    cudaFuncSetAttribute(hmma_gemm<1, true, 0, 2, false>,
        cudaFuncAttributeMaxDynamicSharedMemorySize, SM1);

    __half *xq,*xk_h,*xk_l,*xv;
    __half *wqt_h,*wqt_l,*wkt_h,*wkt_l,*wvt_h,*wvt_l,*mt_h,*mt_l;
    __half *wvo_h,*wvo_l,*wop_h,*wop_l;
    __half *qp,*vt2,*Ps,*ph;
    float *wvec,*colv,*bfin;
    cudaGetSymbolAddress((void**)&xq,   g_xq);
    cudaGetSymbolAddress((void**)&xk_h, g_xk_hi); cudaGetSymbolAddress((void**)&xk_l, g_xk_lo);
    cudaGetSymbolAddress((void**)&xv,   g_xv);
    cudaGetSymbolAddress((void**)&wqt_h,g_wqt_hi);cudaGetSymbolAddress((void**)&wqt_l,g_wqt_lo);
    cudaGetSymbolAddress((void**)&wkt_h,g_wkt_hi);cudaGetSymbolAddress((void**)&wkt_l,g_wkt_lo);
    cudaGetSymbolAddress((void**)&wvt_h,g_wvt_hi);cudaGetSymbolAddress((void**)&wvt_l,g_wvt_lo);
    cudaGetSymbolAddress((void**)&mt_h, g_mt_hi); cudaGetSymbolAddress((void**)&mt_l, g_mt_lo);
    cudaGetSymbolAddress((void**)&wvo_h,g_wvo_hi);cudaGetSymbolAddress((void**)&wvo_l,g_wvo_lo);
    cudaGetSymbolAddress((void**)&wop_h,g_wop_hi);cudaGetSymbolAddress((void**)&wop_l,g_wop_lo);
    cudaGetSymbolAddress((void**)&qp,   g_qp);
    cudaGetSymbolAddress((void**)&vt2,  g_vt2);
    cudaGetSymbolAddress((void**)&Ps,   g_Ps);
    cudaGetSymbolAddress((void**)&ph,   g_ph);
    cudaGetSymbolAddress((void**)&wvec, g_wvec);
    cudaGetSymbolAddress((void**)&colv, g_colv);
    cudaGetSymbolAddress((void**)&bfin, g_bfin);

    const float inv_scale = 1.0f / sqrtf((float)Dn);
    const size_t WW = (size_t)Dn * Dn;

    // ---- conversions ----
    transpose_w_hl<<<dim3(16, 16, Hn), dim3(32, 8)>>>(Wq, wqt_h, wqt_l);
    transpose_w_hl<<<dim3(16, 16, Hn), dim3(32, 8)>>>(Wk, wkt_h, wkt_l);
    transpose_w_hl<<<dim3(16, 16, Hn), dim3(32, 8)>>>(Wv, wvt_h, wvt_l);
    conv_h <<<(unsigned)(XEL / 1024), 256>>>(q, xq);
    conv_hl<<<(unsigned)(XEL / 1024), 256>>>(k, xk_h, xk_l);
    conv_h <<<(unsigned)(XEL / 1024), 256>>>(v, xv);
    conv_wo_p<<<(unsigned)(WEL / 256), 256>>>(Wo, wop_h, wop_l);
    bfin_kernel<<<Dn, 256>>>(Wo, bv, bo, bfin);

    // ---- Mt[h] = Wk^T Wq (3-term, hi/lo out) ----
    hmma_gemm<3, false, 1, 0, false><<<dim3(4, 4, Hn), 256, SM3>>>(
        wkt_h, wkt_l, wqt_h, wqt_l, nullptr, nullptr, mt_h, mt_l,
        Dn, Dn, Dn, Dn, WW, WW, 0, WW, 1.0f);

    // ---- Wvo[h] = Wo_h @ Wv_h (3-term): A = wo_p h-slice, B = Wv^T ----
    hmma_gemm<3, false, 1, 0, false><<<dim3(4, 4, Hn), 256, SM3>>>(
        wop_h, wop_l, wvt_h, wvt_l, nullptr, nullptr, wvo_h, wvo_l,
        Dn, Dn, Hn * Dn /*lda=4096*/, Dn, (size_t)Dn /*sA=512*/, WW, 0, WW, 1.0f);

    // ---- q~ = q @ Mt^T per head (2-term) ----
    dim3 gproj(Dn / 128, Mn / 128, Hn);
    hmma_gemm<2, false, 3, 0, false><<<gproj, 256, SM2>>>(
        xq, nullptr, mt_h, mt_l, nullptr, nullptr, qp, nullptr,
        Dn, Dn, Dn, Dn, 0, WW, 0, (size_t)Mn * Dn, 1.0f);

    // ---- column bias terms ----
    wvec_kernel<<<Hn, Dn>>>(Wk, bq, wvec);
    colv_kernel<<<Mn, 256>>>(k, wvec, colv, inv_scale);

    // ---- v~ = v @ Wvo^T (2-term) -> vt2[b][o][h*1024+j] (OUTM=5) ----
    hmma_gemm<2, false, 5, 0, false><<<gproj, 256, SM2>>>(
        xv, nullptr, wvo_h, wvo_l, nullptr, nullptr, vt2, nullptr,
        Dn, Dn, Dn, Dn, 0, WW, 0, 0, 1.0f);

    // ---- scores: Ps = q~ @ k^T / scale (2-term) -> fp16 ----
    dim3 gsc(Nn / 128, Nn / 128, Hn * Bn);
    hmma_gemm<2, false, 3, 0, true><<<gsc, 256, SM2>>>(
        qp, nullptr, xk_h, xk_l, nullptr, nullptr, Ps, nullptr,
        Nn, Dn, Dn, Dn, (size_t)Nn * Dn, (size_t)Nn * Dn, 0, (size_t)Nn * Nn,
        inv_scale);

    // ---- softmax (+colv), fp16 in -> fp16 out ----
    softmax1024_h<<<Hn * Bn * Nn, 256>>>(Ps, colv, ph);

    // ---- out = sum_h P_h @ v~_h + bfin  (1-term, K=8192, A h-blocked) ----
    // A = ph: row (b,i), col g=(h,j): addr = h*HBLK2 + b*(1024*1024) + i*1024 + j
    dim3 gfin(Dn / 128, Nn / 128, Bn);
    hmma_gemm<1, true, 0, 2, false><<<gfin, 256, SM1>>>(
        ph, nullptr, vt2, nullptr, bfin, out, nullptr, nullptr,
        Dn, Hn * Nn, Nn /*lda*/, Hn * Nn /*ldb=8192*/,
        (size_t)Nn * Nn /*sA: b block*/, (size_t)Dn * Hn * Nn /*sB*/,
        0, (size_t)Nn * Dn /*sC*/, 1.0f);
}

// round 10
// speedup vs baseline: 5.3982x; 1.1306x over previous
#include <cuda_runtime.h>
#include <cuda_fp16.h>
#include <math.h>
#include <stdint.h>

// ---------------------------------------------------------------------------
// Problem constants
// ---------------------------------------------------------------------------
constexpr int Hn = 8, Bn = 16, Nn = 1024, Dn = 512;
constexpr int Mn = Bn * Nn;                               // 16384
constexpr size_t XEL  = (size_t)Mn * Dn;                  // 8,388,608
constexpr size_t WEL  = (size_t)Hn * Dn * Dn;             // 2,097,152
constexpr size_t PROJ = (size_t)Hn * Mn * Dn;             // 67,108,864
constexpr size_t PEL  = (size_t)Hn * Bn * Nn * Nn;        // 134,217,728
constexpr size_t HBLK2 = (size_t)Bn * Nn * Nn;            // 16M: h-block in P

// ---------------------------------------------------------------------------
// Scratch (__device__ globals — allocation-free)
// ---------------------------------------------------------------------------
__device__ __half g_xq[XEL];                       // q single fp16
__device__ __half g_xk[XEL];                       // k single fp16
__device__ __half g_xv[XEL];                       // v single fp16
__device__ __half g_wqt_hi[WEL], g_wqt_lo[WEL];    // Wq^T per head
__device__ __half g_wkt_hi[WEL], g_wkt_lo[WEL];    // Wk^T per head
__device__ __half g_wvt_hi[WEL], g_wvt_lo[WEL];    // Wv^T per head
__device__ __half g_mt_hi[WEL], g_mt_lo[WEL];      // Mt = Wk^T Wq
__device__ __half g_wvo_hi[WEL], g_wvo_lo[WEL];    // Wvo = Wo_h @ Wv_h
__device__ __half g_wop_hi[WEL], g_wop_lo[WEL];    // permuted Wo
__device__ __half g_qp[PROJ];                      // q~ single fp16
__device__ __half g_vt2[PROJ];                     // v~ [b][o][h*1024+j]
__device__ __half g_Ps[PEL];                       // raw scores, fp16
__device__ __half g_ph[PEL];                       // softmax out, fp16
__device__ float  g_wvec[Hn * Dn];                 // Wk^T bq per head
__device__ float  g_colv[(size_t)Hn * Bn * Nn];    // scaled col terms
__device__ float  g_bfin[Dn];                      // bo + sum_h Wo_h bv_h

// ---------------------------------------------------------------------------
// Helpers
// ---------------------------------------------------------------------------
__device__ __forceinline__ uint32_t s2u(const void* p) {
    uint32_t a;
    asm("{ .reg .u64 t; cvta.to.shared.u64 t, %1; cvt.u32.u64 %0, t; }"
        : "=r"(a) : "l"(p));
    return a;
}

__device__ __forceinline__ void cp16(uint32_t saddr, const void* gaddr) {
    asm volatile("cp.async.cg.shared.global [%0], [%1], 16;"
                 :: "r"(saddr), "l"(gaddr) : "memory");
}
__device__ __forceinline__ void cp_commit() {
    asm volatile("cp.async.commit_group;" ::: "memory");
}
template <int N>
__device__ __forceinline__ void cp_wait() {
    asm volatile("cp.async.wait_group %0;" :: "n"(N) : "memory");
}

__device__ __forceinline__ void ldsm4(uint32_t* r, uint32_t addr) {
    asm volatile("ldmatrix.sync.aligned.m8n8.x4.shared.b16 {%0,%1,%2,%3}, [%4];"
        : "=r"(r[0]), "=r"(r[1]), "=r"(r[2]), "=r"(r[3]) : "r"(addr));
}

__device__ __forceinline__ void mma16816(float* d, const uint32_t* a,
                                         uint32_t b0, uint32_t b1) {
    asm volatile(
        "mma.sync.aligned.m16n8k16.row.col.f32.f16.f16.f32 "
        "{%0,%1,%2,%3}, {%4,%5,%6,%7}, {%8,%9}, {%0,%1,%2,%3};"
        : "+f"(d[0]), "+f"(d[1]), "+f"(d[2]), "+f"(d[3])
        : "r"(a[0]), "r"(a[1]), "r"(a[2]), "r"(a[3]), "r"(b0), "r"(b1));
}

__device__ __forceinline__ void split2h(float x, uint16_t& h, uint16_t& l) {
    __half hb = __float2half_rn(x);
    __half lb = __float2half_rn(x - __half2float(hb));
    h = *reinterpret_cast<uint16_t*>(&hb);
    l = *reinterpret_cast<uint16_t*>(&lb);
}
__device__ __forceinline__ uint16_t h1(float x) {
    __half hb = __float2half_rn(x);
    return *reinterpret_cast<uint16_t*>(&hb);
}

// XOR chunk swizzle for 64B rows (4 x 16B chunks): conflict-free ldmatrix.
__device__ __forceinline__ uint32_t swz(uint32_t r, uint32_t ch) {
    return r * 64u + ((ch ^ ((r >> 1) & 3u)) << 4);
}

// ---------------------------------------------------------------------------
// fp16-split batched GEMM via mma.sync (HMMA):
// TERMS=3:  C = alpha*(Ahi+Alo)@(Bhi+Blo)^T
// TERMS=2:  C = alpha* A @(Bhi+Blo)^T (A single)
// TERMS=1:  C = alpha* A @ B^T (both single)
// OUTM : 0=fp32, 1=fp16 hi/lo, 3=single fp16,
//        5=single fp16 to vt2 layout [b][col][z*1024 + (row&1023)]
// AHB  : 0=plain A cols; 2=A col g decomposed (g>>10)*HBLK2 + (g&1023)
// BMODB: B z-index = z & 15 (B shared across heads, z = h*16+b)
// Tile 128x128, BK=32, 8 warps, 3-stage cp.async pipeline, 1 sync/chunk.
// ---------------------------------------------------------------------------
constexpr int TILE_B = 128 * 64;                 // 8192 B per tile

template <int TERMS> struct Cfg {
    static constexpr int NT    = (TERMS == 3) ? 4 : (TERMS == 2) ? 3 : 2;
    static constexpr int STAGE = NT * TILE_B;
    static constexpr int SMEM  = 3 * STAGE + 512;
};

template <int TERMS, bool BIAS, int OUTM, int AHB, bool BMODB>
__global__ void __launch_bounds__(256, 2) hmma_gemm(
    const __half* __restrict__ Ahi, const __half* __restrict__ Alo,
    const __half* __restrict__ Bhi, const __half* __restrict__ Blo,
    const float* __restrict__ biasg,
    float* __restrict__ Cf,
    __half* __restrict__ Chi, __half* __restrict__ Clo,
    int N, int K, int lda, int ldb,
    size_t sA, size_t sB, size_t sBias, size_t sC, float alpha)
{
    constexpr int STAGE = Cfg<TERMS>::STAGE;
    extern __shared__ __align__(16) char smem[];
    const uint32_t sb = s2u(smem);
    float* sbias = reinterpret_cast<float*>(smem + 3 * STAGE);

    const int tid  = threadIdx.x;
    const int wid  = tid >> 5, lane = tid & 31;
    const int wr   = wid >> 2, wc = wid & 3;      // warp grid 2x4
    const int col0 = blockIdx.x * 128, row0 = blockIdx.y * 128;
    const size_t z = blockIdx.z;
    const size_t zb = BMODB ? (z & 15) : z;
    Ahi += z * sA; if (TERMS == 3) Alo += z * sA;
    Bhi += zb * sB; if (TERMS >= 2) Blo += zb * sB;

    if (BIAS && tid < 128) sbias[tid] = biasg[z * sBias + col0 + tid];

    const int nCh = K >> 5;          // BK = 32

    auto prefetch = [&](int c) {
        const int k0 = c << 5;
        const uint32_t boff = sb + (uint32_t)(c % 3) * STAGE;
        size_t aoff;
        if (AHB == 2) aoff = ((size_t)(k0 >> 10)) * HBLK2 + (size_t)(k0 & 1023);
        else          aoff = (size_t)k0;
        constexpr int NT = Cfg<TERMS>::NT;
        constexpr int NA = (TERMS == 3) ? 2 : 1;
        #pragma unroll
        for (int t = 0; t < NT; t++) {
            const __half* s;
            if (TERMS == 3) s = (t == 0) ? Ahi : (t == 1) ? Alo
                              : (t == 2) ? Bhi : Blo;
            else if (TERMS == 2) s = (t == 0) ? Ahi : (t == 1) ? Bhi : Blo;
            else                 s = (t == 0) ? Ahi : Bhi;
            const uint32_t tb = boff + t * TILE_B;
            #pragma unroll
            for (int i = 0; i < 2; i++) {
                uint32_t idx = (uint32_t)(i * 256 + tid);   // 0..511
                uint32_t r = idx >> 2, ch = idx & 3;
                const __half* g;
                if (t < NA) g = s + aoff + (size_t)(row0 + r) * lda + ch * 8;
                else        g = s + (size_t)k0 + (size_t)(col0 + r) * ldb + ch * 8;
                cp16(tb + swz(r, ch), g);
            }
        }
        cp_commit();
    };

    float acc[4][4][4] = {};

    prefetch(0);
    prefetch(1);

    for (int c = 0; c < nCh; ++c) {
        if (c + 1 < nCh) cp_wait<1>(); else cp_wait<0>();
        __syncthreads();
        if (c + 2 < nCh) prefetch(c + 2);

        const uint32_t boff = sb + (uint32_t)(c % 3) * STAGE;
        const uint32_t aHiB = boff;
        const uint32_t aLoB = boff + TILE_B;                 // TERMS==3 only
        const uint32_t bHiB = boff + ((TERMS == 3) ? 2 : 1) * TILE_B;
        const uint32_t bLoB = bHiB + TILE_B;                 // TERMS>=2 only
        const uint32_t lrow = (uint32_t)(lane & 15), lhalf = (uint32_t)(lane >> 4);

        #pragma unroll
        for (int ks = 0; ks < 2; ks++) {
            const uint32_t kch = (uint32_t)ks * 2u + lhalf;   // 16B chunk index
            uint32_t bh[4][2], bl[4][2];
            #pragma unroll
            for (int np = 0; np < 2; np++) {
                uint32_t r = (uint32_t)(wc * 32 + np * 16) + lrow;
                uint32_t t[4];
                ldsm4(t, bHiB + swz(r, kch));
                bh[np*2+0][0] = t[0]; bh[np*2+0][1] = t[2];
                bh[np*2+1][0] = t[1]; bh[np*2+1][1] = t[3];
                if (TERMS >= 2) {
                    ldsm4(t, bLoB + swz(r, kch));
                    bl[np*2+0][0] = t[0]; bl[np*2+0][1] = t[2];
                    bl[np*2+1][0] = t[1]; bl[np*2+1][1] = t[3];
                }
            }
            #pragma unroll
            for (int mt = 0; mt < 4; mt++) {
                uint32_t r = (uint32_t)(wr * 64 + mt * 16) + lrow;
                uint32_t ah[4], al[4];
                ldsm4(ah, aHiB + swz(r, kch));
                if (TERMS == 3) ldsm4(al, aLoB + swz(r, kch));
                #pragma unroll
                for (int nt = 0; nt < 4; nt++) {
                    mma16816(acc[mt][nt], ah, bh[nt][0], bh[nt][1]);
                    if (TERMS >= 2)
                        mma16816(acc[mt][nt], ah, bl[nt][0], bl[nt][1]);
                    if (TERMS == 3)
                        mma16816(acc[mt][nt], al, bh[nt][0], bh[nt][1]);
                }
            }
        }
    }

    // ---- epilogue ----
    const int qr = lane >> 2, qc = lane & 3;
    #pragma unroll
    for (int mt = 0; mt < 4; mt++) {
        #pragma unroll
        for (int nt = 0; nt < 4; nt++) {
            const int lcol = wc * 32 + nt * 8 + qc * 2;
            const float b0 = BIAS ? sbias[lcol]     : 0.f;
            const float b1 = BIAS ? sbias[lcol + 1] : 0.f;
            const int r0 = row0 + wr * 64 + mt * 16 + qr;
            const float v00 = alpha * acc[mt][nt][0] + b0;
            const float v01 = alpha * acc[mt][nt][1] + b1;
            const float v10 = alpha * acc[mt][nt][2] + b0;
            const float v11 = alpha * acc[mt][nt][3] + b1;
            if (OUTM == 0) {
                float* cp = Cf + z * sC + (size_t)r0 * N + col0 + lcol;
                *reinterpret_cast<float2*>(cp)            = make_float2(v00, v01);
                *reinterpret_cast<float2*>(cp + 8ull * N) = make_float2(v10, v11);
            } else if (OUTM == 1) {
                uint16_t h0,l0,h1b,l1,h2,l2,h3,l3;
                split2h(v00, h0, l0); split2h(v01, h1b, l1);
                split2h(v10, h2, l2); split2h(v11, h3, l3);
                size_t o0 = z * sC + (size_t)r0 * N + col0 + lcol;
                size_t o1 = o0 + 8ull * N;
                *reinterpret_cast<uint32_t*>(
                    reinterpret_cast<uint16_t*>(Chi) + o0) = (uint32_t)h0 | ((uint32_t)h1b << 16);
                *reinterpret_cast<uint32_t*>(
                    reinterpret_cast<uint16_t*>(Clo) + o0) = (uint32_t)l0 | ((uint32_t)l1 << 16);
                *reinterpret_cast<uint32_t*>(
                    reinterpret_cast<uint16_t*>(Chi) + o1) = (uint32_t)h2 | ((uint32_t)h3 << 16);
                *reinterpret_cast<uint32_t*>(
                    reinterpret_cast<uint16_t*>(Clo) + o1) = (uint32_t)l2 | ((uint32_t)l3 << 16);
            } else if (OUTM == 3) {
                size_t o0 = z * sC + (size_t)r0 * N + col0 + lcol;
                size_t o1 = o0 + 8ull * N;
                *reinterpret_cast<uint32_t*>(
                    reinterpret_cast<uint16_t*>(Chi) + o0) =
                    (uint32_t)h1(v00) | ((uint32_t)h1(v01) << 16);
                *reinterpret_cast<uint32_t*>(
                    reinterpret_cast<uint16_t*>(Chi) + o1) =
                    (uint32_t)h1(v10) | ((uint32_t)h1(v11) << 16);
            } else {
                // OUTM == 5: vt2[b][col][z*1024 + j],  b = r0>>10, j = r0&1023
                uint16_t* oh = reinterpret_cast<uint16_t*>(Chi);
                const size_t bb = (size_t)(r0 >> 10);
                const int j0 = r0 & 1023;
                const size_t c0a = (bb * 512 + (size_t)(col0 + lcol)) * 8192
                                 + (size_t)z * 1024;
                const size_t c1a = c0a + 8192;       // col+1
                oh[c0a + j0]     = h1(v00);
                oh[c1a + j0]     = h1(v01);
                oh[c0a + j0 + 8] = h1(v10);
                oh[c1a + j0 + 8] = h1(v11);
            }
        }
    }
}

// ---------------------------------------------------------------------------
// fp32 -> fp16 single / hi-lo elementwise conversions
// ---------------------------------------------------------------------------
__global__ void conv_h(const float* __restrict__ s, __half* __restrict__ h) {
    size_t i = ((size_t)blockIdx.x * 256 + threadIdx.x) * 4;
    float4 v = *reinterpret_cast<const float4*>(s + i);
    *reinterpret_cast<uint2*>(h + i) = make_uint2(
        (uint32_t)h1(v.x) | ((uint32_t)h1(v.y) << 16),
        (uint32_t)h1(v.z) | ((uint32_t)h1(v.w) << 16));
}

// ---------------------------------------------------------------------------
// Per-head 512x512 transpose + split: out[h][d][e] = in[h][e][d]
// ---------------------------------------------------------------------------
__global__ void transpose_w_hl(const float* __restrict__ in,
                               __half* __restrict__ oh,
                               __half* __restrict__ ol) {
    __shared__ float t[32][33];
    const size_t z = blockIdx.z;
    in += z * (size_t)(Dn * Dn);
    oh += z * (size_t)(Dn * Dn);
    ol += z * (size_t)(Dn * Dn);
    const int x0 = blockIdx.x * 32;
    const int y0 = blockIdx.y * 32;
    #pragma unroll
    for (int i = 0; i < 4; i++)
        t[threadIdx.y + i * 8][threadIdx.x] =
            in[(size_t)(y0 + threadIdx.y + i * 8) * Dn + x0 + threadIdx.x];
    __syncthreads();
    #pragma unroll
    for (int i = 0; i < 4; i++) {
        float v = t[threadIdx.x][threadIdx.y + i * 8];
        uint16_t h, l;
        split2h(v, h, l);
        size_t o = (size_t)(x0 + threadIdx.y + i * 8) * Dn + y0 + threadIdx.x;
        reinterpret_cast<uint16_t*>(oh)[o] = h;
        reinterpret_cast<uint16_t*>(ol)[o] = l;
    }
}

// ---------------------------------------------------------------------------
// Wo permute + split: wo_p[o][h*512+d] = Wo[o][d*8+h]
// ---------------------------------------------------------------------------
__global__ void conv_wo_p(const float* __restrict__ Wo,
                          __half* __restrict__ oh,
                          __half* __restrict__ ol) {
    size_t idx = (size_t)blockIdx.x * 256 + threadIdx.x;
    int g = (int)(idx & 4095);
    size_t o = idx >> 12;
    int f = ((g & 511) << 3) | (g >> 9);
    float v = Wo[(o << 12) + f];
    uint16_t h, l;
    split2h(v, h, l);
    reinterpret_cast<uint16_t*>(oh)[idx] = h;
    reinterpret_cast<uint16_t*>(ol)[idx] = l;
}

// ---------------------------------------------------------------------------
// bfin[o] = bo[o] + sum_f Wo[o][f] * bv[f&7][f>>3]
// ---------------------------------------------------------------------------
__global__ void bfin_kernel(const float* __restrict__ Wo,
                            const float* __restrict__ bv,
                            const float* __restrict__ bo,
                            float* __restrict__ bfin) {
    __shared__ float red[8];
    const int o = blockIdx.x, tid = threadIdx.x;
    const float* wr = Wo + (size_t)o * 4096;
    float s = 0.f;
    for (int f = tid; f < 4096; f += 256)
        s += wr[f] * bv[(f & 7) * Dn + (f >> 3)];
    #pragma unroll
    for (int off = 16; off > 0; off >>= 1)
        s += __shfl_xor_sync(0xffffffffu, s, off);
    if ((tid & 31) == 0) red[tid >> 5] = s;
    __syncthreads();
    if (tid == 0) {
        float t = 0.f;
        #pragma unroll
        for (int i = 0; i < 8; i++) t += red[i];
        bfin[o] = bo[o] + t;
    }
}

// ---------------------------------------------------------------------------
// wvec[h][d] = sum_e bq[h][e] * Wk[h][e][d]
// ---------------------------------------------------------------------------
__global__ void wvec_kernel(const float* __restrict__ Wk,
                            const float* __restrict__ bq,
                            float* __restrict__ wvec) {
    const int h = blockIdx.x, d = threadIdx.x;
    const float* wk = Wk + (size_t)h * Dn * Dn;
    const float* b  = bq + (size_t)h * Dn;
    float s = 0.f;
    for (int e = 0; e < Dn; e++) s += b[e] * wk[(size_t)e * Dn + d];
    wvec[h * Dn + d] = s;
}

// ---------------------------------------------------------------------------
// colv[(h*16+b)][j] = inv_scale * k[b][j] . wvec[h]
// ---------------------------------------------------------------------------
__global__ void colv_kernel(const float* __restrict__ k,
                            const float* __restrict__ wvec,
                            float* __restrict__ colv, float inv_scale) {
    __shared__ float kr[Dn];
    const size_t bj = blockIdx.x;
    const int tid = threadIdx.x, w = tid >> 5, lane = tid & 31;
    const float* kp = k + bj * Dn;
    #pragma unroll
    for (int i = 0; i < 2; i++) kr[tid + i * 256] = kp[tid + i * 256];
    __syncthreads();
    const float* wv = wvec + w * Dn;
    float s = 0.f;
    #pragma unroll
    for (int t = 0; t < 16; t++) {
        int d = lane + t * 32;
        s += kr[d] * wv[d];
    }
    #pragma unroll
    for (int o = 16; o > 0; o >>= 1)
        s += __shfl_xor_sync(0xffffffffu, s, o);
    if (lane == 0) {
        size_t b = bj >> 10, j = bj & 1023;
        colv[((size_t)w * 16 + b) * 1024 + j] = s * inv_scale;
    }
}

// ---------------------------------------------------------------------------
// Softmax over 1024-wide fp16 rows (+ per-column bias term) -> single fp16
// ---------------------------------------------------------------------------
__global__ void softmax1024_h(const __half* __restrict__ P,
                              const float* __restrict__ colv,
                              __half* __restrict__ Ph) {
    __shared__ float red[8];
    const size_t row = blockIdx.x;
    const size_t z = row >> 10;
    const int tid = threadIdx.x;

    uint2 pr = *reinterpret_cast<const uint2*>(P + row * 1024 + tid * 4);
    __half2 p01 = *reinterpret_cast<__half2*>(&pr.x);
    __half2 p23 = *reinterpret_cast<__half2*>(&pr.y);
    float4 cv = *reinterpret_cast<const float4*>(colv + z * 1024 + tid * 4);
    float x0 = __half2float(__low2half(p01))  + cv.x;
    float x1 = __half2float(__high2half(p01)) + cv.y;
    float x2 = __half2float(__low2half(p23))  + cv.z;
    float x3 = __half2float(__high2half(p23)) + cv.w;

    float m = fmaxf(fmaxf(x0, x1), fmaxf(x2, x3));
    #pragma unroll
    for (int o = 16; o > 0; o >>= 1)
        m = fmaxf(m, __shfl_xor_sync(0xffffffffu, m, o));
    if ((tid & 31) == 0) red[tid >> 5] = m;
    __syncthreads();
    float bm = red[0];
    #pragma unroll
    for (int i = 1; i < 8; i++) bm = fmaxf(bm, red[i]);
    __syncthreads();

    float e0 = __expf(x0 - bm), e1 = __expf(x1 - bm);
    float e2 = __expf(x2 - bm), e3 = __expf(x3 - bm);
    float s = e0 + e1 + e2 + e3;
    #pragma unroll
    for (int o = 16; o > 0; o >>= 1)
        s += __shfl_xor_sync(0xffffffffu, s, o);
    if ((tid & 31) == 0) red[tid >> 5] = s;
    __syncthreads();
    float bs = 0.f;
    #pragma unroll
    for (int i = 0; i < 8; i++) bs += red[i];
    float inv = 1.0f / bs;

    size_t o = row * 1024 + tid * 4;
    *reinterpret_cast<uint2*>(Ph + o) = make_uint2(
        (uint32_t)h1(e0 * inv) | ((uint32_t)h1(e1 * inv) << 16),
        (uint32_t)h1(e2 * inv) | ((uint32_t)h1(e3 * inv) << 16));
}

// ---------------------------------------------------------------------------
// kernel_launch — inputs: k, v, q, Wk, bk, Wv, bv, Wq, bq, Wo, bo
// ---------------------------------------------------------------------------
extern "C" void kernel_launch(void* const* d_in, const int* in_sizes, int n_in,
                              void* d_out, int out_size) {
    (void)in_sizes; (void)n_in; (void)out_size;
    const float* k  = (const float*)d_in[0];
    const float* v  = (const float*)d_in[1];
    const float* q  = (const float*)d_in[2];
    const float* Wk = (const float*)d_in[3];
    const float* Wv = (const float*)d_in[5];
    const float* bv = (const float*)d_in[6];
    const float* Wq = (const float*)d_in[7];
    const float* bq = (const float*)d_in[8];
    const float* Wo = (const float*)d_in[9];
    const float* bo = (const float*)d_in[10];
    float* out = (float*)d_out;

    constexpr int SM3 = Cfg<3>::SMEM;
    constexpr int SM2 = Cfg<2>::SMEM;
    constexpr int SM1 = Cfg<1>::SMEM;
    cudaFuncSetAttribute(hmma_gemm<3, false, 1, 0, false>,
        cudaFuncAttributeMaxDynamicSharedMemorySize, SM3);
    cudaFuncSetAttribute(hmma_gemm<2, false, 3, 0, false>,
        cudaFuncAttributeMaxDynamicSharedMemorySize, SM2);
    cudaFuncSetAttribute(hmma_gemm<2, false, 5, 0, false>,
        cudaFuncAttributeMaxDynamicSharedMemorySize, SM2);
    cudaFuncSetAttribute(hmma_gemm<1, false, 3, 0, true>,
        cudaFuncAttributeMaxDynamicSharedMemorySize, SM1);
    cudaFuncSetAttribute(hmma_gemm<1, true, 0, 2, false>,
        cudaFuncAttributeMaxDynamicSharedMemorySize, SM1);

    __half *xq,*xk,*xv;
    __half *wqt_h,*wqt_l,*wkt_h,*wkt_l,*wvt_h,*wvt_l,*mt_h,*mt_l;
    __half *wvo_h,*wvo_l,*wop_h,*wop_l;
    __half *qp,*vt2,*Ps,*ph;
    float *wvec,*colv,*bfin;
    cudaGetSymbolAddress((void**)&xq,   g_xq);
    cudaGetSymbolAddress((void**)&xk,   g_xk);
    cudaGetSymbolAddress((void**)&xv,   g_xv);
    cudaGetSymbolAddress((void**)&wqt_h,g_wqt_hi);cudaGetSymbolAddress((void**)&wqt_l,g_wqt_lo);
    cudaGetSymbolAddress((void**)&wkt_h,g_wkt_hi);cudaGetSymbolAddress((void**)&wkt_l,g_wkt_lo);
    cudaGetSymbolAddress((void**)&wvt_h,g_wvt_hi);cudaGetSymbolAddress((void**)&wvt_l,g_wvt_lo);
    cudaGetSymbolAddress((void**)&mt_h, g_mt_hi); cudaGetSymbolAddress((void**)&mt_l, g_mt_lo);
    cudaGetSymbolAddress((void**)&wvo_h,g_wvo_hi);cudaGetSymbolAddress((void**)&wvo_l,g_wvo_lo);
    cudaGetSymbolAddress((void**)&wop_h,g_wop_hi);cudaGetSymbolAddress((void**)&wop_l,g_wop_lo);
    cudaGetSymbolAddress((void**)&qp,   g_qp);
    cudaGetSymbolAddress((void**)&vt2,  g_vt2);
    cudaGetSymbolAddress((void**)&Ps,   g_Ps);
    cudaGetSymbolAddress((void**)&ph,   g_ph);
    cudaGetSymbolAddress((void**)&wvec, g_wvec);
    cudaGetSymbolAddress((void**)&colv, g_colv);
    cudaGetSymbolAddress((void**)&bfin, g_bfin);

    const float inv_scale = 1.0f / sqrtf((float)Dn);
    const size_t WW = (size_t)Dn * Dn;

    // ---- conversions ----
    transpose_w_hl<<<dim3(16, 16, Hn), dim3(32, 8)>>>(Wq, wqt_h, wqt_l);
    transpose_w_hl<<<dim3(16, 16, Hn), dim3(32, 8)>>>(Wk, wkt_h, wkt_l);
    transpose_w_hl<<<dim3(16, 16, Hn), dim3(32, 8)>>>(Wv, wvt_h, wvt_l);
    conv_h<<<(unsigned)(XEL / 1024), 256>>>(q, xq);
    conv_h<<<(unsigned)(XEL / 1024), 256>>>(k, xk);
    conv_h<<<(unsigned)(XEL / 1024), 256>>>(v, xv);
    conv_wo_p<<<(unsigned)(WEL / 256), 256>>>(Wo, wop_h, wop_l);
    bfin_kernel<<<Dn, 256>>>(Wo, bv, bo, bfin);

    // ---- Mt[h] = Wk^T Wq (3-term, hi/lo out) ----
    hmma_gemm<3, false, 1, 0, false><<<dim3(4, 4, Hn), 256, SM3>>>(
        wkt_h, wkt_l, wqt_h, wqt_l, nullptr, nullptr, mt_h, mt_l,
        Dn, Dn, Dn, Dn, WW, WW, 0, WW, 1.0f);

    // ---- Wvo[h] = Wo_h @ Wv_h (3-term): A = wo_p h-slice, B = Wv^T ----
    hmma_gemm<3, false, 1, 0, false><<<dim3(4, 4, Hn), 256, SM3>>>(
        wop_h, wop_l, wvt_h, wvt_l, nullptr, nullptr, wvo_h, wvo_l,
        Dn, Dn, Hn * Dn /*lda=4096*/, Dn, (size_t)Dn /*sA=512*/, WW, 0, WW, 1.0f);

    // ---- q~ = q @ Mt^T per head (2-term) ----
    dim3 gproj(Dn / 128, Mn / 128, Hn);
    hmma_gemm<2, false, 3, 0, false><<<gproj, 256, SM2>>>(
        xq, nullptr, mt_h, mt_l, nullptr, nullptr, qp, nullptr,
        Dn, Dn, Dn, Dn, 0, WW, 0, (size_t)Mn * Dn, 1.0f);

    // ---- column bias terms ----
    wvec_kernel<<<Hn, Dn>>>(Wk, bq, wvec);
    colv_kernel<<<Mn, 256>>>(k, wvec, colv, inv_scale);

    // ---- v~ = v @ Wvo^T (2-term) -> vt2[b][o][h*1024+j] (OUTM=5) ----
    hmma_gemm<2, false, 5, 0, false><<<gproj, 256, SM2>>>(
        xv, nullptr, wvo_h, wvo_l, nullptr, nullptr, vt2, nullptr,
        Dn, Dn, Dn, Dn, 0, WW, 0, 0, 1.0f);

    // ---- scores: Ps = q~ @ k^T / scale (1-term: both single fp16) ----
    dim3 gsc(Nn / 128, Nn / 128, Hn * Bn);
    hmma_gemm<1, false, 3, 0, true><<<gsc, 256, SM1>>>(
        qp, nullptr, xk, nullptr, nullptr, nullptr, Ps, nullptr,
        Nn, Dn, Dn, Dn, (size_t)Nn * Dn, (size_t)Nn * Dn, 0, (size_t)Nn * Nn,
        inv_scale);

    // ---- softmax (+colv), fp16 in -> fp16 out ----
    softmax1024_h<<<Hn * Bn * Nn, 256>>>(Ps, colv, ph);

    // ---- out = sum_h P_h @ v~_h + bfin  (1-term, K=8192, A h-blocked) ----
    dim3 gfin(Dn / 128, Nn / 128, Bn);
    hmma_gemm<1, true, 0, 2, false><<<gfin, 256, SM1>>>(
        ph, nullptr, vt2, nullptr, bfin, out, nullptr, nullptr,
        Dn, Hn * Nn, Nn /*lda*/, Hn * Nn /*ldb=8192*/,
        (size_t)Nn * Nn /*sA: b block*/, (size_t)Dn * Hn * Nn /*sB*/,
        0, (size_t)Nn * Dn /*sC*/, 1.0f);
}

// round 11
// speedup vs baseline: 5.4942x; 1.0178x over previous
#include <cuda_runtime.h>
#include <cuda_fp16.h>
#include <math.h>
#include <stdint.h>

// ---------------------------------------------------------------------------
// Problem constants
// ---------------------------------------------------------------------------
constexpr int Hn = 8, Bn = 16, Nn = 1024, Dn = 512;
constexpr int Mn = Bn * Nn;                               // 16384
constexpr size_t XEL  = (size_t)Mn * Dn;                  // 8,388,608
constexpr size_t WEL  = (size_t)Hn * Dn * Dn;             // 2,097,152
constexpr size_t PROJ = (size_t)Hn * Mn * Dn;             // 67,108,864
constexpr size_t PEL  = (size_t)Hn * Bn * Nn * Nn;        // 134,217,728
constexpr size_t HBLK2 = (size_t)Bn * Nn * Nn;            // 16M: h-block in P

// ---------------------------------------------------------------------------
// Scratch (__device__ globals — allocation-free)
// ---------------------------------------------------------------------------
__device__ __half g_xq[XEL];                       // q single fp16
__device__ __half g_xk[XEL];                       // k single fp16
__device__ __half g_xv[XEL];                       // v single fp16
__device__ __half g_wqt_hi[WEL], g_wqt_lo[WEL];    // Wq^T per head
__device__ __half g_wkt_hi[WEL], g_wkt_lo[WEL];    // Wk^T per head
__device__ __half g_wvt_hi[WEL], g_wvt_lo[WEL];    // Wv^T per head
__device__ __half g_mt_hi[WEL], g_mt_lo[WEL];      // Mt = Wk^T Wq
__device__ __half g_wvo_hi[WEL], g_wvo_lo[WEL];    // Wvo = Wo_h @ Wv_h
__device__ __half g_wop_hi[WEL], g_wop_lo[WEL];    // permuted Wo
__device__ __half g_qp[PROJ];                      // q~ single fp16
__device__ __half g_vt2[PROJ];                     // v~ [b][o][h*1024+j]
__device__ __half g_Ps[PEL];                       // e^scores (unnormalized)
__device__ __half g_ph[PEL];                       // normalized P, fp16
__device__ float  g_wvec[Hn * Dn];                 // Wk^T bq per head
__device__ float  g_colv[(size_t)Hn * Bn * Nn];    // scaled col terms
__device__ float  g_bfin[Dn];                      // bo + sum_h Wo_h bv_h

// ---------------------------------------------------------------------------
// Helpers
// ---------------------------------------------------------------------------
__device__ __forceinline__ uint32_t s2u(const void* p) {
    uint32_t a;
    asm("{ .reg .u64 t; cvta.to.shared.u64 t, %1; cvt.u32.u64 %0, t; }"
        : "=r"(a) : "l"(p));
    return a;
}

__device__ __forceinline__ void cp16(uint32_t saddr, const void* gaddr) {
    asm volatile("cp.async.cg.shared.global [%0], [%1], 16;"
                 :: "r"(saddr), "l"(gaddr) : "memory");
}
__device__ __forceinline__ void cp_commit() {
    asm volatile("cp.async.commit_group;" ::: "memory");
}
template <int N>
__device__ __forceinline__ void cp_wait() {
    asm volatile("cp.async.wait_group %0;" :: "n"(N) : "memory");
}

__device__ __forceinline__ void ldsm4(uint32_t* r, uint32_t addr) {
    asm volatile("ldmatrix.sync.aligned.m8n8.x4.shared.b16 {%0,%1,%2,%3}, [%4];"
        : "=r"(r[0]), "=r"(r[1]), "=r"(r[2]), "=r"(r[3]) : "r"(addr));
}

__device__ __forceinline__ void mma16816(float* d, const uint32_t* a,
                                         uint32_t b0, uint32_t b1) {
    asm volatile(
        "mma.sync.aligned.m16n8k16.row.col.f32.f16.f16.f32 "
        "{%0,%1,%2,%3}, {%4,%5,%6,%7}, {%8,%9}, {%0,%1,%2,%3};"
        : "+f"(d[0]), "+f"(d[1]), "+f"(d[2]), "+f"(d[3])
        : "r"(a[0]), "r"(a[1]), "r"(a[2]), "r"(a[3]), "r"(b0), "r"(b1));
}

__device__ __forceinline__ void split2h(float x, uint16_t& h, uint16_t& l) {
    __half hb = __float2half_rn(x);
    __half lb = __float2half_rn(x - __half2float(hb));
    h = *reinterpret_cast<uint16_t*>(&hb);
    l = *reinterpret_cast<uint16_t*>(&lb);
}
__device__ __forceinline__ uint16_t h1(float x) {
    __half hb = __float2half_rn(x);
    return *reinterpret_cast<uint16_t*>(&hb);
}

// XOR chunk swizzle for 64B rows (4 x 16B chunks): conflict-free ldmatrix.
__device__ __forceinline__ uint32_t swz(uint32_t r, uint32_t ch) {
    return r * 64u + ((ch ^ ((r >> 1) & 3u)) << 4);
}

// ---------------------------------------------------------------------------
// fp16-split batched GEMM via mma.sync (HMMA):
// TERMS=3:  C = alpha*(Ahi+Alo)@(Bhi+Blo)^T
// TERMS=2:  C = alpha* A @(Bhi+Blo)^T (A single)
// TERMS=1:  C = alpha* A @ B^T (both single)
// KT   : k-tiles (of 32) per pipeline chunk (1 or 2). KT=2 halves syncs.
// OUTM : 0=fp32, 1=fp16 hi/lo, 3=single fp16,
//        5=single fp16 to vt2 layout [b][col][z*1024 + (row&1023)]
//        6=exp() then single fp16 (unnormalized softmax numerator)
// AHB  : 0=plain A cols; 2=A col g decomposed (g>>10)*HBLK2 + (g&1023)
// BMODB: B z-index = z & 15 (B shared across heads, z = h*16+b)
// Tile 128x128, 8 warps, 3-stage cp.async pipeline, 1 sync/chunk.
// ---------------------------------------------------------------------------
constexpr int TILE_B = 128 * 64;                 // 8192 B per 32-k tile

template <int TERMS, int KT> struct Cfg {
    static constexpr int NOPS  = (TERMS == 3) ? 4 : (TERMS == 2) ? 3 : 2;
    static constexpr int STAGE = NOPS * KT * TILE_B;
    static constexpr int SMEM  = 3 * STAGE + 512;
};

template <int TERMS, int KT, bool BIAS, int OUTM, int AHB, bool BMODB>
__global__ void __launch_bounds__(256, 2) hmma_gemm(
    const __half* __restrict__ Ahi, const __half* __restrict__ Alo,
    const __half* __restrict__ Bhi, const __half* __restrict__ Blo,
    const float* __restrict__ biasg,
    float* __restrict__ Cf,
    __half* __restrict__ Chi, __half* __restrict__ Clo,
    int N, int K, int lda, int ldb,
    size_t sA, size_t sB, size_t sBias, size_t sC, float alpha)
{
    constexpr int STAGE = Cfg<TERMS, KT>::STAGE;
    constexpr int NOPS  = Cfg<TERMS, KT>::NOPS;
    constexpr int NA    = (TERMS == 3) ? 2 : 1;
    extern __shared__ __align__(16) char smem[];
    const uint32_t sb = s2u(smem);
    float* sbias = reinterpret_cast<float*>(smem + 3 * STAGE);

    const int tid  = threadIdx.x;
    const int wid  = tid >> 5, lane = tid & 31;
    const int wr   = wid >> 2, wc = wid & 3;      // warp grid 2x4
    const int col0 = blockIdx.x * 128, row0 = blockIdx.y * 128;
    const size_t z = blockIdx.z;
    const size_t zb = BMODB ? (z & 15) : z;
    Ahi += z * sA; if (TERMS == 3) Alo += z * sA;
    Bhi += zb * sB; if (TERMS >= 2) Blo += zb * sB;

    if (BIAS && tid < 128) sbias[tid] = biasg[z * sBias + col0 + tid];

    const int nCh = K / (32 * KT);

    auto prefetch = [&](int c) {
        const int k0 = c * 32 * KT;
        const uint32_t boff = sb + (uint32_t)(c % 3) * STAGE;
        #pragma unroll
        for (int t = 0; t < NOPS; t++) {
            const __half* s;
            if (TERMS == 3) s = (t == 0) ? Ahi : (t == 1) ? Alo
                              : (t == 2) ? Bhi : Blo;
            else if (TERMS == 2) s = (t == 0) ? Ahi : (t == 1) ? Bhi : Blo;
            else                 s = (t == 0) ? Ahi : Bhi;
            #pragma unroll
            for (int kt = 0; kt < KT; kt++) {
                const int kk = k0 + kt * 32;
                const uint32_t tb = boff + (t * KT + kt) * TILE_B;
                size_t aoff;
                if (AHB == 2) aoff = ((size_t)(kk >> 10)) * HBLK2
                                   + (size_t)(kk & 1023);
                else          aoff = (size_t)kk;
                #pragma unroll
                for (int i = 0; i < 2; i++) {
                    uint32_t idx = (uint32_t)(i * 256 + tid);   // 0..511
                    uint32_t r = idx >> 2, ch = idx & 3;
                    const __half* g;
                    if (t < NA) g = s + aoff + (size_t)(row0 + r) * lda + ch * 8;
                    else        g = s + (size_t)kk + (size_t)(col0 + r) * ldb + ch * 8;
                    cp16(tb + swz(r, ch), g);
                }
            }
        }
        cp_commit();
    };

    float acc[4][4][4] = {};

    prefetch(0);
    prefetch(1);

    for (int c = 0; c < nCh; ++c) {
        if (c + 1 < nCh) cp_wait<1>(); else cp_wait<0>();
        __syncthreads();
        if (c + 2 < nCh) prefetch(c + 2);

        const uint32_t boff = sb + (uint32_t)(c % 3) * STAGE;
        const uint32_t lrow = (uint32_t)(lane & 15), lhalf = (uint32_t)(lane >> 4);

        #pragma unroll
        for (int ks = 0; ks < 2 * KT; ks++) {
            const uint32_t sub = (uint32_t)(ks >> 1) * TILE_B;
            const uint32_t kch = (uint32_t)(ks & 1) * 2u + lhalf;
            const uint32_t aHiB = boff + sub;
            const uint32_t aLoB = boff + KT * TILE_B + sub;          // T3 only
            const uint32_t bHiB = boff + ((TERMS == 3) ? 2 : 1) * KT * TILE_B + sub;
            const uint32_t bLoB = boff + ((TERMS == 3) ? 3 : 2) * KT * TILE_B + sub;

            uint32_t bh[4][2], bl[4][2];
            #pragma unroll
            for (int np = 0; np < 2; np++) {
                uint32_t r = (uint32_t)(wc * 32 + np * 16) + lrow;
                uint32_t t[4];
                ldsm4(t, bHiB + swz(r, kch));
                bh[np*2+0][0] = t[0]; bh[np*2+0][1] = t[2];
                bh[np*2+1][0] = t[1]; bh[np*2+1][1] = t[3];
                if (TERMS >= 2) {
                    ldsm4(t, bLoB + swz(r, kch));
                    bl[np*2+0][0] = t[0]; bl[np*2+0][1] = t[2];
                    bl[np*2+1][0] = t[1]; bl[np*2+1][1] = t[3];
                }
            }
            #pragma unroll
            for (int mt = 0; mt < 4; mt++) {
                uint32_t r = (uint32_t)(wr * 64 + mt * 16) + lrow;
                uint32_t ah[4], al[4];
                ldsm4(ah, aHiB + swz(r, kch));
                if (TERMS == 3) ldsm4(al, aLoB + swz(r, kch));
                #pragma unroll
                for (int nt = 0; nt < 4; nt++) {
                    mma16816(acc[mt][nt], ah, bh[nt][0], bh[nt][1]);
                    if (TERMS >= 2)
                        mma16816(acc[mt][nt], ah, bl[nt][0], bl[nt][1]);
                    if (TERMS == 3)
                        mma16816(acc[mt][nt], al, bh[nt][0], bh[nt][1]);
                }
            }
        }
    }

    // ---- epilogue ----
    const int qr = lane >> 2, qc = lane & 3;
    #pragma unroll
    for (int mt = 0; mt < 4; mt++) {
        #pragma unroll
        for (int nt = 0; nt < 4; nt++) {
            const int lcol = wc * 32 + nt * 8 + qc * 2;
            const float b0 = BIAS ? sbias[lcol]     : 0.f;
            const float b1 = BIAS ? sbias[lcol + 1] : 0.f;
            const int r0 = row0 + wr * 64 + mt * 16 + qr;
            const float v00 = alpha * acc[mt][nt][0] + b0;
            const float v01 = alpha * acc[mt][nt][1] + b1;
            const float v10 = alpha * acc[mt][nt][2] + b0;
            const float v11 = alpha * acc[mt][nt][3] + b1;
            if (OUTM == 0) {
                float* cp = Cf + z * sC + (size_t)r0 * N + col0 + lcol;
                *reinterpret_cast<float2*>(cp)            = make_float2(v00, v01);
                *reinterpret_cast<float2*>(cp + 8ull * N) = make_float2(v10, v11);
            } else if (OUTM == 1) {
                uint16_t h0,l0,h1b,l1,h2,l2,h3,l3;
                split2h(v00, h0, l0); split2h(v01, h1b, l1);
                split2h(v10, h2, l2); split2h(v11, h3, l3);
                size_t o0 = z * sC + (size_t)r0 * N + col0 + lcol;
                size_t o1 = o0 + 8ull * N;
                *reinterpret_cast<uint32_t*>(
                    reinterpret_cast<uint16_t*>(Chi) + o0) = (uint32_t)h0 | ((uint32_t)h1b << 16);
                *reinterpret_cast<uint32_t*>(
                    reinterpret_cast<uint16_t*>(Clo) + o0) = (uint32_t)l0 | ((uint32_t)l1 << 16);
                *reinterpret_cast<uint32_t*>(
                    reinterpret_cast<uint16_t*>(Chi) + o1) = (uint32_t)h2 | ((uint32_t)h3 << 16);
                *reinterpret_cast<uint32_t*>(
                    reinterpret_cast<uint16_t*>(Clo) + o1) = (uint32_t)l2 | ((uint32_t)l3 << 16);
            } else if (OUTM == 3 || OUTM == 6) {
                float e00 = v00, e01 = v01, e10 = v10, e11 = v11;
                if (OUTM == 6) {
                    e00 = __expf(v00); e01 = __expf(v01);
                    e10 = __expf(v10); e11 = __expf(v11);
                }
                size_t o0 = z * sC + (size_t)r0 * N + col0 + lcol;
                size_t o1 = o0 + 8ull * N;
                *reinterpret_cast<uint32_t*>(
                    reinterpret_cast<uint16_t*>(Chi) + o0) =
                    (uint32_t)h1(e00) | ((uint32_t)h1(e01) << 16);
                *reinterpret_cast<uint32_t*>(
                    reinterpret_cast<uint16_t*>(Chi) + o1) =
                    (uint32_t)h1(e10) | ((uint32_t)h1(e11) << 16);
            } else {
                // OUTM == 5: vt2[b][col][z*1024 + j],  b = r0>>10, j = r0&1023
                uint16_t* oh = reinterpret_cast<uint16_t*>(Chi);
                const size_t bb = (size_t)(r0 >> 10);
                const int j0 = r0 & 1023;
                const size_t c0a = (bb * 512 + (size_t)(col0 + lcol)) * 8192
                                 + (size_t)z * 1024;
                const size_t c1a = c0a + 8192;       // col+1
                oh[c0a + j0]     = h1(v00);
                oh[c1a + j0]     = h1(v01);
                oh[c0a + j0 + 8] = h1(v10);
                oh[c1a + j0 + 8] = h1(v11);
            }
        }
    }
}

// ---------------------------------------------------------------------------
// fp32 -> fp16 conversion for q,k,v in one launch (grid.z picks tensor)
// ---------------------------------------------------------------------------
__global__ void conv_h3(const float* __restrict__ s0, __half* __restrict__ d0,
                        const float* __restrict__ s1, __half* __restrict__ d1,
                        const float* __restrict__ s2, __half* __restrict__ d2) {
    const float* s = (blockIdx.z == 0) ? s0 : (blockIdx.z == 1) ? s1 : s2;
    __half*      d = (blockIdx.z == 0) ? d0 : (blockIdx.z == 1) ? d1 : d2;
    size_t i = ((size_t)blockIdx.x * 256 + threadIdx.x) * 4;
    float4 v = *reinterpret_cast<const float4*>(s + i);
    *reinterpret_cast<uint2*>(d + i) = make_uint2(
        (uint32_t)h1(v.x) | ((uint32_t)h1(v.y) << 16),
        (uint32_t)h1(v.z) | ((uint32_t)h1(v.w) << 16));
}

// ---------------------------------------------------------------------------
// Per-head 512x512 transpose + split: out[h][d][e] = in[h][e][d]
// ---------------------------------------------------------------------------
__global__ void transpose_w_hl(const float* __restrict__ in,
                               __half* __restrict__ oh,
                               __half* __restrict__ ol) {
    __shared__ float t[32][33];
    const size_t z = blockIdx.z;
    in += z * (size_t)(Dn * Dn);
    oh += z * (size_t)(Dn * Dn);
    ol += z * (size_t)(Dn * Dn);
    const int x0 = blockIdx.x * 32;
    const int y0 = blockIdx.y * 32;
    #pragma unroll
    for (int i = 0; i < 4; i++)
        t[threadIdx.y + i * 8][threadIdx.x] =
            in[(size_t)(y0 + threadIdx.y + i * 8) * Dn + x0 + threadIdx.x];
    __syncthreads();
    #pragma unroll
    for (int i = 0; i < 4; i++) {
        float v = t[threadIdx.x][threadIdx.y + i * 8];
        uint16_t h, l;
        split2h(v, h, l);
        size_t o = (size_t)(x0 + threadIdx.y + i * 8) * Dn + y0 + threadIdx.x;
        reinterpret_cast<uint16_t*>(oh)[o] = h;
        reinterpret_cast<uint16_t*>(ol)[o] = l;
    }
}

// ---------------------------------------------------------------------------
// Wo permute + split: wo_p[o][h*512+d] = Wo[o][d*8+h]
// ---------------------------------------------------------------------------
__global__ void conv_wo_p(const float* __restrict__ Wo,
                          __half* __restrict__ oh,
                          __half* __restrict__ ol) {
    size_t idx = (size_t)blockIdx.x * 256 + threadIdx.x;
    int g = (int)(idx & 4095);
    size_t o = idx >> 12;
    int f = ((g & 511) << 3) | (g >> 9);
    float v = Wo[(o << 12) + f];
    uint16_t h, l;
    split2h(v, h, l);
    reinterpret_cast<uint16_t*>(oh)[idx] = h;
    reinterpret_cast<uint16_t*>(ol)[idx] = l;
}

// ---------------------------------------------------------------------------
// bfin[o] = bo[o] + sum_f Wo[o][f] * bv[f&7][f>>3]
// ---------------------------------------------------------------------------
__global__ void bfin_kernel(const float* __restrict__ Wo,
                            const float* __restrict__ bv,
                            const float* __restrict__ bo,
                            float* __restrict__ bfin) {
    __shared__ float red[8];
    const int o = blockIdx.x, tid = threadIdx.x;
    const float* wr = Wo + (size_t)o * 4096;
    float s = 0.f;
    for (int f = tid; f < 4096; f += 256)
        s += wr[f] * bv[(f & 7) * Dn + (f >> 3)];
    #pragma unroll
    for (int off = 16; off > 0; off >>= 1)
        s += __shfl_xor_sync(0xffffffffu, s, off);
    if ((tid & 31) == 0) red[tid >> 5] = s;
    __syncthreads();
    if (tid == 0) {
        float t = 0.f;
        #pragma unroll
        for (int i = 0; i < 8; i++) t += red[i];
        bfin[o] = bo[o] + t;
    }
}

// ---------------------------------------------------------------------------
// wvec[h][d] = sum_e bq[h][e] * Wk[h][e][d]
// ---------------------------------------------------------------------------
__global__ void wvec_kernel(const float* __restrict__ Wk,
                            const float* __restrict__ bq,
                            float* __restrict__ wvec) {
    const int h = blockIdx.x, d = threadIdx.x;
    const float* wk = Wk + (size_t)h * Dn * Dn;
    const float* b  = bq + (size_t)h * Dn;
    float s = 0.f;
    for (int e = 0; e < Dn; e++) s += b[e] * wk[(size_t)e * Dn + d];
    wvec[h * Dn + d] = s;
}

// ---------------------------------------------------------------------------
// colv[(h*16+b)][j] = inv_scale * k[b][j] . wvec[h]
// ---------------------------------------------------------------------------
__global__ void colv_kernel(const float* __restrict__ k,
                            const float* __restrict__ wvec,
                            float* __restrict__ colv, float inv_scale) {
    __shared__ float kr[Dn];
    const size_t bj = blockIdx.x;
    const int tid = threadIdx.x, w = tid >> 5, lane = tid & 31;
    const float* kp = k + bj * Dn;
    #pragma unroll
    for (int i = 0; i < 2; i++) kr[tid + i * 256] = kp[tid + i * 256];
    __syncthreads();
    const float* wv = wvec + w * Dn;
    float s = 0.f;
    #pragma unroll
    for (int t = 0; t < 16; t++) {
        int d = lane + t * 32;
        s += kr[d] * wv[d];
    }
    #pragma unroll
    for (int o = 16; o > 0; o >>= 1)
        s += __shfl_xor_sync(0xffffffffu, s, o);
    if (lane == 0) {
        size_t b = bj >> 10, j = bj & 1023;
        colv[((size_t)w * 16 + b) * 1024 + j] = s * inv_scale;
    }
}

// ---------------------------------------------------------------------------
// Normalize pre-exponentiated rows: Ph = E / rowsum(E)   (E in fp16)
// ---------------------------------------------------------------------------
__global__ void norm1024_h(const __half* __restrict__ E,
                           __half* __restrict__ Ph) {
    __shared__ float red[8];
    const size_t row = blockIdx.x;
    const int tid = threadIdx.x;

    uint2 pr = *reinterpret_cast<const uint2*>(E + row * 1024 + tid * 4);
    __half2 p01 = *reinterpret_cast<__half2*>(&pr.x);
    __half2 p23 = *reinterpret_cast<__half2*>(&pr.y);
    float e0 = __half2float(__low2half(p01));
    float e1 = __half2float(__high2half(p01));
    float e2 = __half2float(__low2half(p23));
    float e3 = __half2float(__high2half(p23));

    float s = e0 + e1 + e2 + e3;
    #pragma unroll
    for (int o = 16; o > 0; o >>= 1)
        s += __shfl_xor_sync(0xffffffffu, s, o);
    if ((tid & 31) == 0) red[tid >> 5] = s;
    __syncthreads();
    float bs = 0.f;
    #pragma unroll
    for (int i = 0; i < 8; i++) bs += red[i];
    float inv = 1.0f / bs;

    size_t o = row * 1024 + tid * 4;
    *reinterpret_cast<uint2*>(Ph + o) = make_uint2(
        (uint32_t)h1(e0 * inv) | ((uint32_t)h1(e1 * inv) << 16),
        (uint32_t)h1(e2 * inv) | ((uint32_t)h1(e3 * inv) << 16));
}

// ---------------------------------------------------------------------------
// kernel_launch — inputs: k, v, q, Wk, bk, Wv, bv, Wq, bq, Wo, bo
// ---------------------------------------------------------------------------
extern "C" void kernel_launch(void* const* d_in, const int* in_sizes, int n_in,
                              void* d_out, int out_size) {
    (void)in_sizes; (void)n_in; (void)out_size;
    const float* k  = (const float*)d_in[0];
    const float* v  = (const float*)d_in[1];
    const float* q  = (const float*)d_in[2];
    const float* Wk = (const float*)d_in[3];
    const float* Wv = (const float*)d_in[5];
    const float* bv = (const float*)d_in[6];
    const float* Wq = (const float*)d_in[7];
    const float* bq = (const float*)d_in[8];
    const float* Wo = (const float*)d_in[9];
    const float* bo = (const float*)d_in[10];
    float* out = (float*)d_out;

    constexpr int SM3  = Cfg<3, 1>::SMEM;
    constexpr int SM2  = Cfg<2, 1>::SMEM;
    constexpr int SM1B = Cfg<1, 2>::SMEM;     // 1-term, BK=64
    cudaFuncSetAttribute(hmma_gemm<3, 1, false, 1, 0, false>,
        cudaFuncAttributeMaxDynamicSharedMemorySize, SM3);
    cudaFuncSetAttribute(hmma_gemm<2, 1, false, 3, 0, false>,
        cudaFuncAttributeMaxDynamicSharedMemorySize, SM2);
    cudaFuncSetAttribute(hmma_gemm<2, 1, false, 5, 0, false>,
        cudaFuncAttributeMaxDynamicSharedMemorySize, SM2);
    cudaFuncSetAttribute(hmma_gemm<1, 2, true, 6, 0, true>,
        cudaFuncAttributeMaxDynamicSharedMemorySize, SM1B);
    cudaFuncSetAttribute(hmma_gemm<1, 2, true, 0, 2, false>,
        cudaFuncAttributeMaxDynamicSharedMemorySize, SM1B);

    __half *xq,*xk,*xv;
    __half *wqt_h,*wqt_l,*wkt_h,*wkt_l,*wvt_h,*wvt_l,*mt_h,*mt_l;
    __half *wvo_h,*wvo_l,*wop_h,*wop_l;
    __half *qp,*vt2,*Ps,*ph;
    float *wvec,*colv,*bfin;
    cudaGetSymbolAddress((void**)&xq,   g_xq);
    cudaGetSymbolAddress((void**)&xk,   g_xk);
    cudaGetSymbolAddress((void**)&xv,   g_xv);
    cudaGetSymbolAddress((void**)&wqt_h,g_wqt_hi);cudaGetSymbolAddress((void**)&wqt_l,g_wqt_lo);
    cudaGetSymbolAddress((void**)&wkt_h,g_wkt_hi);cudaGetSymbolAddress((void**)&wkt_l,g_wkt_lo);
    cudaGetSymbolAddress((void**)&wvt_h,g_wvt_hi);cudaGetSymbolAddress((void**)&wvt_l,g_wvt_lo);
    cudaGetSymbolAddress((void**)&mt_h, g_mt_hi); cudaGetSymbolAddress((void**)&mt_l, g_mt_lo);
    cudaGetSymbolAddress((void**)&wvo_h,g_wvo_hi);cudaGetSymbolAddress((void**)&wvo_l,g_wvo_lo);
    cudaGetSymbolAddress((void**)&wop_h,g_wop_hi);cudaGetSymbolAddress((void**)&wop_l,g_wop_lo);
    cudaGetSymbolAddress((void**)&qp,   g_qp);
    cudaGetSymbolAddress((void**)&vt2,  g_vt2);
    cudaGetSymbolAddress((void**)&Ps,   g_Ps);
    cudaGetSymbolAddress((void**)&ph,   g_ph);
    cudaGetSymbolAddress((void**)&wvec, g_wvec);
    cudaGetSymbolAddress((void**)&colv, g_colv);
    cudaGetSymbolAddress((void**)&bfin, g_bfin);

    const float inv_scale = 1.0f / sqrtf((float)Dn);
    const size_t WW = (size_t)Dn * Dn;

    // ---- conversions ----
    transpose_w_hl<<<dim3(16, 16, Hn), dim3(32, 8)>>>(Wq, wqt_h, wqt_l);
    transpose_w_hl<<<dim3(16, 16, Hn), dim3(32, 8)>>>(Wk, wkt_h, wkt_l);
    transpose_w_hl<<<dim3(16, 16, Hn), dim3(32, 8)>>>(Wv, wvt_h, wvt_l);
    conv_h3<<<dim3((unsigned)(XEL / 1024), 1, 3), 256>>>(q, xq, k, xk, v, xv);
    conv_wo_p<<<(unsigned)(WEL / 256), 256>>>(Wo, wop_h, wop_l);
    bfin_kernel<<<Dn, 256>>>(Wo, bv, bo, bfin);

    // ---- Mt[h] = Wk^T Wq (3-term, hi/lo out) ----
    hmma_gemm<3, 1, false, 1, 0, false><<<dim3(4, 4, Hn), 256, SM3>>>(
        wkt_h, wkt_l, wqt_h, wqt_l, nullptr, nullptr, mt_h, mt_l,
        Dn, Dn, Dn, Dn, WW, WW, 0, WW, 1.0f);

    // ---- Wvo[h] = Wo_h @ Wv_h (3-term): A = wo_p h-slice, B = Wv^T ----
    hmma_gemm<3, 1, false, 1, 0, false><<<dim3(4, 4, Hn), 256, SM3>>>(
        wop_h, wop_l, wvt_h, wvt_l, nullptr, nullptr, wvo_h, wvo_l,
        Dn, Dn, Hn * Dn /*lda=4096*/, Dn, (size_t)Dn /*sA=512*/, WW, 0, WW, 1.0f);

    // ---- q~ = q @ Mt^T per head (2-term) ----
    dim3 gproj(Dn / 128, Mn / 128, Hn);
    hmma_gemm<2, 1, false, 3, 0, false><<<gproj, 256, SM2>>>(
        xq, nullptr, mt_h, mt_l, nullptr, nullptr, qp, nullptr,
        Dn, Dn, Dn, Dn, 0, WW, 0, (size_t)Mn * Dn, 1.0f);

    // ---- column bias terms ----
    wvec_kernel<<<Hn, Dn>>>(Wk, bq, wvec);
    colv_kernel<<<Mn, 256>>>(k, wvec, colv, inv_scale);

    // ---- v~ = v @ Wvo^T (2-term) -> vt2[b][o][h*1024+j] (OUTM=5) ----
    hmma_gemm<2, 1, false, 5, 0, false><<<gproj, 256, SM2>>>(
        xv, nullptr, wvo_h, wvo_l, nullptr, nullptr, vt2, nullptr,
        Dn, Dn, Dn, Dn, 0, WW, 0, 0, 1.0f);

    // ---- scores: E = exp(q~ @ k^T / scale + colv)  (1-term, BK=64) ----
    dim3 gsc(Nn / 128, Nn / 128, Hn * Bn);
    hmma_gemm<1, 2, true, 6, 0, true><<<gsc, 256, SM1B>>>(
        qp, nullptr, xk, nullptr, colv, nullptr, Ps, nullptr,
        Nn, Dn, Dn, Dn, (size_t)Nn * Dn, (size_t)Nn * Dn,
        (size_t)Nn /*sBias*/, (size_t)Nn * Nn, inv_scale);

    // ---- normalize rows: Ph = E / rowsum(E) ----
    norm1024_h<<<Hn * Bn * Nn, 256>>>(Ps, ph);

    // ---- out = sum_h P_h @ v~_h + bfin  (1-term, K=8192, BK=64) ----
    dim3 gfin(Dn / 128, Nn / 128, Bn);
    hmma_gemm<1, 2, true, 0, 2, false><<<gfin, 256, SM1B>>>(
        ph, nullptr, vt2, nullptr, bfin, out, nullptr, nullptr,
        Dn, Hn * Nn, Nn /*lda*/, Hn * Nn /*ldb=8192*/,
        (size_t)Nn * Nn /*sA: b block*/, (size_t)Dn * Hn * Nn /*sB*/,
        0, (size_t)Nn * Dn /*sC*/, 1.0f);
}

// round 12
// speedup vs baseline: 6.4275x; 1.1699x over previous
#include <cuda_runtime.h>
#include <cuda_fp16.h>
#include <math.h>
#include <stdint.h>

// ---------------------------------------------------------------------------
// Problem constants
// ---------------------------------------------------------------------------
constexpr int Hn = 8, Bn = 16, Nn = 1024, Dn = 512;
constexpr int Mn = Bn * Nn;                               // 16384
constexpr size_t XEL  = (size_t)Mn * Dn;                  // 8,388,608
constexpr size_t WEL  = (size_t)Hn * Dn * Dn;             // 2,097,152
constexpr size_t PROJ = (size_t)Hn * Mn * Dn;             // 67,108,864
constexpr size_t PEL  = (size_t)Hn * Bn * Nn * Nn;        // 134,217,728
constexpr size_t HBLK2 = (size_t)Bn * Nn * Nn;            // 16M: h-block in P

// ---------------------------------------------------------------------------
// Scratch (__device__ globals — allocation-free)
// ---------------------------------------------------------------------------
__device__ __half g_xq[XEL];                       // q single fp16
__device__ __half g_xk[XEL];                       // k single fp16
__device__ __half g_xv[XEL];                       // v single fp16
__device__ __half g_wqt_hi[WEL], g_wqt_lo[WEL];    // Wq^T per head
__device__ __half g_wkt_hi[WEL], g_wkt_lo[WEL];    // Wk^T per head
__device__ __half g_wvt_hi[WEL], g_wvt_lo[WEL];    // Wv^T per head
__device__ __half g_mt[WEL];                       // Mt = Wk^T Wq (single)
__device__ __half g_wvo[WEL];                      // Wvo = Wo_h @ Wv_h (single)
__device__ __half g_wop_hi[WEL], g_wop_lo[WEL];    // permuted Wo
__device__ __half g_qp[PROJ];                      // q~ single fp16
__device__ __half g_vt2[PROJ];                     // v~ [b][o][h*1024+j]
__device__ __half g_Ps[PEL];                       // e^scores (unnormalized)
__device__ __half g_ph[PEL];                       // normalized P, fp16
__device__ float  g_wvec[Hn * Dn];                 // Wk^T bq per head
__device__ float  g_colv[(size_t)Hn * Bn * Nn];    // scaled col terms
__device__ float  g_bfin[Dn];                      // bo + sum_h Wo_h bv_h

// ---------------------------------------------------------------------------
// Helpers
// ---------------------------------------------------------------------------
__device__ __forceinline__ uint32_t s2u(const void* p) {
    uint32_t a;
    asm("{ .reg .u64 t; cvta.to.shared.u64 t, %1; cvt.u32.u64 %0, t; }"
        : "=r"(a) : "l"(p));
    return a;
}

__device__ __forceinline__ void cp16(uint32_t saddr, const void* gaddr) {
    asm volatile("cp.async.cg.shared.global [%0], [%1], 16;"
                 :: "r"(saddr), "l"(gaddr) : "memory");
}
__device__ __forceinline__ void cp_commit() {
    asm volatile("cp.async.commit_group;" ::: "memory");
}
template <int N>
__device__ __forceinline__ void cp_wait() {
    asm volatile("cp.async.wait_group %0;" :: "n"(N) : "memory");
}

__device__ __forceinline__ void ldsm4(uint32_t* r, uint32_t addr) {
    asm volatile("ldmatrix.sync.aligned.m8n8.x4.shared.b16 {%0,%1,%2,%3}, [%4];"
        : "=r"(r[0]), "=r"(r[1]), "=r"(r[2]), "=r"(r[3]) : "r"(addr));
}

__device__ __forceinline__ void mma16816(float* d, const uint32_t* a,
                                         uint32_t b0, uint32_t b1) {
    asm volatile(
        "mma.sync.aligned.m16n8k16.row.col.f32.f16.f16.f32 "
        "{%0,%1,%2,%3}, {%4,%5,%6,%7}, {%8,%9}, {%0,%1,%2,%3};"
        : "+f"(d[0]), "+f"(d[1]), "+f"(d[2]), "+f"(d[3])
        : "r"(a[0]), "r"(a[1]), "r"(a[2]), "r"(a[3]), "r"(b0), "r"(b1));
}

__device__ __forceinline__ void split2h(float x, uint16_t& h, uint16_t& l) {
    __half hb = __float2half_rn(x);
    __half lb = __float2half_rn(x - __half2float(hb));
    h = *reinterpret_cast<uint16_t*>(&hb);
    l = *reinterpret_cast<uint16_t*>(&lb);
}
__device__ __forceinline__ uint16_t h1(float x) {
    __half hb = __float2half_rn(x);
    return *reinterpret_cast<uint16_t*>(&hb);
}

// XOR chunk swizzle for 64B rows (4 x 16B chunks): conflict-free ldmatrix.
__device__ __forceinline__ uint32_t swz(uint32_t r, uint32_t ch) {
    return r * 64u + ((ch ^ ((r >> 1) & 3u)) << 4);
}

// ---------------------------------------------------------------------------
// fp16-split batched GEMM via mma.sync (HMMA):
// TERMS=3:  C = alpha*(Ahi+Alo)@(Bhi+Blo)^T
// TERMS=2:  C = alpha* A @(Bhi+Blo)^T (A single)
// TERMS=1:  C = alpha* A @ B^T (both single)
// KT   : k-tiles (of 32) per pipeline chunk (1 or 2). KT=2 halves syncs.
// OUTM : 0=fp32, 1=fp16 hi/lo, 3=single fp16,
//        5=single fp16 to vt2 layout [b][col][z*1024 + (row&1023)]
//        6=exp() then single fp16 (unnormalized softmax numerator)
// AHB  : 0=plain A cols; 2=A col g decomposed (g>>10)*HBLK2 + (g&1023)
// BMODB: B z-index = z & 15 (B shared across heads, z = h*16+b)
// Tile 128x128, 8 warps, 3-stage cp.async pipeline, 1 sync/chunk.
// ---------------------------------------------------------------------------
constexpr int TILE_B = 128 * 64;                 // 8192 B per 32-k tile

template <int TERMS, int KT> struct Cfg {
    static constexpr int NOPS  = (TERMS == 3) ? 4 : (TERMS == 2) ? 3 : 2;
    static constexpr int STAGE = NOPS * KT * TILE_B;
    static constexpr int SMEM  = 3 * STAGE + 512;
};

template <int TERMS, int KT, bool BIAS, int OUTM, int AHB, bool BMODB>
__global__ void __launch_bounds__(256, 2) hmma_gemm(
    const __half* __restrict__ Ahi, const __half* __restrict__ Alo,
    const __half* __restrict__ Bhi, const __half* __restrict__ Blo,
    const float* __restrict__ biasg,
    float* __restrict__ Cf,
    __half* __restrict__ Chi, __half* __restrict__ Clo,
    int N, int K, int lda, int ldb,
    size_t sA, size_t sB, size_t sBias, size_t sC, float alpha)
{
    constexpr int STAGE = Cfg<TERMS, KT>::STAGE;
    constexpr int NOPS  = Cfg<TERMS, KT>::NOPS;
    constexpr int NA    = (TERMS == 3) ? 2 : 1;
    extern __shared__ __align__(16) char smem[];
    const uint32_t sb = s2u(smem);
    float* sbias = reinterpret_cast<float*>(smem + 3 * STAGE);

    const int tid  = threadIdx.x;
    const int wid  = tid >> 5, lane = tid & 31;
    const int wr   = wid >> 2, wc = wid & 3;      // warp grid 2x4
    const int col0 = blockIdx.x * 128, row0 = blockIdx.y * 128;
    const size_t z = blockIdx.z;
    const size_t zb = BMODB ? (z & 15) : z;
    Ahi += z * sA; if (TERMS == 3) Alo += z * sA;
    Bhi += zb * sB; if (TERMS >= 2) Blo += zb * sB;

    if (BIAS && tid < 128) sbias[tid] = biasg[z * sBias + col0 + tid];

    const int nCh = K / (32 * KT);

    auto prefetch = [&](int c) {
        const int k0 = c * 32 * KT;
        const uint32_t boff = sb + (uint32_t)(c % 3) * STAGE;
        #pragma unroll
        for (int t = 0; t < NOPS; t++) {
            const __half* s;
            if (TERMS == 3) s = (t == 0) ? Ahi : (t == 1) ? Alo
                              : (t == 2) ? Bhi : Blo;
            else if (TERMS == 2) s = (t == 0) ? Ahi : (t == 1) ? Bhi : Blo;
            else                 s = (t == 0) ? Ahi : Bhi;
            #pragma unroll
            for (int kt = 0; kt < KT; kt++) {
                const int kk = k0 + kt * 32;
                const uint32_t tb = boff + (t * KT + kt) * TILE_B;
                size_t aoff;
                if (AHB == 2) aoff = ((size_t)(kk >> 10)) * HBLK2
                                   + (size_t)(kk & 1023);
                else          aoff = (size_t)kk;
                #pragma unroll
                for (int i = 0; i < 2; i++) {
                    uint32_t idx = (uint32_t)(i * 256 + tid);   // 0..511
                    uint32_t r = idx >> 2, ch = idx & 3;
                    const __half* g;
                    if (t < NA) g = s + aoff + (size_t)(row0 + r) * lda + ch * 8;
                    else        g = s + (size_t)kk + (size_t)(col0 + r) * ldb + ch * 8;
                    cp16(tb + swz(r, ch), g);
                }
            }
        }
        cp_commit();
    };

    float acc[4][4][4] = {};

    prefetch(0);
    prefetch(1);

    for (int c = 0; c < nCh; ++c) {
        if (c + 1 < nCh) cp_wait<1>(); else cp_wait<0>();
        __syncthreads();
        if (c + 2 < nCh) prefetch(c + 2);

        const uint32_t boff = sb + (uint32_t)(c % 3) * STAGE;
        const uint32_t lrow = (uint32_t)(lane & 15), lhalf = (uint32_t)(lane >> 4);

        #pragma unroll
        for (int ks = 0; ks < 2 * KT; ks++) {
            const uint32_t sub = (uint32_t)(ks >> 1) * TILE_B;
            const uint32_t kch = (uint32_t)(ks & 1) * 2u + lhalf;
            const uint32_t aHiB = boff + sub;
            const uint32_t aLoB = boff + KT * TILE_B + sub;          // T3 only
            const uint32_t bHiB = boff + ((TERMS == 3) ? 2 : 1) * KT * TILE_B + sub;
            const uint32_t bLoB = boff + ((TERMS == 3) ? 3 : 2) * KT * TILE_B + sub;

            uint32_t bh[4][2], bl[4][2];
            #pragma unroll
            for (int np = 0; np < 2; np++) {
                uint32_t r = (uint32_t)(wc * 32 + np * 16) + lrow;
                uint32_t t[4];
                ldsm4(t, bHiB + swz(r, kch));
                bh[np*2+0][0] = t[0]; bh[np*2+0][1] = t[2];
                bh[np*2+1][0] = t[1]; bh[np*2+1][1] = t[3];
                if (TERMS >= 2) {
                    ldsm4(t, bLoB + swz(r, kch));
                    bl[np*2+0][0] = t[0]; bl[np*2+0][1] = t[2];
                    bl[np*2+1][0] = t[1]; bl[np*2+1][1] = t[3];
                }
            }
            #pragma unroll
            for (int mt = 0; mt < 4; mt++) {
                uint32_t r = (uint32_t)(wr * 64 + mt * 16) + lrow;
                uint32_t ah[4], al[4];
                ldsm4(ah, aHiB + swz(r, kch));
                if (TERMS == 3) ldsm4(al, aLoB + swz(r, kch));
                #pragma unroll
                for (int nt = 0; nt < 4; nt++) {
                    mma16816(acc[mt][nt], ah, bh[nt][0], bh[nt][1]);
                    if (TERMS >= 2)
                        mma16816(acc[mt][nt], ah, bl[nt][0], bl[nt][1]);
                    if (TERMS == 3)
                        mma16816(acc[mt][nt], al, bh[nt][0], bh[nt][1]);
                }
            }
        }
    }

    // ---- epilogue ----
    const int qr = lane >> 2, qc = lane & 3;
    #pragma unroll
    for (int mt = 0; mt < 4; mt++) {
        #pragma unroll
        for (int nt = 0; nt < 4; nt++) {
            const int lcol = wc * 32 + nt * 8 + qc * 2;
            const float b0 = BIAS ? sbias[lcol]     : 0.f;
            const float b1 = BIAS ? sbias[lcol + 1] : 0.f;
            const int r0 = row0 + wr * 64 + mt * 16 + qr;
            const float v00 = alpha * acc[mt][nt][0] + b0;
            const float v01 = alpha * acc[mt][nt][1] + b1;
            const float v10 = alpha * acc[mt][nt][2] + b0;
            const float v11 = alpha * acc[mt][nt][3] + b1;
            if (OUTM == 0) {
                float* cp = Cf + z * sC + (size_t)r0 * N + col0 + lcol;
                *reinterpret_cast<float2*>(cp)            = make_float2(v00, v01);
                *reinterpret_cast<float2*>(cp + 8ull * N) = make_float2(v10, v11);
            } else if (OUTM == 1) {
                uint16_t h0,l0,h1b,l1,h2,l2,h3,l3;
                split2h(v00, h0, l0); split2h(v01, h1b, l1);
                split2h(v10, h2, l2); split2h(v11, h3, l3);
                size_t o0 = z * sC + (size_t)r0 * N + col0 + lcol;
                size_t o1 = o0 + 8ull * N;
                *reinterpret_cast<uint32_t*>(
                    reinterpret_cast<uint16_t*>(Chi) + o0) = (uint32_t)h0 | ((uint32_t)h1b << 16);
                *reinterpret_cast<uint32_t*>(
                    reinterpret_cast<uint16_t*>(Clo) + o0) = (uint32_t)l0 | ((uint32_t)l1 << 16);
                *reinterpret_cast<uint32_t*>(
                    reinterpret_cast<uint16_t*>(Chi) + o1) = (uint32_t)h2 | ((uint32_t)h3 << 16);
                *reinterpret_cast<uint32_t*>(
                    reinterpret_cast<uint16_t*>(Clo) + o1) = (uint32_t)l2 | ((uint32_t)l3 << 16);
            } else if (OUTM == 3 || OUTM == 6) {
                float e00 = v00, e01 = v01, e10 = v10, e11 = v11;
                if (OUTM == 6) {
                    e00 = __expf(v00); e01 = __expf(v01);
                    e10 = __expf(v10); e11 = __expf(v11);
                }
                size_t o0 = z * sC + (size_t)r0 * N + col0 + lcol;
                size_t o1 = o0 + 8ull * N;
                *reinterpret_cast<uint32_t*>(
                    reinterpret_cast<uint16_t*>(Chi) + o0) =
                    (uint32_t)h1(e00) | ((uint32_t)h1(e01) << 16);
                *reinterpret_cast<uint32_t*>(
                    reinterpret_cast<uint16_t*>(Chi) + o1) =
                    (uint32_t)h1(e10) | ((uint32_t)h1(e11) << 16);
            } else {
                // OUTM == 5: vt2[b][col][z*1024 + j],  b = r0>>10, j = r0&1023
                uint16_t* oh = reinterpret_cast<uint16_t*>(Chi);
                const size_t bb = (size_t)(r0 >> 10);
                const int j0 = r0 & 1023;
                const size_t c0a = (bb * 512 + (size_t)(col0 + lcol)) * 8192
                                 + (size_t)z * 1024;
                const size_t c1a = c0a + 8192;       // col+1
                oh[c0a + j0]     = h1(v00);
                oh[c1a + j0]     = h1(v01);
                oh[c0a + j0 + 8] = h1(v10);
                oh[c1a + j0 + 8] = h1(v11);
            }
        }
    }
}

// ---------------------------------------------------------------------------
// fp32 -> fp16 conversion for q,k,v in one launch (grid.z picks tensor)
// ---------------------------------------------------------------------------
__global__ void conv_h3(const float* __restrict__ s0, __half* __restrict__ d0,
                        const float* __restrict__ s1, __half* __restrict__ d1,
                        const float* __restrict__ s2, __half* __restrict__ d2) {
    const float* s = (blockIdx.z == 0) ? s0 : (blockIdx.z == 1) ? s1 : s2;
    __half*      d = (blockIdx.z == 0) ? d0 : (blockIdx.z == 1) ? d1 : d2;
    size_t i = ((size_t)blockIdx.x * 256 + threadIdx.x) * 4;
    float4 v = *reinterpret_cast<const float4*>(s + i);
    *reinterpret_cast<uint2*>(d + i) = make_uint2(
        (uint32_t)h1(v.x) | ((uint32_t)h1(v.y) << 16),
        (uint32_t)h1(v.z) | ((uint32_t)h1(v.w) << 16));
}

// ---------------------------------------------------------------------------
// Per-head 512x512 transpose + split: out[h][d][e] = in[h][e][d]
// ---------------------------------------------------------------------------
__global__ void transpose_w_hl(const float* __restrict__ in,
                               __half* __restrict__ oh,
                               __half* __restrict__ ol) {
    __shared__ float t[32][33];
    const size_t z = blockIdx.z;
    in += z * (size_t)(Dn * Dn);
    oh += z * (size_t)(Dn * Dn);
    ol += z * (size_t)(Dn * Dn);
    const int x0 = blockIdx.x * 32;
    const int y0 = blockIdx.y * 32;
    #pragma unroll
    for (int i = 0; i < 4; i++)
        t[threadIdx.y + i * 8][threadIdx.x] =
            in[(size_t)(y0 + threadIdx.y + i * 8) * Dn + x0 + threadIdx.x];
    __syncthreads();
    #pragma unroll
    for (int i = 0; i < 4; i++) {
        float v = t[threadIdx.x][threadIdx.y + i * 8];
        uint16_t h, l;
        split2h(v, h, l);
        size_t o = (size_t)(x0 + threadIdx.y + i * 8) * Dn + y0 + threadIdx.x;
        reinterpret_cast<uint16_t*>(oh)[o] = h;
        reinterpret_cast<uint16_t*>(ol)[o] = l;
    }
}

// ---------------------------------------------------------------------------
// Wo permute + split: wo_p[o][h*512+d] = Wo[o][d*8+h]
// ---------------------------------------------------------------------------
__global__ void conv_wo_p(const float* __restrict__ Wo,
                          __half* __restrict__ oh,
                          __half* __restrict__ ol) {
    size_t idx = (size_t)blockIdx.x * 256 + threadIdx.x;
    int g = (int)(idx & 4095);
    size_t o = idx >> 12;
    int f = ((g & 511) << 3) | (g >> 9);
    float v = Wo[(o << 12) + f];
    uint16_t h, l;
    split2h(v, h, l);
    reinterpret_cast<uint16_t*>(oh)[idx] = h;
    reinterpret_cast<uint16_t*>(ol)[idx] = l;
}

// ---------------------------------------------------------------------------
// bfin[o] = bo[o] + sum_f Wo[o][f] * bv[f&7][f>>3]
// ---------------------------------------------------------------------------
__global__ void bfin_kernel(const float* __restrict__ Wo,
                            const float* __restrict__ bv,
                            const float* __restrict__ bo,
                            float* __restrict__ bfin) {
    __shared__ float red[8];
    const int o = blockIdx.x, tid = threadIdx.x;
    const float* wr = Wo + (size_t)o * 4096;
    float s = 0.f;
    for (int f = tid; f < 4096; f += 256)
        s += wr[f] * bv[(f & 7) * Dn + (f >> 3)];
    #pragma unroll
    for (int off = 16; off > 0; off >>= 1)
        s += __shfl_xor_sync(0xffffffffu, s, off);
    if ((tid & 31) == 0) red[tid >> 5] = s;
    __syncthreads();
    if (tid == 0) {
        float t = 0.f;
        #pragma unroll
        for (int i = 0; i < 8; i++) t += red[i];
        bfin[o] = bo[o] + t;
    }
}

// ---------------------------------------------------------------------------
// wvec[h][d] = sum_e bq[h][e] * Wk[h][e][d]
// ---------------------------------------------------------------------------
__global__ void wvec_kernel(const float* __restrict__ Wk,
                            const float* __restrict__ bq,
                            float* __restrict__ wvec) {
    const int h = blockIdx.x, d = threadIdx.x;
    const float* wk = Wk + (size_t)h * Dn * Dn;
    const float* b  = bq + (size_t)h * Dn;
    float s = 0.f;
    for (int e = 0; e < Dn; e++) s += b[e] * wk[(size_t)e * Dn + d];
    wvec[h * Dn + d] = s;
}

// ---------------------------------------------------------------------------
// colv[(h*16+b)][j] = inv_scale * k[b][j] . wvec[h]
// ---------------------------------------------------------------------------
__global__ void colv_kernel(const float* __restrict__ k,
                            const float* __restrict__ wvec,
                            float* __restrict__ colv, float inv_scale) {
    __shared__ float kr[Dn];
    const size_t bj = blockIdx.x;
    const int tid = threadIdx.x, w = tid >> 5, lane = tid & 31;
    const float* kp = k + bj * Dn;
    #pragma unroll
    for (int i = 0; i < 2; i++) kr[tid + i * 256] = kp[tid + i * 256];
    __syncthreads();
    const float* wv = wvec + w * Dn;
    float s = 0.f;
    #pragma unroll
    for (int t = 0; t < 16; t++) {
        int d = lane + t * 32;
        s += kr[d] * wv[d];
    }
    #pragma unroll
    for (int o = 16; o > 0; o >>= 1)
        s += __shfl_xor_sync(0xffffffffu, s, o);
    if (lane == 0) {
        size_t b = bj >> 10, j = bj & 1023;
        colv[((size_t)w * 16 + b) * 1024 + j] = s * inv_scale;
    }
}

// ---------------------------------------------------------------------------
// Normalize pre-exponentiated rows: Ph = E / rowsum(E)   (E in fp16)
// ---------------------------------------------------------------------------
__global__ void norm1024_h(const __half* __restrict__ E,
                           __half* __restrict__ Ph) {
    __shared__ float red[8];
    const size_t row = blockIdx.x;
    const int tid = threadIdx.x;

    uint2 pr = *reinterpret_cast<const uint2*>(E + row * 1024 + tid * 4);
    __half2 p01 = *reinterpret_cast<__half2*>(&pr.x);
    __half2 p23 = *reinterpret_cast<__half2*>(&pr.y);
    float e0 = __half2float(__low2half(p01));
    float e1 = __half2float(__high2half(p01));
    float e2 = __half2float(__low2half(p23));
    float e3 = __half2float(__high2half(p23));

    float s = e0 + e1 + e2 + e3;
    #pragma unroll
    for (int o = 16; o > 0; o >>= 1)
        s += __shfl_xor_sync(0xffffffffu, s, o);
    if ((tid & 31) == 0) red[tid >> 5] = s;
    __syncthreads();
    float bs = 0.f;
    #pragma unroll
    for (int i = 0; i < 8; i++) bs += red[i];
    float inv = 1.0f / bs;

    size_t o = row * 1024 + tid * 4;
    *reinterpret_cast<uint2*>(Ph + o) = make_uint2(
        (uint32_t)h1(e0 * inv) | ((uint32_t)h1(e1 * inv) << 16),
        (uint32_t)h1(e2 * inv) | ((uint32_t)h1(e3 * inv) << 16));
}

// ---------------------------------------------------------------------------
// kernel_launch — inputs: k, v, q, Wk, bk, Wv, bv, Wq, bq, Wo, bo
// ---------------------------------------------------------------------------
extern "C" void kernel_launch(void* const* d_in, const int* in_sizes, int n_in,
                              void* d_out, int out_size) {
    (void)in_sizes; (void)n_in; (void)out_size;
    const float* k  = (const float*)d_in[0];
    const float* v  = (const float*)d_in[1];
    const float* q  = (const float*)d_in[2];
    const float* Wk = (const float*)d_in[3];
    const float* Wv = (const float*)d_in[5];
    const float* bv = (const float*)d_in[6];
    const float* Wq = (const float*)d_in[7];
    const float* bq = (const float*)d_in[8];
    const float* Wo = (const float*)d_in[9];
    const float* bo = (const float*)d_in[10];
    float* out = (float*)d_out;

    constexpr int SM3  = Cfg<3, 1>::SMEM;
    constexpr int SM1B = Cfg<1, 2>::SMEM;     // 1-term, BK=64
    cudaFuncSetAttribute(hmma_gemm<3, 1, false, 3, 0, false>,
        cudaFuncAttributeMaxDynamicSharedMemorySize, SM3);
    cudaFuncSetAttribute(hmma_gemm<1, 2, false, 3, 0, false>,
        cudaFuncAttributeMaxDynamicSharedMemorySize, SM1B);
    cudaFuncSetAttribute(hmma_gemm<1, 2, false, 5, 0, false>,
        cudaFuncAttributeMaxDynamicSharedMemorySize, SM1B);
    cudaFuncSetAttribute(hmma_gemm<1, 2, true, 6, 0, true>,
        cudaFuncAttributeMaxDynamicSharedMemorySize, SM1B);
    cudaFuncSetAttribute(hmma_gemm<1, 2, true, 0, 2, false>,
        cudaFuncAttributeMaxDynamicSharedMemorySize, SM1B);

    __half *xq,*xk,*xv;
    __half *wqt_h,*wqt_l,*wkt_h,*wkt_l,*wvt_h,*wvt_l,*mt,*wvo;
    __half *wop_h,*wop_l;
    __half *qp,*vt2,*Ps,*ph;
    float *wvec,*colv,*bfin;
    cudaGetSymbolAddress((void**)&xq,   g_xq);
    cudaGetSymbolAddress((void**)&xk,   g_xk);
    cudaGetSymbolAddress((void**)&xv,   g_xv);
    cudaGetSymbolAddress((void**)&wqt_h,g_wqt_hi);cudaGetSymbolAddress((void**)&wqt_l,g_wqt_lo);
    cudaGetSymbolAddress((void**)&wkt_h,g_wkt_hi);cudaGetSymbolAddress((void**)&wkt_l,g_wkt_lo);
    cudaGetSymbolAddress((void**)&wvt_h,g_wvt_hi);cudaGetSymbolAddress((void**)&wvt_l,g_wvt_lo);
    cudaGetSymbolAddress((void**)&mt,   g_mt);
    cudaGetSymbolAddress((void**)&wvo,  g_wvo);
    cudaGetSymbolAddress((void**)&wop_h,g_wop_hi);cudaGetSymbolAddress((void**)&wop_l,g_wop_lo);
    cudaGetSymbolAddress((void**)&qp,   g_qp);
    cudaGetSymbolAddress((void**)&vt2,  g_vt2);
    cudaGetSymbolAddress((void**)&Ps,   g_Ps);
    cudaGetSymbolAddress((void**)&ph,   g_ph);
    cudaGetSymbolAddress((void**)&wvec, g_wvec);
    cudaGetSymbolAddress((void**)&colv, g_colv);
    cudaGetSymbolAddress((void**)&bfin, g_bfin);

    const float inv_scale = 1.0f / sqrtf((float)Dn);
    const size_t WW = (size_t)Dn * Dn;

    // ---- conversions ----
    transpose_w_hl<<<dim3(16, 16, Hn), dim3(32, 8)>>>(Wq, wqt_h, wqt_l);
    transpose_w_hl<<<dim3(16, 16, Hn), dim3(32, 8)>>>(Wk, wkt_h, wkt_l);
    transpose_w_hl<<<dim3(16, 16, Hn), dim3(32, 8)>>>(Wv, wvt_h, wvt_l);
    conv_h3<<<dim3((unsigned)(XEL / 1024), 1, 3), 256>>>(q, xq, k, xk, v, xv);
    conv_wo_p<<<(unsigned)(WEL / 256), 256>>>(Wo, wop_h, wop_l);
    bfin_kernel<<<Dn, 256>>>(Wo, bv, bo, bfin);

    // ---- Mt[h] = Wk^T Wq (3-term in, SINGLE fp16 out) ----
    hmma_gemm<3, 1, false, 3, 0, false><<<dim3(4, 4, Hn), 256, SM3>>>(
        wkt_h, wkt_l, wqt_h, wqt_l, nullptr, nullptr, mt, nullptr,
        Dn, Dn, Dn, Dn, WW, WW, 0, WW, 1.0f);

    // ---- Wvo[h] = Wo_h @ Wv_h (3-term in, SINGLE fp16 out) ----
    hmma_gemm<3, 1, false, 3, 0, false><<<dim3(4, 4, Hn), 256, SM3>>>(
        wop_h, wop_l, wvt_h, wvt_l, nullptr, nullptr, wvo, nullptr,
        Dn, Dn, Hn * Dn /*lda=4096*/, Dn, (size_t)Dn /*sA=512*/, WW, 0, WW, 1.0f);

    // ---- q~ = q @ Mt^T per head (1-term, BK=64) ----
    dim3 gproj(Dn / 128, Mn / 128, Hn);
    hmma_gemm<1, 2, false, 3, 0, false><<<gproj, 256, SM1B>>>(
        xq, nullptr, mt, nullptr, nullptr, nullptr, qp, nullptr,
        Dn, Dn, Dn, Dn, 0, WW, 0, (size_t)Mn * Dn, 1.0f);

    // ---- column bias terms ----
    wvec_kernel<<<Hn, Dn>>>(Wk, bq, wvec);
    colv_kernel<<<Mn, 256>>>(k, wvec, colv, inv_scale);

    // ---- v~ = v @ Wvo^T (1-term, BK=64) -> vt2[b][o][h*1024+j] ----
    hmma_gemm<1, 2, false, 5, 0, false><<<gproj, 256, SM1B>>>(
        xv, nullptr, wvo, nullptr, nullptr, nullptr, vt2, nullptr,
        Dn, Dn, Dn, Dn, 0, WW, 0, 0, 1.0f);

    // ---- scores: E = exp(q~ @ k^T / scale + colv)  (1-term, BK=64) ----
    dim3 gsc(Nn / 128, Nn / 128, Hn * Bn);
    hmma_gemm<1, 2, true, 6, 0, true><<<gsc, 256, SM1B>>>(
        qp, nullptr, xk, nullptr, colv, nullptr, Ps, nullptr,
        Nn, Dn, Dn, Dn, (size_t)Nn * Dn, (size_t)Nn * Dn,
        (size_t)Nn /*sBias*/, (size_t)Nn * Nn, inv_scale);

    // ---- normalize rows: Ph = E / rowsum(E) ----
    norm1024_h<<<Hn * Bn * Nn, 256>>>(Ps, ph);

    // ---- out = sum_h P_h @ v~_h + bfin  (1-term, K=8192, BK=64) ----
    dim3 gfin(Dn / 128, Nn / 128, Bn);
    hmma_gemm<1, 2, true, 0, 2, false><<<gfin, 256, SM1B>>>(
        ph, nullptr, vt2, nullptr, bfin, out, nullptr, nullptr,
        Dn, Hn * Nn, Nn /*lda*/, Hn * Nn /*ldb=8192*/,
        (size_t)Nn * Nn /*sA: b block*/, (size_t)Dn * Hn * Nn /*sB*/,
        0, (size_t)Nn * Dn /*sC*/, 1.0f);
}

// round 13
// speedup vs baseline: 6.7249x; 1.0463x over previous
#include <cuda_runtime.h>
#include <cuda_fp16.h>
#include <math.h>
#include <stdint.h>

// ---------------------------------------------------------------------------
// Problem constants
// ---------------------------------------------------------------------------
constexpr int Hn = 8, Bn = 16, Nn = 1024, Dn = 512;
constexpr int Mn = Bn * Nn;                               // 16384
constexpr size_t XEL  = (size_t)Mn * Dn;                  // 8,388,608
constexpr size_t WEL  = (size_t)Hn * Dn * Dn;             // 2,097,152
constexpr size_t PROJ = (size_t)Hn * Mn * Dn;             // 67,108,864
constexpr size_t PEL  = (size_t)Hn * Bn * Nn * Nn;        // 134,217,728
constexpr size_t HBLK2 = (size_t)Bn * Nn * Nn;            // 16M: h-block in P
constexpr size_t NROWS = (size_t)Hn * Bn * Nn;            // 131072 score rows

// ---------------------------------------------------------------------------
// Scratch (__device__ globals — allocation-free)
// ---------------------------------------------------------------------------
__device__ __half g_xq[XEL];                       // q single fp16
__device__ __half g_xk[XEL];                       // k single fp16
__device__ __half g_xv[XEL];                       // v single fp16
__device__ __half g_wqt_hi[WEL], g_wqt_lo[WEL];    // Wq^T per head
__device__ __half g_wkt_hi[WEL], g_wkt_lo[WEL];    // Wk^T per head
__device__ __half g_wvt_hi[WEL], g_wvt_lo[WEL];    // Wv^T per head
__device__ __half g_mt[WEL];                       // Mt = Wk^T Wq (single)
__device__ __half g_wvo[WEL];                      // Wvo = Wo_h @ Wv_h (single)
__device__ __half g_wop_hi[WEL], g_wop_lo[WEL];    // permuted Wo
__device__ __half g_qp[PROJ];                      // q~ single fp16
__device__ __half g_vt2[PROJ];                     // v~ [b][o][h*1024+j]
__device__ __half g_Ps[PEL];                       // e^scores (unnormalized)
__device__ float  g_psum[NROWS * 8];               // partial rowsums per col-tile
__device__ __half g_invr[NROWS];                   // 1/rowsum, fp16
__device__ float  g_wvec[Hn * Dn];                 // Wk^T bq per head
__device__ float  g_colv[NROWS];                   // scaled col terms
__device__ float  g_bfin[Dn];                      // bo + sum_h Wo_h bv_h

// ---------------------------------------------------------------------------
// Helpers
// ---------------------------------------------------------------------------
__device__ __forceinline__ uint32_t s2u(const void* p) {
    uint32_t a;
    asm("{ .reg .u64 t; cvta.to.shared.u64 t, %1; cvt.u32.u64 %0, t; }"
        : "=r"(a) : "l"(p));
    return a;
}

__device__ __forceinline__ void cp16(uint32_t saddr, const void* gaddr) {
    asm volatile("cp.async.cg.shared.global [%0], [%1], 16;"
                 :: "r"(saddr), "l"(gaddr) : "memory");
}
__device__ __forceinline__ void cp_commit() {
    asm volatile("cp.async.commit_group;" ::: "memory");
}
template <int N>
__device__ __forceinline__ void cp_wait() {
    asm volatile("cp.async.wait_group %0;" :: "n"(N) : "memory");
}

__device__ __forceinline__ void ldsm4(uint32_t* r, uint32_t addr) {
    asm volatile("ldmatrix.sync.aligned.m8n8.x4.shared.b16 {%0,%1,%2,%3}, [%4];"
        : "=r"(r[0]), "=r"(r[1]), "=r"(r[2]), "=r"(r[3]) : "r"(addr));
}

__device__ __forceinline__ void mma16816(float* d, const uint32_t* a,
                                         uint32_t b0, uint32_t b1) {
    asm volatile(
        "mma.sync.aligned.m16n8k16.row.col.f32.f16.f16.f32 "
        "{%0,%1,%2,%3}, {%4,%5,%6,%7}, {%8,%9}, {%0,%1,%2,%3};"
        : "+f"(d[0]), "+f"(d[1]), "+f"(d[2]), "+f"(d[3])
        : "r"(a[0]), "r"(a[1]), "r"(a[2]), "r"(a[3]), "r"(b0), "r"(b1));
}

__device__ __forceinline__ void split2h(float x, uint16_t& h, uint16_t& l) {
    __half hb = __float2half_rn(x);
    __half lb = __float2half_rn(x - __half2float(hb));
    h = *reinterpret_cast<uint16_t*>(&hb);
    l = *reinterpret_cast<uint16_t*>(&lb);
}
__device__ __forceinline__ uint16_t h1(float x) {
    __half hb = __float2half_rn(x);
    return *reinterpret_cast<uint16_t*>(&hb);
}

// XOR chunk swizzle for 64B rows (4 x 16B chunks): conflict-free ldmatrix.
__device__ __forceinline__ uint32_t swz(uint32_t r, uint32_t ch) {
    return r * 64u + ((ch ^ ((r >> 1) & 3u)) << 4);
}

// ---------------------------------------------------------------------------
// fp16-split batched GEMM via mma.sync (HMMA):
// TERMS=3:  C = alpha*(Ahi+Alo)@(Bhi+Blo)^T
// TERMS=2:  C = alpha* A @(Bhi+Blo)^T (A single)
// TERMS=1:  C = alpha* A @ B^T (both single)
// KT    : k-tiles (of 32) per pipeline chunk (1 or 2).
// OUTM  : 0=fp32, 1=fp16 hi/lo, 3=single fp16,
//         5=single fp16 to vt2 layout [b][col][z*1024 + (row&1023)]
//         6=exp() then single fp16 + per-CTA partial rowsums to Cf(psum)
// AHB   : 0=plain A cols; 2=A col g decomposed (g>>10)*HBLK2 + (g&1023)
// BMODB : B z-index = z & 15 (B shared across heads, z = h*16+b)
// ASCALE: scale A fp16 fragments by invr[h][z][row] (Alo repurposed as invr;
//         requires TERMS==1, AHB==2)
// Tile 128x128, 8 warps, 3-stage cp.async pipeline, 1 sync/chunk.
// ---------------------------------------------------------------------------
constexpr int TILE_B = 128 * 64;                 // 8192 B per 32-k tile

template <int TERMS, int KT> struct Cfg {
    static constexpr int NOPS  = (TERMS == 3) ? 4 : (TERMS == 2) ? 3 : 2;
    static constexpr int STAGE = NOPS * KT * TILE_B;
    static constexpr int SMEM  = 3 * STAGE + 512 + 2048;  // bias + rowsum red
};

template <int TERMS, int KT, bool BIAS, int OUTM, int AHB, bool BMODB,
          bool ASCALE>
__global__ void __launch_bounds__(256, 2) hmma_gemm(
    const __half* __restrict__ Ahi, const __half* __restrict__ Alo,
    const __half* __restrict__ Bhi, const __half* __restrict__ Blo,
    const float* __restrict__ biasg,
    float* __restrict__ Cf,
    __half* __restrict__ Chi, __half* __restrict__ Clo,
    int N, int K, int lda, int ldb,
    size_t sA, size_t sB, size_t sBias, size_t sC, float alpha)
{
    constexpr int STAGE = Cfg<TERMS, KT>::STAGE;
    constexpr int NOPS  = Cfg<TERMS, KT>::NOPS;
    constexpr int NA    = (TERMS == 3) ? 2 : 1;
    extern __shared__ __align__(16) char smem[];
    const uint32_t sb = s2u(smem);
    float* sbias = reinterpret_cast<float*>(smem + 3 * STAGE);
    float (*rsred)[4] = reinterpret_cast<float(*)[4]>(smem + 3 * STAGE + 512);

    const int tid  = threadIdx.x;
    const int wid  = tid >> 5, lane = tid & 31;
    const int wr   = wid >> 2, wc = wid & 3;      // warp grid 2x4
    const int qr   = lane >> 2, qc = lane & 3;
    const int col0 = blockIdx.x * 128, row0 = blockIdx.y * 128;
    const size_t z = blockIdx.z;
    const size_t zb = BMODB ? (z & 15) : z;
    const __half* invr = ASCALE ? Alo : nullptr;   // repurposed slot
    Ahi += z * sA; if (TERMS == 3) Alo += z * sA;
    Bhi += zb * sB; if (TERMS >= 2) Blo += zb * sB;

    if (BIAS && tid < 128) sbias[tid] = biasg[z * sBias + col0 + tid];

    const int nCh = K / (32 * KT);

    auto prefetch = [&](int c) {
        const int k0 = c * 32 * KT;
        const uint32_t boff = sb + (uint32_t)(c % 3) * STAGE;
        #pragma unroll
        for (int t = 0; t < NOPS; t++) {
            const __half* s;
            if (TERMS == 3) s = (t == 0) ? Ahi : (t == 1) ? Alo
                              : (t == 2) ? Bhi : Blo;
            else if (TERMS == 2) s = (t == 0) ? Ahi : (t == 1) ? Bhi : Blo;
            else                 s = (t == 0) ? Ahi : Bhi;
            #pragma unroll
            for (int kt = 0; kt < KT; kt++) {
                const int kk = k0 + kt * 32;
                const uint32_t tb = boff + (t * KT + kt) * TILE_B;
                size_t aoff;
                if (AHB == 2) aoff = ((size_t)(kk >> 10)) * HBLK2
                                   + (size_t)(kk & 1023);
                else          aoff = (size_t)kk;
                #pragma unroll
                for (int i = 0; i < 2; i++) {
                    uint32_t idx = (uint32_t)(i * 256 + tid);   // 0..511
                    uint32_t r = idx >> 2, ch = idx & 3;
                    const __half* g;
                    if (t < NA) g = s + aoff + (size_t)(row0 + r) * lda + ch * 8;
                    else        g = s + (size_t)kk + (size_t)(col0 + r) * ldb + ch * 8;
                    cp16(tb + swz(r, ch), g);
                }
            }
        }
        cp_commit();
    };

    float acc[4][4][4] = {};
    uint32_t sc[4][2];           // ASCALE: per-row half2 scales

    prefetch(0);
    prefetch(1);

    for (int c = 0; c < nCh; ++c) {
        if (c + 1 < nCh) cp_wait<1>(); else cp_wait<0>();
        __syncthreads();
        if (c + 2 < nCh) prefetch(c + 2);

        if (ASCALE && (c & 15) == 0) {
            const int h = (c * 32 * KT) >> 10;
            const __half* iv = invr + ((size_t)h * Bn + z) * 1024 + row0;
            #pragma unroll
            for (int mt = 0; mt < 4; mt++) {
                #pragma unroll
                for (int rr = 0; rr < 2; rr++) {
                    __half x = iv[wr * 64 + mt * 16 + rr * 8 + qr];
                    __half2 x2 = __half2half2(x);
                    sc[mt][rr] = *reinterpret_cast<uint32_t*>(&x2);
                }
            }
        }

        const uint32_t boff = sb + (uint32_t)(c % 3) * STAGE;
        const uint32_t lrow = (uint32_t)(lane & 15), lhalf = (uint32_t)(lane >> 4);

        #pragma unroll
        for (int ks = 0; ks < 2 * KT; ks++) {
            const uint32_t sub = (uint32_t)(ks >> 1) * TILE_B;
            const uint32_t kch = (uint32_t)(ks & 1) * 2u + lhalf;
            const uint32_t aHiB = boff + sub;
            const uint32_t aLoB = boff + KT * TILE_B + sub;          // T3 only
            const uint32_t bHiB = boff + ((TERMS == 3) ? 2 : 1) * KT * TILE_B + sub;
            const uint32_t bLoB = boff + ((TERMS == 3) ? 3 : 2) * KT * TILE_B + sub;

            uint32_t bh[4][2], bl[4][2];
            #pragma unroll
            for (int np = 0; np < 2; np++) {
                uint32_t r = (uint32_t)(wc * 32 + np * 16) + lrow;
                uint32_t t[4];
                ldsm4(t, bHiB + swz(r, kch));
                bh[np*2+0][0] = t[0]; bh[np*2+0][1] = t[2];
                bh[np*2+1][0] = t[1]; bh[np*2+1][1] = t[3];
                if (TERMS >= 2) {
                    ldsm4(t, bLoB + swz(r, kch));
                    bl[np*2+0][0] = t[0]; bl[np*2+0][1] = t[2];
                    bl[np*2+1][0] = t[1]; bl[np*2+1][1] = t[3];
                }
            }
            #pragma unroll
            for (int mt = 0; mt < 4; mt++) {
                uint32_t r = (uint32_t)(wr * 64 + mt * 16) + lrow;
                uint32_t ah[4], al[4];
                ldsm4(ah, aHiB + swz(r, kch));
                if (ASCALE) {
                    __half2* av = reinterpret_cast<__half2*>(ah);
                    __half2 s0 = *reinterpret_cast<__half2*>(&sc[mt][0]);
                    __half2 s1 = *reinterpret_cast<__half2*>(&sc[mt][1]);
                    av[0] = __hmul2(av[0], s0);
                    av[2] = __hmul2(av[2], s0);
                    av[1] = __hmul2(av[1], s1);
                    av[3] = __hmul2(av[3], s1);
                }
                if (TERMS == 3) ldsm4(al, aLoB + swz(r, kch));
                #pragma unroll
                for (int nt = 0; nt < 4; nt++) {
                    mma16816(acc[mt][nt], ah, bh[nt][0], bh[nt][1]);
                    if (TERMS >= 2)
                        mma16816(acc[mt][nt], ah, bl[nt][0], bl[nt][1]);
                    if (TERMS == 3)
                        mma16816(acc[mt][nt], al, bh[nt][0], bh[nt][1]);
                }
            }
        }
    }

    // ---- epilogue ----
    float rs[4][2] = {};          // OUTM==6 partial rowsums
    #pragma unroll
    for (int mt = 0; mt < 4; mt++) {
        #pragma unroll
        for (int nt = 0; nt < 4; nt++) {
            const int lcol = wc * 32 + nt * 8 + qc * 2;
            const float b0 = BIAS ? sbias[lcol]     : 0.f;
            const float b1 = BIAS ? sbias[lcol + 1] : 0.f;
            const int r0 = row0 + wr * 64 + mt * 16 + qr;
            const float v00 = alpha * acc[mt][nt][0] + b0;
            const float v01 = alpha * acc[mt][nt][1] + b1;
            const float v10 = alpha * acc[mt][nt][2] + b0;
            const float v11 = alpha * acc[mt][nt][3] + b1;
            if (OUTM == 0) {
                float* cp = Cf + z * sC + (size_t)r0 * N + col0 + lcol;
                *reinterpret_cast<float2*>(cp)            = make_float2(v00, v01);
                *reinterpret_cast<float2*>(cp + 8ull * N) = make_float2(v10, v11);
            } else if (OUTM == 1) {
                uint16_t h0,l0,h1b,l1,h2,l2,h3,l3;
                split2h(v00, h0, l0); split2h(v01, h1b, l1);
                split2h(v10, h2, l2); split2h(v11, h3, l3);
                size_t o0 = z * sC + (size_t)r0 * N + col0 + lcol;
                size_t o1 = o0 + 8ull * N;
                *reinterpret_cast<uint32_t*>(
                    reinterpret_cast<uint16_t*>(Chi) + o0) = (uint32_t)h0 | ((uint32_t)h1b << 16);
                *reinterpret_cast<uint32_t*>(
                    reinterpret_cast<uint16_t*>(Clo) + o0) = (uint32_t)l0 | ((uint32_t)l1 << 16);
                *reinterpret_cast<uint32_t*>(
                    reinterpret_cast<uint16_t*>(Chi) + o1) = (uint32_t)h2 | ((uint32_t)h3 << 16);
                *reinterpret_cast<uint32_t*>(
                    reinterpret_cast<uint16_t*>(Clo) + o1) = (uint32_t)l2 | ((uint32_t)l3 << 16);
            } else if (OUTM == 3 || OUTM == 6) {
                float e00 = v00, e01 = v01, e10 = v10, e11 = v11;
                if (OUTM == 6) {
                    e00 = __expf(v00); e01 = __expf(v01);
                    e10 = __expf(v10); e11 = __expf(v11);
                    rs[mt][0] += e00 + e01;
                    rs[mt][1] += e10 + e11;
                }
                size_t o0 = z * sC + (size_t)r0 * N + col0 + lcol;
                size_t o1 = o0 + 8ull * N;
                *reinterpret_cast<uint32_t*>(
                    reinterpret_cast<uint16_t*>(Chi) + o0) =
                    (uint32_t)h1(e00) | ((uint32_t)h1(e01) << 16);
                *reinterpret_cast<uint32_t*>(
                    reinterpret_cast<uint16_t*>(Chi) + o1) =
                    (uint32_t)h1(e10) | ((uint32_t)h1(e11) << 16);
            } else {
                // OUTM == 5: vt2[b][col][z*1024 + j],  b = r0>>10, j = r0&1023
                uint16_t* oh = reinterpret_cast<uint16_t*>(Chi);
                const size_t bb = (size_t)(r0 >> 10);
                const int j0 = r0 & 1023;
                const size_t c0a = (bb * 512 + (size_t)(col0 + lcol)) * 8192
                                 + (size_t)z * 1024;
                const size_t c1a = c0a + 8192;       // col+1
                oh[c0a + j0]     = h1(v00);
                oh[c1a + j0]     = h1(v01);
                oh[c0a + j0 + 8] = h1(v10);
                oh[c1a + j0 + 8] = h1(v11);
            }
        }
    }

    if (OUTM == 6) {
        // reduce rowsums: over qc (shfl), then over wc (smem), write psum
        #pragma unroll
        for (int mt = 0; mt < 4; mt++) {
            #pragma unroll
            for (int rr = 0; rr < 2; rr++) {
                float v = rs[mt][rr];
                v += __shfl_xor_sync(0xffffffffu, v, 1);
                v += __shfl_xor_sync(0xffffffffu, v, 2);
                if (qc == 0)
                    rsred[wr * 64 + mt * 16 + rr * 8 + qr][wc] = v;
            }
        }
        __syncthreads();
        if (tid < 128) {
            float t = rsred[tid][0] + rsred[tid][1]
                    + rsred[tid][2] + rsred[tid][3];
            Cf[((size_t)z * 1024 + row0 + tid) * 8 + blockIdx.x] = t;
        }
    }
}

// ---------------------------------------------------------------------------
// fp32 -> fp16 conversion for q,k,v in one launch (grid.z picks tensor)
// ---------------------------------------------------------------------------
__global__ void conv_h3(const float* __restrict__ s0, __half* __restrict__ d0,
                        const float* __restrict__ s1, __half* __restrict__ d1,
                        const float* __restrict__ s2, __half* __restrict__ d2) {
    const float* s = (blockIdx.z == 0) ? s0 : (blockIdx.z == 1) ? s1 : s2;
    __half*      d = (blockIdx.z == 0) ? d0 : (blockIdx.z == 1) ? d1 : d2;
    size_t i = ((size_t)blockIdx.x * 256 + threadIdx.x) * 4;
    float4 v = *reinterpret_cast<const float4*>(s + i);
    *reinterpret_cast<uint2*>(d + i) = make_uint2(
        (uint32_t)h1(v.x) | ((uint32_t)h1(v.y) << 16),
        (uint32_t)h1(v.z) | ((uint32_t)h1(v.w) << 16));
}

// ---------------------------------------------------------------------------
// Merged per-head 512x512 transpose + split for Wq,Wk,Wv (z = 0..23)
// ---------------------------------------------------------------------------
__global__ void transpose_w3(const float* __restrict__ Wq,
                             __half* __restrict__ oq_h, __half* __restrict__ oq_l,
                             const float* __restrict__ Wk,
                             __half* __restrict__ ok_h, __half* __restrict__ ok_l,
                             const float* __restrict__ Wv,
                             __half* __restrict__ ov_h, __half* __restrict__ ov_l) {
    __shared__ float t[32][33];
    const int sel = blockIdx.z >> 3;
    const size_t z = blockIdx.z & 7;
    const float* in = (sel == 0) ? Wq : (sel == 1) ? Wk : Wv;
    __half* oh = (sel == 0) ? oq_h : (sel == 1) ? ok_h : ov_h;
    __half* ol = (sel == 0) ? oq_l : (sel == 1) ? ok_l : ov_l;
    in += z * (size_t)(Dn * Dn);
    oh += z * (size_t)(Dn * Dn);
    ol += z * (size_t)(Dn * Dn);
    const int x0 = blockIdx.x * 32;
    const int y0 = blockIdx.y * 32;
    #pragma unroll
    for (int i = 0; i < 4; i++)
        t[threadIdx.y + i * 8][threadIdx.x] =
            in[(size_t)(y0 + threadIdx.y + i * 8) * Dn + x0 + threadIdx.x];
    __syncthreads();
    #pragma unroll
    for (int i = 0; i < 4; i++) {
        float v = t[threadIdx.x][threadIdx.y + i * 8];
        uint16_t h, l;
        split2h(v, h, l);
        size_t o = (size_t)(x0 + threadIdx.y + i * 8) * Dn + y0 + threadIdx.x;
        reinterpret_cast<uint16_t*>(oh)[o] = h;
        reinterpret_cast<uint16_t*>(ol)[o] = l;
    }
}

// ---------------------------------------------------------------------------
// Wo permute + split: wo_p[o][h*512+d] = Wo[o][d*8+h]
// ---------------------------------------------------------------------------
__global__ void conv_wo_p(const float* __restrict__ Wo,
                          __half* __restrict__ oh,
                          __half* __restrict__ ol) {
    size_t idx = (size_t)blockIdx.x * 256 + threadIdx.x;
    int g = (int)(idx & 4095);
    size_t o = idx >> 12;
    int f = ((g & 511) << 3) | (g >> 9);
    float v = Wo[(o << 12) + f];
    uint16_t h, l;
    split2h(v, h, l);
    reinterpret_cast<uint16_t*>(oh)[idx] = h;
    reinterpret_cast<uint16_t*>(ol)[idx] = l;
}

// ---------------------------------------------------------------------------
// bfin[o] = bo[o] + sum_f Wo[o][f] * bv[f&7][f>>3]
// ---------------------------------------------------------------------------
__global__ void bfin_kernel(const float* __restrict__ Wo,
                            const float* __restrict__ bv,
                            const float* __restrict__ bo,
                            float* __restrict__ bfin) {
    __shared__ float red[8];
    const int o = blockIdx.x, tid = threadIdx.x;
    const float* wr = Wo + (size_t)o * 4096;
    float s = 0.f;
    for (int f = tid; f < 4096; f += 256)
        s += wr[f] * bv[(f & 7) * Dn + (f >> 3)];
    #pragma unroll
    for (int off = 16; off > 0; off >>= 1)
        s += __shfl_xor_sync(0xffffffffu, s, off);
    if ((tid & 31) == 0) red[tid >> 5] = s;
    __syncthreads();
    if (tid == 0) {
        float t = 0.f;
        #pragma unroll
        for (int i = 0; i < 8; i++) t += red[i];
        bfin[o] = bo[o] + t;
    }
}

// ---------------------------------------------------------------------------
// wvec[h][d] = sum_e bq[h][e] * Wk[h][e][d]
// ---------------------------------------------------------------------------
__global__ void wvec_kernel(const float* __restrict__ Wk,
                            const float* __restrict__ bq,
                            float* __restrict__ wvec) {
    const int h = blockIdx.x, d = threadIdx.x;
    const float* wk = Wk + (size_t)h * Dn * Dn;
    const float* b  = bq + (size_t)h * Dn;
    float s = 0.f;
    for (int e = 0; e < Dn; e++) s += b[e] * wk[(size_t)e * Dn + d];
    wvec[h * Dn + d] = s;
}

// ---------------------------------------------------------------------------
// colv[(h*16+b)][j] = inv_scale * k[b][j] . wvec[h]
// ---------------------------------------------------------------------------
__global__ void colv_kernel(const float* __restrict__ k,
                            const float* __restrict__ wvec,
                            float* __restrict__ colv, float inv_scale) {
    __shared__ float kr[Dn];
    const size_t bj = blockIdx.x;
    const int tid = threadIdx.x, w = tid >> 5, lane = tid & 31;
    const float* kp = k + bj * Dn;
    #pragma unroll
    for (int i = 0; i < 2; i++) kr[tid + i * 256] = kp[tid + i * 256];
    __syncthreads();
    const float* wv = wvec + w * Dn;
    float s = 0.f;
    #pragma unroll
    for (int t = 0; t < 16; t++) {
        int d = lane + t * 32;
        s += kr[d] * wv[d];
    }
    #pragma unroll
    for (int o = 16; o > 0; o >>= 1)
        s += __shfl_xor_sync(0xffffffffu, s, o);
    if (lane == 0) {
        size_t b = bj >> 10, j = bj & 1023;
        colv[((size_t)w * 16 + b) * 1024 + j] = s * inv_scale;
    }
}

// ---------------------------------------------------------------------------
// invr[r] = fp16( 1 / sum_{t=0..7} psum[r*8+t] )
// ---------------------------------------------------------------------------
__global__ void inv_rsum(const float* __restrict__ psum,
                         __half* __restrict__ invr) {
    size_t r = (size_t)blockIdx.x * 256 + threadIdx.x;
    const float4* p = reinterpret_cast<const float4*>(psum + r * 8);
    float4 a = p[0], b = p[1];
    float s = ((a.x + a.y) + (a.z + a.w)) + ((b.x + b.y) + (b.z + b.w));
    invr[r] = __float2half_rn(1.0f / s);
}

// ---------------------------------------------------------------------------
// kernel_launch — inputs: k, v, q, Wk, bk, Wv, bv, Wq, bq, Wo, bo
// Launch order: #4 = q~ GEMM (ncu profiles overall launch 6 = mine+2)
// ---------------------------------------------------------------------------
extern "C" void kernel_launch(void* const* d_in, const int* in_sizes, int n_in,
                              void* d_out, int out_size) {
    (void)in_sizes; (void)n_in; (void)out_size;
    const float* k  = (const float*)d_in[0];
    const float* v  = (const float*)d_in[1];
    const float* q  = (const float*)d_in[2];
    const float* Wk = (const float*)d_in[3];
    const float* Wv = (const float*)d_in[5];
    const float* bv = (const float*)d_in[6];
    const float* Wq = (const float*)d_in[7];
    const float* bq = (const float*)d_in[8];
    const float* Wo = (const float*)d_in[9];
    const float* bo = (const float*)d_in[10];
    float* out = (float*)d_out;

    constexpr int SM3  = Cfg<3, 1>::SMEM;
    constexpr int SM1B = Cfg<1, 2>::SMEM;
    cudaFuncSetAttribute(hmma_gemm<3, 1, false, 3, 0, false, false>,
        cudaFuncAttributeMaxDynamicSharedMemorySize, SM3);
    cudaFuncSetAttribute(hmma_gemm<1, 2, false, 3, 0, false, false>,
        cudaFuncAttributeMaxDynamicSharedMemorySize, SM1B);
    cudaFuncSetAttribute(hmma_gemm<1, 2, false, 5, 0, false, false>,
        cudaFuncAttributeMaxDynamicSharedMemorySize, SM1B);
    cudaFuncSetAttribute(hmma_gemm<1, 2, true, 6, 0, true, false>,
        cudaFuncAttributeMaxDynamicSharedMemorySize, SM1B);
    cudaFuncSetAttribute(hmma_gemm<1, 2, true, 0, 2, false, true>,
        cudaFuncAttributeMaxDynamicSharedMemorySize, SM1B);

    __half *xq,*xk,*xv;
    __half *wqt_h,*wqt_l,*wkt_h,*wkt_l,*wvt_h,*wvt_l,*mt,*wvo;
    __half *wop_h,*wop_l;
    __half *qp,*vt2,*Ps,*invr;
    float *wvec,*colv,*bfin,*psum;
    cudaGetSymbolAddress((void**)&xq,   g_xq);
    cudaGetSymbolAddress((void**)&xk,   g_xk);
    cudaGetSymbolAddress((void**)&xv,   g_xv);
    cudaGetSymbolAddress((void**)&wqt_h,g_wqt_hi);cudaGetSymbolAddress((void**)&wqt_l,g_wqt_lo);
    cudaGetSymbolAddress((void**)&wkt_h,g_wkt_hi);cudaGetSymbolAddress((void**)&wkt_l,g_wkt_lo);
    cudaGetSymbolAddress((void**)&wvt_h,g_wvt_hi);cudaGetSymbolAddress((void**)&wvt_l,g_wvt_lo);
    cudaGetSymbolAddress((void**)&mt,   g_mt);
    cudaGetSymbolAddress((void**)&wvo,  g_wvo);
    cudaGetSymbolAddress((void**)&wop_h,g_wop_hi);cudaGetSymbolAddress((void**)&wop_l,g_wop_lo);
    cudaGetSymbolAddress((void**)&qp,   g_qp);
    cudaGetSymbolAddress((void**)&vt2,  g_vt2);
    cudaGetSymbolAddress((void**)&Ps,   g_Ps);
    cudaGetSymbolAddress((void**)&invr, g_invr);
    cudaGetSymbolAddress((void**)&wvec, g_wvec);
    cudaGetSymbolAddress((void**)&colv, g_colv);
    cudaGetSymbolAddress((void**)&bfin, g_bfin);
    cudaGetSymbolAddress((void**)&psum, g_psum);

    const float inv_scale = 1.0f / sqrtf((float)Dn);
    const size_t WW = (size_t)Dn * Dn;

    // #1: q,k,v -> fp16
    conv_h3<<<dim3((unsigned)(XEL / 1024), 1, 3), 256>>>(q, xq, k, xk, v, xv);
    // #2: Wq,Wk,Wv transpose+split (merged)
    transpose_w3<<<dim3(16, 16, 24), dim3(32, 8)>>>(
        Wq, wqt_h, wqt_l, Wk, wkt_h, wkt_l, Wv, wvt_h, wvt_l);
    // #3: Mt[h] = Wk^T Wq (3-term in, single out)
    hmma_gemm<3, 1, false, 3, 0, false, false><<<dim3(4, 4, Hn), 256, SM3>>>(
        wkt_h, wkt_l, wqt_h, wqt_l, nullptr, nullptr, mt, nullptr,
        Dn, Dn, Dn, Dn, WW, WW, 0, WW, 1.0f);
    // #4: q~ = q @ Mt^T (1-term) — ncu profiling target
    dim3 gproj(Dn / 128, Mn / 128, Hn);
    hmma_gemm<1, 2, false, 3, 0, false, false><<<gproj, 256, SM1B>>>(
        xq, nullptr, mt, nullptr, nullptr, nullptr, qp, nullptr,
        Dn, Dn, Dn, Dn, 0, WW, 0, (size_t)Mn * Dn, 1.0f);

    // remaining prep
    conv_wo_p<<<(unsigned)(WEL / 256), 256>>>(Wo, wop_h, wop_l);
    bfin_kernel<<<Dn, 256>>>(Wo, bv, bo, bfin);
    hmma_gemm<3, 1, false, 3, 0, false, false><<<dim3(4, 4, Hn), 256, SM3>>>(
        wop_h, wop_l, wvt_h, wvt_l, nullptr, nullptr, wvo, nullptr,
        Dn, Dn, Hn * Dn, Dn, (size_t)Dn, WW, 0, WW, 1.0f);
    wvec_kernel<<<Hn, Dn>>>(Wk, bq, wvec);
    colv_kernel<<<Mn, 256>>>(k, wvec, colv, inv_scale);

    // v~ = v @ Wvo^T -> vt2[b][o][h*1024+j]
    hmma_gemm<1, 2, false, 5, 0, false, false><<<gproj, 256, SM1B>>>(
        xv, nullptr, wvo, nullptr, nullptr, nullptr, vt2, nullptr,
        Dn, Dn, Dn, Dn, 0, WW, 0, 0, 1.0f);

    // scores: E = exp(q~ @ k^T / scale + colv), partial rowsums -> psum
    dim3 gsc(Nn / 128, Nn / 128, Hn * Bn);
    hmma_gemm<1, 2, true, 6, 0, true, false><<<gsc, 256, SM1B>>>(
        qp, nullptr, xk, nullptr, colv, psum, Ps, nullptr,
        Nn, Dn, Dn, Dn, (size_t)Nn * Dn, (size_t)Nn * Dn,
        (size_t)Nn, (size_t)Nn * Nn, inv_scale);

    // invr = 1 / rowsum
    inv_rsum<<<(unsigned)(NROWS / 256), 256>>>(psum, invr);

    // out = sum_h (E_h * invr) @ v~_h + bfin  (1-term, K=8192, A-scaled)
    dim3 gfin(Dn / 128, Nn / 128, Bn);
    hmma_gemm<1, 2, true, 0, 2, false, true><<<gfin, 256, SM1B>>>(
        Ps, invr /*repurposed*/, vt2, nullptr, bfin, out, nullptr, nullptr,
        Dn, Hn * Nn, Nn, Hn * Nn,
        (size_t)Nn * Nn, (size_t)Dn * Hn * Nn, 0, (size_t)Nn * Dn, 1.0f);
}

// round 14
// speedup vs baseline: 6.7673x; 1.0063x over previous
#include <cuda_runtime.h>
#include <cuda_fp16.h>
#include <math.h>
#include <stdint.h>

// ---------------------------------------------------------------------------
// Problem constants
// ---------------------------------------------------------------------------
constexpr int Hn = 8, Bn = 16, Nn = 1024, Dn = 512;
constexpr int Mn = Bn * Nn;                               // 16384
constexpr size_t XEL  = (size_t)Mn * Dn;                  // 8,388,608
constexpr size_t WEL  = (size_t)Hn * Dn * Dn;             // 2,097,152
constexpr size_t PROJ = (size_t)Hn * Mn * Dn;             // 67,108,864
constexpr size_t PEL  = (size_t)Hn * Bn * Nn * Nn;        // 134,217,728
constexpr size_t HBLK2 = (size_t)Bn * Nn * Nn;            // 16M: h-block in P
constexpr size_t NROWS = (size_t)Hn * Bn * Nn;            // 131072 score rows

// ---------------------------------------------------------------------------
// Scratch (__device__ globals — allocation-free)
// ---------------------------------------------------------------------------
__device__ __half g_xq[XEL];                       // q single fp16
__device__ __half g_xk[XEL];                       // k single fp16
__device__ __half g_xv[XEL];                       // v single fp16
__device__ __half g_wqt_hi[WEL], g_wqt_lo[WEL];    // Wq^T per head
__device__ __half g_wkt_hi[WEL], g_wkt_lo[WEL];    // Wk^T per head
__device__ __half g_wvt_hi[WEL], g_wvt_lo[WEL];    // Wv^T per head
__device__ __half g_mt[WEL];                       // Mt = Wk^T Wq (single)
__device__ __half g_wvo[WEL];                      // Wvo = Wo_h @ Wv_h (single)
__device__ __half g_wop_hi[WEL], g_wop_lo[WEL];    // permuted Wo
__device__ __half g_qp[PROJ];                      // q~ single fp16
__device__ __half g_vt2[PROJ];                     // v~ [b][o][h*1024+j]
__device__ __half g_Ps[PEL];                       // e^scores (unnormalized)
__device__ float  g_psum[NROWS * 8];               // partial rowsums per col-tile
__device__ __half g_invr[NROWS];                   // 1/rowsum, fp16
__device__ float  g_wvec[Hn * Dn];                 // Wk^T bq per head
__device__ float  g_colv[NROWS];                   // scaled col terms
__device__ float  g_bfin[Dn];                      // bo + sum_h Wo_h bv_h

// ---------------------------------------------------------------------------
// Helpers
// ---------------------------------------------------------------------------
__device__ __forceinline__ uint32_t s2u(const void* p) {
    uint32_t a;
    asm("{ .reg .u64 t; cvta.to.shared.u64 t, %1; cvt.u32.u64 %0, t; }"
        : "=r"(a) : "l"(p));
    return a;
}

__device__ __forceinline__ void cp16(uint32_t saddr, const void* gaddr) {
    asm volatile("cp.async.cg.shared.global [%0], [%1], 16;"
                 :: "r"(saddr), "l"(gaddr) : "memory");
}
__device__ __forceinline__ void cp_commit() {
    asm volatile("cp.async.commit_group;" ::: "memory");
}
template <int N>
__device__ __forceinline__ void cp_wait() {
    asm volatile("cp.async.wait_group %0;" :: "n"(N) : "memory");
}

__device__ __forceinline__ void ldsm4(uint32_t* r, uint32_t addr) {
    asm volatile("ldmatrix.sync.aligned.m8n8.x4.shared.b16 {%0,%1,%2,%3}, [%4];"
        : "=r"(r[0]), "=r"(r[1]), "=r"(r[2]), "=r"(r[3]) : "r"(addr));
}

__device__ __forceinline__ void mma16816(float* d, const uint32_t* a,
                                         uint32_t b0, uint32_t b1) {
    asm volatile(
        "mma.sync.aligned.m16n8k16.row.col.f32.f16.f16.f32 "
        "{%0,%1,%2,%3}, {%4,%5,%6,%7}, {%8,%9}, {%0,%1,%2,%3};"
        : "+f"(d[0]), "+f"(d[1]), "+f"(d[2]), "+f"(d[3])
        : "r"(a[0]), "r"(a[1]), "r"(a[2]), "r"(a[3]), "r"(b0), "r"(b1));
}

__device__ __forceinline__ void split2h(float x, uint16_t& h, uint16_t& l) {
    __half hb = __float2half_rn(x);
    __half lb = __float2half_rn(x - __half2float(hb));
    h = *reinterpret_cast<uint16_t*>(&hb);
    l = *reinterpret_cast<uint16_t*>(&lb);
}
__device__ __forceinline__ uint16_t h1(float x) {
    __half hb = __float2half_rn(x);
    return *reinterpret_cast<uint16_t*>(&hb);
}

// XOR chunk swizzle for 64B rows (4 x 16B chunks): conflict-free ldmatrix.
__device__ __forceinline__ uint32_t swz(uint32_t r, uint32_t ch) {
    return r * 64u + ((ch ^ ((r >> 1) & 3u)) << 4);
}

// ---------------------------------------------------------------------------
// fp16-split batched GEMM via mma.sync (HMMA):
// TERMS=3:  C = alpha*(Ahi+Alo)@(Bhi+Blo)^T   (256 thr, warp 64x32)
// TERMS=1:  C = alpha* A @ B^T (both single)  (128 thr, warp 64x64)
// KT    : k-tiles (of 32) per pipeline chunk.
// OUTM  : 0=fp32, 1=fp16 hi/lo, 3=single fp16,
//         5=single fp16 to vt2 layout [b][col][z*1024 + (row&1023)]
//         6=exp() then single fp16 + per-CTA partial rowsums to Cf(psum)
// AHB   : 0=plain A cols; 2=A col g decomposed (g>>10)*HBLK2 + (g&1023)
// BMODB : B z-index = z & 15 (B shared across heads, z = h*16+b)
// ASCALE: scale A fragments by invr (Alo repurposed; TERMS==1, AHB==2)
// CTA tile 128x128, 3-stage cp.async pipeline, 1 sync/chunk.
// ---------------------------------------------------------------------------
constexpr int TILE_B = 128 * 64;                 // 8192 B per 32-k tile

template <int TERMS, int KT> struct Cfg {
    static constexpr int NOPS    = (TERMS == 3) ? 4 : (TERMS == 2) ? 3 : 2;
    static constexpr int STAGE   = NOPS * KT * TILE_B;
    static constexpr int SMEM    = 3 * STAGE + 512 + 2048;
    static constexpr int THREADS = (TERMS == 1) ? 128 : 256;
    static constexpr int WCN     = (TERMS == 1) ? 2 : 4;   // warp col groups
    static constexpr int NTN     = (TERMS == 1) ? 8 : 4;   // n8 tiles / warp
    static constexpr int CSPAN   = (TERMS == 1) ? 64 : 32; // cols / warp
};

template <int TERMS, int KT, bool BIAS, int OUTM, int AHB, bool BMODB,
          bool ASCALE>
__global__ void __launch_bounds__(Cfg<TERMS, KT>::THREADS, 2) hmma_gemm(
    const __half* __restrict__ Ahi, const __half* __restrict__ Alo,
    const __half* __restrict__ Bhi, const __half* __restrict__ Blo,
    const float* __restrict__ biasg,
    float* __restrict__ Cf,
    __half* __restrict__ Chi, __half* __restrict__ Clo,
    int N, int K, int lda, int ldb,
    size_t sA, size_t sB, size_t sBias, size_t sC, float alpha)
{
    constexpr int STAGE   = Cfg<TERMS, KT>::STAGE;
    constexpr int NOPS    = Cfg<TERMS, KT>::NOPS;
    constexpr int NA      = (TERMS == 3) ? 2 : 1;
    constexpr int THREADS = Cfg<TERMS, KT>::THREADS;
    constexpr int WCN     = Cfg<TERMS, KT>::WCN;
    constexpr int NTN     = Cfg<TERMS, KT>::NTN;
    constexpr int CSPAN   = Cfg<TERMS, KT>::CSPAN;
    extern __shared__ __align__(16) char smem[];
    const uint32_t sb = s2u(smem);
    float* sbias = reinterpret_cast<float*>(smem + 3 * STAGE);
    float (*rsred)[WCN] = reinterpret_cast<float(*)[WCN]>(smem + 3 * STAGE + 512);

    const int tid  = threadIdx.x;
    const int wid  = tid >> 5, lane = tid & 31;
    const int wr   = (TERMS == 1) ? (wid >> 1) : (wid >> 2);
    const int wc   = wid & (WCN - 1);
    const int qr   = lane >> 2, qc = lane & 3;
    const int col0 = blockIdx.x * 128, row0 = blockIdx.y * 128;
    const size_t z = blockIdx.z;
    const size_t zb = BMODB ? (z & 15) : z;
    const __half* invr = ASCALE ? Alo : nullptr;   // repurposed slot
    Ahi += z * sA; if (TERMS == 3) Alo += z * sA;
    Bhi += zb * sB; if (TERMS >= 2) Blo += zb * sB;

    if (BIAS && tid < 128) sbias[tid] = biasg[z * sBias + col0 + tid];

    const int nCh = K / (32 * KT);

    auto prefetch = [&](int c) {
        const int k0 = c * 32 * KT;
        const uint32_t boff = sb + (uint32_t)(c % 3) * STAGE;
        #pragma unroll
        for (int t = 0; t < NOPS; t++) {
            const __half* s;
            if (TERMS == 3) s = (t == 0) ? Ahi : (t == 1) ? Alo
                              : (t == 2) ? Bhi : Blo;
            else            s = (t == 0) ? Ahi : Bhi;
            #pragma unroll
            for (int kt = 0; kt < KT; kt++) {
                const int kk = k0 + kt * 32;
                const uint32_t tb = boff + (t * KT + kt) * TILE_B;
                size_t aoff;
                if (AHB == 2) aoff = ((size_t)(kk >> 10)) * HBLK2
                                   + (size_t)(kk & 1023);
                else          aoff = (size_t)kk;
                #pragma unroll
                for (int i = 0; i < 512 / THREADS; i++) {
                    uint32_t idx = (uint32_t)(i * THREADS + tid);   // 0..511
                    uint32_t r = idx >> 2, ch = idx & 3;
                    const __half* g;
                    if (t < NA) g = s + aoff + (size_t)(row0 + r) * lda + ch * 8;
                    else        g = s + (size_t)kk + (size_t)(col0 + r) * ldb + ch * 8;
                    cp16(tb + swz(r, ch), g);
                }
            }
        }
        cp_commit();
    };

    float acc[4][NTN][4] = {};
    uint32_t sc[4][2];           // ASCALE: per-row half2 scales

    prefetch(0);
    prefetch(1);

    for (int c = 0; c < nCh; ++c) {
        if (c + 1 < nCh) cp_wait<1>(); else cp_wait<0>();
        __syncthreads();
        if (c + 2 < nCh) prefetch(c + 2);

        if (ASCALE && (c & 15) == 0) {
            const int h = (c * 32 * KT) >> 10;
            const __half* iv = invr + ((size_t)h * Bn + z) * 1024 + row0;
            #pragma unroll
            for (int mt = 0; mt < 4; mt++) {
                #pragma unroll
                for (int rr = 0; rr < 2; rr++) {
                    __half x = iv[wr * 64 + mt * 16 + rr * 8 + qr];
                    __half2 x2 = __half2half2(x);
                    sc[mt][rr] = *reinterpret_cast<uint32_t*>(&x2);
                }
            }
        }

        const uint32_t boff = sb + (uint32_t)(c % 3) * STAGE;
        const uint32_t lrow = (uint32_t)(lane & 15), lhalf = (uint32_t)(lane >> 4);

        #pragma unroll
        for (int ks = 0; ks < 2 * KT; ks++) {
            const uint32_t sub = (uint32_t)(ks >> 1) * TILE_B;
            const uint32_t kch = (uint32_t)(ks & 1) * 2u + lhalf;
            const uint32_t aHiB = boff + sub;
            const uint32_t aLoB = boff + KT * TILE_B + sub;          // T3 only
            const uint32_t bHiB = boff + ((TERMS == 3) ? 2 : 1) * KT * TILE_B + sub;
            const uint32_t bLoB = boff + ((TERMS == 3) ? 3 : 2) * KT * TILE_B + sub;

            uint32_t bh[NTN][2], bl[4][2];
            #pragma unroll
            for (int np = 0; np < NTN / 2; np++) {
                uint32_t r = (uint32_t)(wc * CSPAN + np * 16) + lrow;
                uint32_t t[4];
                ldsm4(t, bHiB + swz(r, kch));
                bh[np*2+0][0] = t[0]; bh[np*2+0][1] = t[2];
                bh[np*2+1][0] = t[1]; bh[np*2+1][1] = t[3];
                if (TERMS >= 2) {
                    ldsm4(t, bLoB + swz(r, kch));
                    bl[np*2+0][0] = t[0]; bl[np*2+0][1] = t[2];
                    bl[np*2+1][0] = t[1]; bl[np*2+1][1] = t[3];
                }
            }
            #pragma unroll
            for (int mt = 0; mt < 4; mt++) {
                uint32_t r = (uint32_t)(wr * 64 + mt * 16) + lrow;
                uint32_t ah[4], al[4];
                ldsm4(ah, aHiB + swz(r, kch));
                if (ASCALE) {
                    __half2* av = reinterpret_cast<__half2*>(ah);
                    __half2 s0 = *reinterpret_cast<__half2*>(&sc[mt][0]);
                    __half2 s1 = *reinterpret_cast<__half2*>(&sc[mt][1]);
                    av[0] = __hmul2(av[0], s0);
                    av[2] = __hmul2(av[2], s0);
                    av[1] = __hmul2(av[1], s1);
                    av[3] = __hmul2(av[3], s1);
                }
                if (TERMS == 3) ldsm4(al, aLoB + swz(r, kch));
                #pragma unroll
                for (int nt = 0; nt < NTN; nt++) {
                    mma16816(acc[mt][nt], ah, bh[nt][0], bh[nt][1]);
                    if (TERMS >= 2)
                        mma16816(acc[mt][nt], ah, bl[nt][0], bl[nt][1]);
                    if (TERMS == 3)
                        mma16816(acc[mt][nt], al, bh[nt][0], bh[nt][1]);
                }
            }
        }
    }

    // ---- epilogue ----
    float rs[4][2] = {};          // OUTM==6 partial rowsums
    #pragma unroll
    for (int mt = 0; mt < 4; mt++) {
        #pragma unroll
        for (int nt = 0; nt < NTN; nt++) {
            const int lcol = wc * CSPAN + nt * 8 + qc * 2;
            const float b0 = BIAS ? sbias[lcol]     : 0.f;
            const float b1 = BIAS ? sbias[lcol + 1] : 0.f;
            const int r0 = row0 + wr * 64 + mt * 16 + qr;
            const float v00 = alpha * acc[mt][nt][0] + b0;
            const float v01 = alpha * acc[mt][nt][1] + b1;
            const float v10 = alpha * acc[mt][nt][2] + b0;
            const float v11 = alpha * acc[mt][nt][3] + b1;
            if (OUTM == 0) {
                float* cp = Cf + z * sC + (size_t)r0 * N + col0 + lcol;
                *reinterpret_cast<float2*>(cp)            = make_float2(v00, v01);
                *reinterpret_cast<float2*>(cp + 8ull * N) = make_float2(v10, v11);
            } else if (OUTM == 1) {
                uint16_t h0,l0,h1b,l1,h2,l2,h3,l3;
                split2h(v00, h0, l0); split2h(v01, h1b, l1);
                split2h(v10, h2, l2); split2h(v11, h3, l3);
                size_t o0 = z * sC + (size_t)r0 * N + col0 + lcol;
                size_t o1 = o0 + 8ull * N;
                *reinterpret_cast<uint32_t*>(
                    reinterpret_cast<uint16_t*>(Chi) + o0) = (uint32_t)h0 | ((uint32_t)h1b << 16);
                *reinterpret_cast<uint32_t*>(
                    reinterpret_cast<uint16_t*>(Clo) + o0) = (uint32_t)l0 | ((uint32_t)l1 << 16);
                *reinterpret_cast<uint32_t*>(
                    reinterpret_cast<uint16_t*>(Chi) + o1) = (uint32_t)h2 | ((uint32_t)h3 << 16);
                *reinterpret_cast<uint32_t*>(
                    reinterpret_cast<uint16_t*>(Clo) + o1) = (uint32_t)l2 | ((uint32_t)l3 << 16);
            } else if (OUTM == 3 || OUTM == 6) {
                float e00 = v00, e01 = v01, e10 = v10, e11 = v11;
                if (OUTM == 6) {
                    e00 = __expf(v00); e01 = __expf(v01);
                    e10 = __expf(v10); e11 = __expf(v11);
                    rs[mt][0] += e00 + e01;
                    rs[mt][1] += e10 + e11;
                }
                size_t o0 = z * sC + (size_t)r0 * N + col0 + lcol;
                size_t o1 = o0 + 8ull * N;
                *reinterpret_cast<uint32_t*>(
                    reinterpret_cast<uint16_t*>(Chi) + o0) =
                    (uint32_t)h1(e00) | ((uint32_t)h1(e01) << 16);
                *reinterpret_cast<uint32_t*>(
                    reinterpret_cast<uint16_t*>(Chi) + o1) =
                    (uint32_t)h1(e10) | ((uint32_t)h1(e11) << 16);
            } else {
                // OUTM == 5: vt2[b][col][z*1024 + j],  b = r0>>10, j = r0&1023
                uint16_t* oh = reinterpret_cast<uint16_t*>(Chi);
                const size_t bb = (size_t)(r0 >> 10);
                const int j0 = r0 & 1023;
                const size_t c0a = (bb * 512 + (size_t)(col0 + lcol)) * 8192
                                 + (size_t)z * 1024;
                const size_t c1a = c0a + 8192;       // col+1
                oh[c0a + j0]     = h1(v00);
                oh[c1a + j0]     = h1(v01);
                oh[c0a + j0 + 8] = h1(v10);
                oh[c1a + j0 + 8] = h1(v11);
            }
        }
    }

    if (OUTM == 6) {
        // reduce rowsums: over qc (shfl), then over wc (smem), write psum
        #pragma unroll
        for (int mt = 0; mt < 4; mt++) {
            #pragma unroll
            for (int rr = 0; rr < 2; rr++) {
                float v = rs[mt][rr];
                v += __shfl_xor_sync(0xffffffffu, v, 1);
                v += __shfl_xor_sync(0xffffffffu, v, 2);
                if (qc == 0)
                    rsred[wr * 64 + mt * 16 + rr * 8 + qr][wc] = v;
            }
        }
        __syncthreads();
        if (tid < 128) {
            float t = 0.f;
            #pragma unroll
            for (int u = 0; u < WCN; u++) t += rsred[tid][u];
            Cf[((size_t)z * 1024 + row0 + tid) * 8 + blockIdx.x] = t;
        }
    }
}

// ---------------------------------------------------------------------------
// fp32 -> fp16 conversion for q,k,v in one launch (grid.z picks tensor)
// ---------------------------------------------------------------------------
__global__ void conv_h3(const float* __restrict__ s0, __half* __restrict__ d0,
                        const float* __restrict__ s1, __half* __restrict__ d1,
                        const float* __restrict__ s2, __half* __restrict__ d2) {
    const float* s = (blockIdx.z == 0) ? s0 : (blockIdx.z == 1) ? s1 : s2;
    __half*      d = (blockIdx.z == 0) ? d0 : (blockIdx.z == 1) ? d1 : d2;
    size_t i = ((size_t)blockIdx.x * 256 + threadIdx.x) * 4;
    float4 v = *reinterpret_cast<const float4*>(s + i);
    *reinterpret_cast<uint2*>(d + i) = make_uint2(
        (uint32_t)h1(v.x) | ((uint32_t)h1(v.y) << 16),
        (uint32_t)h1(v.z) | ((uint32_t)h1(v.w) << 16));
}

// ---------------------------------------------------------------------------
// Merged per-head 512x512 transpose + split for Wq,Wk,Wv (z = 0..23)
// ---------------------------------------------------------------------------
__global__ void transpose_w3(const float* __restrict__ Wq,
                             __half* __restrict__ oq_h, __half* __restrict__ oq_l,
                             const float* __restrict__ Wk,
                             __half* __restrict__ ok_h, __half* __restrict__ ok_l,
                             const float* __restrict__ Wv,
                             __half* __restrict__ ov_h, __half* __restrict__ ov_l) {
    __shared__ float t[32][33];
    const int sel = blockIdx.z >> 3;
    const size_t z = blockIdx.z & 7;
    const float* in = (sel == 0) ? Wq : (sel == 1) ? Wk : Wv;
    __half* oh = (sel == 0) ? oq_h : (sel == 1) ? ok_h : ov_h;
    __half* ol = (sel == 0) ? oq_l : (sel == 1) ? ok_l : ov_l;
    in += z * (size_t)(Dn * Dn);
    oh += z * (size_t)(Dn * Dn);
    ol += z * (size_t)(Dn * Dn);
    const int x0 = blockIdx.x * 32;
    const int y0 = blockIdx.y * 32;
    #pragma unroll
    for (int i = 0; i < 4; i++)
        t[threadIdx.y + i * 8][threadIdx.x] =
            in[(size_t)(y0 + threadIdx.y + i * 8) * Dn + x0 + threadIdx.x];
    __syncthreads();
    #pragma unroll
    for (int i = 0; i < 4; i++) {
        float v = t[threadIdx.x][threadIdx.y + i * 8];
        uint16_t h, l;
        split2h(v, h, l);
        size_t o = (size_t)(x0 + threadIdx.y + i * 8) * Dn + y0 + threadIdx.x;
        reinterpret_cast<uint16_t*>(oh)[o] = h;
        reinterpret_cast<uint16_t*>(ol)[o] = l;
    }
}

// ---------------------------------------------------------------------------
// Wo permute + split: wo_p[o][h*512+d] = Wo[o][d*8+h]
// ---------------------------------------------------------------------------
__global__ void conv_wo_p(const float* __restrict__ Wo,
                          __half* __restrict__ oh,
                          __half* __restrict__ ol) {
    size_t idx = (size_t)blockIdx.x * 256 + threadIdx.x;
    int g = (int)(idx & 4095);
    size_t o = idx >> 12;
    int f = ((g & 511) << 3) | (g >> 9);
    float v = Wo[(o << 12) + f];
    uint16_t h, l;
    split2h(v, h, l);
    reinterpret_cast<uint16_t*>(oh)[idx] = h;
    reinterpret_cast<uint16_t*>(ol)[idx] = l;
}

// ---------------------------------------------------------------------------
// bfin[o] = bo[o] + sum_f Wo[o][f] * bv[f&7][f>>3]
// ---------------------------------------------------------------------------
__global__ void bfin_kernel(const float* __restrict__ Wo,
                            const float* __restrict__ bv,
                            const float* __restrict__ bo,
                            float* __restrict__ bfin) {
    __shared__ float red[8];
    const int o = blockIdx.x, tid = threadIdx.x;
    const float* wr = Wo + (size_t)o * 4096;
    float s = 0.f;
    for (int f = tid; f < 4096; f += 256)
        s += wr[f] * bv[(f & 7) * Dn + (f >> 3)];
    #pragma unroll
    for (int off = 16; off > 0; off >>= 1)
        s += __shfl_xor_sync(0xffffffffu, s, off);
    if ((tid & 31) == 0) red[tid >> 5] = s;
    __syncthreads();
    if (tid == 0) {
        float t = 0.f;
        #pragma unroll
        for (int i = 0; i < 8; i++) t += red[i];
        bfin[o] = bo[o] + t;
    }
}

// ---------------------------------------------------------------------------
// wvec[h][d] = sum_e bq[h][e] * Wk[h][e][d]
// ---------------------------------------------------------------------------
__global__ void wvec_kernel(const float* __restrict__ Wk,
                            const float* __restrict__ bq,
                            float* __restrict__ wvec) {
    const int h = blockIdx.x, d = threadIdx.x;
    const float* wk = Wk + (size_t)h * Dn * Dn;
    const float* b  = bq + (size_t)h * Dn;
    float s = 0.f;
    for (int e = 0; e < Dn; e++) s += b[e] * wk[(size_t)e * Dn + d];
    wvec[h * Dn + d] = s;
}

// ---------------------------------------------------------------------------
// colv[(h*16+b)][j] = inv_scale * k[b][j] . wvec[h]
// ---------------------------------------------------------------------------
__global__ void colv_kernel(const float* __restrict__ k,
                            const float* __restrict__ wvec,
                            float* __restrict__ colv, float inv_scale) {
    __shared__ float kr[Dn];
    const size_t bj = blockIdx.x;
    const int tid = threadIdx.x, w = tid >> 5, lane = tid & 31;
    const float* kp = k + bj * Dn;
    #pragma unroll
    for (int i = 0; i < 2; i++) kr[tid + i * 256] = kp[tid + i * 256];
    __syncthreads();
    const float* wv = wvec + w * Dn;
    float s = 0.f;
    #pragma unroll
    for (int t = 0; t < 16; t++) {
        int d = lane + t * 32;
        s += kr[d] * wv[d];
    }
    #pragma unroll
    for (int o = 16; o > 0; o >>= 1)
        s += __shfl_xor_sync(0xffffffffu, s, o);
    if (lane == 0) {
        size_t b = bj >> 10, j = bj & 1023;
        colv[((size_t)w * 16 + b) * 1024 + j] = s * inv_scale;
    }
}

// ---------------------------------------------------------------------------
// invr[r] = fp16( 1 / sum_{t=0..7} psum[r*8+t] )
// ---------------------------------------------------------------------------
__global__ void inv_rsum(const float* __restrict__ psum,
                         __half* __restrict__ invr) {
    size_t r = (size_t)blockIdx.x * 256 + threadIdx.x;
    const float4* p = reinterpret_cast<const float4*>(psum + r * 8);
    float4 a = p[0], b = p[1];
    float s = ((a.x + a.y) + (a.z + a.w)) + ((b.x + b.y) + (b.z + b.w));
    invr[r] = __float2half_rn(1.0f / s);
}

// ---------------------------------------------------------------------------
// kernel_launch — inputs: k, v, q, Wk, bk, Wv, bv, Wq, bq, Wo, bo
// Launch #4 = q~ GEMM (ncu profiling target, harness offset +2)
// ---------------------------------------------------------------------------
extern "C" void kernel_launch(void* const* d_in, const int* in_sizes, int n_in,
                              void* d_out, int out_size) {
    (void)in_sizes; (void)n_in; (void)out_size;
    const float* k  = (const float*)d_in[0];
    const float* v  = (const float*)d_in[1];
    const float* q  = (const float*)d_in[2];
    const float* Wk = (const float*)d_in[3];
    const float* Wv = (const float*)d_in[5];
    const float* bv = (const float*)d_in[6];
    const float* Wq = (const float*)d_in[7];
    const float* bq = (const float*)d_in[8];
    const float* Wo = (const float*)d_in[9];
    const float* bo = (const float*)d_in[10];
    float* out = (float*)d_out;

    constexpr int SM3  = Cfg<3, 1>::SMEM;
    constexpr int SM1B = Cfg<1, 2>::SMEM;
    cudaFuncSetAttribute(hmma_gemm<3, 1, false, 3, 0, false, false>,
        cudaFuncAttributeMaxDynamicSharedMemorySize, SM3);
    cudaFuncSetAttribute(hmma_gemm<1, 2, false, 3, 0, false, false>,
        cudaFuncAttributeMaxDynamicSharedMemorySize, SM1B);
    cudaFuncSetAttribute(hmma_gemm<1, 2, false, 5, 0, false, false>,
        cudaFuncAttributeMaxDynamicSharedMemorySize, SM1B);
    cudaFuncSetAttribute(hmma_gemm<1, 2, true, 6, 0, true, false>,
        cudaFuncAttributeMaxDynamicSharedMemorySize, SM1B);
    cudaFuncSetAttribute(hmma_gemm<1, 2, true, 0, 2, false, true>,
        cudaFuncAttributeMaxDynamicSharedMemorySize, SM1B);

    __half *xq,*xk,*xv;
    __half *wqt_h,*wqt_l,*wkt_h,*wkt_l,*wvt_h,*wvt_l,*mt,*wvo;
    __half *wop_h,*wop_l;
    __half *qp,*vt2,*Ps,*invr;
    float *wvec,*colv,*bfin,*psum;
    cudaGetSymbolAddress((void**)&xq,   g_xq);
    cudaGetSymbolAddress((void**)&xk,   g_xk);
    cudaGetSymbolAddress((void**)&xv,   g_xv);
    cudaGetSymbolAddress((void**)&wqt_h,g_wqt_hi);cudaGetSymbolAddress((void**)&wqt_l,g_wqt_lo);
    cudaGetSymbolAddress((void**)&wkt_h,g_wkt_hi);cudaGetSymbolAddress((void**)&wkt_l,g_wkt_lo);
    cudaGetSymbolAddress((void**)&wvt_h,g_wvt_hi);cudaGetSymbolAddress((void**)&wvt_l,g_wvt_lo);
    cudaGetSymbolAddress((void**)&mt,   g_mt);
    cudaGetSymbolAddress((void**)&wvo,  g_wvo);
    cudaGetSymbolAddress((void**)&wop_h,g_wop_hi);cudaGetSymbolAddress((void**)&wop_l,g_wop_lo);
    cudaGetSymbolAddress((void**)&qp,   g_qp);
    cudaGetSymbolAddress((void**)&vt2,  g_vt2);
    cudaGetSymbolAddress((void**)&Ps,   g_Ps);
    cudaGetSymbolAddress((void**)&invr, g_invr);
    cudaGetSymbolAddress((void**)&wvec, g_wvec);
    cudaGetSymbolAddress((void**)&colv, g_colv);
    cudaGetSymbolAddress((void**)&bfin, g_bfin);
    cudaGetSymbolAddress((void**)&psum, g_psum);

    const float inv_scale = 1.0f / sqrtf((float)Dn);
    const size_t WW = (size_t)Dn * Dn;

    // #1: q,k,v -> fp16
    conv_h3<<<dim3((unsigned)(XEL / 1024), 1, 3), 256>>>(q, xq, k, xk, v, xv);
    // #2: Wq,Wk,Wv transpose+split (merged)
    transpose_w3<<<dim3(16, 16, 24), dim3(32, 8)>>>(
        Wq, wqt_h, wqt_l, Wk, wkt_h, wkt_l, Wv, wvt_h, wvt_l);
    // #3: Mt[h] = Wk^T Wq (3-term in, single out)
    hmma_gemm<3, 1, false, 3, 0, false, false><<<dim3(4, 4, Hn), 256, SM3>>>(
        wkt_h, wkt_l, wqt_h, wqt_l, nullptr, nullptr, mt, nullptr,
        Dn, Dn, Dn, Dn, WW, WW, 0, WW, 1.0f);
    // #4: q~ = q @ Mt^T (1-term, 128 thr) — ncu profiling target
    dim3 gproj(Dn / 128, Mn / 128, Hn);
    hmma_gemm<1, 2, false, 3, 0, false, false><<<gproj, 128, SM1B>>>(
        xq, nullptr, mt, nullptr, nullptr, nullptr, qp, nullptr,
        Dn, Dn, Dn, Dn, 0, WW, 0, (size_t)Mn * Dn, 1.0f);

    // remaining prep
    conv_wo_p<<<(unsigned)(WEL / 256), 256>>>(Wo, wop_h, wop_l);
    bfin_kernel<<<Dn, 256>>>(Wo, bv, bo, bfin);
    hmma_gemm<3, 1, false, 3, 0, false, false><<<dim3(4, 4, Hn), 256, SM3>>>(
        wop_h, wop_l, wvt_h, wvt_l, nullptr, nullptr, wvo, nullptr,
        Dn, Dn, Hn * Dn, Dn, (size_t)Dn, WW, 0, WW, 1.0f);
    wvec_kernel<<<Hn, Dn>>>(Wk, bq, wvec);
    colv_kernel<<<Mn, 256>>>(k, wvec, colv, inv_scale);

    // v~ = v @ Wvo^T -> vt2[b][o][h*1024+j]
    hmma_gemm<1, 2, false, 5, 0, false, false><<<gproj, 128, SM1B>>>(
        xv, nullptr, wvo, nullptr, nullptr, nullptr, vt2, nullptr,
        Dn, Dn, Dn, Dn, 0, WW, 0, 0, 1.0f);

    // scores: E = exp(q~ @ k^T / scale + colv), partial rowsums -> psum
    dim3 gsc(Nn / 128, Nn / 128, Hn * Bn);
    hmma_gemm<1, 2, true, 6, 0, true, false><<<gsc, 128, SM1B>>>(
        qp, nullptr, xk, nullptr, colv, psum, Ps, nullptr,
        Nn, Dn, Dn, Dn, (size_t)Nn * Dn, (size_t)Nn * Dn,
        (size_t)Nn, (size_t)Nn * Nn, inv_scale);

    // invr = 1 / rowsum
    inv_rsum<<<(unsigned)(NROWS / 256), 256>>>(psum, invr);

    // out = sum_h (E_h * invr) @ v~_h + bfin  (1-term, K=8192, A-scaled)
    dim3 gfin(Dn / 128, Nn / 128, Bn);
    hmma_gemm<1, 2, true, 0, 2, false, true><<<gfin, 128, SM1B>>>(
        Ps, invr /*repurposed*/, vt2, nullptr, bfin, out, nullptr, nullptr,
        Dn, Hn * Nn, Nn, Hn * Nn,
        (size_t)Nn * Nn, (size_t)Dn * Hn * Nn, 0, (size_t)Nn * Dn, 1.0f);
}

// round 15
// speedup vs baseline: 7.0242x; 1.0380x over previous
#include <cuda_runtime.h>
#include <cuda_fp16.h>
#include <math.h>
#include <stdint.h>

// ---------------------------------------------------------------------------
// Problem constants
// ---------------------------------------------------------------------------
constexpr int Hn = 8, Bn = 16, Nn = 1024, Dn = 512;
constexpr int Mn = Bn * Nn;                               // 16384
constexpr size_t XEL  = (size_t)Mn * Dn;                  // 8,388,608
constexpr size_t WEL  = (size_t)Hn * Dn * Dn;             // 2,097,152
constexpr size_t PROJ = (size_t)Hn * Mn * Dn;             // 67,108,864
constexpr size_t PEL  = (size_t)Hn * Bn * Nn * Nn;        // 134,217,728
constexpr size_t HBLK2 = (size_t)Bn * Nn * Nn;            // 16M: h-block in P
constexpr size_t NROWS = (size_t)Hn * Bn * Nn;            // 131072 score rows

// ---------------------------------------------------------------------------
// Scratch (__device__ globals — allocation-free)
// ---------------------------------------------------------------------------
__device__ __half g_xq[XEL];                       // q single fp16
__device__ __half g_xk[XEL];                       // k single fp16
__device__ __half g_xv[XEL];                       // v single fp16
__device__ __half g_wqt_hi[WEL], g_wqt_lo[WEL];    // Wq^T per head
__device__ __half g_wkt_hi[WEL], g_wkt_lo[WEL];    // Wk^T per head
__device__ __half g_wvt_hi[WEL], g_wvt_lo[WEL];    // Wv^T per head
__device__ __half g_mt[WEL];                       // Mt = Wk^T Wq (single)
__device__ __half g_wvo[WEL];                      // Wvo = Wo_h @ Wv_h (single)
__device__ __half g_wop_hi[WEL], g_wop_lo[WEL];    // permuted Wo
__device__ __half g_qp[PROJ];                      // q~ single fp16
__device__ __half g_vt2[PROJ];                     // v~ [b][o][h*1024+j]
__device__ __half g_Ps[PEL];                       // e^scores (unnormalized)
__device__ float  g_psum[NROWS * 8];               // partial rowsums per col-tile
__device__ __half g_invr[NROWS];                   // 1/rowsum, fp16
__device__ float  g_wvec[Hn * Dn];                 // Wk^T bq per head
__device__ float  g_colv[NROWS];                   // scaled col terms
__device__ float  g_bfin[Dn];                      // bo + sum_h Wo_h bv_h

// ---------------------------------------------------------------------------
// Helpers
// ---------------------------------------------------------------------------
__device__ __forceinline__ uint32_t s2u(const void* p) {
    uint32_t a;
    asm("{ .reg .u64 t; cvta.to.shared.u64 t, %1; cvt.u32.u64 %0, t; }"
        : "=r"(a) : "l"(p));
    return a;
}

__device__ __forceinline__ void cp16(uint32_t saddr, const void* gaddr) {
    asm volatile("cp.async.cg.shared.global [%0], [%1], 16;"
                 :: "r"(saddr), "l"(gaddr) : "memory");
}
__device__ __forceinline__ void cp_commit() {
    asm volatile("cp.async.commit_group;" ::: "memory");
}
template <int N>
__device__ __forceinline__ void cp_wait() {
    asm volatile("cp.async.wait_group %0;" :: "n"(N) : "memory");
}

__device__ __forceinline__ void ldsm4(uint32_t* r, uint32_t addr) {
    asm volatile("ldmatrix.sync.aligned.m8n8.x4.shared.b16 {%0,%1,%2,%3}, [%4];"
        : "=r"(r[0]), "=r"(r[1]), "=r"(r[2]), "=r"(r[3]) : "r"(addr));
}

__device__ __forceinline__ void mma16816(float* d, const uint32_t* a,
                                         uint32_t b0, uint32_t b1) {
    asm volatile(
        "mma.sync.aligned.m16n8k16.row.col.f32.f16.f16.f32 "
        "{%0,%1,%2,%3}, {%4,%5,%6,%7}, {%8,%9}, {%0,%1,%2,%3};"
        : "+f"(d[0]), "+f"(d[1]), "+f"(d[2]), "+f"(d[3])
        : "r"(a[0]), "r"(a[1]), "r"(a[2]), "r"(a[3]), "r"(b0), "r"(b1));
}

__device__ __forceinline__ void split2h(float x, uint16_t& h, uint16_t& l) {
    __half hb = __float2half_rn(x);
    __half lb = __float2half_rn(x - __half2float(hb));
    h = *reinterpret_cast<uint16_t*>(&hb);
    l = *reinterpret_cast<uint16_t*>(&lb);
}
__device__ __forceinline__ uint16_t h1(float x) {
    __half hb = __float2half_rn(x);
    return *reinterpret_cast<uint16_t*>(&hb);
}

// XOR chunk swizzle for 64B rows (4 x 16B chunks): conflict-free ldmatrix.
__device__ __forceinline__ uint32_t swz(uint32_t r, uint32_t ch) {
    return r * 64u + ((ch ^ ((r >> 1) & 3u)) << 4);
}

// ---------------------------------------------------------------------------
// fp16-split batched GEMM via mma.sync (HMMA):
// TERMS=3:  C = alpha*(Ahi+Alo)@(Bhi+Blo)^T   (256 thr, warp 64x32)
// TERMS=1:  C = alpha* A @ B^T (both single)  (128 thr, warp 64x64)
// KT    : k-tiles (of 32) per pipeline chunk.
// OUTM  : 0=fp32, 1=fp16 hi/lo, 3=single fp16,
//         5=single fp16 to vt2 layout [b][col][z*1024 + (row&1023)]
//         6=exp() then single fp16 + per-CTA partial rowsums to Cf(psum)
// AHB   : 0=plain A cols; 2=A col g decomposed (g>>10)*HBLK2 + (g&1023)
// BMODB : B z-index = z & 15 (B shared across heads, z = h*16+b)
// ASCALE: scale A fragments by invr (Alo repurposed; TERMS==1, AHB==2)
// CTA tile 128x128, 3-stage cp.async pipeline, 1 sync/chunk.
// ---------------------------------------------------------------------------
constexpr int TILE_B = 128 * 64;                 // 8192 B per 32-k tile

template <int TERMS, int KT> struct Cfg {
    static constexpr int NOPS    = (TERMS == 3) ? 4 : (TERMS == 2) ? 3 : 2;
    static constexpr int STAGE   = NOPS * KT * TILE_B;
    static constexpr int SMEM    = 3 * STAGE + 512 + 2048;
    static constexpr int THREADS = (TERMS == 1) ? 128 : 256;
    static constexpr int WCN     = (TERMS == 1) ? 2 : 4;   // warp col groups
    static constexpr int NTN     = (TERMS == 1) ? 8 : 4;   // n8 tiles / warp
    static constexpr int CSPAN   = (TERMS == 1) ? 64 : 32; // cols / warp
};

template <int TERMS, int KT, bool BIAS, int OUTM, int AHB, bool BMODB,
          bool ASCALE>
__global__ void __launch_bounds__(Cfg<TERMS, KT>::THREADS, 2) hmma_gemm(
    const __half* __restrict__ Ahi, const __half* __restrict__ Alo,
    const __half* __restrict__ Bhi, const __half* __restrict__ Blo,
    const float* __restrict__ biasg,
    float* __restrict__ Cf,
    __half* __restrict__ Chi, __half* __restrict__ Clo,
    int N, int K, int lda, int ldb,
    size_t sA, size_t sB, size_t sBias, size_t sC, float alpha)
{
    constexpr int STAGE   = Cfg<TERMS, KT>::STAGE;
    constexpr int NOPS    = Cfg<TERMS, KT>::NOPS;
    constexpr int NA      = (TERMS == 3) ? 2 : 1;
    constexpr int THREADS = Cfg<TERMS, KT>::THREADS;
    constexpr int WCN     = Cfg<TERMS, KT>::WCN;
    constexpr int NTN     = Cfg<TERMS, KT>::NTN;
    constexpr int CSPAN   = Cfg<TERMS, KT>::CSPAN;
    extern __shared__ __align__(16) char smem[];
    const uint32_t sb = s2u(smem);
    float* sbias = reinterpret_cast<float*>(smem + 3 * STAGE);
    float (*rsred)[WCN] = reinterpret_cast<float(*)[WCN]>(smem + 3 * STAGE + 512);

    const int tid  = threadIdx.x;
    const int wid  = tid >> 5, lane = tid & 31;
    const int wr   = (TERMS == 1) ? (wid >> 1) : (wid >> 2);
    const int wc   = wid & (WCN - 1);
    const int qr   = lane >> 2, qc = lane & 3;
    const int col0 = blockIdx.x * 128, row0 = blockIdx.y * 128;
    const size_t z = blockIdx.z;
    const size_t zb = BMODB ? (z & 15) : z;
    const __half* invr = ASCALE ? Alo : nullptr;   // repurposed slot
    Ahi += z * sA; if (TERMS == 3) Alo += z * sA;
    Bhi += zb * sB; if (TERMS >= 2) Blo += zb * sB;

    if (BIAS && tid < 128) sbias[tid] = biasg[z * sBias + col0 + tid];

    const int nCh = K / (32 * KT);

    auto prefetch = [&](int c) {
        const int k0 = c * 32 * KT;
        const uint32_t boff = sb + (uint32_t)(c % 3) * STAGE;
        #pragma unroll
        for (int t = 0; t < NOPS; t++) {
            const __half* s;
            if (TERMS == 3) s = (t == 0) ? Ahi : (t == 1) ? Alo
                              : (t == 2) ? Bhi : Blo;
            else            s = (t == 0) ? Ahi : Bhi;
            #pragma unroll
            for (int kt = 0; kt < KT; kt++) {
                const int kk = k0 + kt * 32;
                const uint32_t tb = boff + (t * KT + kt) * TILE_B;
                size_t aoff;
                if (AHB == 2) aoff = ((size_t)(kk >> 10)) * HBLK2
                                   + (size_t)(kk & 1023);
                else          aoff = (size_t)kk;
                #pragma unroll
                for (int i = 0; i < 512 / THREADS; i++) {
                    uint32_t idx = (uint32_t)(i * THREADS + tid);   // 0..511
                    uint32_t r = idx >> 2, ch = idx & 3;
                    const __half* g;
                    if (t < NA) g = s + aoff + (size_t)(row0 + r) * lda + ch * 8;
                    else        g = s + (size_t)kk + (size_t)(col0 + r) * ldb + ch * 8;
                    cp16(tb + swz(r, ch), g);
                }
            }
        }
        cp_commit();
    };

    float acc[4][NTN][4] = {};
    uint32_t sc[4][2];           // ASCALE: per-row half2 scales

    prefetch(0);
    prefetch(1);

    for (int c = 0; c < nCh; ++c) {
        if (c + 1 < nCh) cp_wait<1>(); else cp_wait<0>();
        __syncthreads();
        if (c + 2 < nCh) prefetch(c + 2);

        if (ASCALE && (c & 15) == 0) {
            const int h = (c * 32 * KT) >> 10;
            const __half* iv = invr + ((size_t)h * Bn + z) * 1024 + row0;
            #pragma unroll
            for (int mt = 0; mt < 4; mt++) {
                #pragma unroll
                for (int rr = 0; rr < 2; rr++) {
                    __half x = iv[wr * 64 + mt * 16 + rr * 8 + qr];
                    __half2 x2 = __half2half2(x);
                    sc[mt][rr] = *reinterpret_cast<uint32_t*>(&x2);
                }
            }
        }

        const uint32_t boff = sb + (uint32_t)(c % 3) * STAGE;
        const uint32_t lrow = (uint32_t)(lane & 15), lhalf = (uint32_t)(lane >> 4);

        #pragma unroll
        for (int ks = 0; ks < 2 * KT; ks++) {
            const uint32_t sub = (uint32_t)(ks >> 1) * TILE_B;
            const uint32_t kch = (uint32_t)(ks & 1) * 2u + lhalf;
            const uint32_t aHiB = boff + sub;
            const uint32_t aLoB = boff + KT * TILE_B + sub;          // T3 only
            const uint32_t bHiB = boff + ((TERMS == 3) ? 2 : 1) * KT * TILE_B + sub;
            const uint32_t bLoB = boff + ((TERMS == 3) ? 3 : 2) * KT * TILE_B + sub;

            uint32_t bh[NTN][2], bl[4][2];
            #pragma unroll
            for (int np = 0; np < NTN / 2; np++) {
                uint32_t r = (uint32_t)(wc * CSPAN + np * 16) + lrow;
                uint32_t t[4];
                ldsm4(t, bHiB + swz(r, kch));
                bh[np*2+0][0] = t[0]; bh[np*2+0][1] = t[2];
                bh[np*2+1][0] = t[1]; bh[np*2+1][1] = t[3];
                if (TERMS >= 2) {
                    ldsm4(t, bLoB + swz(r, kch));
                    bl[np*2+0][0] = t[0]; bl[np*2+0][1] = t[2];
                    bl[np*2+1][0] = t[1]; bl[np*2+1][1] = t[3];
                }
            }
            #pragma unroll
            for (int mt = 0; mt < 4; mt++) {
                uint32_t r = (uint32_t)(wr * 64 + mt * 16) + lrow;
                uint32_t ah[4], al[4];
                ldsm4(ah, aHiB + swz(r, kch));
                if (ASCALE) {
                    __half2* av = reinterpret_cast<__half2*>(ah);
                    __half2 s0 = *reinterpret_cast<__half2*>(&sc[mt][0]);
                    __half2 s1 = *reinterpret_cast<__half2*>(&sc[mt][1]);
                    av[0] = __hmul2(av[0], s0);
                    av[2] = __hmul2(av[2], s0);
                    av[1] = __hmul2(av[1], s1);
                    av[3] = __hmul2(av[3], s1);
                }
                if (TERMS == 3) ldsm4(al, aLoB + swz(r, kch));
                #pragma unroll
                for (int nt = 0; nt < NTN; nt++) {
                    mma16816(acc[mt][nt], ah, bh[nt][0], bh[nt][1]);
                    if (TERMS >= 2)
                        mma16816(acc[mt][nt], ah, bl[nt][0], bl[nt][1]);
                    if (TERMS == 3)
                        mma16816(acc[mt][nt], al, bh[nt][0], bh[nt][1]);
                }
            }
        }
    }

    // ---- epilogue ----
    float rs[4][2] = {};          // OUTM==6 partial rowsums
    #pragma unroll
    for (int mt = 0; mt < 4; mt++) {
        #pragma unroll
        for (int nt = 0; nt < NTN; nt++) {
            const int lcol = wc * CSPAN + nt * 8 + qc * 2;
            const float b0 = BIAS ? sbias[lcol]     : 0.f;
            const float b1 = BIAS ? sbias[lcol + 1] : 0.f;
            const int r0 = row0 + wr * 64 + mt * 16 + qr;
            const float v00 = alpha * acc[mt][nt][0] + b0;
            const float v01 = alpha * acc[mt][nt][1] + b1;
            const float v10 = alpha * acc[mt][nt][2] + b0;
            const float v11 = alpha * acc[mt][nt][3] + b1;
            if (OUTM == 0) {
                float* cp = Cf + z * sC + (size_t)r0 * N + col0 + lcol;
                *reinterpret_cast<float2*>(cp)            = make_float2(v00, v01);
                *reinterpret_cast<float2*>(cp + 8ull * N) = make_float2(v10, v11);
            } else if (OUTM == 1) {
                uint16_t h0,l0,h1b,l1,h2,l2,h3,l3;
                split2h(v00, h0, l0); split2h(v01, h1b, l1);
                split2h(v10, h2, l2); split2h(v11, h3, l3);
                size_t o0 = z * sC + (size_t)r0 * N + col0 + lcol;
                size_t o1 = o0 + 8ull * N;
                *reinterpret_cast<uint32_t*>(
                    reinterpret_cast<uint16_t*>(Chi) + o0) = (uint32_t)h0 | ((uint32_t)h1b << 16);
                *reinterpret_cast<uint32_t*>(
                    reinterpret_cast<uint16_t*>(Clo) + o0) = (uint32_t)l0 | ((uint32_t)l1 << 16);
                *reinterpret_cast<uint32_t*>(
                    reinterpret_cast<uint16_t*>(Chi) + o1) = (uint32_t)h2 | ((uint32_t)h3 << 16);
                *reinterpret_cast<uint32_t*>(
                    reinterpret_cast<uint16_t*>(Clo) + o1) = (uint32_t)l2 | ((uint32_t)l3 << 16);
            } else if (OUTM == 3 || OUTM == 6) {
                float e00 = v00, e01 = v01, e10 = v10, e11 = v11;
                if (OUTM == 6) {
                    e00 = __expf(v00); e01 = __expf(v01);
                    e10 = __expf(v10); e11 = __expf(v11);
                    rs[mt][0] += e00 + e01;
                    rs[mt][1] += e10 + e11;
                }
                size_t o0 = z * sC + (size_t)r0 * N + col0 + lcol;
                size_t o1 = o0 + 8ull * N;
                *reinterpret_cast<uint32_t*>(
                    reinterpret_cast<uint16_t*>(Chi) + o0) =
                    (uint32_t)h1(e00) | ((uint32_t)h1(e01) << 16);
                *reinterpret_cast<uint32_t*>(
                    reinterpret_cast<uint16_t*>(Chi) + o1) =
                    (uint32_t)h1(e10) | ((uint32_t)h1(e11) << 16);
            } else {
                // OUTM == 5: vt2[b][col][z*1024 + j],  b = r0>>10, j = r0&1023
                uint16_t* oh = reinterpret_cast<uint16_t*>(Chi);
                const size_t bb = (size_t)(r0 >> 10);
                const int j0 = r0 & 1023;
                const size_t c0a = (bb * 512 + (size_t)(col0 + lcol)) * 8192
                                 + (size_t)z * 1024;
                const size_t c1a = c0a + 8192;       // col+1
                oh[c0a + j0]     = h1(v00);
                oh[c1a + j0]     = h1(v01);
                oh[c0a + j0 + 8] = h1(v10);
                oh[c1a + j0 + 8] = h1(v11);
            }
        }
    }

    if (OUTM == 6) {
        // reduce rowsums: over qc (shfl), then over wc (smem), write psum
        #pragma unroll
        for (int mt = 0; mt < 4; mt++) {
            #pragma unroll
            for (int rr = 0; rr < 2; rr++) {
                float v = rs[mt][rr];
                v += __shfl_xor_sync(0xffffffffu, v, 1);
                v += __shfl_xor_sync(0xffffffffu, v, 2);
                if (qc == 0)
                    rsred[wr * 64 + mt * 16 + rr * 8 + qr][wc] = v;
            }
        }
        __syncthreads();
        if (tid < 128) {
            float t = 0.f;
            #pragma unroll
            for (int u = 0; u < WCN; u++) t += rsred[tid][u];
            Cf[((size_t)z * 1024 + row0 + tid) * 8 + blockIdx.x] = t;
        }
    }
}

// ---------------------------------------------------------------------------
// fp32 -> fp16 conversion for q,k,v in one launch (grid.z picks tensor)
// ---------------------------------------------------------------------------
__global__ void conv_h3(const float* __restrict__ s0, __half* __restrict__ d0,
                        const float* __restrict__ s1, __half* __restrict__ d1,
                        const float* __restrict__ s2, __half* __restrict__ d2) {
    const float* s = (blockIdx.z == 0) ? s0 : (blockIdx.z == 1) ? s1 : s2;
    __half*      d = (blockIdx.z == 0) ? d0 : (blockIdx.z == 1) ? d1 : d2;
    size_t i = ((size_t)blockIdx.x * 256 + threadIdx.x) * 4;
    float4 v = *reinterpret_cast<const float4*>(s + i);
    *reinterpret_cast<uint2*>(d + i) = make_uint2(
        (uint32_t)h1(v.x) | ((uint32_t)h1(v.y) << 16),
        (uint32_t)h1(v.z) | ((uint32_t)h1(v.w) << 16));
}

// ---------------------------------------------------------------------------
// Merged per-head 512x512 transpose + split for Wq,Wk,Wv (z = 0..23)
// ---------------------------------------------------------------------------
__global__ void transpose_w3(const float* __restrict__ Wq,
                             __half* __restrict__ oq_h, __half* __restrict__ oq_l,
                             const float* __restrict__ Wk,
                             __half* __restrict__ ok_h, __half* __restrict__ ok_l,
                             const float* __restrict__ Wv,
                             __half* __restrict__ ov_h, __half* __restrict__ ov_l) {
    __shared__ float t[32][33];
    const int sel = blockIdx.z >> 3;
    const size_t z = blockIdx.z & 7;
    const float* in = (sel == 0) ? Wq : (sel == 1) ? Wk : Wv;
    __half* oh = (sel == 0) ? oq_h : (sel == 1) ? ok_h : ov_h;
    __half* ol = (sel == 0) ? oq_l : (sel == 1) ? ok_l : ov_l;
    in += z * (size_t)(Dn * Dn);
    oh += z * (size_t)(Dn * Dn);
    ol += z * (size_t)(Dn * Dn);
    const int x0 = blockIdx.x * 32;
    const int y0 = blockIdx.y * 32;
    #pragma unroll
    for (int i = 0; i < 4; i++)
        t[threadIdx.y + i * 8][threadIdx.x] =
            in[(size_t)(y0 + threadIdx.y + i * 8) * Dn + x0 + threadIdx.x];
    __syncthreads();
    #pragma unroll
    for (int i = 0; i < 4; i++) {
        float v = t[threadIdx.x][threadIdx.y + i * 8];
        uint16_t h, l;
        split2h(v, h, l);
        size_t o = (size_t)(x0 + threadIdx.y + i * 8) * Dn + y0 + threadIdx.x;
        reinterpret_cast<uint16_t*>(oh)[o] = h;
        reinterpret_cast<uint16_t*>(ol)[o] = l;
    }
}

// ---------------------------------------------------------------------------
// Wo permute + split: wo_p[o][h*512+d] = Wo[o][d*8+h]
// ---------------------------------------------------------------------------
__global__ void conv_wo_p(const float* __restrict__ Wo,
                          __half* __restrict__ oh,
                          __half* __restrict__ ol) {
    size_t idx = (size_t)blockIdx.x * 256 + threadIdx.x;
    int g = (int)(idx & 4095);
    size_t o = idx >> 12;
    int f = ((g & 511) << 3) | (g >> 9);
    float v = Wo[(o << 12) + f];
    uint16_t h, l;
    split2h(v, h, l);
    reinterpret_cast<uint16_t*>(oh)[idx] = h;
    reinterpret_cast<uint16_t*>(ol)[idx] = l;
}

// ---------------------------------------------------------------------------
// bfin[o] = bo[o] + sum_f Wo[o][f] * bv[f&7][f>>3]
// ---------------------------------------------------------------------------
__global__ void bfin_kernel(const float* __restrict__ Wo,
                            const float* __restrict__ bv,
                            const float* __restrict__ bo,
                            float* __restrict__ bfin) {
    __shared__ float red[8];
    const int o = blockIdx.x, tid = threadIdx.x;
    const float* wr = Wo + (size_t)o * 4096;
    float s = 0.f;
    for (int f = tid; f < 4096; f += 256)
        s += wr[f] * bv[(f & 7) * Dn + (f >> 3)];
    #pragma unroll
    for (int off = 16; off > 0; off >>= 1)
        s += __shfl_xor_sync(0xffffffffu, s, off);
    if ((tid & 31) == 0) red[tid >> 5] = s;
    __syncthreads();
    if (tid == 0) {
        float t = 0.f;
        #pragma unroll
        for (int i = 0; i < 8; i++) t += red[i];
        bfin[o] = bo[o] + t;
    }
}

// ---------------------------------------------------------------------------
// wvec[h][d] = sum_e bq[h][e] * Wk[h][e][d]
// ---------------------------------------------------------------------------
__global__ void wvec_kernel(const float* __restrict__ Wk,
                            const float* __restrict__ bq,
                            float* __restrict__ wvec) {
    const int h = blockIdx.x, d = threadIdx.x;
    const float* wk = Wk + (size_t)h * Dn * Dn;
    const float* b  = bq + (size_t)h * Dn;
    float s = 0.f;
    for (int e = 0; e < Dn; e++) s += b[e] * wk[(size_t)e * Dn + d];
    wvec[h * Dn + d] = s;
}

// ---------------------------------------------------------------------------
// colv[(h*16+b)][j] = inv_scale * k[b][j] . wvec[h]
// ---------------------------------------------------------------------------
__global__ void colv_kernel(const float* __restrict__ k,
                            const float* __restrict__ wvec,
                            float* __restrict__ colv, float inv_scale) {
    __shared__ float kr[Dn];
    const size_t bj = blockIdx.x;
    const int tid = threadIdx.x, w = tid >> 5, lane = tid & 31;
    const float* kp = k + bj * Dn;
    #pragma unroll
    for (int i = 0; i < 2; i++) kr[tid + i * 256] = kp[tid + i * 256];
    __syncthreads();
    const float* wv = wvec + w * Dn;
    float s = 0.f;
    #pragma unroll
    for (int t = 0; t < 16; t++) {
        int d = lane + t * 32;
        s += kr[d] * wv[d];
    }
    #pragma unroll
    for (int o = 16; o > 0; o >>= 1)
        s += __shfl_xor_sync(0xffffffffu, s, o);
    if (lane == 0) {
        size_t b = bj >> 10, j = bj & 1023;
        colv[((size_t)w * 16 + b) * 1024 + j] = s * inv_scale;
    }
}

// ---------------------------------------------------------------------------
// invr[r] = fp16( 1 / sum_{t=0..7} psum[r*8+t] )
// ---------------------------------------------------------------------------
__global__ void inv_rsum(const float* __restrict__ psum,
                         __half* __restrict__ invr) {
    size_t r = (size_t)blockIdx.x * 256 + threadIdx.x;
    const float4* p = reinterpret_cast<const float4*>(psum + r * 8);
    float4 a = p[0], b = p[1];
    float s = ((a.x + a.y) + (a.z + a.w)) + ((b.x + b.y) + (b.z + b.w));
    invr[r] = __float2half_rn(1.0f / s);
}

// ---------------------------------------------------------------------------
// kernel_launch — inputs: k, v, q, Wk, bk, Wv, bv, Wq, bq, Wo, bo
// Multi-stream fork/join (graph-capture-legal). Streams/events are static,
// created on the first (uncaptured) correctness call.
// ---------------------------------------------------------------------------
extern "C" void kernel_launch(void* const* d_in, const int* in_sizes, int n_in,
                              void* d_out, int out_size) {
    (void)in_sizes; (void)n_in; (void)out_size;
    const float* k  = (const float*)d_in[0];
    const float* v  = (const float*)d_in[1];
    const float* q  = (const float*)d_in[2];
    const float* Wk = (const float*)d_in[3];
    const float* Wv = (const float*)d_in[5];
    const float* bv = (const float*)d_in[6];
    const float* Wq = (const float*)d_in[7];
    const float* bq = (const float*)d_in[8];
    const float* Wo = (const float*)d_in[9];
    const float* bo = (const float*)d_in[10];
    float* out = (float*)d_out;

    constexpr int SM3  = Cfg<3, 1>::SMEM;
    constexpr int SM1B = Cfg<1, 2>::SMEM;

    static cudaStream_t s1 = nullptr, s2 = nullptr;
    static cudaEvent_t eRoot, eT, eMt, eWvo, eC, eV, e2end;
    if (s1 == nullptr) {
        cudaStreamCreateWithFlags(&s1, cudaStreamNonBlocking);
        cudaStreamCreateWithFlags(&s2, cudaStreamNonBlocking);
        cudaEventCreateWithFlags(&eRoot, cudaEventDisableTiming);
        cudaEventCreateWithFlags(&eT,    cudaEventDisableTiming);
        cudaEventCreateWithFlags(&eMt,   cudaEventDisableTiming);
        cudaEventCreateWithFlags(&eWvo,  cudaEventDisableTiming);
        cudaEventCreateWithFlags(&eC,    cudaEventDisableTiming);
        cudaEventCreateWithFlags(&eV,    cudaEventDisableTiming);
        cudaEventCreateWithFlags(&e2end, cudaEventDisableTiming);
        cudaFuncSetAttribute(hmma_gemm<3, 1, false, 3, 0, false, false>,
            cudaFuncAttributeMaxDynamicSharedMemorySize, SM3);
        cudaFuncSetAttribute(hmma_gemm<1, 2, false, 3, 0, false, false>,
            cudaFuncAttributeMaxDynamicSharedMemorySize, SM1B);
        cudaFuncSetAttribute(hmma_gemm<1, 2, false, 5, 0, false, false>,
            cudaFuncAttributeMaxDynamicSharedMemorySize, SM1B);
        cudaFuncSetAttribute(hmma_gemm<1, 2, true, 6, 0, true, false>,
            cudaFuncAttributeMaxDynamicSharedMemorySize, SM1B);
        cudaFuncSetAttribute(hmma_gemm<1, 2, true, 0, 2, false, true>,
            cudaFuncAttributeMaxDynamicSharedMemorySize, SM1B);
    }

    __half *xq,*xk,*xv;
    __half *wqt_h,*wqt_l,*wkt_h,*wkt_l,*wvt_h,*wvt_l,*mt,*wvo;
    __half *wop_h,*wop_l;
    __half *qp,*vt2,*Ps,*invr;
    float *wvec,*colv,*bfin,*psum;
    cudaGetSymbolAddress((void**)&xq,   g_xq);
    cudaGetSymbolAddress((void**)&xk,   g_xk);
    cudaGetSymbolAddress((void**)&xv,   g_xv);
    cudaGetSymbolAddress((void**)&wqt_h,g_wqt_hi);cudaGetSymbolAddress((void**)&wqt_l,g_wqt_lo);
    cudaGetSymbolAddress((void**)&wkt_h,g_wkt_hi);cudaGetSymbolAddress((void**)&wkt_l,g_wkt_lo);
    cudaGetSymbolAddress((void**)&wvt_h,g_wvt_hi);cudaGetSymbolAddress((void**)&wvt_l,g_wvt_lo);
    cudaGetSymbolAddress((void**)&mt,   g_mt);
    cudaGetSymbolAddress((void**)&wvo,  g_wvo);
    cudaGetSymbolAddress((void**)&wop_h,g_wop_hi);cudaGetSymbolAddress((void**)&wop_l,g_wop_lo);
    cudaGetSymbolAddress((void**)&qp,   g_qp);
    cudaGetSymbolAddress((void**)&vt2,  g_vt2);
    cudaGetSymbolAddress((void**)&Ps,   g_Ps);
    cudaGetSymbolAddress((void**)&invr, g_invr);
    cudaGetSymbolAddress((void**)&wvec, g_wvec);
    cudaGetSymbolAddress((void**)&colv, g_colv);
    cudaGetSymbolAddress((void**)&bfin, g_bfin);
    cudaGetSymbolAddress((void**)&psum, g_psum);

    const float inv_scale = 1.0f / sqrtf((float)Dn);
    const size_t WW = (size_t)Dn * Dn;
    cudaStream_t s0 = 0;

    // ---- fork ----
    cudaEventRecord(eRoot, s0);
    cudaStreamWaitEvent(s1, eRoot, 0);
    cudaStreamWaitEvent(s2, eRoot, 0);

    // s0: q,k,v -> fp16
    conv_h3<<<dim3((unsigned)(XEL / 1024), 1, 3), 256, 0, s0>>>(
        q, xq, k, xk, v, xv);
    cudaEventRecord(eC, s0);

    // s1: weight transposes -> Mt
    transpose_w3<<<dim3(16, 16, 24), dim3(32, 8), 0, s1>>>(
        Wq, wqt_h, wqt_l, Wk, wkt_h, wkt_l, Wv, wvt_h, wvt_l);
    cudaEventRecord(eT, s1);
    hmma_gemm<3, 1, false, 3, 0, false, false><<<dim3(4, 4, Hn), 256, SM3, s1>>>(
        wkt_h, wkt_l, wqt_h, wqt_l, nullptr, nullptr, mt, nullptr,
        Dn, Dn, Dn, Dn, WW, WW, 0, WW, 1.0f);
    cudaEventRecord(eMt, s1);

    // s2: wvec, bfin, wo permute -> Wvo -> colv
    wvec_kernel<<<Hn, Dn, 0, s2>>>(Wk, bq, wvec);
    bfin_kernel<<<Dn, 256, 0, s2>>>(Wo, bv, bo, bfin);
    conv_wo_p<<<(unsigned)(WEL / 256), 256, 0, s2>>>(Wo, wop_h, wop_l);
    cudaStreamWaitEvent(s2, eT, 0);
    hmma_gemm<3, 1, false, 3, 0, false, false><<<dim3(4, 4, Hn), 256, SM3, s2>>>(
        wop_h, wop_l, wvt_h, wvt_l, nullptr, nullptr, wvo, nullptr,
        Dn, Dn, Hn * Dn, Dn, (size_t)Dn, WW, 0, WW, 1.0f);
    cudaEventRecord(eWvo, s2);
    colv_kernel<<<Mn, 256, 0, s2>>>(k, wvec, colv, inv_scale);
    cudaEventRecord(e2end, s2);

    // s0: q~ = q @ Mt^T  (waits Mt)
    dim3 gproj(Dn / 128, Mn / 128, Hn);
    cudaStreamWaitEvent(s0, eMt, 0);
    hmma_gemm<1, 2, false, 3, 0, false, false><<<gproj, 128, SM1B, s0>>>(
        xq, nullptr, mt, nullptr, nullptr, nullptr, qp, nullptr,
        Dn, Dn, Dn, Dn, 0, WW, 0, (size_t)Mn * Dn, 1.0f);

    // s1: v~ = v @ Wvo^T  (waits Wvo + conv_h3)
    cudaStreamWaitEvent(s1, eWvo, 0);
    cudaStreamWaitEvent(s1, eC, 0);
    hmma_gemm<1, 2, false, 5, 0, false, false><<<gproj, 128, SM1B, s1>>>(
        xv, nullptr, wvo, nullptr, nullptr, nullptr, vt2, nullptr,
        Dn, Dn, Dn, Dn, 0, WW, 0, 0, 1.0f);
    cudaEventRecord(eV, s1);

    // s0: scores (waits s2 join for colv)
    cudaStreamWaitEvent(s0, e2end, 0);
    dim3 gsc(Nn / 128, Nn / 128, Hn * Bn);
    hmma_gemm<1, 2, true, 6, 0, true, false><<<gsc, 128, SM1B, s0>>>(
        qp, nullptr, xk, nullptr, colv, psum, Ps, nullptr,
        Nn, Dn, Dn, Dn, (size_t)Nn * Dn, (size_t)Nn * Dn,
        (size_t)Nn, (size_t)Nn * Nn, inv_scale);

    // s0: invr = 1 / rowsum
    inv_rsum<<<(unsigned)(NROWS / 256), 256, 0, s0>>>(psum, invr);

    // s0: final (waits v~)
    cudaStreamWaitEvent(s0, eV, 0);
    dim3 gfin(Dn / 128, Nn / 128, Bn);
    hmma_gemm<1, 2, true, 0, 2, false, true><<<gfin, 128, SM1B, s0>>>(
        Ps, invr /*repurposed*/, vt2, nullptr, bfin, out, nullptr, nullptr,
        Dn, Hn * Nn, Nn, Hn * Nn,
        (size_t)Nn * Nn, (size_t)Dn * Hn * Nn, 0, (size_t)Nn * Dn, 1.0f);
}